// round 1
// baseline (speedup 1.0000x reference)
#include <cuda_runtime.h>
#include <math.h>

// ---------------------------------------------------------------------------
// EncoderBlock: B=4, L=1024, D=1024, F=4096, H=16, dh=64
// Round 0: correct fp32 baseline. Tiled SGEMMs + fused epilogues.
// ---------------------------------------------------------------------------

#define LSEQ 1024
#define DMODEL 1024
#define BATCH 4
#define NHEAD 16
#define DHEAD 64
#define FFDIM 4096
#define BHDIM 64          /* BATCH*NHEAD */
#define MROWS 4096        /* BATCH*LSEQ  */

// ---- scratch (device globals; no allocation allowed) ----------------------
__device__ float g_q[BATCH * LSEQ * DMODEL];
__device__ float g_k[BATCH * LSEQ * DMODEL];
__device__ float g_v[BATCH * LSEQ * DMODEL];
__device__ float g_s[(size_t)BHDIM * LSEQ * LSEQ];   // 256 MB scores / probs
__device__ float g_av[BATCH * LSEQ * DMODEL];
__device__ float g_attp[BATCH * LSEQ * DMODEL];
__device__ float g_attout[BATCH * LSEQ * DMODEL];
__device__ float g_h1[(size_t)MROWS * FFDIM];        // 64 MB
__device__ float g_ff[BATCH * LSEQ * DMODEL];

// ---------------------------------------------------------------------------
// Generic NT GEMM: C[M,N] = A[M,K] @ W[N,K]^T + bias[N]   (optional ReLU)
// BM=BN=128, BK=16, 256 threads, 8x8 per-thread tile.
// Requires M%128==0, N%128==0, K%16==0 (true for all call sites).
// ---------------------------------------------------------------------------
template <bool RELU>
__global__ void __launch_bounds__(256) gemm_nt_kernel(
    const float* __restrict__ A, const float* __restrict__ W,
    const float* __restrict__ bias, float* __restrict__ C,
    int M, int N, int K)
{
    constexpr int BM = 128, BN = 128, BK = 16;
    __shared__ float As[BK][BM + 4];
    __shared__ float Ws[BK][BN + 4];

    const int t  = threadIdx.x;
    const int ty = t >> 4;   // 0..15
    const int tx = t & 15;   // 0..15
    const int rowBase = blockIdx.y * BM;
    const int colBase = blockIdx.x * BN;

    const float* Ab = A + (size_t)rowBase * K;
    const float* Wb = W + (size_t)colBase * K;

    float acc[8][8];
#pragma unroll
    for (int i = 0; i < 8; i++)
#pragma unroll
        for (int j = 0; j < 8; j++) acc[i][j] = 0.f;

    for (int k0 = 0; k0 < K; k0 += BK) {
#pragma unroll
        for (int i = 0; i < 2; i++) {
            int idx = i * 256 + t;          // 0..511 (512 float4 per tile)
            int r   = idx >> 2;             // row 0..127
            int kk  = (idx & 3) << 2;       // 0,4,8,12
            float4 va = *(const float4*)(Ab + (size_t)r * K + k0 + kk);
            As[kk + 0][r] = va.x; As[kk + 1][r] = va.y;
            As[kk + 2][r] = va.z; As[kk + 3][r] = va.w;
            float4 vw = *(const float4*)(Wb + (size_t)r * K + k0 + kk);
            Ws[kk + 0][r] = vw.x; Ws[kk + 1][r] = vw.y;
            Ws[kk + 2][r] = vw.z; Ws[kk + 3][r] = vw.w;
        }
        __syncthreads();
#pragma unroll
        for (int kk = 0; kk < BK; kk++) {
            float a[8], b[8];
            *(float4*)(a)     = *(const float4*)&As[kk][ty * 8];
            *(float4*)(a + 4) = *(const float4*)&As[kk][ty * 8 + 4];
            *(float4*)(b)     = *(const float4*)&Ws[kk][tx * 8];
            *(float4*)(b + 4) = *(const float4*)&Ws[kk][tx * 8 + 4];
#pragma unroll
            for (int i = 0; i < 8; i++)
#pragma unroll
                for (int j = 0; j < 8; j++)
                    acc[i][j] = fmaf(a[i], b[j], acc[i][j]);
        }
        __syncthreads();
    }

#pragma unroll
    for (int i = 0; i < 8; i++) {
        int r = rowBase + ty * 8 + i;
        float* Crow = C + (size_t)r * N + colBase + tx * 8;
#pragma unroll
        for (int j = 0; j < 8; j += 4) {
            float4 o;
            o.x = acc[i][j + 0] + bias[colBase + tx * 8 + j + 0];
            o.y = acc[i][j + 1] + bias[colBase + tx * 8 + j + 1];
            o.z = acc[i][j + 2] + bias[colBase + tx * 8 + j + 2];
            o.w = acc[i][j + 3] + bias[colBase + tx * 8 + j + 3];
            if (RELU) {
                o.x = fmaxf(o.x, 0.f); o.y = fmaxf(o.y, 0.f);
                o.z = fmaxf(o.z, 0.f); o.w = fmaxf(o.w, 0.f);
            }
            *(float4*)(Crow + j) = o;
        }
    }
}

// ---------------------------------------------------------------------------
// T5 relative-position bucket (bidirectional, NUM_BUCKETS=32, MAX_DIST=128).
// Exact integer replication of numpy:
//   n = k - q; ret = (n<0)*16; n=|n|;
//   bucket = n (n<8)  else 8 + min(7, floor(2*log2(n)) - 6)
// floor(2*log2 n) == ilog2(n*n) exactly for integer n.
// ---------------------------------------------------------------------------
__device__ __forceinline__ int rel_bucket(int qrow, int kcol)
{
    int d   = kcol - qrow;
    int ret = (d < 0) ? (NHEAD) : 0;        // NUM_BUCKETS/2 = 16
    int n   = abs(d);
    int b;
    if (n < 8) {
        b = n;
    } else {
        int j = (31 - __clz(n * n)) - 6;
        j = min(j, 7);
        b = 8 + j;
    }
    return ret + b;
}

// ---------------------------------------------------------------------------
// Attention scores: S[bh, q, k] = qm[bh] @ km[bh]^T + rel_emb[bucket,h] + log(pm[b,k])
// Per bh: M=N=1024, K=64. Grid (8, 8, 64). Same tile scheme as gemm_nt.
// ---------------------------------------------------------------------------
__global__ void __launch_bounds__(256) attn_scores_kernel(
    const float* __restrict__ Q, const float* __restrict__ Kt,
    const float* __restrict__ rel, const int* __restrict__ pm,
    float* __restrict__ S)
{
    constexpr int BM = 128, BN = 128, BK = 16;
    __shared__ float As[BK][BM + 4];
    __shared__ float Ws[BK][BN + 4];

    const int t  = threadIdx.x;
    const int ty = t >> 4;
    const int tx = t & 15;
    const int bh = blockIdx.z;
    const int h  = bh & (NHEAD - 1);
    const int b  = bh >> 4;

    const int rowBase = blockIdx.y * BM;
    const int colBase = blockIdx.x * BN;

    const float* Qb = Q + (size_t)bh * LSEQ * DHEAD + (size_t)rowBase * DHEAD;
    const float* Kb = Kt + (size_t)bh * LSEQ * DHEAD + (size_t)colBase * DHEAD;

    float acc[8][8];
#pragma unroll
    for (int i = 0; i < 8; i++)
#pragma unroll
        for (int j = 0; j < 8; j++) acc[i][j] = 0.f;

    for (int k0 = 0; k0 < DHEAD; k0 += BK) {
#pragma unroll
        for (int i = 0; i < 2; i++) {
            int idx = i * 256 + t;
            int r   = idx >> 2;
            int kk  = (idx & 3) << 2;
            float4 va = *(const float4*)(Qb + (size_t)r * DHEAD + k0 + kk);
            As[kk + 0][r] = va.x; As[kk + 1][r] = va.y;
            As[kk + 2][r] = va.z; As[kk + 3][r] = va.w;
            float4 vw = *(const float4*)(Kb + (size_t)r * DHEAD + k0 + kk);
            Ws[kk + 0][r] = vw.x; Ws[kk + 1][r] = vw.y;
            Ws[kk + 2][r] = vw.z; Ws[kk + 3][r] = vw.w;
        }
        __syncthreads();
#pragma unroll
        for (int kk = 0; kk < BK; kk++) {
            float a[8], bb[8];
            *(float4*)(a)      = *(const float4*)&As[kk][ty * 8];
            *(float4*)(a + 4)  = *(const float4*)&As[kk][ty * 8 + 4];
            *(float4*)(bb)     = *(const float4*)&Ws[kk][tx * 8];
            *(float4*)(bb + 4) = *(const float4*)&Ws[kk][tx * 8 + 4];
#pragma unroll
            for (int i = 0; i < 8; i++)
#pragma unroll
                for (int j = 0; j < 8; j++)
                    acc[i][j] = fmaf(a[i], bb[j], acc[i][j]);
        }
        __syncthreads();
    }

    float* Sbh = S + (size_t)bh * LSEQ * LSEQ;
#pragma unroll
    for (int i = 0; i < 8; i++) {
        int r = rowBase + ty * 8 + i;
        float* Srow = Sbh + (size_t)r * LSEQ;
#pragma unroll
        for (int j = 0; j < 8; j++) {
            int c = colBase + tx * 8 + j;
            float lm = logf((float)pm[b * LSEQ + c]);      // log(1)=0, log(0)=-inf
            float bias = rel[rel_bucket(r, c) * NHEAD + h] + lm;
            Srow[c] = acc[i][j] + bias;
        }
    }
}

// ---------------------------------------------------------------------------
// Row softmax over last dim (L=1024). One 256-thread block per row, in place.
// ---------------------------------------------------------------------------
__global__ void __launch_bounds__(256) softmax_kernel(float* __restrict__ S)
{
    __shared__ float sh[8];
    const size_t row = blockIdx.x;
    float* p = S + row * (size_t)LSEQ;
    const int t = threadIdx.x;

    float4 v = ((float4*)p)[t];
    float m = fmaxf(fmaxf(v.x, v.y), fmaxf(v.z, v.w));
#pragma unroll
    for (int o = 16; o; o >>= 1) m = fmaxf(m, __shfl_xor_sync(0xffffffffu, m, o));
    if ((t & 31) == 0) sh[t >> 5] = m;
    __syncthreads();
    m = sh[0];
#pragma unroll
    for (int i = 1; i < 8; i++) m = fmaxf(m, sh[i]);
    __syncthreads();

    v.x = __expf(v.x - m); v.y = __expf(v.y - m);
    v.z = __expf(v.z - m); v.w = __expf(v.w - m);
    float s = v.x + v.y + v.z + v.w;
#pragma unroll
    for (int o = 16; o; o >>= 1) s += __shfl_xor_sync(0xffffffffu, s, o);
    if ((t & 31) == 0) sh[t >> 5] = s;
    __syncthreads();
    float tot = sh[0];
#pragma unroll
    for (int i = 1; i < 8; i++) tot += sh[i];

    float r = 1.f / tot;
    v.x *= r; v.y *= r; v.z *= r; v.w *= r;
    ((float4*)p)[t] = v;
}

// ---------------------------------------------------------------------------
// PV: O[bh] = P[bh] (L x L) @ V[bh] (L x dh).  NN GEMM, per bh.
// BM=256, BN=64, BK=32, 256 threads, 8x8 per-thread. Grid (1, 4, 64).
// ---------------------------------------------------------------------------
__global__ void __launch_bounds__(256) attn_pv_kernel(
    const float* __restrict__ P, const float* __restrict__ V,
    float* __restrict__ O)
{
    constexpr int BM = 256, BN = 64, BK = 32;
    __shared__ float As[BK][BM + 4];   // ~33 KB
    __shared__ float Bs[BK][BN + 4];   // ~8.7 KB

    const int t  = threadIdx.x;
    const int ty = t >> 3;   // 0..31
    const int tx = t & 7;    // 0..7
    const int bh = blockIdx.z;
    const int rowBase = blockIdx.y * BM;

    const float* Pb = P + (size_t)bh * LSEQ * LSEQ + (size_t)rowBase * LSEQ;
    const float* Vb = V + (size_t)bh * LSEQ * DHEAD;
    float* Ob = O + (size_t)bh * LSEQ * DHEAD + (size_t)rowBase * DHEAD;

    float acc[8][8];
#pragma unroll
    for (int i = 0; i < 8; i++)
#pragma unroll
        for (int j = 0; j < 8; j++) acc[i][j] = 0.f;

    for (int k0 = 0; k0 < LSEQ; k0 += BK) {
        // P tile: 256 rows x 32 cols = 2048 float4, 8 per thread (transposed store)
#pragma unroll
        for (int i = 0; i < 8; i++) {
            int idx = i * 256 + t;           // 0..2047
            int r   = idx >> 3;              // 0..255
            int kk  = (idx & 7) << 2;        // 0..28
            float4 va = *(const float4*)(Pb + (size_t)r * LSEQ + k0 + kk);
            As[kk + 0][r] = va.x; As[kk + 1][r] = va.y;
            As[kk + 2][r] = va.z; As[kk + 3][r] = va.w;
        }
        // V tile: 32 rows x 64 cols = 512 float4, 2 per thread (direct store)
#pragma unroll
        for (int i = 0; i < 2; i++) {
            int idx = i * 256 + t;           // 0..511
            int r   = idx >> 4;              // 0..31
            int c   = (idx & 15) << 2;       // 0..60
            *(float4*)&Bs[r][c] = *(const float4*)(Vb + (size_t)(k0 + r) * DHEAD + c);
        }
        __syncthreads();
#pragma unroll
        for (int kk = 0; kk < BK; kk++) {
            float a[8], bb[8];
            *(float4*)(a)      = *(const float4*)&As[kk][ty * 8];
            *(float4*)(a + 4)  = *(const float4*)&As[kk][ty * 8 + 4];
            *(float4*)(bb)     = *(const float4*)&Bs[kk][tx * 8];
            *(float4*)(bb + 4) = *(const float4*)&Bs[kk][tx * 8 + 4];
#pragma unroll
            for (int i = 0; i < 8; i++)
#pragma unroll
                for (int j = 0; j < 8; j++)
                    acc[i][j] = fmaf(a[i], bb[j], acc[i][j]);
        }
        __syncthreads();
    }

#pragma unroll
    for (int i = 0; i < 8; i++) {
        float* Orow = Ob + (size_t)(ty * 8 + i) * DHEAD + tx * 8;
        float4 o0 = make_float4(acc[i][0], acc[i][1], acc[i][2], acc[i][3]);
        float4 o1 = make_float4(acc[i][4], acc[i][5], acc[i][6], acc[i][7]);
        *(float4*)(Orow)     = o0;
        *(float4*)(Orow + 4) = o1;
    }
}

// ---------------------------------------------------------------------------
// out = LayerNorm(A + B) over last dim (1024), no eps, no affine.
// One 256-thread block per row (4 elems/thread). True two-pass variance.
// ---------------------------------------------------------------------------
__global__ void __launch_bounds__(256) add_ln_kernel(
    const float* __restrict__ A, const float* __restrict__ B,
    float* __restrict__ out)
{
    __shared__ float sh[8];
    const size_t row = blockIdx.x;
    const int t = threadIdx.x;

    float4 a = ((const float4*)(A + row * DMODEL))[t];
    float4 b = ((const float4*)(B + row * DMODEL))[t];
    float4 x;
    x.x = a.x + b.x; x.y = a.y + b.y; x.z = a.z + b.z; x.w = a.w + b.w;

    float s = x.x + x.y + x.z + x.w;
#pragma unroll
    for (int o = 16; o; o >>= 1) s += __shfl_xor_sync(0xffffffffu, s, o);
    if ((t & 31) == 0) sh[t >> 5] = s;
    __syncthreads();
    float tot = sh[0];
#pragma unroll
    for (int i = 1; i < 8; i++) tot += sh[i];
    __syncthreads();
    float mean = tot * (1.f / DMODEL);

    float dx = x.x - mean, dy = x.y - mean, dz = x.z - mean, dw = x.w - mean;
    float s2 = dx * dx + dy * dy + dz * dz + dw * dw;
#pragma unroll
    for (int o = 16; o; o >>= 1) s2 += __shfl_xor_sync(0xffffffffu, s2, o);
    if ((t & 31) == 0) sh[t >> 5] = s2;
    __syncthreads();
    float tot2 = sh[0];
#pragma unroll
    for (int i = 1; i < 8; i++) tot2 += sh[i];
    float inv = rsqrtf(tot2 * (1.f / DMODEL));

    float4 o;
    o.x = dx * inv; o.y = dy * inv; o.z = dz * inv; o.w = dw * inv;
    ((float4*)(out + row * DMODEL))[t] = o;
}

// ---------------------------------------------------------------------------
// Launch sequence (graph-capturable: kernel launches only).
// Input order: x, padding_mask, Wq, bq, Wk, bk, Wv, bv, Wo, bo, rel_emb,
//              W1, b1, W2, b2
// ---------------------------------------------------------------------------
extern "C" void kernel_launch(void* const* d_in, const int* in_sizes, int n_in,
                              void* d_out, int out_size)
{
    const float* x   = (const float*)d_in[0];
    const int*   pm  = (const int*)  d_in[1];
    const float* Wq  = (const float*)d_in[2];
    const float* bq  = (const float*)d_in[3];
    const float* Wk  = (const float*)d_in[4];
    const float* bk  = (const float*)d_in[5];
    const float* Wv  = (const float*)d_in[6];
    const float* bv  = (const float*)d_in[7];
    const float* Wo  = (const float*)d_in[8];
    const float* bo  = (const float*)d_in[9];
    const float* rel = (const float*)d_in[10];
    const float* W1  = (const float*)d_in[11];
    const float* b1  = (const float*)d_in[12];
    const float* W2  = (const float*)d_in[13];
    const float* b2  = (const float*)d_in[14];
    float* out = (float*)d_out;

    float *q, *k, *v, *s, *av, *attp, *attout, *h1, *ff;
    cudaGetSymbolAddress((void**)&q,      g_q);
    cudaGetSymbolAddress((void**)&k,      g_k);
    cudaGetSymbolAddress((void**)&v,      g_v);
    cudaGetSymbolAddress((void**)&s,      g_s);
    cudaGetSymbolAddress((void**)&av,     g_av);
    cudaGetSymbolAddress((void**)&attp,   g_attp);
    cudaGetSymbolAddress((void**)&attout, g_attout);
    cudaGetSymbolAddress((void**)&h1,     g_h1);
    cudaGetSymbolAddress((void**)&ff,     g_ff);

    dim3 blk(256);

    // QKV projections: (4096x1024) @ (1024x1024)^T
    gemm_nt_kernel<false><<<dim3(8, 32), blk>>>(x, Wq, bq, q, MROWS, DMODEL, DMODEL);
    gemm_nt_kernel<false><<<dim3(8, 32), blk>>>(x, Wk, bk, k, MROWS, DMODEL, DMODEL);
    gemm_nt_kernel<false><<<dim3(8, 32), blk>>>(x, Wv, bv, v, MROWS, DMODEL, DMODEL);

    // scores + rel bias + log mask
    attn_scores_kernel<<<dim3(8, 8, BHDIM), blk>>>(q, k, rel, pm, s);

    // softmax over keys
    softmax_kernel<<<BHDIM * LSEQ, blk>>>(s);

    // P @ V
    attn_pv_kernel<<<dim3(1, 4, BHDIM), blk>>>(s, v, av);

    // output projection
    gemm_nt_kernel<false><<<dim3(8, 32), blk>>>(av, Wo, bo, attp, MROWS, DMODEL, DMODEL);

    // att_out = LN(attp + x)
    add_ln_kernel<<<MROWS, blk>>>(attp, x, attout);

    // FFN
    gemm_nt_kernel<true ><<<dim3(32, 32), blk>>>(attout, W1, b1, h1, MROWS, FFDIM, DMODEL);
    gemm_nt_kernel<false><<<dim3(8, 32), blk>>>(h1, W2, b2, ff, MROWS, DMODEL, FFDIM);

    // out = LN(ff + att_out)
    add_ln_kernel<<<MROWS, blk>>>(ff, attout, out);
}

// round 3
// speedup vs baseline: 1.8524x; 1.8524x over previous
#include <cuda_runtime.h>
#include <cuda_bf16.h>
#include <math.h>
#include <stdint.h>

// ---------------------------------------------------------------------------
// EncoderBlock: B=4, L=1024, D=1024, F=4096, H=16, dh=64
// Round 3: dense GEMMs via mma.sync bf16 hi/lo split (sm_103-baseline ISA).
// ---------------------------------------------------------------------------

#define LSEQ 1024
#define DMODEL 1024
#define BATCH 4
#define NHEAD 16
#define DHEAD 64
#define FFDIM 4096
#define BHDIM 64          /* BATCH*NHEAD */
#define MROWS 4096        /* BATCH*LSEQ  */

// ---- fp32 scratch ----------------------------------------------------------
__device__ float g_q[BATCH * LSEQ * DMODEL];
__device__ float g_k[BATCH * LSEQ * DMODEL];
__device__ float g_v[BATCH * LSEQ * DMODEL];
__device__ float g_s[(size_t)BHDIM * LSEQ * LSEQ];   // 256 MB scores / probs
__device__ float g_attp[BATCH * LSEQ * DMODEL];
__device__ float g_attout[BATCH * LSEQ * DMODEL];
__device__ float g_ff[BATCH * LSEQ * DMODEL];

// ---- bf16 hi/lo scratch -----------------------------------------------------
__device__ __nv_bfloat16 g_xh[MROWS * DMODEL],  g_xl[MROWS * DMODEL];
__device__ __nv_bfloat16 g_wqh[DMODEL * DMODEL], g_wql[DMODEL * DMODEL];
__device__ __nv_bfloat16 g_wkh[DMODEL * DMODEL], g_wkl[DMODEL * DMODEL];
__device__ __nv_bfloat16 g_wvh[DMODEL * DMODEL], g_wvl[DMODEL * DMODEL];
__device__ __nv_bfloat16 g_woh[DMODEL * DMODEL], g_wol[DMODEL * DMODEL];
__device__ __nv_bfloat16 g_w1h[FFDIM * DMODEL],  g_w1l[FFDIM * DMODEL];
__device__ __nv_bfloat16 g_w2h[DMODEL * FFDIM],  g_w2l[DMODEL * FFDIM];
__device__ __nv_bfloat16 g_avh[MROWS * DMODEL],  g_avl[MROWS * DMODEL];
__device__ __nv_bfloat16 g_aoh[MROWS * DMODEL],  g_aol[MROWS * DMODEL];
__device__ __nv_bfloat16 g_h1h[(size_t)MROWS * FFDIM], g_h1l[(size_t)MROWS * FFDIM];

// ============================================================================
// helpers
// ============================================================================
__device__ __forceinline__ uint32_t smem_u32(const void* p) {
    uint32_t a;
    asm("{ .reg .u64 t; cvta.to.shared.u64 t, %1; cvt.u32.u64 %0, t; }"
        : "=r"(a) : "l"(p));
    return a;
}
__device__ __forceinline__ void cp16(uint32_t dst, const void* src) {
    asm volatile("cp.async.cg.shared.global [%0], [%1], 16;" :: "r"(dst), "l"(src));
}
__device__ __forceinline__ void ldsm_x4(uint32_t& r0, uint32_t& r1,
                                        uint32_t& r2, uint32_t& r3, uint32_t a) {
    asm volatile("ldmatrix.sync.aligned.m8n8.x4.shared.b16 {%0,%1,%2,%3}, [%4];"
                 : "=r"(r0), "=r"(r1), "=r"(r2), "=r"(r3) : "r"(a));
}
__device__ __forceinline__ void ldsm_x2(uint32_t& r0, uint32_t& r1, uint32_t a) {
    asm volatile("ldmatrix.sync.aligned.m8n8.x2.shared.b16 {%0,%1}, [%2];"
                 : "=r"(r0), "=r"(r1) : "r"(a));
}
__device__ __forceinline__ void mma_bf16(float* c, const uint32_t* a, const uint32_t* b) {
    asm volatile(
        "mma.sync.aligned.m16n8k16.row.col.f32.bf16.bf16.f32 "
        "{%0,%1,%2,%3}, {%4,%5,%6,%7}, {%8,%9}, {%0,%1,%2,%3};"
        : "+f"(c[0]), "+f"(c[1]), "+f"(c[2]), "+f"(c[3])
        : "r"(a[0]), "r"(a[1]), "r"(a[2]), "r"(a[3]), "r"(b[0]), "r"(b[1]));
}

// ============================================================================
// split: X(fp32) -> hi = bf16(X), lo = bf16(X - hi)
// ============================================================================
__global__ void __launch_bounds__(256) split_kernel(
    const float* __restrict__ X, __nv_bfloat16* __restrict__ H,
    __nv_bfloat16* __restrict__ L, int n4)
{
    int i = blockIdx.x * 256 + threadIdx.x;
    if (i >= n4) return;
    float4 v = ((const float4*)X)[i];
    __nv_bfloat16 h0 = __float2bfloat16(v.x);
    __nv_bfloat16 h1 = __float2bfloat16(v.y);
    __nv_bfloat16 h2 = __float2bfloat16(v.z);
    __nv_bfloat16 h3 = __float2bfloat16(v.w);
    __nv_bfloat16 l0 = __float2bfloat16(v.x - __bfloat162float(h0));
    __nv_bfloat16 l1 = __float2bfloat16(v.y - __bfloat162float(h1));
    __nv_bfloat16 l2 = __float2bfloat16(v.z - __bfloat162float(h2));
    __nv_bfloat16 l3 = __float2bfloat16(v.w - __bfloat162float(h3));
    __nv_bfloat162 hp0(h0, h1), hp1(h2, h3), lp0(l0, l1), lp1(l2, l3);
    ((uint2*)H)[i] = make_uint2(*(uint32_t*)&hp0, *(uint32_t*)&hp1);
    ((uint2*)L)[i] = make_uint2(*(uint32_t*)&lp0, *(uint32_t*)&lp1);
}

// ============================================================================
// mma.sync GEMM: C[M,N] = (Ah+Al)[M,K] @ (Bh+Bl)[N,K]^T + bias
// BM=128, BN=128, BK=32, 3-stage cp.async pipeline, 8 warps (2m x 4n).
// SMEM swizzle: 16B chunk c at row r stored at c ^ ((r>>1)&3).
// ============================================================================
#define TBM 128
#define TBN 128
#define TBK 32
#define TSTG 3
#define STG_BYTES 32768   /* 4 arrays x 128 rows x 64 B */
#define TG_SMEM (TSTG * STG_BYTES)

__device__ __forceinline__ uint32_t sw_off(int r, int c) {
    return (uint32_t)(r * 64 + ((c ^ ((r >> 1) & 3)) << 4));
}

__device__ __forceinline__ void tg_load_stage(
    uint32_t sbuf, int t,
    const __nv_bfloat16* __restrict__ Ah, const __nv_bfloat16* __restrict__ Al,
    const __nv_bfloat16* __restrict__ Bh, const __nv_bfloat16* __restrict__ Bl,
    int rowBase, int colBase, int k0, int K)
{
#pragma unroll
    for (int j = 0; j < 8; j++) {
        int i   = j * 256 + t;      // 0..2047
        int arr = i >> 9;           // 0..3 : Ah, Al, Bh, Bl
        int idx = i & 511;
        int r   = idx >> 2;
        int ch  = idx & 3;
        const __nv_bfloat16* base =
            (arr == 0) ? Ah : (arr == 1) ? Al : (arr == 2) ? Bh : Bl;
        int gr = ((arr < 2) ? rowBase : colBase) + r;
        cp16(sbuf + arr * 8192 + sw_off(r, ch),
             base + (size_t)gr * K + k0 + ch * 8);
    }
    asm volatile("cp.async.commit_group;" ::: "memory");
}

template <bool RELU, bool SPLIT>
__global__ void __launch_bounds__(256) tgemm_kernel(
    const __nv_bfloat16* __restrict__ Ah, const __nv_bfloat16* __restrict__ Al,
    const __nv_bfloat16* __restrict__ Bh, const __nv_bfloat16* __restrict__ Bl,
    const float* __restrict__ bias, float* __restrict__ C,
    __nv_bfloat16* __restrict__ Ch, __nv_bfloat16* __restrict__ Cl,
    int M, int N, int K)
{
    extern __shared__ __align__(16) char smem[];
    uint32_t sb = smem_u32(smem);
    const int t = threadIdx.x;
    const int w = t >> 5, lane = t & 31;
    const int wm = w >> 2;          // 0..1
    const int wn = w & 3;           // 0..3
    const int rowBase = blockIdx.y * TBM;
    const int colBase = blockIdx.x * TBN;
    const int KT = K / TBK;

    float acc[4][4][4];
#pragma unroll
    for (int mt = 0; mt < 4; mt++)
#pragma unroll
        for (int nt = 0; nt < 4; nt++)
#pragma unroll
            for (int e = 0; e < 4; e++) acc[mt][nt][e] = 0.f;

    tg_load_stage(sb, t, Ah, Al, Bh, Bl, rowBase, colBase, 0, K);
    tg_load_stage(sb + STG_BYTES, t, Ah, Al, Bh, Bl, rowBase, colBase, TBK, K);

    for (int kt = 0; kt < KT; kt++) {
        if (kt == KT - 1)
            asm volatile("cp.async.wait_group 0;" ::: "memory");
        else
            asm volatile("cp.async.wait_group 1;" ::: "memory");
        __syncthreads();
        if (kt + 2 < KT)
            tg_load_stage(sb + ((kt + 2) % TSTG) * STG_BYTES, t,
                          Ah, Al, Bh, Bl, rowBase, colBase, (kt + 2) * TBK, K);

        uint32_t sbase = sb + (kt % TSTG) * STG_BYTES;
#pragma unroll
        for (int ks = 0; ks < 2; ks++) {
            uint32_t ah[4][4], al[4][4], bh[4][2], bl[4][2];
            const int arow0  = wm * 64 + (lane & 15);
            const int achunk = ks * 2 + (lane >> 4);
#pragma unroll
            for (int mt = 0; mt < 4; mt++) {
                int r = arow0 + mt * 16;
                uint32_t off = sw_off(r, achunk);
                ldsm_x4(ah[mt][0], ah[mt][1], ah[mt][2], ah[mt][3], sbase + off);
                ldsm_x4(al[mt][0], al[mt][1], al[mt][2], al[mt][3], sbase + 8192 + off);
            }
            const int brow0  = wn * 32 + (lane & 7);
            const int bchunk = ks * 2 + (((lane & 15) >> 3) & 1);
#pragma unroll
            for (int nt = 0; nt < 4; nt++) {
                int r = brow0 + nt * 8;
                uint32_t off = sw_off(r, bchunk);
                ldsm_x2(bh[nt][0], bh[nt][1], sbase + 16384 + off);
                ldsm_x2(bl[nt][0], bl[nt][1], sbase + 24576 + off);
            }
#pragma unroll
            for (int mt = 0; mt < 4; mt++)
#pragma unroll
                for (int nt = 0; nt < 4; nt++) {
                    mma_bf16(acc[mt][nt], ah[mt], bh[nt]);
                    mma_bf16(acc[mt][nt], ah[mt], bl[nt]);
                    mma_bf16(acc[mt][nt], al[mt], bh[nt]);
                }
        }
    }

    // Epilogue
#pragma unroll
    for (int mt = 0; mt < 4; mt++) {
        int r0 = rowBase + wm * 64 + mt * 16 + (lane >> 2);
#pragma unroll
        for (int nt = 0; nt < 4; nt++) {
            int c = colBase + wn * 32 + nt * 8 + (lane & 3) * 2;
            float b0 = __ldg(&bias[c]), b1 = __ldg(&bias[c + 1]);
            float v0 = acc[mt][nt][0] + b0, v1 = acc[mt][nt][1] + b1;
            float v2 = acc[mt][nt][2] + b0, v3 = acc[mt][nt][3] + b1;
            if (RELU) {
                v0 = fmaxf(v0, 0.f); v1 = fmaxf(v1, 0.f);
                v2 = fmaxf(v2, 0.f); v3 = fmaxf(v3, 0.f);
            }
            if (SPLIT) {
                __nv_bfloat16 h0 = __float2bfloat16(v0), h1 = __float2bfloat16(v1);
                __nv_bfloat16 h2 = __float2bfloat16(v2), h3 = __float2bfloat16(v3);
                __nv_bfloat162 hp0(h0, h1), hp1(h2, h3);
                __nv_bfloat162 lp0(__float2bfloat16(v0 - __bfloat162float(h0)),
                                   __float2bfloat16(v1 - __bfloat162float(h1)));
                __nv_bfloat162 lp1(__float2bfloat16(v2 - __bfloat162float(h2)),
                                   __float2bfloat16(v3 - __bfloat162float(h3)));
                *(__nv_bfloat162*)(Ch + (size_t)r0 * N + c)       = hp0;
                *(__nv_bfloat162*)(Ch + (size_t)(r0 + 8) * N + c) = hp1;
                *(__nv_bfloat162*)(Cl + (size_t)r0 * N + c)       = lp0;
                *(__nv_bfloat162*)(Cl + (size_t)(r0 + 8) * N + c) = lp1;
            } else {
                *(float2*)(C + (size_t)r0 * N + c)       = make_float2(v0, v1);
                *(float2*)(C + (size_t)(r0 + 8) * N + c) = make_float2(v2, v3);
            }
        }
    }
}

// ============================================================================
// T5 relative-position bucket (exact integer replica of numpy formula)
// ============================================================================
__device__ __forceinline__ int rel_bucket(int qrow, int kcol)
{
    int d   = kcol - qrow;
    int ret = (d < 0) ? NHEAD : 0;
    int n   = abs(d);
    int b;
    if (n < 8) b = n;
    else {
        int j = (31 - __clz(n * n)) - 6;
        j = min(j, 7);
        b = 8 + j;
    }
    return ret + b;
}

// ============================================================================
// Attention scores (fp32 FFMA), logf hoisted to per-block smem table
// ============================================================================
__global__ void __launch_bounds__(256) attn_scores_kernel(
    const float* __restrict__ Q, const float* __restrict__ Kt,
    const float* __restrict__ rel, const int* __restrict__ pm,
    float* __restrict__ S)
{
    constexpr int BM = 128, BN = 128, BK = 16;
    __shared__ float As[BK][BM + 4];
    __shared__ float Ws[BK][BN + 4];
    __shared__ float lm_sh[BN];

    const int t  = threadIdx.x;
    const int ty = t >> 4;
    const int tx = t & 15;
    const int bh = blockIdx.z;
    const int h  = bh & (NHEAD - 1);
    const int b  = bh >> 4;

    const int rowBase = blockIdx.y * BM;
    const int colBase = blockIdx.x * BN;

    if (t < BN) lm_sh[t] = logf((float)pm[b * LSEQ + colBase + t]);

    const float* Qb = Q + (size_t)bh * LSEQ * DHEAD + (size_t)rowBase * DHEAD;
    const float* Kb = Kt + (size_t)bh * LSEQ * DHEAD + (size_t)colBase * DHEAD;

    float acc[8][8];
#pragma unroll
    for (int i = 0; i < 8; i++)
#pragma unroll
        for (int j = 0; j < 8; j++) acc[i][j] = 0.f;

    for (int k0 = 0; k0 < DHEAD; k0 += BK) {
#pragma unroll
        for (int i = 0; i < 2; i++) {
            int idx = i * 256 + t;
            int r   = idx >> 2;
            int kk  = (idx & 3) << 2;
            float4 va = *(const float4*)(Qb + (size_t)r * DHEAD + k0 + kk);
            As[kk + 0][r] = va.x; As[kk + 1][r] = va.y;
            As[kk + 2][r] = va.z; As[kk + 3][r] = va.w;
            float4 vw = *(const float4*)(Kb + (size_t)r * DHEAD + k0 + kk);
            Ws[kk + 0][r] = vw.x; Ws[kk + 1][r] = vw.y;
            Ws[kk + 2][r] = vw.z; Ws[kk + 3][r] = vw.w;
        }
        __syncthreads();
#pragma unroll
        for (int kk = 0; kk < BK; kk++) {
            float a[8], bb[8];
            *(float4*)(a)      = *(const float4*)&As[kk][ty * 8];
            *(float4*)(a + 4)  = *(const float4*)&As[kk][ty * 8 + 4];
            *(float4*)(bb)     = *(const float4*)&Ws[kk][tx * 8];
            *(float4*)(bb + 4) = *(const float4*)&Ws[kk][tx * 8 + 4];
#pragma unroll
            for (int i = 0; i < 8; i++)
#pragma unroll
                for (int j = 0; j < 8; j++)
                    acc[i][j] = fmaf(a[i], bb[j], acc[i][j]);
        }
        __syncthreads();
    }

    float* Sbh = S + (size_t)bh * LSEQ * LSEQ;
#pragma unroll
    for (int i = 0; i < 8; i++) {
        int r = rowBase + ty * 8 + i;
        float* Srow = Sbh + (size_t)r * LSEQ;
#pragma unroll
        for (int j = 0; j < 8; j++) {
            int lc = tx * 8 + j;
            int c  = colBase + lc;
            float bias = rel[rel_bucket(r, c) * NHEAD + h] + lm_sh[lc];
            Srow[c] = acc[i][j] + bias;
        }
    }
}

// ============================================================================
// Row softmax over last dim (in place)
// ============================================================================
__global__ void __launch_bounds__(256) softmax_kernel(float* __restrict__ S)
{
    __shared__ float sh[8];
    const size_t row = blockIdx.x;
    float* p = S + row * (size_t)LSEQ;
    const int t = threadIdx.x;

    float4 v = ((float4*)p)[t];
    float m = fmaxf(fmaxf(v.x, v.y), fmaxf(v.z, v.w));
#pragma unroll
    for (int o = 16; o; o >>= 1) m = fmaxf(m, __shfl_xor_sync(0xffffffffu, m, o));
    if ((t & 31) == 0) sh[t >> 5] = m;
    __syncthreads();
    m = sh[0];
#pragma unroll
    for (int i = 1; i < 8; i++) m = fmaxf(m, sh[i]);
    __syncthreads();

    v.x = __expf(v.x - m); v.y = __expf(v.y - m);
    v.z = __expf(v.z - m); v.w = __expf(v.w - m);
    float s = v.x + v.y + v.z + v.w;
#pragma unroll
    for (int o = 16; o; o >>= 1) s += __shfl_xor_sync(0xffffffffu, s, o);
    if ((t & 31) == 0) sh[t >> 5] = s;
    __syncthreads();
    float tot = sh[0];
#pragma unroll
    for (int i = 1; i < 8; i++) tot += sh[i];

    float r = 1.f / tot;
    v.x *= r; v.y *= r; v.z *= r; v.w *= r;
    ((float4*)p)[t] = v;
}

// ============================================================================
// PV: O[bh] = P[bh] @ V[bh]; epilogue writes bf16 hi/lo directly.
// ============================================================================
__global__ void __launch_bounds__(256) attn_pv_kernel(
    const float* __restrict__ P, const float* __restrict__ V,
    __nv_bfloat16* __restrict__ OH, __nv_bfloat16* __restrict__ OL)
{
    constexpr int BM = 256, BN = 64, BK = 32;
    __shared__ float As[BK][BM + 4];
    __shared__ float Bs[BK][BN + 4];

    const int t  = threadIdx.x;
    const int ty = t >> 3;
    const int tx = t & 7;
    const int bh = blockIdx.z;
    const int rowBase = blockIdx.y * BM;

    const float* Pb = P + (size_t)bh * LSEQ * LSEQ + (size_t)rowBase * LSEQ;
    const float* Vb = V + (size_t)bh * LSEQ * DHEAD;
    size_t obase = (size_t)bh * LSEQ * DHEAD + (size_t)rowBase * DHEAD;

    float acc[8][8];
#pragma unroll
    for (int i = 0; i < 8; i++)
#pragma unroll
        for (int j = 0; j < 8; j++) acc[i][j] = 0.f;

    for (int k0 = 0; k0 < LSEQ; k0 += BK) {
#pragma unroll
        for (int i = 0; i < 8; i++) {
            int idx = i * 256 + t;
            int r   = idx >> 3;
            int kk  = (idx & 7) << 2;
            float4 va = *(const float4*)(Pb + (size_t)r * LSEQ + k0 + kk);
            As[kk + 0][r] = va.x; As[kk + 1][r] = va.y;
            As[kk + 2][r] = va.z; As[kk + 3][r] = va.w;
        }
#pragma unroll
        for (int i = 0; i < 2; i++) {
            int idx = i * 256 + t;
            int r   = idx >> 4;
            int c   = (idx & 15) << 2;
            *(float4*)&Bs[r][c] = *(const float4*)(Vb + (size_t)(k0 + r) * DHEAD + c);
        }
        __syncthreads();
#pragma unroll
        for (int kk = 0; kk < BK; kk++) {
            float a[8], bb[8];
            *(float4*)(a)      = *(const float4*)&As[kk][ty * 8];
            *(float4*)(a + 4)  = *(const float4*)&As[kk][ty * 8 + 4];
            *(float4*)(bb)     = *(const float4*)&Bs[kk][tx * 8];
            *(float4*)(bb + 4) = *(const float4*)&Bs[kk][tx * 8 + 4];
#pragma unroll
            for (int i = 0; i < 8; i++)
#pragma unroll
                for (int j = 0; j < 8; j++)
                    acc[i][j] = fmaf(a[i], bb[j], acc[i][j]);
        }
        __syncthreads();
    }

#pragma unroll
    for (int i = 0; i < 8; i++) {
        size_t o = obase + (size_t)(ty * 8 + i) * DHEAD + tx * 8;
#pragma unroll
        for (int j = 0; j < 8; j += 2) {
            float v0 = acc[i][j], v1 = acc[i][j + 1];
            __nv_bfloat16 h0 = __float2bfloat16(v0), h1 = __float2bfloat16(v1);
            __nv_bfloat162 hp(h0, h1);
            __nv_bfloat162 lp(__float2bfloat16(v0 - __bfloat162float(h0)),
                              __float2bfloat16(v1 - __bfloat162float(h1)));
            *(__nv_bfloat162*)(OH + o + j) = hp;
            *(__nv_bfloat162*)(OL + o + j) = lp;
        }
    }
}

// ============================================================================
// out = LayerNorm(A + B); optional bf16 hi/lo side output
// ============================================================================
template <bool SPLIT>
__global__ void __launch_bounds__(256) add_ln_kernel(
    const float* __restrict__ A, const float* __restrict__ B,
    float* __restrict__ out,
    __nv_bfloat16* __restrict__ OH, __nv_bfloat16* __restrict__ OL)
{
    __shared__ float sh[8];
    const size_t row = blockIdx.x;
    const int t = threadIdx.x;

    float4 a = ((const float4*)(A + row * DMODEL))[t];
    float4 b = ((const float4*)(B + row * DMODEL))[t];
    float4 x;
    x.x = a.x + b.x; x.y = a.y + b.y; x.z = a.z + b.z; x.w = a.w + b.w;

    float s = x.x + x.y + x.z + x.w;
#pragma unroll
    for (int o = 16; o; o >>= 1) s += __shfl_xor_sync(0xffffffffu, s, o);
    if ((t & 31) == 0) sh[t >> 5] = s;
    __syncthreads();
    float tot = sh[0];
#pragma unroll
    for (int i = 1; i < 8; i++) tot += sh[i];
    __syncthreads();
    float mean = tot * (1.f / DMODEL);

    float dx = x.x - mean, dy = x.y - mean, dz = x.z - mean, dw = x.w - mean;
    float s2 = dx * dx + dy * dy + dz * dz + dw * dw;
#pragma unroll
    for (int o = 16; o; o >>= 1) s2 += __shfl_xor_sync(0xffffffffu, s2, o);
    if ((t & 31) == 0) sh[t >> 5] = s2;
    __syncthreads();
    float tot2 = sh[0];
#pragma unroll
    for (int i = 1; i < 8; i++) tot2 += sh[i];
    float inv = rsqrtf(tot2 * (1.f / DMODEL));

    float4 o;
    o.x = dx * inv; o.y = dy * inv; o.z = dz * inv; o.w = dw * inv;
    ((float4*)(out + row * DMODEL))[t] = o;

    if (SPLIT) {
        __nv_bfloat16 h0 = __float2bfloat16(o.x), h1 = __float2bfloat16(o.y);
        __nv_bfloat16 h2 = __float2bfloat16(o.z), h3 = __float2bfloat16(o.w);
        __nv_bfloat162 hp0(h0, h1), hp1(h2, h3);
        __nv_bfloat162 lp0(__float2bfloat16(o.x - __bfloat162float(h0)),
                           __float2bfloat16(o.y - __bfloat162float(h1)));
        __nv_bfloat162 lp1(__float2bfloat16(o.z - __bfloat162float(h2)),
                           __float2bfloat16(o.w - __bfloat162float(h3)));
        size_t base = row * DMODEL + t * 4;
        *(__nv_bfloat162*)(OH + base)     = hp0;
        *(__nv_bfloat162*)(OH + base + 2) = hp1;
        *(__nv_bfloat162*)(OL + base)     = lp0;
        *(__nv_bfloat162*)(OL + base + 2) = lp1;
    }
}

// ============================================================================
// Launch sequence
// ============================================================================
extern "C" void kernel_launch(void* const* d_in, const int* in_sizes, int n_in,
                              void* d_out, int out_size)
{
    const float* x   = (const float*)d_in[0];
    const int*   pm  = (const int*)  d_in[1];
    const float* Wq  = (const float*)d_in[2];
    const float* bq  = (const float*)d_in[3];
    const float* Wk  = (const float*)d_in[4];
    const float* bk  = (const float*)d_in[5];
    const float* Wv  = (const float*)d_in[6];
    const float* bv  = (const float*)d_in[7];
    const float* Wo  = (const float*)d_in[8];
    const float* bo  = (const float*)d_in[9];
    const float* rel = (const float*)d_in[10];
    const float* W1  = (const float*)d_in[11];
    const float* b1  = (const float*)d_in[12];
    const float* W2  = (const float*)d_in[13];
    const float* b2  = (const float*)d_in[14];
    float* out = (float*)d_out;

    float *q, *k, *v, *s, *attp, *attout, *ff;
    cudaGetSymbolAddress((void**)&q,      g_q);
    cudaGetSymbolAddress((void**)&k,      g_k);
    cudaGetSymbolAddress((void**)&v,      g_v);
    cudaGetSymbolAddress((void**)&s,      g_s);
    cudaGetSymbolAddress((void**)&attp,   g_attp);
    cudaGetSymbolAddress((void**)&attout, g_attout);
    cudaGetSymbolAddress((void**)&ff,     g_ff);

    __nv_bfloat16 *xh, *xl, *wqh, *wql, *wkh, *wkl, *wvh, *wvl, *woh, *wol;
    __nv_bfloat16 *w1h, *w1l, *w2h, *w2l, *avh, *avl, *aoh, *aol, *h1h, *h1l;
    cudaGetSymbolAddress((void**)&xh,  g_xh);  cudaGetSymbolAddress((void**)&xl,  g_xl);
    cudaGetSymbolAddress((void**)&wqh, g_wqh); cudaGetSymbolAddress((void**)&wql, g_wql);
    cudaGetSymbolAddress((void**)&wkh, g_wkh); cudaGetSymbolAddress((void**)&wkl, g_wkl);
    cudaGetSymbolAddress((void**)&wvh, g_wvh); cudaGetSymbolAddress((void**)&wvl, g_wvl);
    cudaGetSymbolAddress((void**)&woh, g_woh); cudaGetSymbolAddress((void**)&wol, g_wol);
    cudaGetSymbolAddress((void**)&w1h, g_w1h); cudaGetSymbolAddress((void**)&w1l, g_w1l);
    cudaGetSymbolAddress((void**)&w2h, g_w2h); cudaGetSymbolAddress((void**)&w2l, g_w2l);
    cudaGetSymbolAddress((void**)&avh, g_avh); cudaGetSymbolAddress((void**)&avl, g_avl);
    cudaGetSymbolAddress((void**)&aoh, g_aoh); cudaGetSymbolAddress((void**)&aol, g_aol);
    cudaGetSymbolAddress((void**)&h1h, g_h1h); cudaGetSymbolAddress((void**)&h1l, g_h1l);

    static bool attr_done = false;
    if (!attr_done) {
        cudaFuncSetAttribute(tgemm_kernel<false, false>,
                             cudaFuncAttributeMaxDynamicSharedMemorySize, TG_SMEM);
        cudaFuncSetAttribute(tgemm_kernel<true, true>,
                             cudaFuncAttributeMaxDynamicSharedMemorySize, TG_SMEM);
        attr_done = true;
    }

    dim3 blk(256);
    auto splits = [&](const float* src, __nv_bfloat16* H, __nv_bfloat16* L, size_t n) {
        int n4 = (int)(n / 4);
        split_kernel<<<(n4 + 255) / 256, blk>>>(src, H, L, n4);
    };

    // convert inputs / weights to bf16 hi/lo
    splits(x,  xh,  xl,  (size_t)MROWS * DMODEL);
    splits(Wq, wqh, wql, (size_t)DMODEL * DMODEL);
    splits(Wk, wkh, wkl, (size_t)DMODEL * DMODEL);
    splits(Wv, wvh, wvl, (size_t)DMODEL * DMODEL);
    splits(Wo, woh, wol, (size_t)DMODEL * DMODEL);
    splits(W1, w1h, w1l, (size_t)FFDIM * DMODEL);
    splits(W2, w2h, w2l, (size_t)DMODEL * FFDIM);

    // QKV projections (tensor cores)
    dim3 gQ(DMODEL / TBN, MROWS / TBM);     // (8, 32)
    tgemm_kernel<false, false><<<gQ, blk, TG_SMEM>>>(
        xh, xl, wqh, wql, bq, q, nullptr, nullptr, MROWS, DMODEL, DMODEL);
    tgemm_kernel<false, false><<<gQ, blk, TG_SMEM>>>(
        xh, xl, wkh, wkl, bk, k, nullptr, nullptr, MROWS, DMODEL, DMODEL);
    tgemm_kernel<false, false><<<gQ, blk, TG_SMEM>>>(
        xh, xl, wvh, wvl, bv, v, nullptr, nullptr, MROWS, DMODEL, DMODEL);

    // attention (fp32)
    attn_scores_kernel<<<dim3(8, 8, BHDIM), blk>>>(q, k, rel, pm, s);
    softmax_kernel<<<BHDIM * LSEQ, blk>>>(s);
    attn_pv_kernel<<<dim3(1, 4, BHDIM), blk>>>(s, v, avh, avl);

    // O projection
    tgemm_kernel<false, false><<<gQ, blk, TG_SMEM>>>(
        avh, avl, woh, wol, bo, attp, nullptr, nullptr, MROWS, DMODEL, DMODEL);

    // residual + LN (+ split for FFN input)
    add_ln_kernel<true><<<MROWS, blk>>>(attp, x, attout, aoh, aol);

    // FFN
    dim3 g1(FFDIM / TBN, MROWS / TBM);      // (32, 32)
    tgemm_kernel<true, true><<<g1, blk, TG_SMEM>>>(
        aoh, aol, w1h, w1l, b1, nullptr, h1h, h1l, MROWS, FFDIM, DMODEL);
    dim3 g2(DMODEL / TBN, MROWS / TBM);     // (8, 32)
    tgemm_kernel<false, false><<<g2, blk, TG_SMEM>>>(
        h1h, h1l, w2h, w2l, b2, ff, nullptr, nullptr, MROWS, DMODEL, FFDIM);

    // final residual + LN
    add_ln_kernel<false><<<MROWS, blk>>>(ff, attout, out, nullptr, nullptr);
}

// round 4
// speedup vs baseline: 2.6527x; 1.4320x over previous
#include <cuda_runtime.h>
#include <cuda_bf16.h>
#include <math.h>
#include <stdint.h>

// ---------------------------------------------------------------------------
// EncoderBlock: B=4, L=1024, D=1024, F=4096, H=16, dh=64
// Round 4: fused flash attention (mma.sync, hi/lo splits) + split GEMMs.
// ---------------------------------------------------------------------------

#define LSEQ 1024
#define DMODEL 1024
#define BATCH 4
#define NHEAD 16
#define DHEAD 64
#define FFDIM 4096
#define BHDIM 64          /* BATCH*NHEAD */
#define MROWS 4096        /* BATCH*LSEQ  */

// ---- fp32 scratch ----------------------------------------------------------
__device__ float g_attp[BATCH * LSEQ * DMODEL];
__device__ float g_attout[BATCH * LSEQ * DMODEL];
__device__ float g_ff[BATCH * LSEQ * DMODEL];

// ---- bf16 hi/lo scratch -----------------------------------------------------
__device__ __nv_bfloat16 g_xh[MROWS * DMODEL],  g_xl[MROWS * DMODEL];
__device__ __nv_bfloat16 g_wqh[DMODEL * DMODEL], g_wql[DMODEL * DMODEL];
__device__ __nv_bfloat16 g_wkh[DMODEL * DMODEL], g_wkl[DMODEL * DMODEL];
__device__ __nv_bfloat16 g_wvh[DMODEL * DMODEL], g_wvl[DMODEL * DMODEL];
__device__ __nv_bfloat16 g_woh[DMODEL * DMODEL], g_wol[DMODEL * DMODEL];
__device__ __nv_bfloat16 g_w1h[FFDIM * DMODEL],  g_w1l[FFDIM * DMODEL];
__device__ __nv_bfloat16 g_w2h[DMODEL * FFDIM],  g_w2l[DMODEL * FFDIM];
__device__ __nv_bfloat16 g_qh[MROWS * DMODEL],   g_ql[MROWS * DMODEL];
__device__ __nv_bfloat16 g_kh[MROWS * DMODEL],   g_kl[MROWS * DMODEL];
__device__ __nv_bfloat16 g_vh[MROWS * DMODEL],   g_vl[MROWS * DMODEL];
__device__ __nv_bfloat16 g_avh[MROWS * DMODEL],  g_avl[MROWS * DMODEL];
__device__ __nv_bfloat16 g_aoh[MROWS * DMODEL],  g_aol[MROWS * DMODEL];
__device__ __nv_bfloat16 g_h1h[(size_t)MROWS * FFDIM], g_h1l[(size_t)MROWS * FFDIM];

// ============================================================================
// helpers
// ============================================================================
__device__ __forceinline__ uint32_t smem_u32(const void* p) {
    uint32_t a;
    asm("{ .reg .u64 t; cvta.to.shared.u64 t, %1; cvt.u32.u64 %0, t; }"
        : "=r"(a) : "l"(p));
    return a;
}
__device__ __forceinline__ void cp16(uint32_t dst, const void* src) {
    asm volatile("cp.async.cg.shared.global [%0], [%1], 16;" :: "r"(dst), "l"(src));
}
__device__ __forceinline__ void ldsm_x4(uint32_t& r0, uint32_t& r1,
                                        uint32_t& r2, uint32_t& r3, uint32_t a) {
    asm volatile("ldmatrix.sync.aligned.m8n8.x4.shared.b16 {%0,%1,%2,%3}, [%4];"
                 : "=r"(r0), "=r"(r1), "=r"(r2), "=r"(r3) : "r"(a));
}
__device__ __forceinline__ void ldsm_x2(uint32_t& r0, uint32_t& r1, uint32_t a) {
    asm volatile("ldmatrix.sync.aligned.m8n8.x2.shared.b16 {%0,%1}, [%2];"
                 : "=r"(r0), "=r"(r1) : "r"(a));
}
__device__ __forceinline__ void ldsm_x2t(uint32_t& r0, uint32_t& r1, uint32_t a) {
    asm volatile("ldmatrix.sync.aligned.m8n8.x2.trans.shared.b16 {%0,%1}, [%2];"
                 : "=r"(r0), "=r"(r1) : "r"(a));
}
__device__ __forceinline__ void mma_bf16(float* c, const uint32_t* a, const uint32_t* b) {
    asm volatile(
        "mma.sync.aligned.m16n8k16.row.col.f32.bf16.bf16.f32 "
        "{%0,%1,%2,%3}, {%4,%5,%6,%7}, {%8,%9}, {%0,%1,%2,%3};"
        : "+f"(c[0]), "+f"(c[1]), "+f"(c[2]), "+f"(c[3])
        : "r"(a[0]), "r"(a[1]), "r"(a[2]), "r"(a[3]), "r"(b[0]), "r"(b[1]));
}
__device__ __forceinline__ uint32_t packbf2(float x, float y) {
    __nv_bfloat162 t2(__float2bfloat16(x), __float2bfloat16(y));
    return *(uint32_t*)&t2;
}

// ============================================================================
// split: X(fp32) -> hi = bf16(X), lo = bf16(X - hi)
// ============================================================================
__global__ void __launch_bounds__(256) split_kernel(
    const float* __restrict__ X, __nv_bfloat16* __restrict__ H,
    __nv_bfloat16* __restrict__ L, int n4)
{
    int i = blockIdx.x * 256 + threadIdx.x;
    if (i >= n4) return;
    float4 v = ((const float4*)X)[i];
    __nv_bfloat16 h0 = __float2bfloat16(v.x);
    __nv_bfloat16 h1 = __float2bfloat16(v.y);
    __nv_bfloat16 h2 = __float2bfloat16(v.z);
    __nv_bfloat16 h3 = __float2bfloat16(v.w);
    __nv_bfloat16 l0 = __float2bfloat16(v.x - __bfloat162float(h0));
    __nv_bfloat16 l1 = __float2bfloat16(v.y - __bfloat162float(h1));
    __nv_bfloat16 l2 = __float2bfloat16(v.z - __bfloat162float(h2));
    __nv_bfloat16 l3 = __float2bfloat16(v.w - __bfloat162float(h3));
    __nv_bfloat162 hp0(h0, h1), hp1(h2, h3), lp0(l0, l1), lp1(l2, l3);
    ((uint2*)H)[i] = make_uint2(*(uint32_t*)&hp0, *(uint32_t*)&hp1);
    ((uint2*)L)[i] = make_uint2(*(uint32_t*)&lp0, *(uint32_t*)&lp1);
}

// ============================================================================
// mma.sync GEMM: C[M,N] = (Ah+Al)[M,K] @ (Bh+Bl)[N,K]^T + bias
// ============================================================================
#define TBM 128
#define TBN 128
#define TBK 32
#define TSTG 3
#define STG_BYTES 32768
#define TG_SMEM (TSTG * STG_BYTES)

__device__ __forceinline__ uint32_t sw_off(int r, int c) {
    return (uint32_t)(r * 64 + ((c ^ ((r >> 1) & 3)) << 4));
}

__device__ __forceinline__ void tg_load_stage(
    uint32_t sbuf, int t,
    const __nv_bfloat16* __restrict__ Ah, const __nv_bfloat16* __restrict__ Al,
    const __nv_bfloat16* __restrict__ Bh, const __nv_bfloat16* __restrict__ Bl,
    int rowBase, int colBase, int k0, int K)
{
#pragma unroll
    for (int j = 0; j < 8; j++) {
        int i   = j * 256 + t;
        int arr = i >> 9;
        int idx = i & 511;
        int r   = idx >> 2;
        int ch  = idx & 3;
        const __nv_bfloat16* base =
            (arr == 0) ? Ah : (arr == 1) ? Al : (arr == 2) ? Bh : Bl;
        int gr = ((arr < 2) ? rowBase : colBase) + r;
        cp16(sbuf + arr * 8192 + sw_off(r, ch),
             base + (size_t)gr * K + k0 + ch * 8);
    }
    asm volatile("cp.async.commit_group;" ::: "memory");
}

template <bool RELU, bool SPLIT>
__global__ void __launch_bounds__(256) tgemm_kernel(
    const __nv_bfloat16* __restrict__ Ah, const __nv_bfloat16* __restrict__ Al,
    const __nv_bfloat16* __restrict__ Bh, const __nv_bfloat16* __restrict__ Bl,
    const float* __restrict__ bias, float* __restrict__ C,
    __nv_bfloat16* __restrict__ Ch, __nv_bfloat16* __restrict__ Cl,
    int M, int N, int K)
{
    extern __shared__ __align__(16) char smem[];
    uint32_t sb = smem_u32(smem);
    const int t = threadIdx.x;
    const int w = t >> 5, lane = t & 31;
    const int wm = w >> 2;
    const int wn = w & 3;
    const int rowBase = blockIdx.y * TBM;
    const int colBase = blockIdx.x * TBN;
    const int KT = K / TBK;

    float acc[4][4][4];
#pragma unroll
    for (int mt = 0; mt < 4; mt++)
#pragma unroll
        for (int nt = 0; nt < 4; nt++)
#pragma unroll
            for (int e = 0; e < 4; e++) acc[mt][nt][e] = 0.f;

    tg_load_stage(sb, t, Ah, Al, Bh, Bl, rowBase, colBase, 0, K);
    tg_load_stage(sb + STG_BYTES, t, Ah, Al, Bh, Bl, rowBase, colBase, TBK, K);

    for (int kt = 0; kt < KT; kt++) {
        if (kt == KT - 1)
            asm volatile("cp.async.wait_group 0;" ::: "memory");
        else
            asm volatile("cp.async.wait_group 1;" ::: "memory");
        __syncthreads();
        if (kt + 2 < KT)
            tg_load_stage(sb + ((kt + 2) % TSTG) * STG_BYTES, t,
                          Ah, Al, Bh, Bl, rowBase, colBase, (kt + 2) * TBK, K);

        uint32_t sbase = sb + (kt % TSTG) * STG_BYTES;
#pragma unroll
        for (int ks = 0; ks < 2; ks++) {
            uint32_t ah[4][4], al[4][4], bh[4][2], bl[4][2];
            const int arow0  = wm * 64 + (lane & 15);
            const int achunk = ks * 2 + (lane >> 4);
#pragma unroll
            for (int mt = 0; mt < 4; mt++) {
                int r = arow0 + mt * 16;
                uint32_t off = sw_off(r, achunk);
                ldsm_x4(ah[mt][0], ah[mt][1], ah[mt][2], ah[mt][3], sbase + off);
                ldsm_x4(al[mt][0], al[mt][1], al[mt][2], al[mt][3], sbase + 8192 + off);
            }
            const int brow0  = wn * 32 + (lane & 7);
            const int bchunk = ks * 2 + (((lane & 15) >> 3) & 1);
#pragma unroll
            for (int nt = 0; nt < 4; nt++) {
                int r = brow0 + nt * 8;
                uint32_t off = sw_off(r, bchunk);
                ldsm_x2(bh[nt][0], bh[nt][1], sbase + 16384 + off);
                ldsm_x2(bl[nt][0], bl[nt][1], sbase + 24576 + off);
            }
#pragma unroll
            for (int mt = 0; mt < 4; mt++)
#pragma unroll
                for (int nt = 0; nt < 4; nt++) {
                    mma_bf16(acc[mt][nt], ah[mt], bh[nt]);
                    mma_bf16(acc[mt][nt], ah[mt], bl[nt]);
                    mma_bf16(acc[mt][nt], al[mt], bh[nt]);
                }
        }
    }

#pragma unroll
    for (int mt = 0; mt < 4; mt++) {
        int r0 = rowBase + wm * 64 + mt * 16 + (lane >> 2);
#pragma unroll
        for (int nt = 0; nt < 4; nt++) {
            int c = colBase + wn * 32 + nt * 8 + (lane & 3) * 2;
            float b0 = __ldg(&bias[c]), b1 = __ldg(&bias[c + 1]);
            float v0 = acc[mt][nt][0] + b0, v1 = acc[mt][nt][1] + b1;
            float v2 = acc[mt][nt][2] + b0, v3 = acc[mt][nt][3] + b1;
            if (RELU) {
                v0 = fmaxf(v0, 0.f); v1 = fmaxf(v1, 0.f);
                v2 = fmaxf(v2, 0.f); v3 = fmaxf(v3, 0.f);
            }
            if (SPLIT) {
                __nv_bfloat16 h0 = __float2bfloat16(v0), h1 = __float2bfloat16(v1);
                __nv_bfloat16 h2 = __float2bfloat16(v2), h3 = __float2bfloat16(v3);
                __nv_bfloat162 hp0(h0, h1), hp1(h2, h3);
                __nv_bfloat162 lp0(__float2bfloat16(v0 - __bfloat162float(h0)),
                                   __float2bfloat16(v1 - __bfloat162float(h1)));
                __nv_bfloat162 lp1(__float2bfloat16(v2 - __bfloat162float(h2)),
                                   __float2bfloat16(v3 - __bfloat162float(h3)));
                *(__nv_bfloat162*)(Ch + (size_t)r0 * N + c)       = hp0;
                *(__nv_bfloat162*)(Ch + (size_t)(r0 + 8) * N + c) = hp1;
                *(__nv_bfloat162*)(Cl + (size_t)r0 * N + c)       = lp0;
                *(__nv_bfloat162*)(Cl + (size_t)(r0 + 8) * N + c) = lp1;
            } else {
                *(float2*)(C + (size_t)r0 * N + c)       = make_float2(v0, v1);
                *(float2*)(C + (size_t)(r0 + 8) * N + c) = make_float2(v2, v3);
            }
        }
    }
}

// ============================================================================
// T5 relative-position bucket for displacement d = kcol - qrow
// ============================================================================
__device__ __forceinline__ int rel_bucket_d(int d)
{
    int ret = (d < 0) ? NHEAD : 0;
    int n   = abs(d);
    int b;
    if (n < 8) b = n;
    else {
        int j = (31 - __clz(n * n)) - 6;
        j = min(j, 7);
        b = 8 + j;
    }
    return ret + b;
}

// ============================================================================
// Fused flash attention.
// grid (8 q-tiles, 64 bh), 256 threads. Warp w owns 16 q rows.
// Q/K/V given as bf16 hi/lo, raw-reshaped [bh][lseq][64] flat buffers.
// Output: av (hi/lo) in the same flat layout.
// ============================================================================
#define AT_Q   0
#define AT_QL  16384
#define AT_KH  32768
#define AT_KL  49152
#define AT_VH  65536
#define AT_VL  81920
#define AT_LM  98304
#define AT_BD  102400
#define AT_SMEM (AT_BD + 8192)

__device__ __forceinline__ uint32_t swz128(int r, int c) {
    return (uint32_t)(r * 128 + ((c ^ (r & 7)) << 4));
}

__global__ void __launch_bounds__(256, 1) attn_fused_kernel(
    const __nv_bfloat16* __restrict__ QH, const __nv_bfloat16* __restrict__ QL,
    const __nv_bfloat16* __restrict__ KH, const __nv_bfloat16* __restrict__ KL,
    const __nv_bfloat16* __restrict__ VH, const __nv_bfloat16* __restrict__ VL,
    const float* __restrict__ rel, const int* __restrict__ pm,
    __nv_bfloat16* __restrict__ OH, __nv_bfloat16* __restrict__ OL)
{
    extern __shared__ __align__(16) char smem[];
    uint32_t sb = smem_u32(smem);
    float* lm_s = (float*)(smem + AT_LM);   // log(pm) per key, 1024
    float* bd_s = (float*)(smem + AT_BD);   // rel bias per displacement, 2047

    const int t = threadIdx.x, w = t >> 5, lane = t & 31;
    const int qt = blockIdx.x, bh = blockIdx.y;
    const int h = bh & (NHEAD - 1), b = bh >> 4;
    const size_t slab = (size_t)bh * (LSEQ * DHEAD);

    // ---- tables ----
    for (int i = t; i < LSEQ; i += 256)
        lm_s[i] = logf((float)pm[b * LSEQ + i]);
    for (int i = t; i < 2047; i += 256)
        bd_s[i] = rel[rel_bucket_d(i - 1023) * NHEAD + h];

    // ---- load Q tile + K/V tile 0 ----
    {
        size_t qbase = slab + (size_t)qt * 128 * DHEAD;
        for (int i = t; i < 1024; i += 256) {
            int r = i >> 3, c = i & 7;
            uint32_t off = swz128(r, c);
            size_t g = qbase + r * DHEAD + c * 8;
            cp16(sb + AT_Q  + off, QH + g);
            cp16(sb + AT_QL + off, QL + g);
        }
        for (int i = t; i < 1024; i += 256) {
            int r = i >> 3, c = i & 7;
            uint32_t off = swz128(r, c);
            size_t g = slab + r * DHEAD + c * 8;
            cp16(sb + AT_KH + off, KH + g);
            cp16(sb + AT_KL + off, KL + g);
            cp16(sb + AT_VH + off, VH + g);
            cp16(sb + AT_VL + off, VL + g);
        }
        asm volatile("cp.async.commit_group;" ::: "memory");
        asm volatile("cp.async.wait_group 0;" ::: "memory");
    }
    __syncthreads();

    // ---- Q fragments (kept in registers) ----
    uint32_t qfh[4][4], qfl[4][4];
    {
        int r = w * 16 + (lane & 15);
#pragma unroll
        for (int ks = 0; ks < 4; ks++) {
            int c = ks * 2 + (lane >> 4);
            uint32_t off = swz128(r, c);
            ldsm_x4(qfh[ks][0], qfh[ks][1], qfh[ks][2], qfh[ks][3], sb + AT_Q  + off);
            ldsm_x4(qfl[ks][0], qfl[ks][1], qfl[ks][2], qfl[ks][3], sb + AT_QL + off);
        }
    }

    float O[8][4];
#pragma unroll
    for (int nt = 0; nt < 8; nt++)
#pragma unroll
        for (int e = 0; e < 4; e++) O[nt][e] = 0.f;
    float m0 = -3.0e38f, m1 = -3.0e38f, l0 = 0.f, l1 = 0.f;

    const int r0 = qt * 128 + w * 16 + (lane >> 2);
    const int r1 = r0 + 8;

    for (int kt = 0; kt < 8; kt++) {
        // ---- S = Q K^T (3-product split) ----
        float S[16][4];
#pragma unroll
        for (int j = 0; j < 16; j++)
#pragma unroll
            for (int e = 0; e < 4; e++) S[j][e] = 0.f;

#pragma unroll
        for (int ks = 0; ks < 4; ks++) {
            const int rr = (lane & 7);
            const int cc = ks * 2 + ((lane >> 3) & 1);
#pragma unroll
            for (int j = 0; j < 16; j++) {
                uint32_t off = swz128(j * 8 + rr, cc);
                uint32_t kb[2], kl2[2];
                ldsm_x2(kb[0],  kb[1],  sb + AT_KH + off);
                ldsm_x2(kl2[0], kl2[1], sb + AT_KL + off);
                mma_bf16(S[j], qfh[ks], kb);
                mma_bf16(S[j], qfh[ks], kl2);
                mma_bf16(S[j], qfl[ks], kb);
            }
        }

        // ---- bias ----
        const int ktbase = kt * 128;
#pragma unroll
        for (int j = 0; j < 16; j++) {
            int c = ktbase + j * 8 + (lane & 3) * 2;
            float lc0 = lm_s[c], lc1 = lm_s[c + 1];
            S[j][0] += bd_s[c - r0 + 1023] + lc0;
            S[j][1] += bd_s[c + 1 - r0 + 1023] + lc1;
            S[j][2] += bd_s[c - r1 + 1023] + lc0;
            S[j][3] += bd_s[c + 1 - r1 + 1023] + lc1;
        }

        // ---- online softmax ----
        float tm0 = -3.0e38f, tm1 = -3.0e38f;
#pragma unroll
        for (int j = 0; j < 16; j++) {
            tm0 = fmaxf(tm0, fmaxf(S[j][0], S[j][1]));
            tm1 = fmaxf(tm1, fmaxf(S[j][2], S[j][3]));
        }
        tm0 = fmaxf(tm0, __shfl_xor_sync(0xffffffffu, tm0, 1));
        tm0 = fmaxf(tm0, __shfl_xor_sync(0xffffffffu, tm0, 2));
        tm1 = fmaxf(tm1, __shfl_xor_sync(0xffffffffu, tm1, 1));
        tm1 = fmaxf(tm1, __shfl_xor_sync(0xffffffffu, tm1, 2));
        float mn0 = fmaxf(m0, tm0), mn1 = fmaxf(m1, tm1);
        float a0 = __expf(m0 - mn0), a1 = __expf(m1 - mn1);
        m0 = mn0; m1 = mn1;

        float s0 = 0.f, s1 = 0.f;
#pragma unroll
        for (int j = 0; j < 16; j++) {
            S[j][0] = __expf(S[j][0] - mn0); s0 += S[j][0];
            S[j][1] = __expf(S[j][1] - mn0); s0 += S[j][1];
            S[j][2] = __expf(S[j][2] - mn1); s1 += S[j][2];
            S[j][3] = __expf(S[j][3] - mn1); s1 += S[j][3];
        }
        s0 += __shfl_xor_sync(0xffffffffu, s0, 1);
        s0 += __shfl_xor_sync(0xffffffffu, s0, 2);
        s1 += __shfl_xor_sync(0xffffffffu, s1, 1);
        s1 += __shfl_xor_sync(0xffffffffu, s1, 2);
        l0 = l0 * a0 + s0;
        l1 = l1 * a1 + s1;

#pragma unroll
        for (int nt = 0; nt < 8; nt++) {
            O[nt][0] *= a0; O[nt][1] *= a0;
            O[nt][2] *= a1; O[nt][3] *= a1;
        }

        // ---- O += P @ V (3-product split) ----
#pragma unroll
        for (int kk = 0; kk < 8; kk++) {
            float* p0 = S[2 * kk];
            float* p1 = S[2 * kk + 1];
            uint32_t ph[4], pl[4];
            {
                float e00 = p0[0], e01 = p0[1], e02 = p0[2], e03 = p0[3];
                float e10 = p1[0], e11 = p1[1], e12 = p1[2], e13 = p1[3];
                __nv_bfloat16 h00 = __float2bfloat16(e00), h01 = __float2bfloat16(e01);
                __nv_bfloat16 h02 = __float2bfloat16(e02), h03 = __float2bfloat16(e03);
                __nv_bfloat16 h10 = __float2bfloat16(e10), h11 = __float2bfloat16(e11);
                __nv_bfloat16 h12 = __float2bfloat16(e12), h13 = __float2bfloat16(e13);
                __nv_bfloat162 t0(h00, h01), t1(h02, h03), t2(h10, h11), t3(h12, h13);
                ph[0] = *(uint32_t*)&t0; ph[1] = *(uint32_t*)&t1;
                ph[2] = *(uint32_t*)&t2; ph[3] = *(uint32_t*)&t3;
                pl[0] = packbf2(e00 - __bfloat162float(h00), e01 - __bfloat162float(h01));
                pl[1] = packbf2(e02 - __bfloat162float(h02), e03 - __bfloat162float(h03));
                pl[2] = packbf2(e10 - __bfloat162float(h10), e11 - __bfloat162float(h11));
                pl[3] = packbf2(e12 - __bfloat162float(h12), e13 - __bfloat162float(h13));
            }
            const int rr = kk * 16 + (lane & 15);
#pragma unroll
            for (int nt = 0; nt < 8; nt++) {
                uint32_t off = swz128(rr, nt);
                uint32_t vb[2], vl2[2];
                ldsm_x2t(vb[0],  vb[1],  sb + AT_VH + off);
                ldsm_x2t(vl2[0], vl2[1], sb + AT_VL + off);
                mma_bf16(O[nt], ph, vb);
                mma_bf16(O[nt], ph, vl2);
                mma_bf16(O[nt], pl, vb);
            }
        }

        // ---- stage next K/V tile ----
        __syncthreads();
        if (kt < 7) {
            size_t kb = slab + (size_t)(kt + 1) * 128 * DHEAD;
            for (int i = t; i < 1024; i += 256) {
                int r = i >> 3, c = i & 7;
                uint32_t off = swz128(r, c);
                size_t g = kb + r * DHEAD + c * 8;
                cp16(sb + AT_KH + off, KH + g);
                cp16(sb + AT_KL + off, KL + g);
                cp16(sb + AT_VH + off, VH + g);
                cp16(sb + AT_VL + off, VL + g);
            }
            asm volatile("cp.async.commit_group;" ::: "memory");
            asm volatile("cp.async.wait_group 0;" ::: "memory");
        }
        __syncthreads();
    }

    // ---- epilogue: normalize, split hi/lo, store ----
    float inv0 = 1.f / l0, inv1 = 1.f / l1;
    size_t ob0 = slab + (size_t)(qt * 128 + w * 16 + (lane >> 2)) * DHEAD;
    size_t ob1 = ob0 + 8 * DHEAD;
#pragma unroll
    for (int nt = 0; nt < 8; nt++) {
        int c = nt * 8 + (lane & 3) * 2;
        float v0 = O[nt][0] * inv0, v1 = O[nt][1] * inv0;
        float v2 = O[nt][2] * inv1, v3 = O[nt][3] * inv1;
        __nv_bfloat16 h0 = __float2bfloat16(v0), h1 = __float2bfloat16(v1);
        __nv_bfloat16 h2 = __float2bfloat16(v2), h3 = __float2bfloat16(v3);
        __nv_bfloat162 hp0(h0, h1), hp1(h2, h3);
        *(__nv_bfloat162*)(OH + ob0 + c) = hp0;
        *(__nv_bfloat162*)(OH + ob1 + c) = hp1;
        *(__nv_bfloat162*)(OL + ob0 + c) =
            __nv_bfloat162(__float2bfloat16(v0 - __bfloat162float(h0)),
                           __float2bfloat16(v1 - __bfloat162float(h1)));
        *(__nv_bfloat162*)(OL + ob1 + c) =
            __nv_bfloat162(__float2bfloat16(v2 - __bfloat162float(h2)),
                           __float2bfloat16(v3 - __bfloat162float(h3)));
    }
}

// ============================================================================
// out = LayerNorm(A + B); optional bf16 hi/lo side output
// ============================================================================
template <bool SPLIT>
__global__ void __launch_bounds__(256) add_ln_kernel(
    const float* __restrict__ A, const float* __restrict__ B,
    float* __restrict__ out,
    __nv_bfloat16* __restrict__ OH, __nv_bfloat16* __restrict__ OL)
{
    __shared__ float sh[8];
    const size_t row = blockIdx.x;
    const int t = threadIdx.x;

    float4 a = ((const float4*)(A + row * DMODEL))[t];
    float4 b = ((const float4*)(B + row * DMODEL))[t];
    float4 x;
    x.x = a.x + b.x; x.y = a.y + b.y; x.z = a.z + b.z; x.w = a.w + b.w;

    float s = x.x + x.y + x.z + x.w;
#pragma unroll
    for (int o = 16; o; o >>= 1) s += __shfl_xor_sync(0xffffffffu, s, o);
    if ((t & 31) == 0) sh[t >> 5] = s;
    __syncthreads();
    float tot = sh[0];
#pragma unroll
    for (int i = 1; i < 8; i++) tot += sh[i];
    __syncthreads();
    float mean = tot * (1.f / DMODEL);

    float dx = x.x - mean, dy = x.y - mean, dz = x.z - mean, dw = x.w - mean;
    float s2 = dx * dx + dy * dy + dz * dz + dw * dw;
#pragma unroll
    for (int o = 16; o; o >>= 1) s2 += __shfl_xor_sync(0xffffffffu, s2, o);
    if ((t & 31) == 0) sh[t >> 5] = s2;
    __syncthreads();
    float tot2 = sh[0];
#pragma unroll
    for (int i = 1; i < 8; i++) tot2 += sh[i];
    float inv = rsqrtf(tot2 * (1.f / DMODEL));

    float4 o;
    o.x = dx * inv; o.y = dy * inv; o.z = dz * inv; o.w = dw * inv;
    ((float4*)(out + row * DMODEL))[t] = o;

    if (SPLIT) {
        __nv_bfloat16 h0 = __float2bfloat16(o.x), h1 = __float2bfloat16(o.y);
        __nv_bfloat16 h2 = __float2bfloat16(o.z), h3 = __float2bfloat16(o.w);
        __nv_bfloat162 hp0(h0, h1), hp1(h2, h3);
        __nv_bfloat162 lp0(__float2bfloat16(o.x - __bfloat162float(h0)),
                           __float2bfloat16(o.y - __bfloat162float(h1)));
        __nv_bfloat162 lp1(__float2bfloat16(o.z - __bfloat162float(h2)),
                           __float2bfloat16(o.w - __bfloat162float(h3)));
        size_t base = row * DMODEL + t * 4;
        *(__nv_bfloat162*)(OH + base)     = hp0;
        *(__nv_bfloat162*)(OH + base + 2) = hp1;
        *(__nv_bfloat162*)(OL + base)     = lp0;
        *(__nv_bfloat162*)(OL + base + 2) = lp1;
    }
}

// ============================================================================
// Launch sequence
// ============================================================================
extern "C" void kernel_launch(void* const* d_in, const int* in_sizes, int n_in,
                              void* d_out, int out_size)
{
    const float* x   = (const float*)d_in[0];
    const int*   pm  = (const int*)  d_in[1];
    const float* Wq  = (const float*)d_in[2];
    const float* bq  = (const float*)d_in[3];
    const float* Wk  = (const float*)d_in[4];
    const float* bk  = (const float*)d_in[5];
    const float* Wv  = (const float*)d_in[6];
    const float* bv  = (const float*)d_in[7];
    const float* Wo  = (const float*)d_in[8];
    const float* bo  = (const float*)d_in[9];
    const float* rel = (const float*)d_in[10];
    const float* W1  = (const float*)d_in[11];
    const float* b1  = (const float*)d_in[12];
    const float* W2  = (const float*)d_in[13];
    const float* b2  = (const float*)d_in[14];
    float* out = (float*)d_out;

    float *attp, *attout, *ff;
    cudaGetSymbolAddress((void**)&attp,   g_attp);
    cudaGetSymbolAddress((void**)&attout, g_attout);
    cudaGetSymbolAddress((void**)&ff,     g_ff);

    __nv_bfloat16 *xh, *xl, *wqh, *wql, *wkh, *wkl, *wvh, *wvl, *woh, *wol;
    __nv_bfloat16 *w1h, *w1l, *w2h, *w2l, *avh, *avl, *aoh, *aol, *h1h, *h1l;
    __nv_bfloat16 *qh, *ql, *kh, *kl, *vh, *vl;
    cudaGetSymbolAddress((void**)&xh,  g_xh);  cudaGetSymbolAddress((void**)&xl,  g_xl);
    cudaGetSymbolAddress((void**)&wqh, g_wqh); cudaGetSymbolAddress((void**)&wql, g_wql);
    cudaGetSymbolAddress((void**)&wkh, g_wkh); cudaGetSymbolAddress((void**)&wkl, g_wkl);
    cudaGetSymbolAddress((void**)&wvh, g_wvh); cudaGetSymbolAddress((void**)&wvl, g_wvl);
    cudaGetSymbolAddress((void**)&woh, g_woh); cudaGetSymbolAddress((void**)&wol, g_wol);
    cudaGetSymbolAddress((void**)&w1h, g_w1h); cudaGetSymbolAddress((void**)&w1l, g_w1l);
    cudaGetSymbolAddress((void**)&w2h, g_w2h); cudaGetSymbolAddress((void**)&w2l, g_w2l);
    cudaGetSymbolAddress((void**)&avh, g_avh); cudaGetSymbolAddress((void**)&avl, g_avl);
    cudaGetSymbolAddress((void**)&aoh, g_aoh); cudaGetSymbolAddress((void**)&aol, g_aol);
    cudaGetSymbolAddress((void**)&h1h, g_h1h); cudaGetSymbolAddress((void**)&h1l, g_h1l);
    cudaGetSymbolAddress((void**)&qh,  g_qh);  cudaGetSymbolAddress((void**)&ql,  g_ql);
    cudaGetSymbolAddress((void**)&kh,  g_kh);  cudaGetSymbolAddress((void**)&kl,  g_kl);
    cudaGetSymbolAddress((void**)&vh,  g_vh);  cudaGetSymbolAddress((void**)&vl,  g_vl);

    static bool attr_done = false;
    if (!attr_done) {
        cudaFuncSetAttribute(tgemm_kernel<false, false>,
                             cudaFuncAttributeMaxDynamicSharedMemorySize, TG_SMEM);
        cudaFuncSetAttribute(tgemm_kernel<false, true>,
                             cudaFuncAttributeMaxDynamicSharedMemorySize, TG_SMEM);
        cudaFuncSetAttribute(tgemm_kernel<true, true>,
                             cudaFuncAttributeMaxDynamicSharedMemorySize, TG_SMEM);
        cudaFuncSetAttribute(attn_fused_kernel,
                             cudaFuncAttributeMaxDynamicSharedMemorySize, AT_SMEM);
        attr_done = true;
    }

    dim3 blk(256);
    auto splits = [&](const float* src, __nv_bfloat16* H, __nv_bfloat16* L, size_t n) {
        int n4 = (int)(n / 4);
        split_kernel<<<(n4 + 255) / 256, blk>>>(src, H, L, n4);
    };

    // convert inputs / weights to bf16 hi/lo
    splits(x,  xh,  xl,  (size_t)MROWS * DMODEL);
    splits(Wq, wqh, wql, (size_t)DMODEL * DMODEL);
    splits(Wk, wkh, wkl, (size_t)DMODEL * DMODEL);
    splits(Wv, wvh, wvl, (size_t)DMODEL * DMODEL);
    splits(Wo, woh, wol, (size_t)DMODEL * DMODEL);
    splits(W1, w1h, w1l, (size_t)FFDIM * DMODEL);
    splits(W2, w2h, w2l, (size_t)DMODEL * FFDIM);

    // QKV projections -> bf16 hi/lo directly
    dim3 gQ(DMODEL / TBN, MROWS / TBM);
    tgemm_kernel<false, true><<<gQ, blk, TG_SMEM>>>(
        xh, xl, wqh, wql, bq, nullptr, qh, ql, MROWS, DMODEL, DMODEL);
    tgemm_kernel<false, true><<<gQ, blk, TG_SMEM>>>(
        xh, xl, wkh, wkl, bk, nullptr, kh, kl, MROWS, DMODEL, DMODEL);
    tgemm_kernel<false, true><<<gQ, blk, TG_SMEM>>>(
        xh, xl, wvh, wvl, bv, nullptr, vh, vl, MROWS, DMODEL, DMODEL);

    // fused attention -> avh/avl
    attn_fused_kernel<<<dim3(8, BHDIM), blk, AT_SMEM>>>(
        qh, ql, kh, kl, vh, vl, rel, pm, avh, avl);

    // O projection
    tgemm_kernel<false, false><<<gQ, blk, TG_SMEM>>>(
        avh, avl, woh, wol, bo, attp, nullptr, nullptr, MROWS, DMODEL, DMODEL);

    // residual + LN (+ split for FFN input)
    add_ln_kernel<true><<<MROWS, blk>>>(attp, x, attout, aoh, aol);

    // FFN
    dim3 g1(FFDIM / TBN, MROWS / TBM);
    tgemm_kernel<true, true><<<g1, blk, TG_SMEM>>>(
        aoh, aol, w1h, w1l, b1, nullptr, h1h, h1l, MROWS, FFDIM, DMODEL);
    dim3 g2(DMODEL / TBN, MROWS / TBM);
    tgemm_kernel<false, false><<<g2, blk, TG_SMEM>>>(
        h1h, h1l, w2h, w2l, b2, ff, nullptr, nullptr, MROWS, DMODEL, FFDIM);

    // final residual + LN
    add_ln_kernel<false><<<MROWS, blk>>>(ff, attout, out, nullptr, nullptr);
}

// round 5
// speedup vs baseline: 2.6913x; 1.0146x over previous
#include <cuda_runtime.h>
#include <cuda_bf16.h>
#include <math.h>
#include <stdint.h>

// ---------------------------------------------------------------------------
// EncoderBlock: B=4, L=1024, D=1024, F=4096, H=16, dh=64
// Round 5: fused QKV GEMM, 4-stage cp.async pipeline, bias hoist.
// ---------------------------------------------------------------------------

#define LSEQ 1024
#define DMODEL 1024
#define BATCH 4
#define NHEAD 16
#define DHEAD 64
#define FFDIM 4096
#define BHDIM 64
#define MROWS 4096

// ---- fp32 scratch ----------------------------------------------------------
__device__ float g_attp[BATCH * LSEQ * DMODEL];
__device__ float g_attout[BATCH * LSEQ * DMODEL];
__device__ float g_ff[BATCH * LSEQ * DMODEL];
__device__ float g_bqkv[3 * DMODEL];

// ---- bf16 hi/lo scratch -----------------------------------------------------
__device__ __nv_bfloat16 g_xh[MROWS * DMODEL],  g_xl[MROWS * DMODEL];
__device__ __nv_bfloat16 g_wqkvh[3 * DMODEL * DMODEL], g_wqkvl[3 * DMODEL * DMODEL];
__device__ __nv_bfloat16 g_woh[DMODEL * DMODEL], g_wol[DMODEL * DMODEL];
__device__ __nv_bfloat16 g_w1h[FFDIM * DMODEL],  g_w1l[FFDIM * DMODEL];
__device__ __nv_bfloat16 g_w2h[DMODEL * FFDIM],  g_w2l[DMODEL * FFDIM];
__device__ __nv_bfloat16 g_qkvh[3 * MROWS * DMODEL], g_qkvl[3 * MROWS * DMODEL];
__device__ __nv_bfloat16 g_avh[MROWS * DMODEL],  g_avl[MROWS * DMODEL];
__device__ __nv_bfloat16 g_aoh[MROWS * DMODEL],  g_aol[MROWS * DMODEL];
__device__ __nv_bfloat16 g_h1h[(size_t)MROWS * FFDIM], g_h1l[(size_t)MROWS * FFDIM];

// ============================================================================
// helpers
// ============================================================================
__device__ __forceinline__ uint32_t smem_u32(const void* p) {
    uint32_t a;
    asm("{ .reg .u64 t; cvta.to.shared.u64 t, %1; cvt.u32.u64 %0, t; }"
        : "=r"(a) : "l"(p));
    return a;
}
__device__ __forceinline__ void cp16(uint32_t dst, const void* src) {
    asm volatile("cp.async.cg.shared.global [%0], [%1], 16;" :: "r"(dst), "l"(src));
}
__device__ __forceinline__ void ldsm_x4(uint32_t& r0, uint32_t& r1,
                                        uint32_t& r2, uint32_t& r3, uint32_t a) {
    asm volatile("ldmatrix.sync.aligned.m8n8.x4.shared.b16 {%0,%1,%2,%3}, [%4];"
                 : "=r"(r0), "=r"(r1), "=r"(r2), "=r"(r3) : "r"(a));
}
__device__ __forceinline__ void ldsm_x2(uint32_t& r0, uint32_t& r1, uint32_t a) {
    asm volatile("ldmatrix.sync.aligned.m8n8.x2.shared.b16 {%0,%1}, [%2];"
                 : "=r"(r0), "=r"(r1) : "r"(a));
}
__device__ __forceinline__ void ldsm_x2t(uint32_t& r0, uint32_t& r1, uint32_t a) {
    asm volatile("ldmatrix.sync.aligned.m8n8.x2.trans.shared.b16 {%0,%1}, [%2];"
                 : "=r"(r0), "=r"(r1) : "r"(a));
}
__device__ __forceinline__ void mma_bf16(float* c, const uint32_t* a, const uint32_t* b) {
    asm volatile(
        "mma.sync.aligned.m16n8k16.row.col.f32.bf16.bf16.f32 "
        "{%0,%1,%2,%3}, {%4,%5,%6,%7}, {%8,%9}, {%0,%1,%2,%3};"
        : "+f"(c[0]), "+f"(c[1]), "+f"(c[2]), "+f"(c[3])
        : "r"(a[0]), "r"(a[1]), "r"(a[2]), "r"(a[3]), "r"(b[0]), "r"(b[1]));
}
__device__ __forceinline__ uint32_t packbf2(float x, float y) {
    __nv_bfloat162 t2(__float2bfloat16(x), __float2bfloat16(y));
    return *(uint32_t*)&t2;
}

// ============================================================================
// split: X(fp32) -> hi = bf16(X), lo = bf16(X - hi)
// ============================================================================
__global__ void __launch_bounds__(256) split_kernel(
    const float* __restrict__ X, __nv_bfloat16* __restrict__ H,
    __nv_bfloat16* __restrict__ L, int n4)
{
    int i = blockIdx.x * 256 + threadIdx.x;
    if (i >= n4) return;
    float4 v = ((const float4*)X)[i];
    __nv_bfloat16 h0 = __float2bfloat16(v.x);
    __nv_bfloat16 h1 = __float2bfloat16(v.y);
    __nv_bfloat16 h2 = __float2bfloat16(v.z);
    __nv_bfloat16 h3 = __float2bfloat16(v.w);
    __nv_bfloat162 hp0(h0, h1), hp1(h2, h3);
    __nv_bfloat162 lp0(__float2bfloat16(v.x - __bfloat162float(h0)),
                       __float2bfloat16(v.y - __bfloat162float(h1)));
    __nv_bfloat162 lp1(__float2bfloat16(v.z - __bfloat162float(h2)),
                       __float2bfloat16(v.w - __bfloat162float(h3)));
    ((uint2*)H)[i] = make_uint2(*(uint32_t*)&hp0, *(uint32_t*)&hp1);
    ((uint2*)L)[i] = make_uint2(*(uint32_t*)&lp0, *(uint32_t*)&lp1);
}

// ============================================================================
// split + pack Wq/Wk/Wv into one [3072,1024] hi/lo pair; pack biases.
// ============================================================================
__global__ void __launch_bounds__(256) splitw_qkv_kernel(
    const float* __restrict__ Wq, const float* __restrict__ Wk,
    const float* __restrict__ Wv,
    const float* __restrict__ bq, const float* __restrict__ bk,
    const float* __restrict__ bv,
    __nv_bfloat16* __restrict__ H, __nv_bfloat16* __restrict__ L,
    float* __restrict__ bpack)
{
    const int n4m = DMODEL * DMODEL / 4;     // 262144 per matrix
    int i = blockIdx.x * 256 + threadIdx.x;
    if (i < 3 * n4m) {
        int m = i / n4m, off = i - m * n4m;
        const float* W = (m == 0) ? Wq : (m == 1) ? Wk : Wv;
        float4 v = ((const float4*)W)[off];
        __nv_bfloat16 h0 = __float2bfloat16(v.x);
        __nv_bfloat16 h1 = __float2bfloat16(v.y);
        __nv_bfloat16 h2 = __float2bfloat16(v.z);
        __nv_bfloat16 h3 = __float2bfloat16(v.w);
        __nv_bfloat162 hp0(h0, h1), hp1(h2, h3);
        __nv_bfloat162 lp0(__float2bfloat16(v.x - __bfloat162float(h0)),
                           __float2bfloat16(v.y - __bfloat162float(h1)));
        __nv_bfloat162 lp1(__float2bfloat16(v.z - __bfloat162float(h2)),
                           __float2bfloat16(v.w - __bfloat162float(h3)));
        ((uint2*)H)[i] = make_uint2(*(uint32_t*)&hp0, *(uint32_t*)&hp1);
        ((uint2*)L)[i] = make_uint2(*(uint32_t*)&lp0, *(uint32_t*)&lp1);
    }
    if (i < 3 * DMODEL) {
        float b = (i < DMODEL) ? bq[i] : (i < 2 * DMODEL) ? bk[i - DMODEL]
                                                          : bv[i - 2 * DMODEL];
        bpack[i] = b;
    }
}

// ============================================================================
// mma.sync GEMM: C[M,N] = (Ah+Al)[M,K] @ (Bh+Bl)[N,K]^T + bias
// BM=BN=128, BK=32, 4-stage cp.async pipeline (prefetch distance 3).
// OUT: 0 = fp32 C; 1 = bf16 hi/lo (Ch/Cl); 2 = QKV scatter into qkv slab.
// ============================================================================
#define TBM 128
#define TBN 128
#define TBK 32
#define TSTG 4
#define STG_BYTES 32768
#define TG_SMEM (TSTG * STG_BYTES)

__device__ __forceinline__ uint32_t sw_off(int r, int c) {
    return (uint32_t)(r * 64 + ((c ^ ((r >> 1) & 3)) << 4));
}

__device__ __forceinline__ void tg_load_stage(
    uint32_t sbuf, int t,
    const __nv_bfloat16* __restrict__ Ah, const __nv_bfloat16* __restrict__ Al,
    const __nv_bfloat16* __restrict__ Bh, const __nv_bfloat16* __restrict__ Bl,
    int rowBase, int colBase, int k0, int K)
{
#pragma unroll
    for (int j = 0; j < 8; j++) {
        int i   = j * 256 + t;
        int arr = i >> 9;
        int idx = i & 511;
        int r   = idx >> 2;
        int ch  = idx & 3;
        const __nv_bfloat16* base =
            (arr == 0) ? Ah : (arr == 1) ? Al : (arr == 2) ? Bh : Bl;
        int gr = ((arr < 2) ? rowBase : colBase) + r;
        cp16(sbuf + arr * 8192 + sw_off(r, ch),
             base + (size_t)gr * K + k0 + ch * 8);
    }
    asm volatile("cp.async.commit_group;" ::: "memory");
}

template <bool RELU, int OUT>
__global__ void __launch_bounds__(256) tgemm_kernel(
    const __nv_bfloat16* __restrict__ Ah, const __nv_bfloat16* __restrict__ Al,
    const __nv_bfloat16* __restrict__ Bh, const __nv_bfloat16* __restrict__ Bl,
    const float* __restrict__ bias, float* __restrict__ C,
    __nv_bfloat16* __restrict__ Ch, __nv_bfloat16* __restrict__ Cl,
    int M, int N, int K)
{
    extern __shared__ __align__(16) char smem[];
    uint32_t sb = smem_u32(smem);
    const int t = threadIdx.x;
    const int w = t >> 5, lane = t & 31;
    const int wm = w >> 2;
    const int wn = w & 3;
    const int rowBase = blockIdx.y * TBM;
    const int colBase = blockIdx.x * TBN;
    const int KT = K / TBK;

    float acc[4][4][4];
#pragma unroll
    for (int mt = 0; mt < 4; mt++)
#pragma unroll
        for (int nt = 0; nt < 4; nt++)
#pragma unroll
            for (int e = 0; e < 4; e++) acc[mt][nt][e] = 0.f;

    tg_load_stage(sb,                 t, Ah, Al, Bh, Bl, rowBase, colBase, 0 * TBK, K);
    tg_load_stage(sb + 1 * STG_BYTES, t, Ah, Al, Bh, Bl, rowBase, colBase, 1 * TBK, K);
    tg_load_stage(sb + 2 * STG_BYTES, t, Ah, Al, Bh, Bl, rowBase, colBase, 2 * TBK, K);

    for (int kt = 0; kt < KT; kt++) {
        asm volatile("cp.async.wait_group 2;" ::: "memory");
        __syncthreads();
        if (kt + 3 < KT)
            tg_load_stage(sb + ((kt + 3) & 3) * STG_BYTES, t,
                          Ah, Al, Bh, Bl, rowBase, colBase, (kt + 3) * TBK, K);

        uint32_t sbase = sb + (kt & 3) * STG_BYTES;
#pragma unroll
        for (int ks = 0; ks < 2; ks++) {
            uint32_t ah[4][4], al[4][4], bh[4][2], bl[4][2];
            const int arow0  = wm * 64 + (lane & 15);
            const int achunk = ks * 2 + (lane >> 4);
#pragma unroll
            for (int mt = 0; mt < 4; mt++) {
                int r = arow0 + mt * 16;
                uint32_t off = sw_off(r, achunk);
                ldsm_x4(ah[mt][0], ah[mt][1], ah[mt][2], ah[mt][3], sbase + off);
                ldsm_x4(al[mt][0], al[mt][1], al[mt][2], al[mt][3], sbase + 8192 + off);
            }
            const int brow0  = wn * 32 + (lane & 7);
            const int bchunk = ks * 2 + (((lane & 15) >> 3) & 1);
#pragma unroll
            for (int nt = 0; nt < 4; nt++) {
                int r = brow0 + nt * 8;
                uint32_t off = sw_off(r, bchunk);
                ldsm_x2(bh[nt][0], bh[nt][1], sbase + 16384 + off);
                ldsm_x2(bl[nt][0], bl[nt][1], sbase + 24576 + off);
            }
#pragma unroll
            for (int mt = 0; mt < 4; mt++)
#pragma unroll
                for (int nt = 0; nt < 4; nt++) {
                    mma_bf16(acc[mt][nt], ah[mt], bh[nt]);
                    mma_bf16(acc[mt][nt], ah[mt], bl[nt]);
                    mma_bf16(acc[mt][nt], al[mt], bh[nt]);
                }
        }
    }

    // Epilogue (nt outer: bias + target hoisted per column pair)
#pragma unroll
    for (int nt = 0; nt < 4; nt++) {
        int c = colBase + wn * 32 + nt * 8 + (lane & 3) * 2;
        float b0 = __ldg(&bias[c]), b1 = __ldg(&bias[c + 1]);
        // QKV scatter target
        __nv_bfloat16* qh_t = Ch;
        __nv_bfloat16* ql_t = Cl;
        int cc = c;
        int on = N;
        if (OUT == 2) {
            int sel = c >> 10;                       // 0=q, 1=k, 2=v
            qh_t = Ch + (size_t)sel * MROWS * DMODEL;
            ql_t = Cl + (size_t)sel * MROWS * DMODEL;
            cc = c & 1023;
            on = DMODEL;
        }
#pragma unroll
        for (int mt = 0; mt < 4; mt++) {
            int r0 = rowBase + wm * 64 + mt * 16 + (lane >> 2);
            float v0 = acc[mt][nt][0] + b0, v1 = acc[mt][nt][1] + b1;
            float v2 = acc[mt][nt][2] + b0, v3 = acc[mt][nt][3] + b1;
            if (RELU) {
                v0 = fmaxf(v0, 0.f); v1 = fmaxf(v1, 0.f);
                v2 = fmaxf(v2, 0.f); v3 = fmaxf(v3, 0.f);
            }
            if (OUT == 0) {
                *(float2*)(C + (size_t)r0 * N + c)       = make_float2(v0, v1);
                *(float2*)(C + (size_t)(r0 + 8) * N + c) = make_float2(v2, v3);
            } else {
                __nv_bfloat16 h0 = __float2bfloat16(v0), h1 = __float2bfloat16(v1);
                __nv_bfloat16 h2 = __float2bfloat16(v2), h3 = __float2bfloat16(v3);
                __nv_bfloat162 hp0(h0, h1), hp1(h2, h3);
                __nv_bfloat162 lp0(__float2bfloat16(v0 - __bfloat162float(h0)),
                                   __float2bfloat16(v1 - __bfloat162float(h1)));
                __nv_bfloat162 lp1(__float2bfloat16(v2 - __bfloat162float(h2)),
                                   __float2bfloat16(v3 - __bfloat162float(h3)));
                *(__nv_bfloat162*)(qh_t + (size_t)r0 * on + cc)       = hp0;
                *(__nv_bfloat162*)(qh_t + (size_t)(r0 + 8) * on + cc) = hp1;
                *(__nv_bfloat162*)(ql_t + (size_t)r0 * on + cc)       = lp0;
                *(__nv_bfloat162*)(ql_t + (size_t)(r0 + 8) * on + cc) = lp1;
            }
        }
    }
}

// ============================================================================
// T5 relative-position bucket for displacement d
// ============================================================================
__device__ __forceinline__ int rel_bucket_d(int d)
{
    int ret = (d < 0) ? NHEAD : 0;
    int n   = abs(d);
    int b;
    if (n < 8) b = n;
    else {
        int j = (31 - __clz(n * n)) - 6;
        j = min(j, 7);
        b = 8 + j;
    }
    return ret + b;
}

// ============================================================================
// Fused flash attention (unchanged from R4)
// ============================================================================
#define AT_Q   0
#define AT_QL  16384
#define AT_KH  32768
#define AT_KL  49152
#define AT_VH  65536
#define AT_VL  81920
#define AT_LM  98304
#define AT_BD  102400
#define AT_SMEM (AT_BD + 8192)

__device__ __forceinline__ uint32_t swz128(int r, int c) {
    return (uint32_t)(r * 128 + ((c ^ (r & 7)) << 4));
}

__global__ void __launch_bounds__(256, 1) attn_fused_kernel(
    const __nv_bfloat16* __restrict__ QH, const __nv_bfloat16* __restrict__ QL,
    const __nv_bfloat16* __restrict__ KH, const __nv_bfloat16* __restrict__ KL,
    const __nv_bfloat16* __restrict__ VH, const __nv_bfloat16* __restrict__ VL,
    const float* __restrict__ rel, const int* __restrict__ pm,
    __nv_bfloat16* __restrict__ OH, __nv_bfloat16* __restrict__ OL)
{
    extern __shared__ __align__(16) char smem[];
    uint32_t sb = smem_u32(smem);
    float* lm_s = (float*)(smem + AT_LM);
    float* bd_s = (float*)(smem + AT_BD);

    const int t = threadIdx.x, w = t >> 5, lane = t & 31;
    const int qt = blockIdx.x, bh = blockIdx.y;
    const int h = bh & (NHEAD - 1), b = bh >> 4;
    const size_t slab = (size_t)bh * (LSEQ * DHEAD);

    for (int i = t; i < LSEQ; i += 256)
        lm_s[i] = logf((float)pm[b * LSEQ + i]);
    for (int i = t; i < 2047; i += 256)
        bd_s[i] = rel[rel_bucket_d(i - 1023) * NHEAD + h];

    {
        size_t qbase = slab + (size_t)qt * 128 * DHEAD;
        for (int i = t; i < 1024; i += 256) {
            int r = i >> 3, c = i & 7;
            uint32_t off = swz128(r, c);
            size_t g = qbase + r * DHEAD + c * 8;
            cp16(sb + AT_Q  + off, QH + g);
            cp16(sb + AT_QL + off, QL + g);
        }
        for (int i = t; i < 1024; i += 256) {
            int r = i >> 3, c = i & 7;
            uint32_t off = swz128(r, c);
            size_t g = slab + r * DHEAD + c * 8;
            cp16(sb + AT_KH + off, KH + g);
            cp16(sb + AT_KL + off, KL + g);
            cp16(sb + AT_VH + off, VH + g);
            cp16(sb + AT_VL + off, VL + g);
        }
        asm volatile("cp.async.commit_group;" ::: "memory");
        asm volatile("cp.async.wait_group 0;" ::: "memory");
    }
    __syncthreads();

    uint32_t qfh[4][4], qfl[4][4];
    {
        int r = w * 16 + (lane & 15);
#pragma unroll
        for (int ks = 0; ks < 4; ks++) {
            int c = ks * 2 + (lane >> 4);
            uint32_t off = swz128(r, c);
            ldsm_x4(qfh[ks][0], qfh[ks][1], qfh[ks][2], qfh[ks][3], sb + AT_Q  + off);
            ldsm_x4(qfl[ks][0], qfl[ks][1], qfl[ks][2], qfl[ks][3], sb + AT_QL + off);
        }
    }

    float O[8][4];
#pragma unroll
    for (int nt = 0; nt < 8; nt++)
#pragma unroll
        for (int e = 0; e < 4; e++) O[nt][e] = 0.f;
    float m0 = -3.0e38f, m1 = -3.0e38f, l0 = 0.f, l1 = 0.f;

    const int r0 = qt * 128 + w * 16 + (lane >> 2);
    const int r1 = r0 + 8;

    for (int kt = 0; kt < 8; kt++) {
        float S[16][4];
#pragma unroll
        for (int j = 0; j < 16; j++)
#pragma unroll
            for (int e = 0; e < 4; e++) S[j][e] = 0.f;

#pragma unroll
        for (int ks = 0; ks < 4; ks++) {
            const int rr = (lane & 7);
            const int cc = ks * 2 + ((lane >> 3) & 1);
#pragma unroll
            for (int j = 0; j < 16; j++) {
                uint32_t off = swz128(j * 8 + rr, cc);
                uint32_t kb[2], kl2[2];
                ldsm_x2(kb[0],  kb[1],  sb + AT_KH + off);
                ldsm_x2(kl2[0], kl2[1], sb + AT_KL + off);
                mma_bf16(S[j], qfh[ks], kb);
                mma_bf16(S[j], qfh[ks], kl2);
                mma_bf16(S[j], qfl[ks], kb);
            }
        }

        const int ktbase = kt * 128;
#pragma unroll
        for (int j = 0; j < 16; j++) {
            int c = ktbase + j * 8 + (lane & 3) * 2;
            float lc0 = lm_s[c], lc1 = lm_s[c + 1];
            S[j][0] += bd_s[c - r0 + 1023] + lc0;
            S[j][1] += bd_s[c + 1 - r0 + 1023] + lc1;
            S[j][2] += bd_s[c - r1 + 1023] + lc0;
            S[j][3] += bd_s[c + 1 - r1 + 1023] + lc1;
        }

        float tm0 = -3.0e38f, tm1 = -3.0e38f;
#pragma unroll
        for (int j = 0; j < 16; j++) {
            tm0 = fmaxf(tm0, fmaxf(S[j][0], S[j][1]));
            tm1 = fmaxf(tm1, fmaxf(S[j][2], S[j][3]));
        }
        tm0 = fmaxf(tm0, __shfl_xor_sync(0xffffffffu, tm0, 1));
        tm0 = fmaxf(tm0, __shfl_xor_sync(0xffffffffu, tm0, 2));
        tm1 = fmaxf(tm1, __shfl_xor_sync(0xffffffffu, tm1, 1));
        tm1 = fmaxf(tm1, __shfl_xor_sync(0xffffffffu, tm1, 2));
        float mn0 = fmaxf(m0, tm0), mn1 = fmaxf(m1, tm1);
        float a0 = __expf(m0 - mn0), a1 = __expf(m1 - mn1);
        m0 = mn0; m1 = mn1;

        float s0 = 0.f, s1 = 0.f;
#pragma unroll
        for (int j = 0; j < 16; j++) {
            S[j][0] = __expf(S[j][0] - mn0); s0 += S[j][0];
            S[j][1] = __expf(S[j][1] - mn0); s0 += S[j][1];
            S[j][2] = __expf(S[j][2] - mn1); s1 += S[j][2];
            S[j][3] = __expf(S[j][3] - mn1); s1 += S[j][3];
        }
        s0 += __shfl_xor_sync(0xffffffffu, s0, 1);
        s0 += __shfl_xor_sync(0xffffffffu, s0, 2);
        s1 += __shfl_xor_sync(0xffffffffu, s1, 1);
        s1 += __shfl_xor_sync(0xffffffffu, s1, 2);
        l0 = l0 * a0 + s0;
        l1 = l1 * a1 + s1;

#pragma unroll
        for (int nt = 0; nt < 8; nt++) {
            O[nt][0] *= a0; O[nt][1] *= a0;
            O[nt][2] *= a1; O[nt][3] *= a1;
        }

#pragma unroll
        for (int kk = 0; kk < 8; kk++) {
            float* p0 = S[2 * kk];
            float* p1 = S[2 * kk + 1];
            uint32_t ph[4], pl[4];
            {
                __nv_bfloat16 h00 = __float2bfloat16(p0[0]), h01 = __float2bfloat16(p0[1]);
                __nv_bfloat16 h02 = __float2bfloat16(p0[2]), h03 = __float2bfloat16(p0[3]);
                __nv_bfloat16 h10 = __float2bfloat16(p1[0]), h11 = __float2bfloat16(p1[1]);
                __nv_bfloat16 h12 = __float2bfloat16(p1[2]), h13 = __float2bfloat16(p1[3]);
                __nv_bfloat162 t0(h00, h01), t1(h02, h03), t2(h10, h11), t3(h12, h13);
                ph[0] = *(uint32_t*)&t0; ph[1] = *(uint32_t*)&t1;
                ph[2] = *(uint32_t*)&t2; ph[3] = *(uint32_t*)&t3;
                pl[0] = packbf2(p0[0] - __bfloat162float(h00), p0[1] - __bfloat162float(h01));
                pl[1] = packbf2(p0[2] - __bfloat162float(h02), p0[3] - __bfloat162float(h03));
                pl[2] = packbf2(p1[0] - __bfloat162float(h10), p1[1] - __bfloat162float(h11));
                pl[3] = packbf2(p1[2] - __bfloat162float(h12), p1[3] - __bfloat162float(h13));
            }
            const int rr = kk * 16 + (lane & 15);
#pragma unroll
            for (int nt = 0; nt < 8; nt++) {
                uint32_t off = swz128(rr, nt);
                uint32_t vb[2], vl2[2];
                ldsm_x2t(vb[0],  vb[1],  sb + AT_VH + off);
                ldsm_x2t(vl2[0], vl2[1], sb + AT_VL + off);
                mma_bf16(O[nt], ph, vb);
                mma_bf16(O[nt], ph, vl2);
                mma_bf16(O[nt], pl, vb);
            }
        }

        __syncthreads();
        if (kt < 7) {
            size_t kb = slab + (size_t)(kt + 1) * 128 * DHEAD;
            for (int i = t; i < 1024; i += 256) {
                int r = i >> 3, c = i & 7;
                uint32_t off = swz128(r, c);
                size_t g = kb + r * DHEAD + c * 8;
                cp16(sb + AT_KH + off, KH + g);
                cp16(sb + AT_KL + off, KL + g);
                cp16(sb + AT_VH + off, VH + g);
                cp16(sb + AT_VL + off, VL + g);
            }
            asm volatile("cp.async.commit_group;" ::: "memory");
            asm volatile("cp.async.wait_group 0;" ::: "memory");
        }
        __syncthreads();
    }

    float inv0 = 1.f / l0, inv1 = 1.f / l1;
    size_t ob0 = slab + (size_t)(qt * 128 + w * 16 + (lane >> 2)) * DHEAD;
    size_t ob1 = ob0 + 8 * DHEAD;
#pragma unroll
    for (int nt = 0; nt < 8; nt++) {
        int c = nt * 8 + (lane & 3) * 2;
        float v0 = O[nt][0] * inv0, v1 = O[nt][1] * inv0;
        float v2 = O[nt][2] * inv1, v3 = O[nt][3] * inv1;
        __nv_bfloat16 h0 = __float2bfloat16(v0), h1 = __float2bfloat16(v1);
        __nv_bfloat16 h2 = __float2bfloat16(v2), h3 = __float2bfloat16(v3);
        __nv_bfloat162 hp0(h0, h1), hp1(h2, h3);
        *(__nv_bfloat162*)(OH + ob0 + c) = hp0;
        *(__nv_bfloat162*)(OH + ob1 + c) = hp1;
        *(__nv_bfloat162*)(OL + ob0 + c) =
            __nv_bfloat162(__float2bfloat16(v0 - __bfloat162float(h0)),
                           __float2bfloat16(v1 - __bfloat162float(h1)));
        *(__nv_bfloat162*)(OL + ob1 + c) =
            __nv_bfloat162(__float2bfloat16(v2 - __bfloat162float(h2)),
                           __float2bfloat16(v3 - __bfloat162float(h3)));
    }
}

// ============================================================================
// out = LayerNorm(A + B); optional bf16 hi/lo side output
// ============================================================================
template <bool SPLIT>
__global__ void __launch_bounds__(256) add_ln_kernel(
    const float* __restrict__ A, const float* __restrict__ B,
    float* __restrict__ out,
    __nv_bfloat16* __restrict__ OH, __nv_bfloat16* __restrict__ OL)
{
    __shared__ float sh[8];
    const size_t row = blockIdx.x;
    const int t = threadIdx.x;

    float4 a = ((const float4*)(A + row * DMODEL))[t];
    float4 b = ((const float4*)(B + row * DMODEL))[t];
    float4 x;
    x.x = a.x + b.x; x.y = a.y + b.y; x.z = a.z + b.z; x.w = a.w + b.w;

    float s = x.x + x.y + x.z + x.w;
#pragma unroll
    for (int o = 16; o; o >>= 1) s += __shfl_xor_sync(0xffffffffu, s, o);
    if ((t & 31) == 0) sh[t >> 5] = s;
    __syncthreads();
    float tot = sh[0];
#pragma unroll
    for (int i = 1; i < 8; i++) tot += sh[i];
    __syncthreads();
    float mean = tot * (1.f / DMODEL);

    float dx = x.x - mean, dy = x.y - mean, dz = x.z - mean, dw = x.w - mean;
    float s2 = dx * dx + dy * dy + dz * dz + dw * dw;
#pragma unroll
    for (int o = 16; o; o >>= 1) s2 += __shfl_xor_sync(0xffffffffu, s2, o);
    if ((t & 31) == 0) sh[t >> 5] = s2;
    __syncthreads();
    float tot2 = sh[0];
#pragma unroll
    for (int i = 1; i < 8; i++) tot2 += sh[i];
    float inv = rsqrtf(tot2 * (1.f / DMODEL));

    float4 o;
    o.x = dx * inv; o.y = dy * inv; o.z = dz * inv; o.w = dw * inv;
    ((float4*)(out + row * DMODEL))[t] = o;

    if (SPLIT) {
        __nv_bfloat16 h0 = __float2bfloat16(o.x), h1 = __float2bfloat16(o.y);
        __nv_bfloat16 h2 = __float2bfloat16(o.z), h3 = __float2bfloat16(o.w);
        __nv_bfloat162 hp0(h0, h1), hp1(h2, h3);
        __nv_bfloat162 lp0(__float2bfloat16(o.x - __bfloat162float(h0)),
                           __float2bfloat16(o.y - __bfloat162float(h1)));
        __nv_bfloat162 lp1(__float2bfloat16(o.z - __bfloat162float(h2)),
                           __float2bfloat16(o.w - __bfloat162float(h3)));
        size_t base = row * DMODEL + t * 4;
        *(__nv_bfloat162*)(OH + base)     = hp0;
        *(__nv_bfloat162*)(OH + base + 2) = hp1;
        *(__nv_bfloat162*)(OL + base)     = lp0;
        *(__nv_bfloat162*)(OL + base + 2) = lp1;
    }
}

// ============================================================================
// Launch sequence
// ============================================================================
extern "C" void kernel_launch(void* const* d_in, const int* in_sizes, int n_in,
                              void* d_out, int out_size)
{
    const float* x   = (const float*)d_in[0];
    const int*   pm  = (const int*)  d_in[1];
    const float* Wq  = (const float*)d_in[2];
    const float* bq  = (const float*)d_in[3];
    const float* Wk  = (const float*)d_in[4];
    const float* bk  = (const float*)d_in[5];
    const float* Wv  = (const float*)d_in[6];
    const float* bv  = (const float*)d_in[7];
    const float* Wo  = (const float*)d_in[8];
    const float* bo  = (const float*)d_in[9];
    const float* rel = (const float*)d_in[10];
    const float* W1  = (const float*)d_in[11];
    const float* b1  = (const float*)d_in[12];
    const float* W2  = (const float*)d_in[13];
    const float* b2  = (const float*)d_in[14];
    float* out = (float*)d_out;

    float *attp, *attout, *ff, *bqkv;
    cudaGetSymbolAddress((void**)&attp,   g_attp);
    cudaGetSymbolAddress((void**)&attout, g_attout);
    cudaGetSymbolAddress((void**)&ff,     g_ff);
    cudaGetSymbolAddress((void**)&bqkv,   g_bqkv);

    __nv_bfloat16 *xh, *xl, *wqkvh, *wqkvl, *woh, *wol;
    __nv_bfloat16 *w1h, *w1l, *w2h, *w2l, *avh, *avl, *aoh, *aol, *h1h, *h1l;
    __nv_bfloat16 *qkvh, *qkvl;
    cudaGetSymbolAddress((void**)&xh,    g_xh);    cudaGetSymbolAddress((void**)&xl,    g_xl);
    cudaGetSymbolAddress((void**)&wqkvh, g_wqkvh); cudaGetSymbolAddress((void**)&wqkvl, g_wqkvl);
    cudaGetSymbolAddress((void**)&woh,   g_woh);   cudaGetSymbolAddress((void**)&wol,   g_wol);
    cudaGetSymbolAddress((void**)&w1h,   g_w1h);   cudaGetSymbolAddress((void**)&w1l,   g_w1l);
    cudaGetSymbolAddress((void**)&w2h,   g_w2h);   cudaGetSymbolAddress((void**)&w2l,   g_w2l);
    cudaGetSymbolAddress((void**)&avh,   g_avh);   cudaGetSymbolAddress((void**)&avl,   g_avl);
    cudaGetSymbolAddress((void**)&aoh,   g_aoh);   cudaGetSymbolAddress((void**)&aol,   g_aol);
    cudaGetSymbolAddress((void**)&h1h,   g_h1h);   cudaGetSymbolAddress((void**)&h1l,   g_h1l);
    cudaGetSymbolAddress((void**)&qkvh,  g_qkvh);  cudaGetSymbolAddress((void**)&qkvl,  g_qkvl);

    static bool attr_done = false;
    if (!attr_done) {
        cudaFuncSetAttribute(tgemm_kernel<false, 0>,
                             cudaFuncAttributeMaxDynamicSharedMemorySize, TG_SMEM);
        cudaFuncSetAttribute(tgemm_kernel<false, 1>,
                             cudaFuncAttributeMaxDynamicSharedMemorySize, TG_SMEM);
        cudaFuncSetAttribute(tgemm_kernel<false, 2>,
                             cudaFuncAttributeMaxDynamicSharedMemorySize, TG_SMEM);
        cudaFuncSetAttribute(tgemm_kernel<true, 1>,
                             cudaFuncAttributeMaxDynamicSharedMemorySize, TG_SMEM);
        cudaFuncSetAttribute(attn_fused_kernel,
                             cudaFuncAttributeMaxDynamicSharedMemorySize, AT_SMEM);
        attr_done = true;
    }

    dim3 blk(256);

    // L1: split x
    split_kernel<<<(MROWS * DMODEL / 4 + 255) / 256, blk>>>(
        x, xh, xl, MROWS * DMODEL / 4);
    // L2: split+pack Wqkv + bias
    splitw_qkv_kernel<<<(3 * DMODEL * DMODEL / 4 + 255) / 256, blk>>>(
        Wq, Wk, Wv, bq, bk, bv, wqkvh, wqkvl, bqkv);
    // L3-5: split Wo, W1, W2
    split_kernel<<<(DMODEL * DMODEL / 4 + 255) / 256, blk>>>(
        Wo, woh, wol, DMODEL * DMODEL / 4);
    split_kernel<<<(FFDIM * DMODEL / 4 + 255) / 256, blk>>>(
        W1, w1h, w1l, FFDIM * DMODEL / 4);
    split_kernel<<<(DMODEL * FFDIM / 4 + 255) / 256, blk>>>(
        W2, w2h, w2l, DMODEL * FFDIM / 4);

    // L6: fused QKV projection (profiled launch)
    dim3 gqkv(3 * DMODEL / TBN, MROWS / TBM);    // (24, 32)
    tgemm_kernel<false, 2><<<gqkv, blk, TG_SMEM>>>(
        xh, xl, wqkvh, wqkvl, bqkv, nullptr, qkvh, qkvl, MROWS, 3 * DMODEL, DMODEL);

    // attention
    const size_t SLAB = (size_t)MROWS * DMODEL;
    attn_fused_kernel<<<dim3(8, BHDIM), blk, AT_SMEM>>>(
        qkvh, qkvl, qkvh + SLAB, qkvl + SLAB, qkvh + 2 * SLAB, qkvl + 2 * SLAB,
        rel, pm, avh, avl);

    // O projection
    dim3 gO(DMODEL / TBN, MROWS / TBM);
    tgemm_kernel<false, 0><<<gO, blk, TG_SMEM>>>(
        avh, avl, woh, wol, bo, attp, nullptr, nullptr, MROWS, DMODEL, DMODEL);

    // residual + LN (+ split)
    add_ln_kernel<true><<<MROWS, blk>>>(attp, x, attout, aoh, aol);

    // FFN
    dim3 g1(FFDIM / TBN, MROWS / TBM);
    tgemm_kernel<true, 1><<<g1, blk, TG_SMEM>>>(
        aoh, aol, w1h, w1l, b1, nullptr, h1h, h1l, MROWS, FFDIM, DMODEL);
    dim3 g2(DMODEL / TBN, MROWS / TBM);
    tgemm_kernel<false, 0><<<g2, blk, TG_SMEM>>>(
        h1h, h1l, w2h, w2l, b2, ff, nullptr, nullptr, MROWS, DMODEL, FFDIM);

    // final residual + LN
    add_ln_kernel<false><<<MROWS, blk>>>(ff, attout, out, nullptr, nullptr);
}

// round 6
// speedup vs baseline: 2.7270x; 1.0132x over previous
#include <cuda_runtime.h>
#include <cuda_bf16.h>
#include <math.h>
#include <stdint.h>

// ---------------------------------------------------------------------------
// EncoderBlock: B=4, L=1024, D=1024, F=4096, H=16, dh=64
// Round 6: LDSM x4 B-operand loads (GEMM + attention) — LSU debottleneck.
// ---------------------------------------------------------------------------

#define LSEQ 1024
#define DMODEL 1024
#define BATCH 4
#define NHEAD 16
#define DHEAD 64
#define FFDIM 4096
#define BHDIM 64
#define MROWS 4096

// ---- fp32 scratch ----------------------------------------------------------
__device__ float g_attp[BATCH * LSEQ * DMODEL];
__device__ float g_attout[BATCH * LSEQ * DMODEL];
__device__ float g_ff[BATCH * LSEQ * DMODEL];
__device__ float g_bqkv[3 * DMODEL];

// ---- bf16 hi/lo scratch -----------------------------------------------------
__device__ __nv_bfloat16 g_xh[MROWS * DMODEL],  g_xl[MROWS * DMODEL];
__device__ __nv_bfloat16 g_wqkvh[3 * DMODEL * DMODEL], g_wqkvl[3 * DMODEL * DMODEL];
__device__ __nv_bfloat16 g_woh[DMODEL * DMODEL], g_wol[DMODEL * DMODEL];
__device__ __nv_bfloat16 g_w1h[FFDIM * DMODEL],  g_w1l[FFDIM * DMODEL];
__device__ __nv_bfloat16 g_w2h[DMODEL * FFDIM],  g_w2l[DMODEL * FFDIM];
__device__ __nv_bfloat16 g_qkvh[3 * MROWS * DMODEL], g_qkvl[3 * MROWS * DMODEL];
__device__ __nv_bfloat16 g_avh[MROWS * DMODEL],  g_avl[MROWS * DMODEL];
__device__ __nv_bfloat16 g_aoh[MROWS * DMODEL],  g_aol[MROWS * DMODEL];
__device__ __nv_bfloat16 g_h1h[(size_t)MROWS * FFDIM], g_h1l[(size_t)MROWS * FFDIM];

// ============================================================================
// helpers
// ============================================================================
__device__ __forceinline__ uint32_t smem_u32(const void* p) {
    uint32_t a;
    asm("{ .reg .u64 t; cvta.to.shared.u64 t, %1; cvt.u32.u64 %0, t; }"
        : "=r"(a) : "l"(p));
    return a;
}
__device__ __forceinline__ void cp16(uint32_t dst, const void* src) {
    asm volatile("cp.async.cg.shared.global [%0], [%1], 16;" :: "r"(dst), "l"(src));
}
__device__ __forceinline__ void ldsm_x4(uint32_t& r0, uint32_t& r1,
                                        uint32_t& r2, uint32_t& r3, uint32_t a) {
    asm volatile("ldmatrix.sync.aligned.m8n8.x4.shared.b16 {%0,%1,%2,%3}, [%4];"
                 : "=r"(r0), "=r"(r1), "=r"(r2), "=r"(r3) : "r"(a));
}
__device__ __forceinline__ void ldsm_x4t(uint32_t& r0, uint32_t& r1,
                                         uint32_t& r2, uint32_t& r3, uint32_t a) {
    asm volatile("ldmatrix.sync.aligned.m8n8.x4.trans.shared.b16 {%0,%1,%2,%3}, [%4];"
                 : "=r"(r0), "=r"(r1), "=r"(r2), "=r"(r3) : "r"(a));
}
__device__ __forceinline__ void mma_bf16(float* c, const uint32_t* a, const uint32_t* b) {
    asm volatile(
        "mma.sync.aligned.m16n8k16.row.col.f32.bf16.bf16.f32 "
        "{%0,%1,%2,%3}, {%4,%5,%6,%7}, {%8,%9}, {%0,%1,%2,%3};"
        : "+f"(c[0]), "+f"(c[1]), "+f"(c[2]), "+f"(c[3])
        : "r"(a[0]), "r"(a[1]), "r"(a[2]), "r"(a[3]), "r"(b[0]), "r"(b[1]));
}
__device__ __forceinline__ uint32_t packbf2(float x, float y) {
    __nv_bfloat162 t2(__float2bfloat16(x), __float2bfloat16(y));
    return *(uint32_t*)&t2;
}

// ============================================================================
// split: X(fp32) -> hi = bf16(X), lo = bf16(X - hi)
// ============================================================================
__global__ void __launch_bounds__(256) split_kernel(
    const float* __restrict__ X, __nv_bfloat16* __restrict__ H,
    __nv_bfloat16* __restrict__ L, int n4)
{
    int i = blockIdx.x * 256 + threadIdx.x;
    if (i >= n4) return;
    float4 v = ((const float4*)X)[i];
    __nv_bfloat16 h0 = __float2bfloat16(v.x);
    __nv_bfloat16 h1 = __float2bfloat16(v.y);
    __nv_bfloat16 h2 = __float2bfloat16(v.z);
    __nv_bfloat16 h3 = __float2bfloat16(v.w);
    __nv_bfloat162 hp0(h0, h1), hp1(h2, h3);
    __nv_bfloat162 lp0(__float2bfloat16(v.x - __bfloat162float(h0)),
                       __float2bfloat16(v.y - __bfloat162float(h1)));
    __nv_bfloat162 lp1(__float2bfloat16(v.z - __bfloat162float(h2)),
                       __float2bfloat16(v.w - __bfloat162float(h3)));
    ((uint2*)H)[i] = make_uint2(*(uint32_t*)&hp0, *(uint32_t*)&hp1);
    ((uint2*)L)[i] = make_uint2(*(uint32_t*)&lp0, *(uint32_t*)&lp1);
}

// ============================================================================
// split + pack Wq/Wk/Wv into one [3072,1024] hi/lo pair; pack biases.
// ============================================================================
__global__ void __launch_bounds__(256) splitw_qkv_kernel(
    const float* __restrict__ Wq, const float* __restrict__ Wk,
    const float* __restrict__ Wv,
    const float* __restrict__ bq, const float* __restrict__ bk,
    const float* __restrict__ bv,
    __nv_bfloat16* __restrict__ H, __nv_bfloat16* __restrict__ L,
    float* __restrict__ bpack)
{
    const int n4m = DMODEL * DMODEL / 4;
    int i = blockIdx.x * 256 + threadIdx.x;
    if (i < 3 * n4m) {
        int m = i / n4m, off = i - m * n4m;
        const float* W = (m == 0) ? Wq : (m == 1) ? Wk : Wv;
        float4 v = ((const float4*)W)[off];
        __nv_bfloat16 h0 = __float2bfloat16(v.x);
        __nv_bfloat16 h1 = __float2bfloat16(v.y);
        __nv_bfloat16 h2 = __float2bfloat16(v.z);
        __nv_bfloat16 h3 = __float2bfloat16(v.w);
        __nv_bfloat162 hp0(h0, h1), hp1(h2, h3);
        __nv_bfloat162 lp0(__float2bfloat16(v.x - __bfloat162float(h0)),
                           __float2bfloat16(v.y - __bfloat162float(h1)));
        __nv_bfloat162 lp1(__float2bfloat16(v.z - __bfloat162float(h2)),
                           __float2bfloat16(v.w - __bfloat162float(h3)));
        ((uint2*)H)[i] = make_uint2(*(uint32_t*)&hp0, *(uint32_t*)&hp1);
        ((uint2*)L)[i] = make_uint2(*(uint32_t*)&lp0, *(uint32_t*)&lp1);
    }
    if (i < 3 * DMODEL) {
        float b = (i < DMODEL) ? bq[i] : (i < 2 * DMODEL) ? bk[i - DMODEL]
                                                          : bv[i - 2 * DMODEL];
        bpack[i] = b;
    }
}

// ============================================================================
// mma.sync GEMM: C[M,N] = (Ah+Al)[M,K] @ (Bh+Bl)[N,K]^T + bias
// BM=BN=128, BK=32, 4-stage cp.async pipeline, x4 LDSM for both operands.
// OUT: 0 = fp32 C; 1 = bf16 hi/lo; 2 = QKV scatter.
// ============================================================================
#define TBM 128
#define TBN 128
#define TBK 32
#define TSTG 4
#define STG_BYTES 32768
#define TG_SMEM (TSTG * STG_BYTES)

__device__ __forceinline__ uint32_t sw_off(int r, int c) {
    return (uint32_t)(r * 64 + ((c ^ ((r >> 1) & 3)) << 4));
}

__device__ __forceinline__ void tg_load_stage(
    uint32_t sbuf, int t,
    const __nv_bfloat16* __restrict__ Ah, const __nv_bfloat16* __restrict__ Al,
    const __nv_bfloat16* __restrict__ Bh, const __nv_bfloat16* __restrict__ Bl,
    int rowBase, int colBase, int k0, int K)
{
#pragma unroll
    for (int j = 0; j < 8; j++) {
        int i   = j * 256 + t;
        int arr = i >> 9;
        int idx = i & 511;
        int r   = idx >> 2;
        int ch  = idx & 3;
        const __nv_bfloat16* base =
            (arr == 0) ? Ah : (arr == 1) ? Al : (arr == 2) ? Bh : Bl;
        int gr = ((arr < 2) ? rowBase : colBase) + r;
        cp16(sbuf + arr * 8192 + sw_off(r, ch),
             base + (size_t)gr * K + k0 + ch * 8);
    }
    asm volatile("cp.async.commit_group;" ::: "memory");
}

template <bool RELU, int OUT>
__global__ void __launch_bounds__(256) tgemm_kernel(
    const __nv_bfloat16* __restrict__ Ah, const __nv_bfloat16* __restrict__ Al,
    const __nv_bfloat16* __restrict__ Bh, const __nv_bfloat16* __restrict__ Bl,
    const float* __restrict__ bias, float* __restrict__ C,
    __nv_bfloat16* __restrict__ Ch, __nv_bfloat16* __restrict__ Cl,
    int M, int N, int K)
{
    extern __shared__ __align__(16) char smem[];
    uint32_t sb = smem_u32(smem);
    const int t = threadIdx.x;
    const int w = t >> 5, lane = t & 31;
    const int wm = w >> 2;
    const int wn = w & 3;
    const int rowBase = blockIdx.y * TBM;
    const int colBase = blockIdx.x * TBN;
    const int KT = K / TBK;

    float acc[4][4][4];
#pragma unroll
    for (int mt = 0; mt < 4; mt++)
#pragma unroll
        for (int nt = 0; nt < 4; nt++)
#pragma unroll
            for (int e = 0; e < 4; e++) acc[mt][nt][e] = 0.f;

    tg_load_stage(sb,                 t, Ah, Al, Bh, Bl, rowBase, colBase, 0 * TBK, K);
    tg_load_stage(sb + 1 * STG_BYTES, t, Ah, Al, Bh, Bl, rowBase, colBase, 1 * TBK, K);
    tg_load_stage(sb + 2 * STG_BYTES, t, Ah, Al, Bh, Bl, rowBase, colBase, 2 * TBK, K);

    for (int kt = 0; kt < KT; kt++) {
        asm volatile("cp.async.wait_group 2;" ::: "memory");
        __syncthreads();
        if (kt + 3 < KT)
            tg_load_stage(sb + ((kt + 3) & 3) * STG_BYTES, t,
                          Ah, Al, Bh, Bl, rowBase, colBase, (kt + 3) * TBK, K);

        uint32_t sbase = sb + (kt & 3) * STG_BYTES;
#pragma unroll
        for (int ks = 0; ks < 2; ks++) {
            uint32_t ah[4][4], al[4][4], bh[4][2], bl[4][2];
            // A fragments: x4 per mt per array
            const int arow0  = wm * 64 + (lane & 15);
            const int achunk = ks * 2 + (lane >> 4);
#pragma unroll
            for (int mt = 0; mt < 4; mt++) {
                int r = arow0 + mt * 16;
                uint32_t off = sw_off(r, achunk);
                ldsm_x4(ah[mt][0], ah[mt][1], ah[mt][2], ah[mt][3], sbase + off);
                ldsm_x4(al[mt][0], al[mt][1], al[mt][2], al[mt][3], sbase + 8192 + off);
            }
            // B fragments: one x4 covers TWO nt tiles.
            // lanes 0-7: n rows base..+7, chunk k-lo; 8-15: same rows, k-hi;
            // 16-23: rows +8, k-lo; 24-31: rows +8, k-hi.
            const int brow = wn * 32 + ((lane >> 4) << 3) + (lane & 7);
            const int bch  = ks * 2 + ((lane >> 3) & 1);
#pragma unroll
            for (int np = 0; np < 2; np++) {
                uint32_t off = sw_off(brow + np * 16, bch);
                ldsm_x4(bh[2 * np][0], bh[2 * np][1],
                        bh[2 * np + 1][0], bh[2 * np + 1][1], sbase + 16384 + off);
                ldsm_x4(bl[2 * np][0], bl[2 * np][1],
                        bl[2 * np + 1][0], bl[2 * np + 1][1], sbase + 24576 + off);
            }
#pragma unroll
            for (int mt = 0; mt < 4; mt++)
#pragma unroll
                for (int nt = 0; nt < 4; nt++) {
                    mma_bf16(acc[mt][nt], ah[mt], bh[nt]);
                    mma_bf16(acc[mt][nt], ah[mt], bl[nt]);
                    mma_bf16(acc[mt][nt], al[mt], bh[nt]);
                }
        }
    }

    // Epilogue
#pragma unroll
    for (int nt = 0; nt < 4; nt++) {
        int c = colBase + wn * 32 + nt * 8 + (lane & 3) * 2;
        float b0 = __ldg(&bias[c]), b1 = __ldg(&bias[c + 1]);
        __nv_bfloat16* qh_t = Ch;
        __nv_bfloat16* ql_t = Cl;
        int cc = c;
        int on = N;
        if (OUT == 2) {
            int sel = c >> 10;
            qh_t = Ch + (size_t)sel * MROWS * DMODEL;
            ql_t = Cl + (size_t)sel * MROWS * DMODEL;
            cc = c & 1023;
            on = DMODEL;
        }
#pragma unroll
        for (int mt = 0; mt < 4; mt++) {
            int r0 = rowBase + wm * 64 + mt * 16 + (lane >> 2);
            float v0 = acc[mt][nt][0] + b0, v1 = acc[mt][nt][1] + b1;
            float v2 = acc[mt][nt][2] + b0, v3 = acc[mt][nt][3] + b1;
            if (RELU) {
                v0 = fmaxf(v0, 0.f); v1 = fmaxf(v1, 0.f);
                v2 = fmaxf(v2, 0.f); v3 = fmaxf(v3, 0.f);
            }
            if (OUT == 0) {
                *(float2*)(C + (size_t)r0 * N + c)       = make_float2(v0, v1);
                *(float2*)(C + (size_t)(r0 + 8) * N + c) = make_float2(v2, v3);
            } else {
                __nv_bfloat16 h0 = __float2bfloat16(v0), h1 = __float2bfloat16(v1);
                __nv_bfloat16 h2 = __float2bfloat16(v2), h3 = __float2bfloat16(v3);
                __nv_bfloat162 hp0(h0, h1), hp1(h2, h3);
                __nv_bfloat162 lp0(__float2bfloat16(v0 - __bfloat162float(h0)),
                                   __float2bfloat16(v1 - __bfloat162float(h1)));
                __nv_bfloat162 lp1(__float2bfloat16(v2 - __bfloat162float(h2)),
                                   __float2bfloat16(v3 - __bfloat162float(h3)));
                *(__nv_bfloat162*)(qh_t + (size_t)r0 * on + cc)       = hp0;
                *(__nv_bfloat162*)(qh_t + (size_t)(r0 + 8) * on + cc) = hp1;
                *(__nv_bfloat162*)(ql_t + (size_t)r0 * on + cc)       = lp0;
                *(__nv_bfloat162*)(ql_t + (size_t)(r0 + 8) * on + cc) = lp1;
            }
        }
    }
}

// ============================================================================
// T5 relative-position bucket for displacement d
// ============================================================================
__device__ __forceinline__ int rel_bucket_d(int d)
{
    int ret = (d < 0) ? NHEAD : 0;
    int n   = abs(d);
    int b;
    if (n < 8) b = n;
    else {
        int j = (31 - __clz(n * n)) - 6;
        j = min(j, 7);
        b = 8 + j;
    }
    return ret + b;
}

// ============================================================================
// Fused flash attention: x4 LDSM for K and V fragments.
// ============================================================================
#define AT_Q   0
#define AT_QL  16384
#define AT_KH  32768
#define AT_KL  49152
#define AT_VH  65536
#define AT_VL  81920
#define AT_LM  98304
#define AT_BD  102400
#define AT_SMEM (AT_BD + 8192)

__device__ __forceinline__ uint32_t swz128(int r, int c) {
    return (uint32_t)(r * 128 + ((c ^ (r & 7)) << 4));
}

__global__ void __launch_bounds__(256, 1) attn_fused_kernel(
    const __nv_bfloat16* __restrict__ QH, const __nv_bfloat16* __restrict__ QL,
    const __nv_bfloat16* __restrict__ KH, const __nv_bfloat16* __restrict__ KL,
    const __nv_bfloat16* __restrict__ VH, const __nv_bfloat16* __restrict__ VL,
    const float* __restrict__ rel, const int* __restrict__ pm,
    __nv_bfloat16* __restrict__ OH, __nv_bfloat16* __restrict__ OL)
{
    extern __shared__ __align__(16) char smem[];
    uint32_t sb = smem_u32(smem);
    float* lm_s = (float*)(smem + AT_LM);
    float* bd_s = (float*)(smem + AT_BD);

    const int t = threadIdx.x, w = t >> 5, lane = t & 31;
    const int qt = blockIdx.x, bh = blockIdx.y;
    const int h = bh & (NHEAD - 1), b = bh >> 4;
    const size_t slab = (size_t)bh * (LSEQ * DHEAD);

    for (int i = t; i < LSEQ; i += 256)
        lm_s[i] = logf((float)pm[b * LSEQ + i]);
    for (int i = t; i < 2047; i += 256)
        bd_s[i] = rel[rel_bucket_d(i - 1023) * NHEAD + h];

    {
        size_t qbase = slab + (size_t)qt * 128 * DHEAD;
        for (int i = t; i < 1024; i += 256) {
            int r = i >> 3, c = i & 7;
            uint32_t off = swz128(r, c);
            size_t g = qbase + r * DHEAD + c * 8;
            cp16(sb + AT_Q  + off, QH + g);
            cp16(sb + AT_QL + off, QL + g);
        }
        for (int i = t; i < 1024; i += 256) {
            int r = i >> 3, c = i & 7;
            uint32_t off = swz128(r, c);
            size_t g = slab + r * DHEAD + c * 8;
            cp16(sb + AT_KH + off, KH + g);
            cp16(sb + AT_KL + off, KL + g);
            cp16(sb + AT_VH + off, VH + g);
            cp16(sb + AT_VL + off, VL + g);
        }
        asm volatile("cp.async.commit_group;" ::: "memory");
        asm volatile("cp.async.wait_group 0;" ::: "memory");
    }
    __syncthreads();

    uint32_t qfh[4][4], qfl[4][4];
    {
        int r = w * 16 + (lane & 15);
#pragma unroll
        for (int ks = 0; ks < 4; ks++) {
            int c = ks * 2 + (lane >> 4);
            uint32_t off = swz128(r, c);
            ldsm_x4(qfh[ks][0], qfh[ks][1], qfh[ks][2], qfh[ks][3], sb + AT_Q  + off);
            ldsm_x4(qfl[ks][0], qfl[ks][1], qfl[ks][2], qfl[ks][3], sb + AT_QL + off);
        }
    }

    float O[8][4];
#pragma unroll
    for (int nt = 0; nt < 8; nt++)
#pragma unroll
        for (int e = 0; e < 4; e++) O[nt][e] = 0.f;
    float m0 = -3.0e38f, m1 = -3.0e38f, l0 = 0.f, l1 = 0.f;

    const int r0 = qt * 128 + w * 16 + (lane >> 2);
    const int r1 = r0 + 8;

    for (int kt = 0; kt < 8; kt++) {
        float S[16][4];
#pragma unroll
        for (int j = 0; j < 16; j++)
#pragma unroll
            for (int e = 0; e < 4; e++) S[j][e] = 0.f;

        // S = Q K^T — one x4 per j-pair per array
#pragma unroll
        for (int ks = 0; ks < 4; ks++) {
            const int krow = ((lane >> 4) << 3) + (lane & 7);
            const int kch  = ks * 2 + ((lane >> 3) & 1);
#pragma unroll
            for (int jp = 0; jp < 8; jp++) {
                uint32_t off = swz128(jp * 16 + krow, kch);
                uint32_t kb[4], kl2[4];
                ldsm_x4(kb[0],  kb[1],  kb[2],  kb[3],  sb + AT_KH + off);
                ldsm_x4(kl2[0], kl2[1], kl2[2], kl2[3], sb + AT_KL + off);
                mma_bf16(S[2 * jp],     qfh[ks], kb);
                mma_bf16(S[2 * jp],     qfh[ks], kl2);
                mma_bf16(S[2 * jp],     qfl[ks], kb);
                mma_bf16(S[2 * jp + 1], qfh[ks], kb + 2);
                mma_bf16(S[2 * jp + 1], qfh[ks], kl2 + 2);
                mma_bf16(S[2 * jp + 1], qfl[ks], kb + 2);
            }
        }

        const int ktbase = kt * 128;
#pragma unroll
        for (int j = 0; j < 16; j++) {
            int c = ktbase + j * 8 + (lane & 3) * 2;
            float lc0 = lm_s[c], lc1 = lm_s[c + 1];
            S[j][0] += bd_s[c - r0 + 1023] + lc0;
            S[j][1] += bd_s[c + 1 - r0 + 1023] + lc1;
            S[j][2] += bd_s[c - r1 + 1023] + lc0;
            S[j][3] += bd_s[c + 1 - r1 + 1023] + lc1;
        }

        float tm0 = -3.0e38f, tm1 = -3.0e38f;
#pragma unroll
        for (int j = 0; j < 16; j++) {
            tm0 = fmaxf(tm0, fmaxf(S[j][0], S[j][1]));
            tm1 = fmaxf(tm1, fmaxf(S[j][2], S[j][3]));
        }
        tm0 = fmaxf(tm0, __shfl_xor_sync(0xffffffffu, tm0, 1));
        tm0 = fmaxf(tm0, __shfl_xor_sync(0xffffffffu, tm0, 2));
        tm1 = fmaxf(tm1, __shfl_xor_sync(0xffffffffu, tm1, 1));
        tm1 = fmaxf(tm1, __shfl_xor_sync(0xffffffffu, tm1, 2));
        float mn0 = fmaxf(m0, tm0), mn1 = fmaxf(m1, tm1);
        float a0 = __expf(m0 - mn0), a1 = __expf(m1 - mn1);
        m0 = mn0; m1 = mn1;

        float s0 = 0.f, s1 = 0.f;
#pragma unroll
        for (int j = 0; j < 16; j++) {
            S[j][0] = __expf(S[j][0] - mn0); s0 += S[j][0];
            S[j][1] = __expf(S[j][1] - mn0); s0 += S[j][1];
            S[j][2] = __expf(S[j][2] - mn1); s1 += S[j][2];
            S[j][3] = __expf(S[j][3] - mn1); s1 += S[j][3];
        }
        s0 += __shfl_xor_sync(0xffffffffu, s0, 1);
        s0 += __shfl_xor_sync(0xffffffffu, s0, 2);
        s1 += __shfl_xor_sync(0xffffffffu, s1, 1);
        s1 += __shfl_xor_sync(0xffffffffu, s1, 2);
        l0 = l0 * a0 + s0;
        l1 = l1 * a1 + s1;

#pragma unroll
        for (int nt = 0; nt < 8; nt++) {
            O[nt][0] *= a0; O[nt][1] *= a0;
            O[nt][2] *= a1; O[nt][3] *= a1;
        }

        // O += P @ V — one x4t per nt-pair per array
#pragma unroll
        for (int kk = 0; kk < 8; kk++) {
            float* p0 = S[2 * kk];
            float* p1 = S[2 * kk + 1];
            uint32_t ph[4], pl[4];
            {
                __nv_bfloat16 h00 = __float2bfloat16(p0[0]), h01 = __float2bfloat16(p0[1]);
                __nv_bfloat16 h02 = __float2bfloat16(p0[2]), h03 = __float2bfloat16(p0[3]);
                __nv_bfloat16 h10 = __float2bfloat16(p1[0]), h11 = __float2bfloat16(p1[1]);
                __nv_bfloat16 h12 = __float2bfloat16(p1[2]), h13 = __float2bfloat16(p1[3]);
                __nv_bfloat162 t0(h00, h01), t1(h02, h03), t2(h10, h11), t3(h12, h13);
                ph[0] = *(uint32_t*)&t0; ph[1] = *(uint32_t*)&t1;
                ph[2] = *(uint32_t*)&t2; ph[3] = *(uint32_t*)&t3;
                pl[0] = packbf2(p0[0] - __bfloat162float(h00), p0[1] - __bfloat162float(h01));
                pl[1] = packbf2(p0[2] - __bfloat162float(h02), p0[3] - __bfloat162float(h03));
                pl[2] = packbf2(p1[0] - __bfloat162float(h10), p1[1] - __bfloat162float(h11));
                pl[3] = packbf2(p1[2] - __bfloat162float(h12), p1[3] - __bfloat162float(h13));
            }
            const int vrow = kk * 16 + (lane & 15);
            const int vcp  = (lane >> 4) & 1;
#pragma unroll
            for (int np = 0; np < 4; np++) {
                uint32_t off = swz128(vrow, np * 2 + vcp);
                uint32_t vb[4], vl2[4];
                ldsm_x4t(vb[0],  vb[1],  vb[2],  vb[3],  sb + AT_VH + off);
                ldsm_x4t(vl2[0], vl2[1], vl2[2], vl2[3], sb + AT_VL + off);
                mma_bf16(O[2 * np],     ph, vb);
                mma_bf16(O[2 * np],     ph, vl2);
                mma_bf16(O[2 * np],     pl, vb);
                mma_bf16(O[2 * np + 1], ph, vb + 2);
                mma_bf16(O[2 * np + 1], ph, vl2 + 2);
                mma_bf16(O[2 * np + 1], pl, vb + 2);
            }
        }

        __syncthreads();
        if (kt < 7) {
            size_t kb = slab + (size_t)(kt + 1) * 128 * DHEAD;
            for (int i = t; i < 1024; i += 256) {
                int r = i >> 3, c = i & 7;
                uint32_t off = swz128(r, c);
                size_t g = kb + r * DHEAD + c * 8;
                cp16(sb + AT_KH + off, KH + g);
                cp16(sb + AT_KL + off, KL + g);
                cp16(sb + AT_VH + off, VH + g);
                cp16(sb + AT_VL + off, VL + g);
            }
            asm volatile("cp.async.commit_group;" ::: "memory");
            asm volatile("cp.async.wait_group 0;" ::: "memory");
        }
        __syncthreads();
    }

    float inv0 = 1.f / l0, inv1 = 1.f / l1;
    size_t ob0 = slab + (size_t)(qt * 128 + w * 16 + (lane >> 2)) * DHEAD;
    size_t ob1 = ob0 + 8 * DHEAD;
#pragma unroll
    for (int nt = 0; nt < 8; nt++) {
        int c = nt * 8 + (lane & 3) * 2;
        float v0 = O[nt][0] * inv0, v1 = O[nt][1] * inv0;
        float v2 = O[nt][2] * inv1, v3 = O[nt][3] * inv1;
        __nv_bfloat16 h0 = __float2bfloat16(v0), h1 = __float2bfloat16(v1);
        __nv_bfloat16 h2 = __float2bfloat16(v2), h3 = __float2bfloat16(v3);
        __nv_bfloat162 hp0(h0, h1), hp1(h2, h3);
        *(__nv_bfloat162*)(OH + ob0 + c) = hp0;
        *(__nv_bfloat162*)(OH + ob1 + c) = hp1;
        *(__nv_bfloat162*)(OL + ob0 + c) =
            __nv_bfloat162(__float2bfloat16(v0 - __bfloat162float(h0)),
                           __float2bfloat16(v1 - __bfloat162float(h1)));
        *(__nv_bfloat162*)(OL + ob1 + c) =
            __nv_bfloat162(__float2bfloat16(v2 - __bfloat162float(h2)),
                           __float2bfloat16(v3 - __bfloat162float(h3)));
    }
}

// ============================================================================
// out = LayerNorm(A + B); optional bf16 hi/lo side output
// ============================================================================
template <bool SPLIT>
__global__ void __launch_bounds__(256) add_ln_kernel(
    const float* __restrict__ A, const float* __restrict__ B,
    float* __restrict__ out,
    __nv_bfloat16* __restrict__ OH, __nv_bfloat16* __restrict__ OL)
{
    __shared__ float sh[8];
    const size_t row = blockIdx.x;
    const int t = threadIdx.x;

    float4 a = ((const float4*)(A + row * DMODEL))[t];
    float4 b = ((const float4*)(B + row * DMODEL))[t];
    float4 x;
    x.x = a.x + b.x; x.y = a.y + b.y; x.z = a.z + b.z; x.w = a.w + b.w;

    float s = x.x + x.y + x.z + x.w;
#pragma unroll
    for (int o = 16; o; o >>= 1) s += __shfl_xor_sync(0xffffffffu, s, o);
    if ((t & 31) == 0) sh[t >> 5] = s;
    __syncthreads();
    float tot = sh[0];
#pragma unroll
    for (int i = 1; i < 8; i++) tot += sh[i];
    __syncthreads();
    float mean = tot * (1.f / DMODEL);

    float dx = x.x - mean, dy = x.y - mean, dz = x.z - mean, dw = x.w - mean;
    float s2 = dx * dx + dy * dy + dz * dz + dw * dw;
#pragma unroll
    for (int o = 16; o; o >>= 1) s2 += __shfl_xor_sync(0xffffffffu, s2, o);
    if ((t & 31) == 0) sh[t >> 5] = s2;
    __syncthreads();
    float tot2 = sh[0];
#pragma unroll
    for (int i = 1; i < 8; i++) tot2 += sh[i];
    float inv = rsqrtf(tot2 * (1.f / DMODEL));

    float4 o;
    o.x = dx * inv; o.y = dy * inv; o.z = dz * inv; o.w = dw * inv;
    ((float4*)(out + row * DMODEL))[t] = o;

    if (SPLIT) {
        __nv_bfloat16 h0 = __float2bfloat16(o.x), h1 = __float2bfloat16(o.y);
        __nv_bfloat16 h2 = __float2bfloat16(o.z), h3 = __float2bfloat16(o.w);
        __nv_bfloat162 hp0(h0, h1), hp1(h2, h3);
        __nv_bfloat162 lp0(__float2bfloat16(o.x - __bfloat162float(h0)),
                           __float2bfloat16(o.y - __bfloat162float(h1)));
        __nv_bfloat162 lp1(__float2bfloat16(o.z - __bfloat162float(h2)),
                           __float2bfloat16(o.w - __bfloat162float(h3)));
        size_t base = row * DMODEL + t * 4;
        *(__nv_bfloat162*)(OH + base)     = hp0;
        *(__nv_bfloat162*)(OH + base + 2) = hp1;
        *(__nv_bfloat162*)(OL + base)     = lp0;
        *(__nv_bfloat162*)(OL + base + 2) = lp1;
    }
}

// ============================================================================
// Launch sequence
// ============================================================================
extern "C" void kernel_launch(void* const* d_in, const int* in_sizes, int n_in,
                              void* d_out, int out_size)
{
    const float* x   = (const float*)d_in[0];
    const int*   pm  = (const int*)  d_in[1];
    const float* Wq  = (const float*)d_in[2];
    const float* bq  = (const float*)d_in[3];
    const float* Wk  = (const float*)d_in[4];
    const float* bk  = (const float*)d_in[5];
    const float* Wv  = (const float*)d_in[6];
    const float* bv  = (const float*)d_in[7];
    const float* Wo  = (const float*)d_in[8];
    const float* bo  = (const float*)d_in[9];
    const float* rel = (const float*)d_in[10];
    const float* W1  = (const float*)d_in[11];
    const float* b1  = (const float*)d_in[12];
    const float* W2  = (const float*)d_in[13];
    const float* b2  = (const float*)d_in[14];
    float* out = (float*)d_out;

    float *attp, *attout, *ff, *bqkv;
    cudaGetSymbolAddress((void**)&attp,   g_attp);
    cudaGetSymbolAddress((void**)&attout, g_attout);
    cudaGetSymbolAddress((void**)&ff,     g_ff);
    cudaGetSymbolAddress((void**)&bqkv,   g_bqkv);

    __nv_bfloat16 *xh, *xl, *wqkvh, *wqkvl, *woh, *wol;
    __nv_bfloat16 *w1h, *w1l, *w2h, *w2l, *avh, *avl, *aoh, *aol, *h1h, *h1l;
    __nv_bfloat16 *qkvh, *qkvl;
    cudaGetSymbolAddress((void**)&xh,    g_xh);    cudaGetSymbolAddress((void**)&xl,    g_xl);
    cudaGetSymbolAddress((void**)&wqkvh, g_wqkvh); cudaGetSymbolAddress((void**)&wqkvl, g_wqkvl);
    cudaGetSymbolAddress((void**)&woh,   g_woh);   cudaGetSymbolAddress((void**)&wol,   g_wol);
    cudaGetSymbolAddress((void**)&w1h,   g_w1h);   cudaGetSymbolAddress((void**)&w1l,   g_w1l);
    cudaGetSymbolAddress((void**)&w2h,   g_w2h);   cudaGetSymbolAddress((void**)&w2l,   g_w2l);
    cudaGetSymbolAddress((void**)&avh,   g_avh);   cudaGetSymbolAddress((void**)&avl,   g_avl);
    cudaGetSymbolAddress((void**)&aoh,   g_aoh);   cudaGetSymbolAddress((void**)&aol,   g_aol);
    cudaGetSymbolAddress((void**)&h1h,   g_h1h);   cudaGetSymbolAddress((void**)&h1l,   g_h1l);
    cudaGetSymbolAddress((void**)&qkvh,  g_qkvh);  cudaGetSymbolAddress((void**)&qkvl,  g_qkvl);

    static bool attr_done = false;
    if (!attr_done) {
        cudaFuncSetAttribute(tgemm_kernel<false, 0>,
                             cudaFuncAttributeMaxDynamicSharedMemorySize, TG_SMEM);
        cudaFuncSetAttribute(tgemm_kernel<false, 1>,
                             cudaFuncAttributeMaxDynamicSharedMemorySize, TG_SMEM);
        cudaFuncSetAttribute(tgemm_kernel<false, 2>,
                             cudaFuncAttributeMaxDynamicSharedMemorySize, TG_SMEM);
        cudaFuncSetAttribute(tgemm_kernel<true, 1>,
                             cudaFuncAttributeMaxDynamicSharedMemorySize, TG_SMEM);
        cudaFuncSetAttribute(attn_fused_kernel,
                             cudaFuncAttributeMaxDynamicSharedMemorySize, AT_SMEM);
        attr_done = true;
    }

    dim3 blk(256);

    split_kernel<<<(MROWS * DMODEL / 4 + 255) / 256, blk>>>(
        x, xh, xl, MROWS * DMODEL / 4);
    splitw_qkv_kernel<<<(3 * DMODEL * DMODEL / 4 + 255) / 256, blk>>>(
        Wq, Wk, Wv, bq, bk, bv, wqkvh, wqkvl, bqkv);
    split_kernel<<<(DMODEL * DMODEL / 4 + 255) / 256, blk>>>(
        Wo, woh, wol, DMODEL * DMODEL / 4);
    split_kernel<<<(FFDIM * DMODEL / 4 + 255) / 256, blk>>>(
        W1, w1h, w1l, FFDIM * DMODEL / 4);
    split_kernel<<<(DMODEL * FFDIM / 4 + 255) / 256, blk>>>(
        W2, w2h, w2l, DMODEL * FFDIM / 4);

    // fused QKV projection
    dim3 gqkv(3 * DMODEL / TBN, MROWS / TBM);
    tgemm_kernel<false, 2><<<gqkv, blk, TG_SMEM>>>(
        xh, xl, wqkvh, wqkvl, bqkv, nullptr, qkvh, qkvl, MROWS, 3 * DMODEL, DMODEL);

    // attention
    const size_t SLAB = (size_t)MROWS * DMODEL;
    attn_fused_kernel<<<dim3(8, BHDIM), blk, AT_SMEM>>>(
        qkvh, qkvl, qkvh + SLAB, qkvl + SLAB, qkvh + 2 * SLAB, qkvl + 2 * SLAB,
        rel, pm, avh, avl);

    // O projection
    dim3 gO(DMODEL / TBN, MROWS / TBM);
    tgemm_kernel<false, 0><<<gO, blk, TG_SMEM>>>(
        avh, avl, woh, wol, bo, attp, nullptr, nullptr, MROWS, DMODEL, DMODEL);

    // residual + LN (+ split)
    add_ln_kernel<true><<<MROWS, blk>>>(attp, x, attout, aoh, aol);

    // FFN
    dim3 g1(FFDIM / TBN, MROWS / TBM);
    tgemm_kernel<true, 1><<<g1, blk, TG_SMEM>>>(
        aoh, aol, w1h, w1l, b1, nullptr, h1h, h1l, MROWS, FFDIM, DMODEL);
    dim3 g2(DMODEL / TBN, MROWS / TBM);
    tgemm_kernel<false, 0><<<g2, blk, TG_SMEM>>>(
        h1h, h1l, w2h, w2l, b2, ff, nullptr, nullptr, MROWS, DMODEL, FFDIM);

    // final residual + LN
    add_ln_kernel<false><<<MROWS, blk>>>(ff, attout, out, nullptr, nullptr);
}

// round 7
// speedup vs baseline: 3.0145x; 1.1054x over previous
#include <cuda_runtime.h>
#include <cuda_bf16.h>
#include <math.h>
#include <stdint.h>

// ---------------------------------------------------------------------------
// EncoderBlock: B=4, L=1024, D=1024, F=4096, H=16, dh=64
// Round 7: 2-stage pipeline + 2 blocks/SM occupancy; merged weight splits.
// ---------------------------------------------------------------------------

#define LSEQ 1024
#define DMODEL 1024
#define BATCH 4
#define NHEAD 16
#define DHEAD 64
#define FFDIM 4096
#define BHDIM 64
#define MROWS 4096

// ---- fp32 scratch ----------------------------------------------------------
__device__ float g_attp[BATCH * LSEQ * DMODEL];
__device__ float g_attout[BATCH * LSEQ * DMODEL];
__device__ float g_ff[BATCH * LSEQ * DMODEL];
__device__ float g_bqkv[3 * DMODEL];

// ---- bf16 hi/lo scratch -----------------------------------------------------
__device__ __nv_bfloat16 g_xh[MROWS * DMODEL],  g_xl[MROWS * DMODEL];
__device__ __nv_bfloat16 g_wqkvh[3 * DMODEL * DMODEL], g_wqkvl[3 * DMODEL * DMODEL];
__device__ __nv_bfloat16 g_woh[DMODEL * DMODEL], g_wol[DMODEL * DMODEL];
__device__ __nv_bfloat16 g_w1h[FFDIM * DMODEL],  g_w1l[FFDIM * DMODEL];
__device__ __nv_bfloat16 g_w2h[DMODEL * FFDIM],  g_w2l[DMODEL * FFDIM];
__device__ __nv_bfloat16 g_qkvh[3 * MROWS * DMODEL], g_qkvl[3 * MROWS * DMODEL];
__device__ __nv_bfloat16 g_avh[MROWS * DMODEL],  g_avl[MROWS * DMODEL];
__device__ __nv_bfloat16 g_aoh[MROWS * DMODEL],  g_aol[MROWS * DMODEL];
__device__ __nv_bfloat16 g_h1h[(size_t)MROWS * FFDIM], g_h1l[(size_t)MROWS * FFDIM];

// ============================================================================
// helpers
// ============================================================================
__device__ __forceinline__ uint32_t smem_u32(const void* p) {
    uint32_t a;
    asm("{ .reg .u64 t; cvta.to.shared.u64 t, %1; cvt.u32.u64 %0, t; }"
        : "=r"(a) : "l"(p));
    return a;
}
__device__ __forceinline__ void cp16(uint32_t dst, const void* src) {
    asm volatile("cp.async.cg.shared.global [%0], [%1], 16;" :: "r"(dst), "l"(src));
}
__device__ __forceinline__ void ldsm_x4(uint32_t& r0, uint32_t& r1,
                                        uint32_t& r2, uint32_t& r3, uint32_t a) {
    asm volatile("ldmatrix.sync.aligned.m8n8.x4.shared.b16 {%0,%1,%2,%3}, [%4];"
                 : "=r"(r0), "=r"(r1), "=r"(r2), "=r"(r3) : "r"(a));
}
__device__ __forceinline__ void ldsm_x4t(uint32_t& r0, uint32_t& r1,
                                         uint32_t& r2, uint32_t& r3, uint32_t a) {
    asm volatile("ldmatrix.sync.aligned.m8n8.x4.trans.shared.b16 {%0,%1,%2,%3}, [%4];"
                 : "=r"(r0), "=r"(r1), "=r"(r2), "=r"(r3) : "r"(a));
}
__device__ __forceinline__ void mma_bf16(float* c, const uint32_t* a, const uint32_t* b) {
    asm volatile(
        "mma.sync.aligned.m16n8k16.row.col.f32.bf16.bf16.f32 "
        "{%0,%1,%2,%3}, {%4,%5,%6,%7}, {%8,%9}, {%0,%1,%2,%3};"
        : "+f"(c[0]), "+f"(c[1]), "+f"(c[2]), "+f"(c[3])
        : "r"(a[0]), "r"(a[1]), "r"(a[2]), "r"(a[3]), "r"(b[0]), "r"(b[1]));
}
__device__ __forceinline__ uint32_t packbf2(float x, float y) {
    __nv_bfloat162 t2(__float2bfloat16(x), __float2bfloat16(y));
    return *(uint32_t*)&t2;
}

// ============================================================================
// split: X(fp32) -> hi = bf16(X), lo = bf16(X - hi)
// ============================================================================
__global__ void __launch_bounds__(256) split_kernel(
    const float* __restrict__ X, __nv_bfloat16* __restrict__ H,
    __nv_bfloat16* __restrict__ L, int n4)
{
    int i = blockIdx.x * 256 + threadIdx.x;
    if (i >= n4) return;
    float4 v = ((const float4*)X)[i];
    __nv_bfloat16 h0 = __float2bfloat16(v.x);
    __nv_bfloat16 h1 = __float2bfloat16(v.y);
    __nv_bfloat16 h2 = __float2bfloat16(v.z);
    __nv_bfloat16 h3 = __float2bfloat16(v.w);
    __nv_bfloat162 hp0(h0, h1), hp1(h2, h3);
    __nv_bfloat162 lp0(__float2bfloat16(v.x - __bfloat162float(h0)),
                       __float2bfloat16(v.y - __bfloat162float(h1)));
    __nv_bfloat162 lp1(__float2bfloat16(v.z - __bfloat162float(h2)),
                       __float2bfloat16(v.w - __bfloat162float(h3)));
    ((uint2*)H)[i] = make_uint2(*(uint32_t*)&hp0, *(uint32_t*)&hp1);
    ((uint2*)L)[i] = make_uint2(*(uint32_t*)&lp0, *(uint32_t*)&lp1);
}

// ============================================================================
// One kernel splitting ALL weights (Wq|Wk|Wv packed, Wo, W1, W2) + qkv bias.
// Segment layout in float4 units.
// ============================================================================
#define SEG_QKV (3 * DMODEL * DMODEL / 4)     /* 786432 */
#define SEG_WO  (DMODEL * DMODEL / 4)         /* 262144 */
#define SEG_W1  (FFDIM * DMODEL / 4)          /* 1048576 */
#define SEG_W2  (DMODEL * FFDIM / 4)          /* 1048576 */
#define SEG_TOTAL (SEG_QKV + SEG_WO + SEG_W1 + SEG_W2)

__global__ void __launch_bounds__(256) splitw_all_kernel(
    const float* __restrict__ Wq, const float* __restrict__ Wk,
    const float* __restrict__ Wv, const float* __restrict__ Wo,
    const float* __restrict__ W1, const float* __restrict__ W2,
    const float* __restrict__ bq, const float* __restrict__ bk,
    const float* __restrict__ bv,
    __nv_bfloat16* __restrict__ QKVH, __nv_bfloat16* __restrict__ QKVL,
    __nv_bfloat16* __restrict__ WOH,  __nv_bfloat16* __restrict__ WOL,
    __nv_bfloat16* __restrict__ W1H,  __nv_bfloat16* __restrict__ W1L,
    __nv_bfloat16* __restrict__ W2H,  __nv_bfloat16* __restrict__ W2L,
    float* __restrict__ bpack)
{
    int i = blockIdx.x * 256 + threadIdx.x;
    if (i < 3 * DMODEL) {
        float b = (i < DMODEL) ? bq[i] : (i < 2 * DMODEL) ? bk[i - DMODEL]
                                                          : bv[i - 2 * DMODEL];
        bpack[i] = b;
    }
    if (i >= SEG_TOTAL) return;

    const float* src;
    __nv_bfloat16 *H, *L;
    int off;
    if (i < SEG_QKV) {
        const int n4m = DMODEL * DMODEL / 4;
        int m = i / n4m;
        off = i - m * n4m;
        src = (m == 0) ? Wq : (m == 1) ? Wk : Wv;
        H = QKVH + (size_t)i * 4 - (size_t)off * 4;   // base of segment m
        // simpler: H points so that index 'off' lands right:
        H = QKVH + (size_t)m * DMODEL * DMODEL;
        L = QKVL + (size_t)m * DMODEL * DMODEL;
    } else if (i < SEG_QKV + SEG_WO) {
        off = i - SEG_QKV; src = Wo; H = WOH; L = WOL;
    } else if (i < SEG_QKV + SEG_WO + SEG_W1) {
        off = i - SEG_QKV - SEG_WO; src = W1; H = W1H; L = W1L;
    } else {
        off = i - SEG_QKV - SEG_WO - SEG_W1; src = W2; H = W2H; L = W2L;
    }

    float4 v = ((const float4*)src)[off];
    __nv_bfloat16 h0 = __float2bfloat16(v.x);
    __nv_bfloat16 h1 = __float2bfloat16(v.y);
    __nv_bfloat16 h2 = __float2bfloat16(v.z);
    __nv_bfloat16 h3 = __float2bfloat16(v.w);
    __nv_bfloat162 hp0(h0, h1), hp1(h2, h3);
    __nv_bfloat162 lp0(__float2bfloat16(v.x - __bfloat162float(h0)),
                       __float2bfloat16(v.y - __bfloat162float(h1)));
    __nv_bfloat162 lp1(__float2bfloat16(v.z - __bfloat162float(h2)),
                       __float2bfloat16(v.w - __bfloat162float(h3)));
    ((uint2*)H)[off] = make_uint2(*(uint32_t*)&hp0, *(uint32_t*)&hp1);
    ((uint2*)L)[off] = make_uint2(*(uint32_t*)&lp0, *(uint32_t*)&lp1);
}

// ============================================================================
// mma.sync GEMM: C[M,N] = (Ah+Al)[M,K] @ (Bh+Bl)[N,K]^T + bias
// BM=BN=128, BK=32, 2-stage double buffer, 2 blocks/SM.
// OUT: 0 = fp32 C; 1 = bf16 hi/lo; 2 = QKV scatter.
// ============================================================================
#define TBM 128
#define TBN 128
#define TBK 32
#define STG_BYTES 32768
#define TG_SMEM (2 * STG_BYTES)

__device__ __forceinline__ uint32_t sw_off(int r, int c) {
    return (uint32_t)(r * 64 + ((c ^ ((r >> 1) & 3)) << 4));
}

__device__ __forceinline__ void tg_load_stage(
    uint32_t sbuf, int t,
    const __nv_bfloat16* __restrict__ Ah, const __nv_bfloat16* __restrict__ Al,
    const __nv_bfloat16* __restrict__ Bh, const __nv_bfloat16* __restrict__ Bl,
    int rowBase, int colBase, int k0, int K)
{
#pragma unroll
    for (int j = 0; j < 8; j++) {
        int i   = j * 256 + t;
        int arr = i >> 9;
        int idx = i & 511;
        int r   = idx >> 2;
        int ch  = idx & 3;
        const __nv_bfloat16* base =
            (arr == 0) ? Ah : (arr == 1) ? Al : (arr == 2) ? Bh : Bl;
        int gr = ((arr < 2) ? rowBase : colBase) + r;
        cp16(sbuf + arr * 8192 + sw_off(r, ch),
             base + (size_t)gr * K + k0 + ch * 8);
    }
    asm volatile("cp.async.commit_group;" ::: "memory");
}

template <bool RELU, int OUT>
__global__ void __launch_bounds__(256, 2) tgemm_kernel(
    const __nv_bfloat16* __restrict__ Ah, const __nv_bfloat16* __restrict__ Al,
    const __nv_bfloat16* __restrict__ Bh, const __nv_bfloat16* __restrict__ Bl,
    const float* __restrict__ bias, float* __restrict__ C,
    __nv_bfloat16* __restrict__ Ch, __nv_bfloat16* __restrict__ Cl,
    int M, int N, int K)
{
    extern __shared__ __align__(16) char smem[];
    uint32_t sb = smem_u32(smem);
    const int t = threadIdx.x;
    const int w = t >> 5, lane = t & 31;
    const int wm = w >> 2;
    const int wn = w & 3;
    const int rowBase = blockIdx.y * TBM;
    const int colBase = blockIdx.x * TBN;
    const int KT = K / TBK;

    float acc[4][4][4];
#pragma unroll
    for (int mt = 0; mt < 4; mt++)
#pragma unroll
        for (int nt = 0; nt < 4; nt++)
#pragma unroll
            for (int e = 0; e < 4; e++) acc[mt][nt][e] = 0.f;

    tg_load_stage(sb,             t, Ah, Al, Bh, Bl, rowBase, colBase, 0 * TBK, K);
    tg_load_stage(sb + STG_BYTES, t, Ah, Al, Bh, Bl, rowBase, colBase, 1 * TBK, K);

    for (int kt = 0; kt < KT; kt++) {
        asm volatile("cp.async.wait_group 1;" ::: "memory");
        __syncthreads();

        uint32_t sbase = sb + (kt & 1) * STG_BYTES;
#pragma unroll
        for (int ks = 0; ks < 2; ks++) {
            uint32_t ah[4][4], al[4][4], bh[4][2], bl[4][2];
            const int arow0  = wm * 64 + (lane & 15);
            const int achunk = ks * 2 + (lane >> 4);
#pragma unroll
            for (int mt = 0; mt < 4; mt++) {
                int r = arow0 + mt * 16;
                uint32_t off = sw_off(r, achunk);
                ldsm_x4(ah[mt][0], ah[mt][1], ah[mt][2], ah[mt][3], sbase + off);
                ldsm_x4(al[mt][0], al[mt][1], al[mt][2], al[mt][3], sbase + 8192 + off);
            }
            const int brow = wn * 32 + ((lane >> 4) << 3) + (lane & 7);
            const int bch  = ks * 2 + ((lane >> 3) & 1);
#pragma unroll
            for (int np = 0; np < 2; np++) {
                uint32_t off = sw_off(brow + np * 16, bch);
                ldsm_x4(bh[2 * np][0], bh[2 * np][1],
                        bh[2 * np + 1][0], bh[2 * np + 1][1], sbase + 16384 + off);
                ldsm_x4(bl[2 * np][0], bl[2 * np][1],
                        bl[2 * np + 1][0], bl[2 * np + 1][1], sbase + 24576 + off);
            }
#pragma unroll
            for (int mt = 0; mt < 4; mt++)
#pragma unroll
                for (int nt = 0; nt < 4; nt++) {
                    mma_bf16(acc[mt][nt], ah[mt], bh[nt]);
                    mma_bf16(acc[mt][nt], ah[mt], bl[nt]);
                    mma_bf16(acc[mt][nt], al[mt], bh[nt]);
                }
        }

        __syncthreads();
        if (kt + 2 < KT)
            tg_load_stage(sb + (kt & 1) * STG_BYTES, t,
                          Ah, Al, Bh, Bl, rowBase, colBase, (kt + 2) * TBK, K);
    }

    // Epilogue
#pragma unroll
    for (int nt = 0; nt < 4; nt++) {
        int c = colBase + wn * 32 + nt * 8 + (lane & 3) * 2;
        float b0 = __ldg(&bias[c]), b1 = __ldg(&bias[c + 1]);
        __nv_bfloat16* qh_t = Ch;
        __nv_bfloat16* ql_t = Cl;
        int cc = c;
        int on = N;
        if (OUT == 2) {
            int sel = c >> 10;
            qh_t = Ch + (size_t)sel * MROWS * DMODEL;
            ql_t = Cl + (size_t)sel * MROWS * DMODEL;
            cc = c & 1023;
            on = DMODEL;
        }
#pragma unroll
        for (int mt = 0; mt < 4; mt++) {
            int r0 = rowBase + wm * 64 + mt * 16 + (lane >> 2);
            float v0 = acc[mt][nt][0] + b0, v1 = acc[mt][nt][1] + b1;
            float v2 = acc[mt][nt][2] + b0, v3 = acc[mt][nt][3] + b1;
            if (RELU) {
                v0 = fmaxf(v0, 0.f); v1 = fmaxf(v1, 0.f);
                v2 = fmaxf(v2, 0.f); v3 = fmaxf(v3, 0.f);
            }
            if (OUT == 0) {
                *(float2*)(C + (size_t)r0 * N + c)       = make_float2(v0, v1);
                *(float2*)(C + (size_t)(r0 + 8) * N + c) = make_float2(v2, v3);
            } else {
                __nv_bfloat16 h0 = __float2bfloat16(v0), h1 = __float2bfloat16(v1);
                __nv_bfloat16 h2 = __float2bfloat16(v2), h3 = __float2bfloat16(v3);
                __nv_bfloat162 hp0(h0, h1), hp1(h2, h3);
                __nv_bfloat162 lp0(__float2bfloat16(v0 - __bfloat162float(h0)),
                                   __float2bfloat16(v1 - __bfloat162float(h1)));
                __nv_bfloat162 lp1(__float2bfloat16(v2 - __bfloat162float(h2)),
                                   __float2bfloat16(v3 - __bfloat162float(h3)));
                *(__nv_bfloat162*)(qh_t + (size_t)r0 * on + cc)       = hp0;
                *(__nv_bfloat162*)(qh_t + (size_t)(r0 + 8) * on + cc) = hp1;
                *(__nv_bfloat162*)(ql_t + (size_t)r0 * on + cc)       = lp0;
                *(__nv_bfloat162*)(ql_t + (size_t)(r0 + 8) * on + cc) = lp1;
            }
        }
    }
}

// ============================================================================
// T5 relative-position bucket for displacement d
// ============================================================================
__device__ __forceinline__ int rel_bucket_d(int d)
{
    int ret = (d < 0) ? NHEAD : 0;
    int n   = abs(d);
    int b;
    if (n < 8) b = n;
    else {
        int j = (31 - __clz(n * n)) - 6;
        j = min(j, 7);
        b = 8 + j;
    }
    return ret + b;
}

// ============================================================================
// Fused flash attention (unchanged from R6)
// ============================================================================
#define AT_Q   0
#define AT_QL  16384
#define AT_KH  32768
#define AT_KL  49152
#define AT_VH  65536
#define AT_VL  81920
#define AT_LM  98304
#define AT_BD  102400
#define AT_SMEM (AT_BD + 8192)

__device__ __forceinline__ uint32_t swz128(int r, int c) {
    return (uint32_t)(r * 128 + ((c ^ (r & 7)) << 4));
}

__global__ void __launch_bounds__(256, 1) attn_fused_kernel(
    const __nv_bfloat16* __restrict__ QH, const __nv_bfloat16* __restrict__ QL,
    const __nv_bfloat16* __restrict__ KH, const __nv_bfloat16* __restrict__ KL,
    const __nv_bfloat16* __restrict__ VH, const __nv_bfloat16* __restrict__ VL,
    const float* __restrict__ rel, const int* __restrict__ pm,
    __nv_bfloat16* __restrict__ OH, __nv_bfloat16* __restrict__ OL)
{
    extern __shared__ __align__(16) char smem[];
    uint32_t sb = smem_u32(smem);
    float* lm_s = (float*)(smem + AT_LM);
    float* bd_s = (float*)(smem + AT_BD);

    const int t = threadIdx.x, w = t >> 5, lane = t & 31;
    const int qt = blockIdx.x, bh = blockIdx.y;
    const int h = bh & (NHEAD - 1), b = bh >> 4;
    const size_t slab = (size_t)bh * (LSEQ * DHEAD);

    for (int i = t; i < LSEQ; i += 256)
        lm_s[i] = logf((float)pm[b * LSEQ + i]);
    for (int i = t; i < 2047; i += 256)
        bd_s[i] = rel[rel_bucket_d(i - 1023) * NHEAD + h];

    {
        size_t qbase = slab + (size_t)qt * 128 * DHEAD;
        for (int i = t; i < 1024; i += 256) {
            int r = i >> 3, c = i & 7;
            uint32_t off = swz128(r, c);
            size_t g = qbase + r * DHEAD + c * 8;
            cp16(sb + AT_Q  + off, QH + g);
            cp16(sb + AT_QL + off, QL + g);
        }
        for (int i = t; i < 1024; i += 256) {
            int r = i >> 3, c = i & 7;
            uint32_t off = swz128(r, c);
            size_t g = slab + r * DHEAD + c * 8;
            cp16(sb + AT_KH + off, KH + g);
            cp16(sb + AT_KL + off, KL + g);
            cp16(sb + AT_VH + off, VH + g);
            cp16(sb + AT_VL + off, VL + g);
        }
        asm volatile("cp.async.commit_group;" ::: "memory");
        asm volatile("cp.async.wait_group 0;" ::: "memory");
    }
    __syncthreads();

    uint32_t qfh[4][4], qfl[4][4];
    {
        int r = w * 16 + (lane & 15);
#pragma unroll
        for (int ks = 0; ks < 4; ks++) {
            int c = ks * 2 + (lane >> 4);
            uint32_t off = swz128(r, c);
            ldsm_x4(qfh[ks][0], qfh[ks][1], qfh[ks][2], qfh[ks][3], sb + AT_Q  + off);
            ldsm_x4(qfl[ks][0], qfl[ks][1], qfl[ks][2], qfl[ks][3], sb + AT_QL + off);
        }
    }

    float O[8][4];
#pragma unroll
    for (int nt = 0; nt < 8; nt++)
#pragma unroll
        for (int e = 0; e < 4; e++) O[nt][e] = 0.f;
    float m0 = -3.0e38f, m1 = -3.0e38f, l0 = 0.f, l1 = 0.f;

    const int r0 = qt * 128 + w * 16 + (lane >> 2);
    const int r1 = r0 + 8;

    for (int kt = 0; kt < 8; kt++) {
        float S[16][4];
#pragma unroll
        for (int j = 0; j < 16; j++)
#pragma unroll
            for (int e = 0; e < 4; e++) S[j][e] = 0.f;

#pragma unroll
        for (int ks = 0; ks < 4; ks++) {
            const int krow = ((lane >> 4) << 3) + (lane & 7);
            const int kch  = ks * 2 + ((lane >> 3) & 1);
#pragma unroll
            for (int jp = 0; jp < 8; jp++) {
                uint32_t off = swz128(jp * 16 + krow, kch);
                uint32_t kb[4], kl2[4];
                ldsm_x4(kb[0],  kb[1],  kb[2],  kb[3],  sb + AT_KH + off);
                ldsm_x4(kl2[0], kl2[1], kl2[2], kl2[3], sb + AT_KL + off);
                mma_bf16(S[2 * jp],     qfh[ks], kb);
                mma_bf16(S[2 * jp],     qfh[ks], kl2);
                mma_bf16(S[2 * jp],     qfl[ks], kb);
                mma_bf16(S[2 * jp + 1], qfh[ks], kb + 2);
                mma_bf16(S[2 * jp + 1], qfh[ks], kl2 + 2);
                mma_bf16(S[2 * jp + 1], qfl[ks], kb + 2);
            }
        }

        const int ktbase = kt * 128;
#pragma unroll
        for (int j = 0; j < 16; j++) {
            int c = ktbase + j * 8 + (lane & 3) * 2;
            float lc0 = lm_s[c], lc1 = lm_s[c + 1];
            S[j][0] += bd_s[c - r0 + 1023] + lc0;
            S[j][1] += bd_s[c + 1 - r0 + 1023] + lc1;
            S[j][2] += bd_s[c - r1 + 1023] + lc0;
            S[j][3] += bd_s[c + 1 - r1 + 1023] + lc1;
        }

        float tm0 = -3.0e38f, tm1 = -3.0e38f;
#pragma unroll
        for (int j = 0; j < 16; j++) {
            tm0 = fmaxf(tm0, fmaxf(S[j][0], S[j][1]));
            tm1 = fmaxf(tm1, fmaxf(S[j][2], S[j][3]));
        }
        tm0 = fmaxf(tm0, __shfl_xor_sync(0xffffffffu, tm0, 1));
        tm0 = fmaxf(tm0, __shfl_xor_sync(0xffffffffu, tm0, 2));
        tm1 = fmaxf(tm1, __shfl_xor_sync(0xffffffffu, tm1, 1));
        tm1 = fmaxf(tm1, __shfl_xor_sync(0xffffffffu, tm1, 2));
        float mn0 = fmaxf(m0, tm0), mn1 = fmaxf(m1, tm1);
        float a0 = __expf(m0 - mn0), a1 = __expf(m1 - mn1);
        m0 = mn0; m1 = mn1;

        float s0 = 0.f, s1 = 0.f;
#pragma unroll
        for (int j = 0; j < 16; j++) {
            S[j][0] = __expf(S[j][0] - mn0); s0 += S[j][0];
            S[j][1] = __expf(S[j][1] - mn0); s0 += S[j][1];
            S[j][2] = __expf(S[j][2] - mn1); s1 += S[j][2];
            S[j][3] = __expf(S[j][3] - mn1); s1 += S[j][3];
        }
        s0 += __shfl_xor_sync(0xffffffffu, s0, 1);
        s0 += __shfl_xor_sync(0xffffffffu, s0, 2);
        s1 += __shfl_xor_sync(0xffffffffu, s1, 1);
        s1 += __shfl_xor_sync(0xffffffffu, s1, 2);
        l0 = l0 * a0 + s0;
        l1 = l1 * a1 + s1;

#pragma unroll
        for (int nt = 0; nt < 8; nt++) {
            O[nt][0] *= a0; O[nt][1] *= a0;
            O[nt][2] *= a1; O[nt][3] *= a1;
        }

#pragma unroll
        for (int kk = 0; kk < 8; kk++) {
            float* p0 = S[2 * kk];
            float* p1 = S[2 * kk + 1];
            uint32_t ph[4], pl[4];
            {
                __nv_bfloat16 h00 = __float2bfloat16(p0[0]), h01 = __float2bfloat16(p0[1]);
                __nv_bfloat16 h02 = __float2bfloat16(p0[2]), h03 = __float2bfloat16(p0[3]);
                __nv_bfloat16 h10 = __float2bfloat16(p1[0]), h11 = __float2bfloat16(p1[1]);
                __nv_bfloat16 h12 = __float2bfloat16(p1[2]), h13 = __float2bfloat16(p1[3]);
                __nv_bfloat162 t0(h00, h01), t1(h02, h03), t2(h10, h11), t3(h12, h13);
                ph[0] = *(uint32_t*)&t0; ph[1] = *(uint32_t*)&t1;
                ph[2] = *(uint32_t*)&t2; ph[3] = *(uint32_t*)&t3;
                pl[0] = packbf2(p0[0] - __bfloat162float(h00), p0[1] - __bfloat162float(h01));
                pl[1] = packbf2(p0[2] - __bfloat162float(h02), p0[3] - __bfloat162float(h03));
                pl[2] = packbf2(p1[0] - __bfloat162float(h10), p1[1] - __bfloat162float(h11));
                pl[3] = packbf2(p1[2] - __bfloat162float(h12), p1[3] - __bfloat162float(h13));
            }
            const int vrow = kk * 16 + (lane & 15);
            const int vcp  = (lane >> 4) & 1;
#pragma unroll
            for (int np = 0; np < 4; np++) {
                uint32_t off = swz128(vrow, np * 2 + vcp);
                uint32_t vb[4], vl2[4];
                ldsm_x4t(vb[0],  vb[1],  vb[2],  vb[3],  sb + AT_VH + off);
                ldsm_x4t(vl2[0], vl2[1], vl2[2], vl2[3], sb + AT_VL + off);
                mma_bf16(O[2 * np],     ph, vb);
                mma_bf16(O[2 * np],     ph, vl2);
                mma_bf16(O[2 * np],     pl, vb);
                mma_bf16(O[2 * np + 1], ph, vb + 2);
                mma_bf16(O[2 * np + 1], ph, vl2 + 2);
                mma_bf16(O[2 * np + 1], pl, vb + 2);
            }
        }

        __syncthreads();
        if (kt < 7) {
            size_t kb = slab + (size_t)(kt + 1) * 128 * DHEAD;
            for (int i = t; i < 1024; i += 256) {
                int r = i >> 3, c = i & 7;
                uint32_t off = swz128(r, c);
                size_t g = kb + r * DHEAD + c * 8;
                cp16(sb + AT_KH + off, KH + g);
                cp16(sb + AT_KL + off, KL + g);
                cp16(sb + AT_VH + off, VH + g);
                cp16(sb + AT_VL + off, VL + g);
            }
            asm volatile("cp.async.commit_group;" ::: "memory");
            asm volatile("cp.async.wait_group 0;" ::: "memory");
        }
        __syncthreads();
    }

    float inv0 = 1.f / l0, inv1 = 1.f / l1;
    size_t ob0 = slab + (size_t)(qt * 128 + w * 16 + (lane >> 2)) * DHEAD;
    size_t ob1 = ob0 + 8 * DHEAD;
#pragma unroll
    for (int nt = 0; nt < 8; nt++) {
        int c = nt * 8 + (lane & 3) * 2;
        float v0 = O[nt][0] * inv0, v1 = O[nt][1] * inv0;
        float v2 = O[nt][2] * inv1, v3 = O[nt][3] * inv1;
        __nv_bfloat16 h0 = __float2bfloat16(v0), h1 = __float2bfloat16(v1);
        __nv_bfloat16 h2 = __float2bfloat16(v2), h3 = __float2bfloat16(v3);
        __nv_bfloat162 hp0(h0, h1), hp1(h2, h3);
        *(__nv_bfloat162*)(OH + ob0 + c) = hp0;
        *(__nv_bfloat162*)(OH + ob1 + c) = hp1;
        *(__nv_bfloat162*)(OL + ob0 + c) =
            __nv_bfloat162(__float2bfloat16(v0 - __bfloat162float(h0)),
                           __float2bfloat16(v1 - __bfloat162float(h1)));
        *(__nv_bfloat162*)(OL + ob1 + c) =
            __nv_bfloat162(__float2bfloat16(v2 - __bfloat162float(h2)),
                           __float2bfloat16(v3 - __bfloat162float(h3)));
    }
}

// ============================================================================
// out = LayerNorm(A + B); optional bf16 hi/lo side output
// ============================================================================
template <bool SPLIT>
__global__ void __launch_bounds__(256) add_ln_kernel(
    const float* __restrict__ A, const float* __restrict__ B,
    float* __restrict__ out,
    __nv_bfloat16* __restrict__ OH, __nv_bfloat16* __restrict__ OL)
{
    __shared__ float sh[8];
    const size_t row = blockIdx.x;
    const int t = threadIdx.x;

    float4 a = ((const float4*)(A + row * DMODEL))[t];
    float4 b = ((const float4*)(B + row * DMODEL))[t];
    float4 x;
    x.x = a.x + b.x; x.y = a.y + b.y; x.z = a.z + b.z; x.w = a.w + b.w;

    float s = x.x + x.y + x.z + x.w;
#pragma unroll
    for (int o = 16; o; o >>= 1) s += __shfl_xor_sync(0xffffffffu, s, o);
    if ((t & 31) == 0) sh[t >> 5] = s;
    __syncthreads();
    float tot = sh[0];
#pragma unroll
    for (int i = 1; i < 8; i++) tot += sh[i];
    __syncthreads();
    float mean = tot * (1.f / DMODEL);

    float dx = x.x - mean, dy = x.y - mean, dz = x.z - mean, dw = x.w - mean;
    float s2 = dx * dx + dy * dy + dz * dz + dw * dw;
#pragma unroll
    for (int o = 16; o; o >>= 1) s2 += __shfl_xor_sync(0xffffffffu, s2, o);
    if ((t & 31) == 0) sh[t >> 5] = s2;
    __syncthreads();
    float tot2 = sh[0];
#pragma unroll
    for (int i = 1; i < 8; i++) tot2 += sh[i];
    float inv = rsqrtf(tot2 * (1.f / DMODEL));

    float4 o;
    o.x = dx * inv; o.y = dy * inv; o.z = dz * inv; o.w = dw * inv;
    ((float4*)(out + row * DMODEL))[t] = o;

    if (SPLIT) {
        __nv_bfloat16 h0 = __float2bfloat16(o.x), h1 = __float2bfloat16(o.y);
        __nv_bfloat16 h2 = __float2bfloat16(o.z), h3 = __float2bfloat16(o.w);
        __nv_bfloat162 hp0(h0, h1), hp1(h2, h3);
        __nv_bfloat162 lp0(__float2bfloat16(o.x - __bfloat162float(h0)),
                           __float2bfloat16(o.y - __bfloat162float(h1)));
        __nv_bfloat162 lp1(__float2bfloat16(o.z - __bfloat162float(h2)),
                           __float2bfloat16(o.w - __bfloat162float(h3)));
        size_t base = row * DMODEL + t * 4;
        *(__nv_bfloat162*)(OH + base)     = hp0;
        *(__nv_bfloat162*)(OH + base + 2) = hp1;
        *(__nv_bfloat162*)(OL + base)     = lp0;
        *(__nv_bfloat162*)(OL + base + 2) = lp1;
    }
}

// ============================================================================
// Launch sequence
// ============================================================================
extern "C" void kernel_launch(void* const* d_in, const int* in_sizes, int n_in,
                              void* d_out, int out_size)
{
    const float* x   = (const float*)d_in[0];
    const int*   pm  = (const int*)  d_in[1];
    const float* Wq  = (const float*)d_in[2];
    const float* bq  = (const float*)d_in[3];
    const float* Wk  = (const float*)d_in[4];
    const float* bk  = (const float*)d_in[5];
    const float* Wv  = (const float*)d_in[6];
    const float* bv  = (const float*)d_in[7];
    const float* Wo  = (const float*)d_in[8];
    const float* bo  = (const float*)d_in[9];
    const float* rel = (const float*)d_in[10];
    const float* W1  = (const float*)d_in[11];
    const float* b1  = (const float*)d_in[12];
    const float* W2  = (const float*)d_in[13];
    const float* b2  = (const float*)d_in[14];
    float* out = (float*)d_out;

    float *attp, *attout, *ff, *bqkv;
    cudaGetSymbolAddress((void**)&attp,   g_attp);
    cudaGetSymbolAddress((void**)&attout, g_attout);
    cudaGetSymbolAddress((void**)&ff,     g_ff);
    cudaGetSymbolAddress((void**)&bqkv,   g_bqkv);

    __nv_bfloat16 *xh, *xl, *wqkvh, *wqkvl, *woh, *wol;
    __nv_bfloat16 *w1h, *w1l, *w2h, *w2l, *avh, *avl, *aoh, *aol, *h1h, *h1l;
    __nv_bfloat16 *qkvh, *qkvl;
    cudaGetSymbolAddress((void**)&xh,    g_xh);    cudaGetSymbolAddress((void**)&xl,    g_xl);
    cudaGetSymbolAddress((void**)&wqkvh, g_wqkvh); cudaGetSymbolAddress((void**)&wqkvl, g_wqkvl);
    cudaGetSymbolAddress((void**)&woh,   g_woh);   cudaGetSymbolAddress((void**)&wol,   g_wol);
    cudaGetSymbolAddress((void**)&w1h,   g_w1h);   cudaGetSymbolAddress((void**)&w1l,   g_w1l);
    cudaGetSymbolAddress((void**)&w2h,   g_w2h);   cudaGetSymbolAddress((void**)&w2l,   g_w2l);
    cudaGetSymbolAddress((void**)&avh,   g_avh);   cudaGetSymbolAddress((void**)&avl,   g_avl);
    cudaGetSymbolAddress((void**)&aoh,   g_aoh);   cudaGetSymbolAddress((void**)&aol,   g_aol);
    cudaGetSymbolAddress((void**)&h1h,   g_h1h);   cudaGetSymbolAddress((void**)&h1l,   g_h1l);
    cudaGetSymbolAddress((void**)&qkvh,  g_qkvh);  cudaGetSymbolAddress((void**)&qkvl,  g_qkvl);

    static bool attr_done = false;
    if (!attr_done) {
        cudaFuncSetAttribute(tgemm_kernel<false, 0>,
                             cudaFuncAttributeMaxDynamicSharedMemorySize, TG_SMEM);
        cudaFuncSetAttribute(tgemm_kernel<false, 1>,
                             cudaFuncAttributeMaxDynamicSharedMemorySize, TG_SMEM);
        cudaFuncSetAttribute(tgemm_kernel<false, 2>,
                             cudaFuncAttributeMaxDynamicSharedMemorySize, TG_SMEM);
        cudaFuncSetAttribute(tgemm_kernel<true, 1>,
                             cudaFuncAttributeMaxDynamicSharedMemorySize, TG_SMEM);
        cudaFuncSetAttribute(attn_fused_kernel,
                             cudaFuncAttributeMaxDynamicSharedMemorySize, AT_SMEM);
        attr_done = true;
    }

    dim3 blk(256);

    // L1: split x; L2: split all weights (+bias pack)
    split_kernel<<<(MROWS * DMODEL / 4 + 255) / 256, blk>>>(
        x, xh, xl, MROWS * DMODEL / 4);
    splitw_all_kernel<<<(SEG_TOTAL + 255) / 256, blk>>>(
        Wq, Wk, Wv, Wo, W1, W2, bq, bk, bv,
        wqkvh, wqkvl, woh, wol, w1h, w1l, w2h, w2l, bqkv);

    // L3: fused QKV projection
    dim3 gqkv(3 * DMODEL / TBN, MROWS / TBM);
    tgemm_kernel<false, 2><<<gqkv, blk, TG_SMEM>>>(
        xh, xl, wqkvh, wqkvl, bqkv, nullptr, qkvh, qkvl, MROWS, 3 * DMODEL, DMODEL);

    // L4: attention
    const size_t SLAB = (size_t)MROWS * DMODEL;
    attn_fused_kernel<<<dim3(8, BHDIM), blk, AT_SMEM>>>(
        qkvh, qkvl, qkvh + SLAB, qkvl + SLAB, qkvh + 2 * SLAB, qkvl + 2 * SLAB,
        rel, pm, avh, avl);

    // L5: O projection
    dim3 gO(DMODEL / TBN, MROWS / TBM);
    tgemm_kernel<false, 0><<<gO, blk, TG_SMEM>>>(
        avh, avl, woh, wol, bo, attp, nullptr, nullptr, MROWS, DMODEL, DMODEL);

    // L6: residual + LN (+ split)
    add_ln_kernel<true><<<MROWS, blk>>>(attp, x, attout, aoh, aol);

    // L7/L8: FFN
    dim3 g1(FFDIM / TBN, MROWS / TBM);
    tgemm_kernel<true, 1><<<g1, blk, TG_SMEM>>>(
        aoh, aol, w1h, w1l, b1, nullptr, h1h, h1l, MROWS, FFDIM, DMODEL);
    dim3 g2(DMODEL / TBN, MROWS / TBM);
    tgemm_kernel<false, 0><<<g2, blk, TG_SMEM>>>(
        h1h, h1l, w2h, w2l, b2, ff, nullptr, nullptr, MROWS, DMODEL, FFDIM);

    // L9: final residual + LN
    add_ln_kernel<false><<<MROWS, blk>>>(ff, attout, out, nullptr, nullptr);
}

// round 8
// speedup vs baseline: 3.1157x; 1.0336x over previous
#include <cuda_runtime.h>
#include <cuda_bf16.h>
#include <math.h>
#include <stdint.h>

// ---------------------------------------------------------------------------
// EncoderBlock: B=4, L=1024, D=1024, F=4096, H=16, dh=64
// Round 8: tgemm 3-stage single-barrier pipeline (+tail-wait fix);
//          attention double-buffered K/V with one-tile lookahead.
// ---------------------------------------------------------------------------

#define LSEQ 1024
#define DMODEL 1024
#define BATCH 4
#define NHEAD 16
#define DHEAD 64
#define FFDIM 4096
#define BHDIM 64
#define MROWS 4096

// ---- fp32 scratch ----------------------------------------------------------
__device__ float g_attp[BATCH * LSEQ * DMODEL];
__device__ float g_attout[BATCH * LSEQ * DMODEL];
__device__ float g_ff[BATCH * LSEQ * DMODEL];
__device__ float g_bqkv[3 * DMODEL];

// ---- bf16 hi/lo scratch -----------------------------------------------------
__device__ __nv_bfloat16 g_xh[MROWS * DMODEL],  g_xl[MROWS * DMODEL];
__device__ __nv_bfloat16 g_wqkvh[3 * DMODEL * DMODEL], g_wqkvl[3 * DMODEL * DMODEL];
__device__ __nv_bfloat16 g_woh[DMODEL * DMODEL], g_wol[DMODEL * DMODEL];
__device__ __nv_bfloat16 g_w1h[FFDIM * DMODEL],  g_w1l[FFDIM * DMODEL];
__device__ __nv_bfloat16 g_w2h[DMODEL * FFDIM],  g_w2l[DMODEL * FFDIM];
__device__ __nv_bfloat16 g_qkvh[3 * MROWS * DMODEL], g_qkvl[3 * MROWS * DMODEL];
__device__ __nv_bfloat16 g_avh[MROWS * DMODEL],  g_avl[MROWS * DMODEL];
__device__ __nv_bfloat16 g_aoh[MROWS * DMODEL],  g_aol[MROWS * DMODEL];
__device__ __nv_bfloat16 g_h1h[(size_t)MROWS * FFDIM], g_h1l[(size_t)MROWS * FFDIM];

// ============================================================================
// helpers
// ============================================================================
__device__ __forceinline__ uint32_t smem_u32(const void* p) {
    uint32_t a;
    asm("{ .reg .u64 t; cvta.to.shared.u64 t, %1; cvt.u32.u64 %0, t; }"
        : "=r"(a) : "l"(p));
    return a;
}
__device__ __forceinline__ void cp16(uint32_t dst, const void* src) {
    asm volatile("cp.async.cg.shared.global [%0], [%1], 16;" :: "r"(dst), "l"(src));
}
__device__ __forceinline__ void ldsm_x4(uint32_t& r0, uint32_t& r1,
                                        uint32_t& r2, uint32_t& r3, uint32_t a) {
    asm volatile("ldmatrix.sync.aligned.m8n8.x4.shared.b16 {%0,%1,%2,%3}, [%4];"
                 : "=r"(r0), "=r"(r1), "=r"(r2), "=r"(r3) : "r"(a));
}
__device__ __forceinline__ void ldsm_x4t(uint32_t& r0, uint32_t& r1,
                                         uint32_t& r2, uint32_t& r3, uint32_t a) {
    asm volatile("ldmatrix.sync.aligned.m8n8.x4.trans.shared.b16 {%0,%1,%2,%3}, [%4];"
                 : "=r"(r0), "=r"(r1), "=r"(r2), "=r"(r3) : "r"(a));
}
__device__ __forceinline__ void mma_bf16(float* c, const uint32_t* a, const uint32_t* b) {
    asm volatile(
        "mma.sync.aligned.m16n8k16.row.col.f32.bf16.bf16.f32 "
        "{%0,%1,%2,%3}, {%4,%5,%6,%7}, {%8,%9}, {%0,%1,%2,%3};"
        : "+f"(c[0]), "+f"(c[1]), "+f"(c[2]), "+f"(c[3])
        : "r"(a[0]), "r"(a[1]), "r"(a[2]), "r"(a[3]), "r"(b[0]), "r"(b[1]));
}
__device__ __forceinline__ uint32_t packbf2(float x, float y) {
    __nv_bfloat162 t2(__float2bfloat16(x), __float2bfloat16(y));
    return *(uint32_t*)&t2;
}

// ============================================================================
// split: X(fp32) -> hi = bf16(X), lo = bf16(X - hi)
// ============================================================================
__global__ void __launch_bounds__(256) split_kernel(
    const float* __restrict__ X, __nv_bfloat16* __restrict__ H,
    __nv_bfloat16* __restrict__ L, int n4)
{
    int i = blockIdx.x * 256 + threadIdx.x;
    if (i >= n4) return;
    float4 v = ((const float4*)X)[i];
    __nv_bfloat16 h0 = __float2bfloat16(v.x);
    __nv_bfloat16 h1 = __float2bfloat16(v.y);
    __nv_bfloat16 h2 = __float2bfloat16(v.z);
    __nv_bfloat16 h3 = __float2bfloat16(v.w);
    __nv_bfloat162 hp0(h0, h1), hp1(h2, h3);
    __nv_bfloat162 lp0(__float2bfloat16(v.x - __bfloat162float(h0)),
                       __float2bfloat16(v.y - __bfloat162float(h1)));
    __nv_bfloat162 lp1(__float2bfloat16(v.z - __bfloat162float(h2)),
                       __float2bfloat16(v.w - __bfloat162float(h3)));
    ((uint2*)H)[i] = make_uint2(*(uint32_t*)&hp0, *(uint32_t*)&hp1);
    ((uint2*)L)[i] = make_uint2(*(uint32_t*)&lp0, *(uint32_t*)&lp1);
}

// ============================================================================
// One kernel splitting ALL weights + qkv bias pack.
// ============================================================================
#define SEG_QKV (3 * DMODEL * DMODEL / 4)
#define SEG_WO  (DMODEL * DMODEL / 4)
#define SEG_W1  (FFDIM * DMODEL / 4)
#define SEG_W2  (DMODEL * FFDIM / 4)
#define SEG_TOTAL (SEG_QKV + SEG_WO + SEG_W1 + SEG_W2)

__global__ void __launch_bounds__(256) splitw_all_kernel(
    const float* __restrict__ Wq, const float* __restrict__ Wk,
    const float* __restrict__ Wv, const float* __restrict__ Wo,
    const float* __restrict__ W1, const float* __restrict__ W2,
    const float* __restrict__ bq, const float* __restrict__ bk,
    const float* __restrict__ bv,
    __nv_bfloat16* __restrict__ QKVH, __nv_bfloat16* __restrict__ QKVL,
    __nv_bfloat16* __restrict__ WOH,  __nv_bfloat16* __restrict__ WOL,
    __nv_bfloat16* __restrict__ W1H,  __nv_bfloat16* __restrict__ W1L,
    __nv_bfloat16* __restrict__ W2H,  __nv_bfloat16* __restrict__ W2L,
    float* __restrict__ bpack)
{
    int i = blockIdx.x * 256 + threadIdx.x;
    if (i < 3 * DMODEL) {
        float b = (i < DMODEL) ? bq[i] : (i < 2 * DMODEL) ? bk[i - DMODEL]
                                                          : bv[i - 2 * DMODEL];
        bpack[i] = b;
    }
    if (i >= SEG_TOTAL) return;

    const float* src;
    __nv_bfloat16 *H, *L;
    int off;
    if (i < SEG_QKV) {
        const int n4m = DMODEL * DMODEL / 4;
        int m = i / n4m;
        off = i - m * n4m;
        src = (m == 0) ? Wq : (m == 1) ? Wk : Wv;
        H = QKVH + (size_t)m * DMODEL * DMODEL;
        L = QKVL + (size_t)m * DMODEL * DMODEL;
    } else if (i < SEG_QKV + SEG_WO) {
        off = i - SEG_QKV; src = Wo; H = WOH; L = WOL;
    } else if (i < SEG_QKV + SEG_WO + SEG_W1) {
        off = i - SEG_QKV - SEG_WO; src = W1; H = W1H; L = W1L;
    } else {
        off = i - SEG_QKV - SEG_WO - SEG_W1; src = W2; H = W2H; L = W2L;
    }

    float4 v = ((const float4*)src)[off];
    __nv_bfloat16 h0 = __float2bfloat16(v.x);
    __nv_bfloat16 h1 = __float2bfloat16(v.y);
    __nv_bfloat16 h2 = __float2bfloat16(v.z);
    __nv_bfloat16 h3 = __float2bfloat16(v.w);
    __nv_bfloat162 hp0(h0, h1), hp1(h2, h3);
    __nv_bfloat162 lp0(__float2bfloat16(v.x - __bfloat162float(h0)),
                       __float2bfloat16(v.y - __bfloat162float(h1)));
    __nv_bfloat162 lp1(__float2bfloat16(v.z - __bfloat162float(h2)),
                       __float2bfloat16(v.w - __bfloat162float(h3)));
    ((uint2*)H)[off] = make_uint2(*(uint32_t*)&hp0, *(uint32_t*)&hp1);
    ((uint2*)L)[off] = make_uint2(*(uint32_t*)&lp0, *(uint32_t*)&lp1);
}

// ============================================================================
// mma.sync GEMM: 3-stage pipeline, ONE barrier per k-iter, correct tail waits.
// ============================================================================
#define TBM 128
#define TBN 128
#define TBK 32
#define STG_BYTES 32768
#define TG_SMEM (3 * STG_BYTES)

__device__ __forceinline__ uint32_t sw_off(int r, int c) {
    return (uint32_t)(r * 64 + ((c ^ ((r >> 1) & 3)) << 4));
}

__device__ __forceinline__ void tg_load_stage(
    uint32_t sbuf, int t,
    const __nv_bfloat16* __restrict__ Ah, const __nv_bfloat16* __restrict__ Al,
    const __nv_bfloat16* __restrict__ Bh, const __nv_bfloat16* __restrict__ Bl,
    int rowBase, int colBase, int k0, int K)
{
#pragma unroll
    for (int j = 0; j < 8; j++) {
        int i   = j * 256 + t;
        int arr = i >> 9;
        int idx = i & 511;
        int r   = idx >> 2;
        int ch  = idx & 3;
        const __nv_bfloat16* base =
            (arr == 0) ? Ah : (arr == 1) ? Al : (arr == 2) ? Bh : Bl;
        int gr = ((arr < 2) ? rowBase : colBase) + r;
        cp16(sbuf + arr * 8192 + sw_off(r, ch),
             base + (size_t)gr * K + k0 + ch * 8);
    }
    asm volatile("cp.async.commit_group;" ::: "memory");
}

template <bool RELU, int OUT>
__global__ void __launch_bounds__(256, 2) tgemm_kernel(
    const __nv_bfloat16* __restrict__ Ah, const __nv_bfloat16* __restrict__ Al,
    const __nv_bfloat16* __restrict__ Bh, const __nv_bfloat16* __restrict__ Bl,
    const float* __restrict__ bias, float* __restrict__ C,
    __nv_bfloat16* __restrict__ Ch, __nv_bfloat16* __restrict__ Cl,
    int M, int N, int K)
{
    extern __shared__ __align__(16) char smem[];
    uint32_t sb = smem_u32(smem);
    const int t = threadIdx.x;
    const int w = t >> 5, lane = t & 31;
    const int wm = w >> 2;
    const int wn = w & 3;
    const int rowBase = blockIdx.y * TBM;
    const int colBase = blockIdx.x * TBN;
    const int KT = K / TBK;

    float acc[4][4][4];
#pragma unroll
    for (int mt = 0; mt < 4; mt++)
#pragma unroll
        for (int nt = 0; nt < 4; nt++)
#pragma unroll
            for (int e = 0; e < 4; e++) acc[mt][nt][e] = 0.f;

    tg_load_stage(sb,                 t, Ah, Al, Bh, Bl, rowBase, colBase, 0 * TBK, K);
    tg_load_stage(sb + 1 * STG_BYTES, t, Ah, Al, Bh, Bl, rowBase, colBase, 1 * TBK, K);

    int stage = 0;   // stage index of kt in {0,1,2}
    for (int kt = 0; kt < KT; kt++) {
        // g(kt) must be complete; g(kt+1) is the only possibly-younger group.
        if (kt + 1 < KT)
            asm volatile("cp.async.wait_group 1;" ::: "memory");
        else
            asm volatile("cp.async.wait_group 0;" ::: "memory");
        __syncthreads();

        // Prefetch kt+2 into the slot consumed at kt-1 (all warps passed barrier).
        if (kt + 2 < KT) {
            int ps = stage + 2; if (ps >= 3) ps -= 3;
            tg_load_stage(sb + ps * STG_BYTES, t,
                          Ah, Al, Bh, Bl, rowBase, colBase, (kt + 2) * TBK, K);
        }

        uint32_t sbase = sb + stage * STG_BYTES;
#pragma unroll
        for (int ks = 0; ks < 2; ks++) {
            uint32_t ah[4][4], al[4][4], bh[4][2], bl[4][2];
            const int arow0  = wm * 64 + (lane & 15);
            const int achunk = ks * 2 + (lane >> 4);
#pragma unroll
            for (int mt = 0; mt < 4; mt++) {
                int r = arow0 + mt * 16;
                uint32_t off = sw_off(r, achunk);
                ldsm_x4(ah[mt][0], ah[mt][1], ah[mt][2], ah[mt][3], sbase + off);
                ldsm_x4(al[mt][0], al[mt][1], al[mt][2], al[mt][3], sbase + 8192 + off);
            }
            const int brow = wn * 32 + ((lane >> 4) << 3) + (lane & 7);
            const int bch  = ks * 2 + ((lane >> 3) & 1);
#pragma unroll
            for (int np = 0; np < 2; np++) {
                uint32_t off = sw_off(brow + np * 16, bch);
                ldsm_x4(bh[2 * np][0], bh[2 * np][1],
                        bh[2 * np + 1][0], bh[2 * np + 1][1], sbase + 16384 + off);
                ldsm_x4(bl[2 * np][0], bl[2 * np][1],
                        bl[2 * np + 1][0], bl[2 * np + 1][1], sbase + 24576 + off);
            }
#pragma unroll
            for (int mt = 0; mt < 4; mt++)
#pragma unroll
                for (int nt = 0; nt < 4; nt++) {
                    mma_bf16(acc[mt][nt], ah[mt], bh[nt]);
                    mma_bf16(acc[mt][nt], ah[mt], bl[nt]);
                    mma_bf16(acc[mt][nt], al[mt], bh[nt]);
                }
        }
        stage++; if (stage == 3) stage = 0;
    }

    // Epilogue
#pragma unroll
    for (int nt = 0; nt < 4; nt++) {
        int c = colBase + wn * 32 + nt * 8 + (lane & 3) * 2;
        float b0 = __ldg(&bias[c]), b1 = __ldg(&bias[c + 1]);
        __nv_bfloat16* qh_t = Ch;
        __nv_bfloat16* ql_t = Cl;
        int cc = c;
        int on = N;
        if (OUT == 2) {
            int sel = c >> 10;
            qh_t = Ch + (size_t)sel * MROWS * DMODEL;
            ql_t = Cl + (size_t)sel * MROWS * DMODEL;
            cc = c & 1023;
            on = DMODEL;
        }
#pragma unroll
        for (int mt = 0; mt < 4; mt++) {
            int r0 = rowBase + wm * 64 + mt * 16 + (lane >> 2);
            float v0 = acc[mt][nt][0] + b0, v1 = acc[mt][nt][1] + b1;
            float v2 = acc[mt][nt][2] + b0, v3 = acc[mt][nt][3] + b1;
            if (RELU) {
                v0 = fmaxf(v0, 0.f); v1 = fmaxf(v1, 0.f);
                v2 = fmaxf(v2, 0.f); v3 = fmaxf(v3, 0.f);
            }
            if (OUT == 0) {
                *(float2*)(C + (size_t)r0 * N + c)       = make_float2(v0, v1);
                *(float2*)(C + (size_t)(r0 + 8) * N + c) = make_float2(v2, v3);
            } else {
                __nv_bfloat16 h0 = __float2bfloat16(v0), h1 = __float2bfloat16(v1);
                __nv_bfloat16 h2 = __float2bfloat16(v2), h3 = __float2bfloat16(v3);
                __nv_bfloat162 hp0(h0, h1), hp1(h2, h3);
                __nv_bfloat162 lp0(__float2bfloat16(v0 - __bfloat162float(h0)),
                                   __float2bfloat16(v1 - __bfloat162float(h1)));
                __nv_bfloat162 lp1(__float2bfloat16(v2 - __bfloat162float(h2)),
                                   __float2bfloat16(v3 - __bfloat162float(h3)));
                *(__nv_bfloat162*)(qh_t + (size_t)r0 * on + cc)       = hp0;
                *(__nv_bfloat162*)(qh_t + (size_t)(r0 + 8) * on + cc) = hp1;
                *(__nv_bfloat162*)(ql_t + (size_t)r0 * on + cc)       = lp0;
                *(__nv_bfloat162*)(ql_t + (size_t)(r0 + 8) * on + cc) = lp1;
            }
        }
    }
}

// ============================================================================
// T5 relative-position bucket for displacement d
// ============================================================================
__device__ __forceinline__ int rel_bucket_d(int d)
{
    int ret = (d < 0) ? NHEAD : 0;
    int n   = abs(d);
    int b;
    if (n < 8) b = n;
    else {
        int j = (31 - __clz(n * n)) - 6;
        j = min(j, 7);
        b = 8 + j;
    }
    return ret + b;
}

// ============================================================================
// Fused flash attention — double-buffered K/V with one-tile lookahead.
// smem: Q 16K | QL 16K | KV stage0 64K | KV stage1 64K | lm 4K | bd 8K = 172KB
// ============================================================================
#define AT_Q    0
#define AT_QL   16384
#define AT_KV   32768          /* + stage*65536; KH,KL,VH,VL each 16384 */
#define AT_LM   163840
#define AT_BD   167936
#define AT_SMEM 176128

__device__ __forceinline__ uint32_t swz128(int r, int c) {
    return (uint32_t)(r * 128 + ((c ^ (r & 7)) << 4));
}

__device__ __forceinline__ void at_load_kv(
    uint32_t kvbase, int t, size_t slab, int kt,
    const __nv_bfloat16* __restrict__ KH, const __nv_bfloat16* __restrict__ KL,
    const __nv_bfloat16* __restrict__ VH, const __nv_bfloat16* __restrict__ VL)
{
    size_t gb = slab + (size_t)kt * 128 * DHEAD;
    for (int i = t; i < 1024; i += 256) {
        int r = i >> 3, c = i & 7;
        uint32_t off = swz128(r, c);
        size_t g = gb + r * DHEAD + c * 8;
        cp16(kvbase + off,         KH + g);
        cp16(kvbase + 16384 + off, KL + g);
        cp16(kvbase + 32768 + off, VH + g);
        cp16(kvbase + 49152 + off, VL + g);
    }
    asm volatile("cp.async.commit_group;" ::: "memory");
}

__global__ void __launch_bounds__(256, 1) attn_fused_kernel(
    const __nv_bfloat16* __restrict__ QH, const __nv_bfloat16* __restrict__ QL,
    const __nv_bfloat16* __restrict__ KH, const __nv_bfloat16* __restrict__ KL,
    const __nv_bfloat16* __restrict__ VH, const __nv_bfloat16* __restrict__ VL,
    const float* __restrict__ rel, const int* __restrict__ pm,
    __nv_bfloat16* __restrict__ OH, __nv_bfloat16* __restrict__ OL)
{
    extern __shared__ __align__(16) char smem[];
    uint32_t sb = smem_u32(smem);
    float* lm_s = (float*)(smem + AT_LM);
    float* bd_s = (float*)(smem + AT_BD);

    const int t = threadIdx.x, w = t >> 5, lane = t & 31;
    const int qt = blockIdx.x, bh = blockIdx.y;
    const int h = bh & (NHEAD - 1), b = bh >> 4;
    const size_t slab = (size_t)bh * (LSEQ * DHEAD);

    for (int i = t; i < LSEQ; i += 256)
        lm_s[i] = logf((float)pm[b * LSEQ + i]);
    for (int i = t; i < 2047; i += 256)
        bd_s[i] = rel[rel_bucket_d(i - 1023) * NHEAD + h];

    // ---- prologue: Q + KV0 (group 0), KV1 (group 1) ----
    {
        size_t qbase = slab + (size_t)qt * 128 * DHEAD;
        for (int i = t; i < 1024; i += 256) {
            int r = i >> 3, c = i & 7;
            uint32_t off = swz128(r, c);
            size_t g = qbase + r * DHEAD + c * 8;
            cp16(sb + AT_Q  + off, QH + g);
            cp16(sb + AT_QL + off, QL + g);
        }
        at_load_kv(sb + AT_KV, t, slab, 0, KH, KL, VH, VL);       // Q shares group 0
        at_load_kv(sb + AT_KV + 65536, t, slab, 1, KH, KL, VH, VL);
        asm volatile("cp.async.wait_group 1;" ::: "memory");       // Q + KV0 ready
    }
    __syncthreads();

    // ---- Q fragments ----
    uint32_t qfh[4][4], qfl[4][4];
    {
        int r = w * 16 + (lane & 15);
#pragma unroll
        for (int ks = 0; ks < 4; ks++) {
            int c = ks * 2 + (lane >> 4);
            uint32_t off = swz128(r, c);
            ldsm_x4(qfh[ks][0], qfh[ks][1], qfh[ks][2], qfh[ks][3], sb + AT_Q  + off);
            ldsm_x4(qfl[ks][0], qfl[ks][1], qfl[ks][2], qfl[ks][3], sb + AT_QL + off);
        }
    }

    float O[8][4];
#pragma unroll
    for (int nt = 0; nt < 8; nt++)
#pragma unroll
        for (int e = 0; e < 4; e++) O[nt][e] = 0.f;
    float m0 = -3.0e38f, m1 = -3.0e38f, l0 = 0.f, l1 = 0.f;

    const int r0 = qt * 128 + w * 16 + (lane >> 2);
    const int r1 = r0 + 8;

    for (int kt = 0; kt < 8; kt++) {
        if (kt > 0) {
            // g(kt) complete; g(kt+1) is the only possibly-younger group.
            if (kt < 7)
                asm volatile("cp.async.wait_group 1;" ::: "memory");
            else
                asm volatile("cp.async.wait_group 0;" ::: "memory");
            __syncthreads();
        }
        uint32_t kv = sb + AT_KV + (kt & 1) * 65536;

        float S[16][4];
#pragma unroll
        for (int j = 0; j < 16; j++)
#pragma unroll
            for (int e = 0; e < 4; e++) S[j][e] = 0.f;

        // S = Q K^T
#pragma unroll
        for (int ks = 0; ks < 4; ks++) {
            const int krow = ((lane >> 4) << 3) + (lane & 7);
            const int kch  = ks * 2 + ((lane >> 3) & 1);
#pragma unroll
            for (int jp = 0; jp < 8; jp++) {
                uint32_t off = swz128(jp * 16 + krow, kch);
                uint32_t kb[4], kl2[4];
                ldsm_x4(kb[0],  kb[1],  kb[2],  kb[3],  kv + off);
                ldsm_x4(kl2[0], kl2[1], kl2[2], kl2[3], kv + 16384 + off);
                mma_bf16(S[2 * jp],     qfh[ks], kb);
                mma_bf16(S[2 * jp],     qfh[ks], kl2);
                mma_bf16(S[2 * jp],     qfl[ks], kb);
                mma_bf16(S[2 * jp + 1], qfh[ks], kb + 2);
                mma_bf16(S[2 * jp + 1], qfh[ks], kl2 + 2);
                mma_bf16(S[2 * jp + 1], qfl[ks], kb + 2);
            }
        }

        const int ktbase = kt * 128;
#pragma unroll
        for (int j = 0; j < 16; j++) {
            int c = ktbase + j * 8 + (lane & 3) * 2;
            float lc0 = lm_s[c], lc1 = lm_s[c + 1];
            S[j][0] += bd_s[c - r0 + 1023] + lc0;
            S[j][1] += bd_s[c + 1 - r0 + 1023] + lc1;
            S[j][2] += bd_s[c - r1 + 1023] + lc0;
            S[j][3] += bd_s[c + 1 - r1 + 1023] + lc1;
        }

        float tm0 = -3.0e38f, tm1 = -3.0e38f;
#pragma unroll
        for (int j = 0; j < 16; j++) {
            tm0 = fmaxf(tm0, fmaxf(S[j][0], S[j][1]));
            tm1 = fmaxf(tm1, fmaxf(S[j][2], S[j][3]));
        }
        tm0 = fmaxf(tm0, __shfl_xor_sync(0xffffffffu, tm0, 1));
        tm0 = fmaxf(tm0, __shfl_xor_sync(0xffffffffu, tm0, 2));
        tm1 = fmaxf(tm1, __shfl_xor_sync(0xffffffffu, tm1, 1));
        tm1 = fmaxf(tm1, __shfl_xor_sync(0xffffffffu, tm1, 2));
        float mn0 = fmaxf(m0, tm0), mn1 = fmaxf(m1, tm1);
        float a0 = __expf(m0 - mn0), a1 = __expf(m1 - mn1);
        m0 = mn0; m1 = mn1;

        float s0 = 0.f, s1 = 0.f;
#pragma unroll
        for (int j = 0; j < 16; j++) {
            S[j][0] = __expf(S[j][0] - mn0); s0 += S[j][0];
            S[j][1] = __expf(S[j][1] - mn0); s0 += S[j][1];
            S[j][2] = __expf(S[j][2] - mn1); s1 += S[j][2];
            S[j][3] = __expf(S[j][3] - mn1); s1 += S[j][3];
        }
        s0 += __shfl_xor_sync(0xffffffffu, s0, 1);
        s0 += __shfl_xor_sync(0xffffffffu, s0, 2);
        s1 += __shfl_xor_sync(0xffffffffu, s1, 1);
        s1 += __shfl_xor_sync(0xffffffffu, s1, 2);
        l0 = l0 * a0 + s0;
        l1 = l1 * a1 + s1;

#pragma unroll
        for (int nt = 0; nt < 8; nt++) {
            O[nt][0] *= a0; O[nt][1] *= a0;
            O[nt][2] *= a1; O[nt][3] *= a1;
        }

        // O += P @ V
#pragma unroll
        for (int kk = 0; kk < 8; kk++) {
            float* p0 = S[2 * kk];
            float* p1 = S[2 * kk + 1];
            uint32_t ph[4], pl[4];
            {
                __nv_bfloat16 h00 = __float2bfloat16(p0[0]), h01 = __float2bfloat16(p0[1]);
                __nv_bfloat16 h02 = __float2bfloat16(p0[2]), h03 = __float2bfloat16(p0[3]);
                __nv_bfloat16 h10 = __float2bfloat16(p1[0]), h11 = __float2bfloat16(p1[1]);
                __nv_bfloat16 h12 = __float2bfloat16(p1[2]), h13 = __float2bfloat16(p1[3]);
                __nv_bfloat162 t0(h00, h01), t1(h02, h03), t2(h10, h11), t3(h12, h13);
                ph[0] = *(uint32_t*)&t0; ph[1] = *(uint32_t*)&t1;
                ph[2] = *(uint32_t*)&t2; ph[3] = *(uint32_t*)&t3;
                pl[0] = packbf2(p0[0] - __bfloat162float(h00), p0[1] - __bfloat162float(h01));
                pl[1] = packbf2(p0[2] - __bfloat162float(h02), p0[3] - __bfloat162float(h03));
                pl[2] = packbf2(p1[0] - __bfloat162float(h10), p1[1] - __bfloat162float(h11));
                pl[3] = packbf2(p1[2] - __bfloat162float(h12), p1[3] - __bfloat162float(h13));
            }
            const int vrow = kk * 16 + (lane & 15);
            const int vcp  = (lane >> 4) & 1;
#pragma unroll
            for (int np = 0; np < 4; np++) {
                uint32_t off = swz128(vrow, np * 2 + vcp);
                uint32_t vb[4], vl2[4];
                ldsm_x4t(vb[0],  vb[1],  vb[2],  vb[3],  kv + 32768 + off);
                ldsm_x4t(vl2[0], vl2[1], vl2[2], vl2[3], kv + 49152 + off);
                mma_bf16(O[2 * np],     ph, vb);
                mma_bf16(O[2 * np],     ph, vl2);
                mma_bf16(O[2 * np],     pl, vb);
                mma_bf16(O[2 * np + 1], ph, vb + 2);
                mma_bf16(O[2 * np + 1], ph, vl2 + 2);
                mma_bf16(O[2 * np + 1], pl, vb + 2);
            }
        }

        // done reading buffer kt&1 — prefetch KV(kt+2) into it
        __syncthreads();
        if (kt + 2 < 8)
            at_load_kv(sb + AT_KV + (kt & 1) * 65536, t, slab, kt + 2,
                       KH, KL, VH, VL);
    }

    float inv0 = 1.f / l0, inv1 = 1.f / l1;
    size_t ob0 = slab + (size_t)(qt * 128 + w * 16 + (lane >> 2)) * DHEAD;
    size_t ob1 = ob0 + 8 * DHEAD;
#pragma unroll
    for (int nt = 0; nt < 8; nt++) {
        int c = nt * 8 + (lane & 3) * 2;
        float v0 = O[nt][0] * inv0, v1 = O[nt][1] * inv0;
        float v2 = O[nt][2] * inv1, v3 = O[nt][3] * inv1;
        __nv_bfloat16 h0 = __float2bfloat16(v0), h1 = __float2bfloat16(v1);
        __nv_bfloat16 h2 = __float2bfloat16(v2), h3 = __float2bfloat16(v3);
        __nv_bfloat162 hp0(h0, h1), hp1(h2, h3);
        *(__nv_bfloat162*)(OH + ob0 + c) = hp0;
        *(__nv_bfloat162*)(OH + ob1 + c) = hp1;
        *(__nv_bfloat162*)(OL + ob0 + c) =
            __nv_bfloat162(__float2bfloat16(v0 - __bfloat162float(h0)),
                           __float2bfloat16(v1 - __bfloat162float(h1)));
        *(__nv_bfloat162*)(OL + ob1 + c) =
            __nv_bfloat162(__float2bfloat16(v2 - __bfloat162float(h2)),
                           __float2bfloat16(v3 - __bfloat162float(h3)));
    }
}

// ============================================================================
// out = LayerNorm(A + B); optional bf16 hi/lo side output
// ============================================================================
template <bool SPLIT>
__global__ void __launch_bounds__(256) add_ln_kernel(
    const float* __restrict__ A, const float* __restrict__ B,
    float* __restrict__ out,
    __nv_bfloat16* __restrict__ OH, __nv_bfloat16* __restrict__ OL)
{
    __shared__ float sh[8];
    const size_t row = blockIdx.x;
    const int t = threadIdx.x;

    float4 a = ((const float4*)(A + row * DMODEL))[t];
    float4 b = ((const float4*)(B + row * DMODEL))[t];
    float4 x;
    x.x = a.x + b.x; x.y = a.y + b.y; x.z = a.z + b.z; x.w = a.w + b.w;

    float s = x.x + x.y + x.z + x.w;
#pragma unroll
    for (int o = 16; o; o >>= 1) s += __shfl_xor_sync(0xffffffffu, s, o);
    if ((t & 31) == 0) sh[t >> 5] = s;
    __syncthreads();
    float tot = sh[0];
#pragma unroll
    for (int i = 1; i < 8; i++) tot += sh[i];
    __syncthreads();
    float mean = tot * (1.f / DMODEL);

    float dx = x.x - mean, dy = x.y - mean, dz = x.z - mean, dw = x.w - mean;
    float s2 = dx * dx + dy * dy + dz * dz + dw * dw;
#pragma unroll
    for (int o = 16; o; o >>= 1) s2 += __shfl_xor_sync(0xffffffffu, s2, o);
    if ((t & 31) == 0) sh[t >> 5] = s2;
    __syncthreads();
    float tot2 = sh[0];
#pragma unroll
    for (int i = 1; i < 8; i++) tot2 += sh[i];
    float inv = rsqrtf(tot2 * (1.f / DMODEL));

    float4 o;
    o.x = dx * inv; o.y = dy * inv; o.z = dz * inv; o.w = dw * inv;
    ((float4*)(out + row * DMODEL))[t] = o;

    if (SPLIT) {
        __nv_bfloat16 h0 = __float2bfloat16(o.x), h1 = __float2bfloat16(o.y);
        __nv_bfloat16 h2 = __float2bfloat16(o.z), h3 = __float2bfloat16(o.w);
        __nv_bfloat162 hp0(h0, h1), hp1(h2, h3);
        __nv_bfloat162 lp0(__float2bfloat16(o.x - __bfloat162float(h0)),
                           __float2bfloat16(o.y - __bfloat162float(h1)));
        __nv_bfloat162 lp1(__float2bfloat16(o.z - __bfloat162float(h2)),
                           __float2bfloat16(o.w - __bfloat162float(h3)));
        size_t base = row * DMODEL + t * 4;
        *(__nv_bfloat162*)(OH + base)     = hp0;
        *(__nv_bfloat162*)(OH + base + 2) = hp1;
        *(__nv_bfloat162*)(OL + base)     = lp0;
        *(__nv_bfloat162*)(OL + base + 2) = lp1;
    }
}

// ============================================================================
// Launch sequence
// ============================================================================
extern "C" void kernel_launch(void* const* d_in, const int* in_sizes, int n_in,
                              void* d_out, int out_size)
{
    const float* x   = (const float*)d_in[0];
    const int*   pm  = (const int*)  d_in[1];
    const float* Wq  = (const float*)d_in[2];
    const float* bq  = (const float*)d_in[3];
    const float* Wk  = (const float*)d_in[4];
    const float* bk  = (const float*)d_in[5];
    const float* Wv  = (const float*)d_in[6];
    const float* bv  = (const float*)d_in[7];
    const float* Wo  = (const float*)d_in[8];
    const float* bo  = (const float*)d_in[9];
    const float* rel = (const float*)d_in[10];
    const float* W1  = (const float*)d_in[11];
    const float* b1  = (const float*)d_in[12];
    const float* W2  = (const float*)d_in[13];
    const float* b2  = (const float*)d_in[14];
    float* out = (float*)d_out;

    float *attp, *attout, *ff, *bqkv;
    cudaGetSymbolAddress((void**)&attp,   g_attp);
    cudaGetSymbolAddress((void**)&attout, g_attout);
    cudaGetSymbolAddress((void**)&ff,     g_ff);
    cudaGetSymbolAddress((void**)&bqkv,   g_bqkv);

    __nv_bfloat16 *xh, *xl, *wqkvh, *wqkvl, *woh, *wol;
    __nv_bfloat16 *w1h, *w1l, *w2h, *w2l, *avh, *avl, *aoh, *aol, *h1h, *h1l;
    __nv_bfloat16 *qkvh, *qkvl;
    cudaGetSymbolAddress((void**)&xh,    g_xh);    cudaGetSymbolAddress((void**)&xl,    g_xl);
    cudaGetSymbolAddress((void**)&wqkvh, g_wqkvh); cudaGetSymbolAddress((void**)&wqkvl, g_wqkvl);
    cudaGetSymbolAddress((void**)&woh,   g_woh);   cudaGetSymbolAddress((void**)&wol,   g_wol);
    cudaGetSymbolAddress((void**)&w1h,   g_w1h);   cudaGetSymbolAddress((void**)&w1l,   g_w1l);
    cudaGetSymbolAddress((void**)&w2h,   g_w2h);   cudaGetSymbolAddress((void**)&w2l,   g_w2l);
    cudaGetSymbolAddress((void**)&avh,   g_avh);   cudaGetSymbolAddress((void**)&avl,   g_avl);
    cudaGetSymbolAddress((void**)&aoh,   g_aoh);   cudaGetSymbolAddress((void**)&aol,   g_aol);
    cudaGetSymbolAddress((void**)&h1h,   g_h1h);   cudaGetSymbolAddress((void**)&h1l,   g_h1l);
    cudaGetSymbolAddress((void**)&qkvh,  g_qkvh);  cudaGetSymbolAddress((void**)&qkvl,  g_qkvl);

    static bool attr_done = false;
    if (!attr_done) {
        cudaFuncSetAttribute(tgemm_kernel<false, 0>,
                             cudaFuncAttributeMaxDynamicSharedMemorySize, TG_SMEM);
        cudaFuncSetAttribute(tgemm_kernel<false, 1>,
                             cudaFuncAttributeMaxDynamicSharedMemorySize, TG_SMEM);
        cudaFuncSetAttribute(tgemm_kernel<false, 2>,
                             cudaFuncAttributeMaxDynamicSharedMemorySize, TG_SMEM);
        cudaFuncSetAttribute(tgemm_kernel<true, 1>,
                             cudaFuncAttributeMaxDynamicSharedMemorySize, TG_SMEM);
        cudaFuncSetAttribute(attn_fused_kernel,
                             cudaFuncAttributeMaxDynamicSharedMemorySize, AT_SMEM);
        attr_done = true;
    }

    dim3 blk(256);

    split_kernel<<<(MROWS * DMODEL / 4 + 255) / 256, blk>>>(
        x, xh, xl, MROWS * DMODEL / 4);
    splitw_all_kernel<<<(SEG_TOTAL + 255) / 256, blk>>>(
        Wq, Wk, Wv, Wo, W1, W2, bq, bk, bv,
        wqkvh, wqkvl, woh, wol, w1h, w1l, w2h, w2l, bqkv);

    // fused QKV projection
    dim3 gqkv(3 * DMODEL / TBN, MROWS / TBM);
    tgemm_kernel<false, 2><<<gqkv, blk, TG_SMEM>>>(
        xh, xl, wqkvh, wqkvl, bqkv, nullptr, qkvh, qkvl, MROWS, 3 * DMODEL, DMODEL);

    // attention
    const size_t SLAB = (size_t)MROWS * DMODEL;
    attn_fused_kernel<<<dim3(8, BHDIM), blk, AT_SMEM>>>(
        qkvh, qkvl, qkvh + SLAB, qkvl + SLAB, qkvh + 2 * SLAB, qkvl + 2 * SLAB,
        rel, pm, avh, avl);

    // O projection
    dim3 gO(DMODEL / TBN, MROWS / TBM);
    tgemm_kernel<false, 0><<<gO, blk, TG_SMEM>>>(
        avh, avl, woh, wol, bo, attp, nullptr, nullptr, MROWS, DMODEL, DMODEL);

    // residual + LN (+ split)
    add_ln_kernel<true><<<MROWS, blk>>>(attp, x, attout, aoh, aol);

    // FFN
    dim3 g1(FFDIM / TBN, MROWS / TBM);
    tgemm_kernel<true, 1><<<g1, blk, TG_SMEM>>>(
        aoh, aol, w1h, w1l, b1, nullptr, h1h, h1l, MROWS, FFDIM, DMODEL);
    dim3 g2(DMODEL / TBN, MROWS / TBM);
    tgemm_kernel<false, 0><<<g2, blk, TG_SMEM>>>(
        h1h, h1l, w2h, w2l, b2, ff, nullptr, nullptr, MROWS, DMODEL, FFDIM);

    // final residual + LN
    add_ln_kernel<false><<<MROWS, blk>>>(ff, attout, out, nullptr, nullptr);
}

// round 9
// speedup vs baseline: 3.1456x; 1.0096x over previous
#include <cuda_runtime.h>
#include <cuda_bf16.h>
#include <math.h>
#include <stdint.h>

// ---------------------------------------------------------------------------
// EncoderBlock: B=4, L=1024, D=1024, F=4096, H=16, dh=64
// Round 9: product-major MMA ordering (break RAW chains);
//          attention log2-domain softmax + bf16x2 fast packing.
// ---------------------------------------------------------------------------

#define LSEQ 1024
#define DMODEL 1024
#define BATCH 4
#define NHEAD 16
#define DHEAD 64
#define FFDIM 4096
#define BHDIM 64
#define MROWS 4096
#define LOG2E 1.4426950408889634f

// ---- fp32 scratch ----------------------------------------------------------
__device__ float g_attp[BATCH * LSEQ * DMODEL];
__device__ float g_attout[BATCH * LSEQ * DMODEL];
__device__ float g_ff[BATCH * LSEQ * DMODEL];
__device__ float g_bqkv[3 * DMODEL];

// ---- bf16 hi/lo scratch -----------------------------------------------------
__device__ __nv_bfloat16 g_xh[MROWS * DMODEL],  g_xl[MROWS * DMODEL];
__device__ __nv_bfloat16 g_wqkvh[3 * DMODEL * DMODEL], g_wqkvl[3 * DMODEL * DMODEL];
__device__ __nv_bfloat16 g_woh[DMODEL * DMODEL], g_wol[DMODEL * DMODEL];
__device__ __nv_bfloat16 g_w1h[FFDIM * DMODEL],  g_w1l[FFDIM * DMODEL];
__device__ __nv_bfloat16 g_w2h[DMODEL * FFDIM],  g_w2l[DMODEL * FFDIM];
__device__ __nv_bfloat16 g_qkvh[3 * MROWS * DMODEL], g_qkvl[3 * MROWS * DMODEL];
__device__ __nv_bfloat16 g_avh[MROWS * DMODEL],  g_avl[MROWS * DMODEL];
__device__ __nv_bfloat16 g_aoh[MROWS * DMODEL],  g_aol[MROWS * DMODEL];
__device__ __nv_bfloat16 g_h1h[(size_t)MROWS * FFDIM], g_h1l[(size_t)MROWS * FFDIM];

// ============================================================================
// helpers
// ============================================================================
__device__ __forceinline__ uint32_t smem_u32(const void* p) {
    uint32_t a;
    asm("{ .reg .u64 t; cvta.to.shared.u64 t, %1; cvt.u32.u64 %0, t; }"
        : "=r"(a) : "l"(p));
    return a;
}
__device__ __forceinline__ void cp16(uint32_t dst, const void* src) {
    asm volatile("cp.async.cg.shared.global [%0], [%1], 16;" :: "r"(dst), "l"(src));
}
__device__ __forceinline__ void ldsm_x4(uint32_t& r0, uint32_t& r1,
                                        uint32_t& r2, uint32_t& r3, uint32_t a) {
    asm volatile("ldmatrix.sync.aligned.m8n8.x4.shared.b16 {%0,%1,%2,%3}, [%4];"
                 : "=r"(r0), "=r"(r1), "=r"(r2), "=r"(r3) : "r"(a));
}
__device__ __forceinline__ void ldsm_x4t(uint32_t& r0, uint32_t& r1,
                                         uint32_t& r2, uint32_t& r3, uint32_t a) {
    asm volatile("ldmatrix.sync.aligned.m8n8.x4.trans.shared.b16 {%0,%1,%2,%3}, [%4];"
                 : "=r"(r0), "=r"(r1), "=r"(r2), "=r"(r3) : "r"(a));
}
__device__ __forceinline__ void mma_bf16(float* c, const uint32_t* a, const uint32_t* b) {
    asm volatile(
        "mma.sync.aligned.m16n8k16.row.col.f32.bf16.bf16.f32 "
        "{%0,%1,%2,%3}, {%4,%5,%6,%7}, {%8,%9}, {%0,%1,%2,%3};"
        : "+f"(c[0]), "+f"(c[1]), "+f"(c[2]), "+f"(c[3])
        : "r"(a[0]), "r"(a[1]), "r"(a[2]), "r"(a[3]), "r"(b[0]), "r"(b[1]));
}
// pack two floats to bf16x2 (lo, hi) in one cvt
__device__ __forceinline__ uint32_t cvt_bf2(float lo, float hi) {
    uint32_t r;
    asm("cvt.rn.bf16x2.f32 %0, %1, %2;" : "=r"(r) : "f"(hi), "f"(lo));
    return r;
}
// recover the two bf16 values of a packed bf16x2 as floats
__device__ __forceinline__ float bf2_lo_f(uint32_t r) {
    return __uint_as_float(r << 16);
}
__device__ __forceinline__ float bf2_hi_f(uint32_t r) {
    return __uint_as_float(r & 0xFFFF0000u);
}

// ============================================================================
// split: X(fp32) -> hi = bf16(X), lo = bf16(X - hi)
// ============================================================================
__global__ void __launch_bounds__(256) split_kernel(
    const float* __restrict__ X, __nv_bfloat16* __restrict__ H,
    __nv_bfloat16* __restrict__ L, int n4)
{
    int i = blockIdx.x * 256 + threadIdx.x;
    if (i >= n4) return;
    float4 v = ((const float4*)X)[i];
    uint32_t h01 = cvt_bf2(v.x, v.y);
    uint32_t h23 = cvt_bf2(v.z, v.w);
    uint32_t l01 = cvt_bf2(v.x - bf2_lo_f(h01), v.y - bf2_hi_f(h01));
    uint32_t l23 = cvt_bf2(v.z - bf2_lo_f(h23), v.w - bf2_hi_f(h23));
    ((uint2*)H)[i] = make_uint2(h01, h23);
    ((uint2*)L)[i] = make_uint2(l01, l23);
}

// ============================================================================
// One kernel splitting ALL weights + qkv bias pack.
// ============================================================================
#define SEG_QKV (3 * DMODEL * DMODEL / 4)
#define SEG_WO  (DMODEL * DMODEL / 4)
#define SEG_W1  (FFDIM * DMODEL / 4)
#define SEG_W2  (DMODEL * FFDIM / 4)
#define SEG_TOTAL (SEG_QKV + SEG_WO + SEG_W1 + SEG_W2)

__global__ void __launch_bounds__(256) splitw_all_kernel(
    const float* __restrict__ Wq, const float* __restrict__ Wk,
    const float* __restrict__ Wv, const float* __restrict__ Wo,
    const float* __restrict__ W1, const float* __restrict__ W2,
    const float* __restrict__ bq, const float* __restrict__ bk,
    const float* __restrict__ bv,
    __nv_bfloat16* __restrict__ QKVH, __nv_bfloat16* __restrict__ QKVL,
    __nv_bfloat16* __restrict__ WOH,  __nv_bfloat16* __restrict__ WOL,
    __nv_bfloat16* __restrict__ W1H,  __nv_bfloat16* __restrict__ W1L,
    __nv_bfloat16* __restrict__ W2H,  __nv_bfloat16* __restrict__ W2L,
    float* __restrict__ bpack)
{
    int i = blockIdx.x * 256 + threadIdx.x;
    if (i < 3 * DMODEL) {
        float b = (i < DMODEL) ? bq[i] : (i < 2 * DMODEL) ? bk[i - DMODEL]
                                                          : bv[i - 2 * DMODEL];
        bpack[i] = b;
    }
    if (i >= SEG_TOTAL) return;

    const float* src;
    __nv_bfloat16 *H, *L;
    int off;
    if (i < SEG_QKV) {
        const int n4m = DMODEL * DMODEL / 4;
        int m = i / n4m;
        off = i - m * n4m;
        src = (m == 0) ? Wq : (m == 1) ? Wk : Wv;
        H = QKVH + (size_t)m * DMODEL * DMODEL;
        L = QKVL + (size_t)m * DMODEL * DMODEL;
    } else if (i < SEG_QKV + SEG_WO) {
        off = i - SEG_QKV; src = Wo; H = WOH; L = WOL;
    } else if (i < SEG_QKV + SEG_WO + SEG_W1) {
        off = i - SEG_QKV - SEG_WO; src = W1; H = W1H; L = W1L;
    } else {
        off = i - SEG_QKV - SEG_WO - SEG_W1; src = W2; H = W2H; L = W2L;
    }

    float4 v = ((const float4*)src)[off];
    uint32_t h01 = cvt_bf2(v.x, v.y);
    uint32_t h23 = cvt_bf2(v.z, v.w);
    uint32_t l01 = cvt_bf2(v.x - bf2_lo_f(h01), v.y - bf2_hi_f(h01));
    uint32_t l23 = cvt_bf2(v.z - bf2_lo_f(h23), v.w - bf2_hi_f(h23));
    ((uint2*)H)[off] = make_uint2(h01, h23);
    ((uint2*)L)[off] = make_uint2(l01, l23);
}

// ============================================================================
// mma.sync GEMM: 3-stage pipeline, product-major MMA ordering.
// ============================================================================
#define TBM 128
#define TBN 128
#define TBK 32
#define STG_BYTES 32768
#define TG_SMEM (3 * STG_BYTES)

__device__ __forceinline__ uint32_t sw_off(int r, int c) {
    return (uint32_t)(r * 64 + ((c ^ ((r >> 1) & 3)) << 4));
}

__device__ __forceinline__ void tg_load_stage(
    uint32_t sbuf, int t,
    const __nv_bfloat16* __restrict__ Ah, const __nv_bfloat16* __restrict__ Al,
    const __nv_bfloat16* __restrict__ Bh, const __nv_bfloat16* __restrict__ Bl,
    int rowBase, int colBase, int k0, int K)
{
#pragma unroll
    for (int j = 0; j < 8; j++) {
        int i   = j * 256 + t;
        int arr = i >> 9;
        int idx = i & 511;
        int r   = idx >> 2;
        int ch  = idx & 3;
        const __nv_bfloat16* base =
            (arr == 0) ? Ah : (arr == 1) ? Al : (arr == 2) ? Bh : Bl;
        int gr = ((arr < 2) ? rowBase : colBase) + r;
        cp16(sbuf + arr * 8192 + sw_off(r, ch),
             base + (size_t)gr * K + k0 + ch * 8);
    }
    asm volatile("cp.async.commit_group;" ::: "memory");
}

template <bool RELU, int OUT>
__global__ void __launch_bounds__(256, 2) tgemm_kernel(
    const __nv_bfloat16* __restrict__ Ah, const __nv_bfloat16* __restrict__ Al,
    const __nv_bfloat16* __restrict__ Bh, const __nv_bfloat16* __restrict__ Bl,
    const float* __restrict__ bias, float* __restrict__ C,
    __nv_bfloat16* __restrict__ Ch, __nv_bfloat16* __restrict__ Cl,
    int M, int N, int K)
{
    extern __shared__ __align__(16) char smem[];
    uint32_t sb = smem_u32(smem);
    const int t = threadIdx.x;
    const int w = t >> 5, lane = t & 31;
    const int wm = w >> 2;
    const int wn = w & 3;
    const int rowBase = blockIdx.y * TBM;
    const int colBase = blockIdx.x * TBN;
    const int KT = K / TBK;

    float acc[4][4][4];
#pragma unroll
    for (int mt = 0; mt < 4; mt++)
#pragma unroll
        for (int nt = 0; nt < 4; nt++)
#pragma unroll
            for (int e = 0; e < 4; e++) acc[mt][nt][e] = 0.f;

    tg_load_stage(sb,                 t, Ah, Al, Bh, Bl, rowBase, colBase, 0 * TBK, K);
    tg_load_stage(sb + 1 * STG_BYTES, t, Ah, Al, Bh, Bl, rowBase, colBase, 1 * TBK, K);

    int stage = 0;
    for (int kt = 0; kt < KT; kt++) {
        if (kt + 1 < KT)
            asm volatile("cp.async.wait_group 1;" ::: "memory");
        else
            asm volatile("cp.async.wait_group 0;" ::: "memory");
        __syncthreads();

        if (kt + 2 < KT) {
            int ps = stage + 2; if (ps >= 3) ps -= 3;
            tg_load_stage(sb + ps * STG_BYTES, t,
                          Ah, Al, Bh, Bl, rowBase, colBase, (kt + 2) * TBK, K);
        }

        uint32_t sbase = sb + stage * STG_BYTES;
#pragma unroll
        for (int ks = 0; ks < 2; ks++) {
            uint32_t ah[4][4], al[4][4], bh[4][2], bl[4][2];
            const int arow0  = wm * 64 + (lane & 15);
            const int achunk = ks * 2 + (lane >> 4);
#pragma unroll
            for (int mt = 0; mt < 4; mt++) {
                int r = arow0 + mt * 16;
                uint32_t off = sw_off(r, achunk);
                ldsm_x4(ah[mt][0], ah[mt][1], ah[mt][2], ah[mt][3], sbase + off);
                ldsm_x4(al[mt][0], al[mt][1], al[mt][2], al[mt][3], sbase + 8192 + off);
            }
            const int brow = wn * 32 + ((lane >> 4) << 3) + (lane & 7);
            const int bch  = ks * 2 + ((lane >> 3) & 1);
#pragma unroll
            for (int np = 0; np < 2; np++) {
                uint32_t off = sw_off(brow + np * 16, bch);
                ldsm_x4(bh[2 * np][0], bh[2 * np][1],
                        bh[2 * np + 1][0], bh[2 * np + 1][1], sbase + 16384 + off);
                ldsm_x4(bl[2 * np][0], bl[2 * np][1],
                        bl[2 * np + 1][0], bl[2 * np + 1][1], sbase + 24576 + off);
            }
            // product-major: 16 independent accs between dependent MMAs
#pragma unroll
            for (int mt = 0; mt < 4; mt++)
#pragma unroll
                for (int nt = 0; nt < 4; nt++)
                    mma_bf16(acc[mt][nt], ah[mt], bh[nt]);
#pragma unroll
            for (int mt = 0; mt < 4; mt++)
#pragma unroll
                for (int nt = 0; nt < 4; nt++)
                    mma_bf16(acc[mt][nt], ah[mt], bl[nt]);
#pragma unroll
            for (int mt = 0; mt < 4; mt++)
#pragma unroll
                for (int nt = 0; nt < 4; nt++)
                    mma_bf16(acc[mt][nt], al[mt], bh[nt]);
        }
        stage++; if (stage == 3) stage = 0;
    }

    // Epilogue
#pragma unroll
    for (int nt = 0; nt < 4; nt++) {
        int c = colBase + wn * 32 + nt * 8 + (lane & 3) * 2;
        float b0 = __ldg(&bias[c]), b1 = __ldg(&bias[c + 1]);
        __nv_bfloat16* qh_t = Ch;
        __nv_bfloat16* ql_t = Cl;
        int cc = c;
        int on = N;
        if (OUT == 2) {
            int sel = c >> 10;
            qh_t = Ch + (size_t)sel * MROWS * DMODEL;
            ql_t = Cl + (size_t)sel * MROWS * DMODEL;
            cc = c & 1023;
            on = DMODEL;
        }
#pragma unroll
        for (int mt = 0; mt < 4; mt++) {
            int r0 = rowBase + wm * 64 + mt * 16 + (lane >> 2);
            float v0 = acc[mt][nt][0] + b0, v1 = acc[mt][nt][1] + b1;
            float v2 = acc[mt][nt][2] + b0, v3 = acc[mt][nt][3] + b1;
            if (RELU) {
                v0 = fmaxf(v0, 0.f); v1 = fmaxf(v1, 0.f);
                v2 = fmaxf(v2, 0.f); v3 = fmaxf(v3, 0.f);
            }
            if (OUT == 0) {
                *(float2*)(C + (size_t)r0 * N + c)       = make_float2(v0, v1);
                *(float2*)(C + (size_t)(r0 + 8) * N + c) = make_float2(v2, v3);
            } else {
                uint32_t hp0 = cvt_bf2(v0, v1), hp1 = cvt_bf2(v2, v3);
                uint32_t lp0 = cvt_bf2(v0 - bf2_lo_f(hp0), v1 - bf2_hi_f(hp0));
                uint32_t lp1 = cvt_bf2(v2 - bf2_lo_f(hp1), v3 - bf2_hi_f(hp1));
                *(uint32_t*)(qh_t + (size_t)r0 * on + cc)       = hp0;
                *(uint32_t*)(qh_t + (size_t)(r0 + 8) * on + cc) = hp1;
                *(uint32_t*)(ql_t + (size_t)r0 * on + cc)       = lp0;
                *(uint32_t*)(ql_t + (size_t)(r0 + 8) * on + cc) = lp1;
            }
        }
    }
}

// ============================================================================
// T5 relative-position bucket for displacement d
// ============================================================================
__device__ __forceinline__ int rel_bucket_d(int d)
{
    int ret = (d < 0) ? NHEAD : 0;
    int n   = abs(d);
    int b;
    if (n < 8) b = n;
    else {
        int j = (31 - __clz(n * n)) - 6;
        j = min(j, 7);
        b = 8 + j;
    }
    return ret + b;
}

// ============================================================================
// Fused flash attention — log2-domain softmax, product-major MMAs,
// double-buffered K/V.
// ============================================================================
#define AT_Q    0
#define AT_QL   16384
#define AT_KV   32768
#define AT_LM   163840
#define AT_BD   167936
#define AT_SMEM 176128

__device__ __forceinline__ uint32_t swz128(int r, int c) {
    return (uint32_t)(r * 128 + ((c ^ (r & 7)) << 4));
}

__device__ __forceinline__ void at_load_kv(
    uint32_t kvbase, int t, size_t slab, int kt,
    const __nv_bfloat16* __restrict__ KH, const __nv_bfloat16* __restrict__ KL,
    const __nv_bfloat16* __restrict__ VH, const __nv_bfloat16* __restrict__ VL)
{
    size_t gb = slab + (size_t)kt * 128 * DHEAD;
    for (int i = t; i < 1024; i += 256) {
        int r = i >> 3, c = i & 7;
        uint32_t off = swz128(r, c);
        size_t g = gb + r * DHEAD + c * 8;
        cp16(kvbase + off,         KH + g);
        cp16(kvbase + 16384 + off, KL + g);
        cp16(kvbase + 32768 + off, VH + g);
        cp16(kvbase + 49152 + off, VL + g);
    }
    asm volatile("cp.async.commit_group;" ::: "memory");
}

__global__ void __launch_bounds__(256, 1) attn_fused_kernel(
    const __nv_bfloat16* __restrict__ QH, const __nv_bfloat16* __restrict__ QL,
    const __nv_bfloat16* __restrict__ KH, const __nv_bfloat16* __restrict__ KL,
    const __nv_bfloat16* __restrict__ VH, const __nv_bfloat16* __restrict__ VL,
    const float* __restrict__ rel, const int* __restrict__ pm,
    __nv_bfloat16* __restrict__ OH, __nv_bfloat16* __restrict__ OL)
{
    extern __shared__ __align__(16) char smem[];
    uint32_t sb = smem_u32(smem);
    float* lm_s = (float*)(smem + AT_LM);
    float* bd_s = (float*)(smem + AT_BD);

    const int t = threadIdx.x, w = t >> 5, lane = t & 31;
    const int qt = blockIdx.x, bh = blockIdx.y;
    const int h = bh & (NHEAD - 1), b = bh >> 4;
    const size_t slab = (size_t)bh * (LSEQ * DHEAD);

    // tables in log2 domain
    for (int i = t; i < LSEQ; i += 256)
        lm_s[i] = log2f((float)pm[b * LSEQ + i]);
    for (int i = t; i < 2047; i += 256)
        bd_s[i] = rel[rel_bucket_d(i - 1023) * NHEAD + h] * LOG2E;

    {
        size_t qbase = slab + (size_t)qt * 128 * DHEAD;
        for (int i = t; i < 1024; i += 256) {
            int r = i >> 3, c = i & 7;
            uint32_t off = swz128(r, c);
            size_t g = qbase + r * DHEAD + c * 8;
            cp16(sb + AT_Q  + off, QH + g);
            cp16(sb + AT_QL + off, QL + g);
        }
        at_load_kv(sb + AT_KV, t, slab, 0, KH, KL, VH, VL);
        at_load_kv(sb + AT_KV + 65536, t, slab, 1, KH, KL, VH, VL);
        asm volatile("cp.async.wait_group 1;" ::: "memory");
    }
    __syncthreads();

    uint32_t qfh[4][4], qfl[4][4];
    {
        int r = w * 16 + (lane & 15);
#pragma unroll
        for (int ks = 0; ks < 4; ks++) {
            int c = ks * 2 + (lane >> 4);
            uint32_t off = swz128(r, c);
            ldsm_x4(qfh[ks][0], qfh[ks][1], qfh[ks][2], qfh[ks][3], sb + AT_Q  + off);
            ldsm_x4(qfl[ks][0], qfl[ks][1], qfl[ks][2], qfl[ks][3], sb + AT_QL + off);
        }
    }

    float O[8][4];
#pragma unroll
    for (int nt = 0; nt < 8; nt++)
#pragma unroll
        for (int e = 0; e < 4; e++) O[nt][e] = 0.f;
    float m0 = -3.0e38f, m1 = -3.0e38f, l0 = 0.f, l1 = 0.f;

    const int r0 = qt * 128 + w * 16 + (lane >> 2);
    const int r1 = r0 + 8;

    for (int kt = 0; kt < 8; kt++) {
        if (kt > 0) {
            if (kt < 7)
                asm volatile("cp.async.wait_group 1;" ::: "memory");
            else
                asm volatile("cp.async.wait_group 0;" ::: "memory");
            __syncthreads();
        }
        uint32_t kv = sb + AT_KV + (kt & 1) * 65536;

        float S[16][4];
#pragma unroll
        for (int j = 0; j < 16; j++)
#pragma unroll
            for (int e = 0; e < 4; e++) S[j][e] = 0.f;

        // S = Q K^T : jp-pairs, product-major across 4 accs
#pragma unroll
        for (int ks = 0; ks < 4; ks++) {
            const int krow = ((lane >> 4) << 3) + (lane & 7);
            const int kch  = ks * 2 + ((lane >> 3) & 1);
#pragma unroll
            for (int jq = 0; jq < 4; jq++) {
                uint32_t kb0[4], kl0[4], kb1[4], kl1[4];
                uint32_t off0 = swz128((2 * jq) * 16 + krow, kch);
                uint32_t off1 = swz128((2 * jq + 1) * 16 + krow, kch);
                ldsm_x4(kb0[0], kb0[1], kb0[2], kb0[3], kv + off0);
                ldsm_x4(kl0[0], kl0[1], kl0[2], kl0[3], kv + 16384 + off0);
                ldsm_x4(kb1[0], kb1[1], kb1[2], kb1[3], kv + off1);
                ldsm_x4(kl1[0], kl1[1], kl1[2], kl1[3], kv + 16384 + off1);
                mma_bf16(S[4 * jq + 0], qfh[ks], kb0);
                mma_bf16(S[4 * jq + 1], qfh[ks], kb0 + 2);
                mma_bf16(S[4 * jq + 2], qfh[ks], kb1);
                mma_bf16(S[4 * jq + 3], qfh[ks], kb1 + 2);
                mma_bf16(S[4 * jq + 0], qfh[ks], kl0);
                mma_bf16(S[4 * jq + 1], qfh[ks], kl0 + 2);
                mma_bf16(S[4 * jq + 2], qfh[ks], kl1);
                mma_bf16(S[4 * jq + 3], qfh[ks], kl1 + 2);
                mma_bf16(S[4 * jq + 0], qfl[ks], kb0);
                mma_bf16(S[4 * jq + 1], qfl[ks], kb0 + 2);
                mma_bf16(S[4 * jq + 2], qfl[ks], kb1);
                mma_bf16(S[4 * jq + 3], qfl[ks], kb1 + 2);
            }
        }

        // bias in log2 domain: S' = S*log2e + (bd + lm)
        const int ktbase = kt * 128;
#pragma unroll
        for (int j = 0; j < 16; j++) {
            int c = ktbase + j * 8 + (lane & 3) * 2;
            float t00 = bd_s[c - r0 + 1023] + lm_s[c];
            float t01 = bd_s[c + 1 - r0 + 1023] + lm_s[c + 1];
            float t10 = bd_s[c - r1 + 1023] + lm_s[c];
            float t11 = bd_s[c + 1 - r1 + 1023] + lm_s[c + 1];
            S[j][0] = fmaf(S[j][0], LOG2E, t00);
            S[j][1] = fmaf(S[j][1], LOG2E, t01);
            S[j][2] = fmaf(S[j][2], LOG2E, t10);
            S[j][3] = fmaf(S[j][3], LOG2E, t11);
        }

        float tm0 = -3.0e38f, tm1 = -3.0e38f;
#pragma unroll
        for (int j = 0; j < 16; j++) {
            tm0 = fmaxf(tm0, fmaxf(S[j][0], S[j][1]));
            tm1 = fmaxf(tm1, fmaxf(S[j][2], S[j][3]));
        }
        tm0 = fmaxf(tm0, __shfl_xor_sync(0xffffffffu, tm0, 1));
        tm0 = fmaxf(tm0, __shfl_xor_sync(0xffffffffu, tm0, 2));
        tm1 = fmaxf(tm1, __shfl_xor_sync(0xffffffffu, tm1, 1));
        tm1 = fmaxf(tm1, __shfl_xor_sync(0xffffffffu, tm1, 2));
        float mn0 = fmaxf(m0, tm0), mn1 = fmaxf(m1, tm1);
        float a0 = exp2f(m0 - mn0), a1 = exp2f(m1 - mn1);
        m0 = mn0; m1 = mn1;

        float s0 = 0.f, s1 = 0.f;
#pragma unroll
        for (int j = 0; j < 16; j++) {
            S[j][0] = exp2f(S[j][0] - mn0); s0 += S[j][0];
            S[j][1] = exp2f(S[j][1] - mn0); s0 += S[j][1];
            S[j][2] = exp2f(S[j][2] - mn1); s1 += S[j][2];
            S[j][3] = exp2f(S[j][3] - mn1); s1 += S[j][3];
        }
        s0 += __shfl_xor_sync(0xffffffffu, s0, 1);
        s0 += __shfl_xor_sync(0xffffffffu, s0, 2);
        s1 += __shfl_xor_sync(0xffffffffu, s1, 1);
        s1 += __shfl_xor_sync(0xffffffffu, s1, 2);
        l0 = l0 * a0 + s0;
        l1 = l1 * a1 + s1;

#pragma unroll
        for (int nt = 0; nt < 8; nt++) {
            O[nt][0] *= a0; O[nt][1] *= a0;
            O[nt][2] *= a1; O[nt][3] *= a1;
        }

        // O += P @ V : product-major across 8 accs per kk
#pragma unroll
        for (int kk = 0; kk < 8; kk++) {
            float* p0 = S[2 * kk];
            float* p1 = S[2 * kk + 1];
            uint32_t ph[4], pl[4];
            {
                ph[0] = cvt_bf2(p0[0], p0[1]);
                ph[1] = cvt_bf2(p0[2], p0[3]);
                ph[2] = cvt_bf2(p1[0], p1[1]);
                ph[3] = cvt_bf2(p1[2], p1[3]);
                pl[0] = cvt_bf2(p0[0] - bf2_lo_f(ph[0]), p0[1] - bf2_hi_f(ph[0]));
                pl[1] = cvt_bf2(p0[2] - bf2_lo_f(ph[1]), p0[3] - bf2_hi_f(ph[1]));
                pl[2] = cvt_bf2(p1[0] - bf2_lo_f(ph[2]), p1[1] - bf2_hi_f(ph[2]));
                pl[3] = cvt_bf2(p1[2] - bf2_lo_f(ph[3]), p1[3] - bf2_hi_f(ph[3]));
            }
            const int vrow = kk * 16 + (lane & 15);
            const int vcp  = (lane >> 4) & 1;
            uint32_t vh[4][4], vl[4][4];
#pragma unroll
            for (int np = 0; np < 4; np++) {
                uint32_t off = swz128(vrow, np * 2 + vcp);
                ldsm_x4t(vh[np][0], vh[np][1], vh[np][2], vh[np][3], kv + 32768 + off);
                ldsm_x4t(vl[np][0], vl[np][1], vl[np][2], vl[np][3], kv + 49152 + off);
            }
#pragma unroll
            for (int np = 0; np < 4; np++) {
                mma_bf16(O[2 * np],     ph, vh[np]);
                mma_bf16(O[2 * np + 1], ph, vh[np] + 2);
            }
#pragma unroll
            for (int np = 0; np < 4; np++) {
                mma_bf16(O[2 * np],     ph, vl[np]);
                mma_bf16(O[2 * np + 1], ph, vl[np] + 2);
            }
#pragma unroll
            for (int np = 0; np < 4; np++) {
                mma_bf16(O[2 * np],     pl, vh[np]);
                mma_bf16(O[2 * np + 1], pl, vh[np] + 2);
            }
        }

        __syncthreads();
        if (kt + 2 < 8)
            at_load_kv(sb + AT_KV + (kt & 1) * 65536, t, slab, kt + 2,
                       KH, KL, VH, VL);
    }

    float inv0 = 1.f / l0, inv1 = 1.f / l1;
    size_t ob0 = slab + (size_t)(qt * 128 + w * 16 + (lane >> 2)) * DHEAD;
    size_t ob1 = ob0 + 8 * DHEAD;
#pragma unroll
    for (int nt = 0; nt < 8; nt++) {
        int c = nt * 8 + (lane & 3) * 2;
        float v0 = O[nt][0] * inv0, v1 = O[nt][1] * inv0;
        float v2 = O[nt][2] * inv1, v3 = O[nt][3] * inv1;
        uint32_t hp0 = cvt_bf2(v0, v1), hp1 = cvt_bf2(v2, v3);
        uint32_t lp0 = cvt_bf2(v0 - bf2_lo_f(hp0), v1 - bf2_hi_f(hp0));
        uint32_t lp1 = cvt_bf2(v2 - bf2_lo_f(hp1), v3 - bf2_hi_f(hp1));
        *(uint32_t*)(OH + ob0 + c) = hp0;
        *(uint32_t*)(OH + ob1 + c) = hp1;
        *(uint32_t*)(OL + ob0 + c) = lp0;
        *(uint32_t*)(OL + ob1 + c) = lp1;
    }
}

// ============================================================================
// out = LayerNorm(A + B); optional bf16 hi/lo side output
// ============================================================================
template <bool SPLIT>
__global__ void __launch_bounds__(256) add_ln_kernel(
    const float* __restrict__ A, const float* __restrict__ B,
    float* __restrict__ out,
    __nv_bfloat16* __restrict__ OH, __nv_bfloat16* __restrict__ OL)
{
    __shared__ float sh[8];
    const size_t row = blockIdx.x;
    const int t = threadIdx.x;

    float4 a = ((const float4*)(A + row * DMODEL))[t];
    float4 b = ((const float4*)(B + row * DMODEL))[t];
    float4 x;
    x.x = a.x + b.x; x.y = a.y + b.y; x.z = a.z + b.z; x.w = a.w + b.w;

    float s = x.x + x.y + x.z + x.w;
#pragma unroll
    for (int o = 16; o; o >>= 1) s += __shfl_xor_sync(0xffffffffu, s, o);
    if ((t & 31) == 0) sh[t >> 5] = s;
    __syncthreads();
    float tot = sh[0];
#pragma unroll
    for (int i = 1; i < 8; i++) tot += sh[i];
    __syncthreads();
    float mean = tot * (1.f / DMODEL);

    float dx = x.x - mean, dy = x.y - mean, dz = x.z - mean, dw = x.w - mean;
    float s2 = dx * dx + dy * dy + dz * dz + dw * dw;
#pragma unroll
    for (int o = 16; o; o >>= 1) s2 += __shfl_xor_sync(0xffffffffu, s2, o);
    if ((t & 31) == 0) sh[t >> 5] = s2;
    __syncthreads();
    float tot2 = sh[0];
#pragma unroll
    for (int i = 1; i < 8; i++) tot2 += sh[i];
    float inv = rsqrtf(tot2 * (1.f / DMODEL));

    float4 o;
    o.x = dx * inv; o.y = dy * inv; o.z = dz * inv; o.w = dw * inv;
    ((float4*)(out + row * DMODEL))[t] = o;

    if (SPLIT) {
        uint32_t hp0 = cvt_bf2(o.x, o.y), hp1 = cvt_bf2(o.z, o.w);
        uint32_t lp0 = cvt_bf2(o.x - bf2_lo_f(hp0), o.y - bf2_hi_f(hp0));
        uint32_t lp1 = cvt_bf2(o.z - bf2_lo_f(hp1), o.w - bf2_hi_f(hp1));
        size_t base = row * DMODEL + t * 4;
        *(uint32_t*)(OH + base)     = hp0;
        *(uint32_t*)(OH + base + 2) = hp1;
        *(uint32_t*)(OL + base)     = lp0;
        *(uint32_t*)(OL + base + 2) = lp1;
    }
}

// ============================================================================
// Launch sequence
// ============================================================================
extern "C" void kernel_launch(void* const* d_in, const int* in_sizes, int n_in,
                              void* d_out, int out_size)
{
    const float* x   = (const float*)d_in[0];
    const int*   pm  = (const int*)  d_in[1];
    const float* Wq  = (const float*)d_in[2];
    const float* bq  = (const float*)d_in[3];
    const float* Wk  = (const float*)d_in[4];
    const float* bk  = (const float*)d_in[5];
    const float* Wv  = (const float*)d_in[6];
    const float* bv  = (const float*)d_in[7];
    const float* Wo  = (const float*)d_in[8];
    const float* bo  = (const float*)d_in[9];
    const float* rel = (const float*)d_in[10];
    const float* W1  = (const float*)d_in[11];
    const float* b1  = (const float*)d_in[12];
    const float* W2  = (const float*)d_in[13];
    const float* b2  = (const float*)d_in[14];
    float* out = (float*)d_out;

    float *attp, *attout, *ff, *bqkv;
    cudaGetSymbolAddress((void**)&attp,   g_attp);
    cudaGetSymbolAddress((void**)&attout, g_attout);
    cudaGetSymbolAddress((void**)&ff,     g_ff);
    cudaGetSymbolAddress((void**)&bqkv,   g_bqkv);

    __nv_bfloat16 *xh, *xl, *wqkvh, *wqkvl, *woh, *wol;
    __nv_bfloat16 *w1h, *w1l, *w2h, *w2l, *avh, *avl, *aoh, *aol, *h1h, *h1l;
    __nv_bfloat16 *qkvh, *qkvl;
    cudaGetSymbolAddress((void**)&xh,    g_xh);    cudaGetSymbolAddress((void**)&xl,    g_xl);
    cudaGetSymbolAddress((void**)&wqkvh, g_wqkvh); cudaGetSymbolAddress((void**)&wqkvl, g_wqkvl);
    cudaGetSymbolAddress((void**)&woh,   g_woh);   cudaGetSymbolAddress((void**)&wol,   g_wol);
    cudaGetSymbolAddress((void**)&w1h,   g_w1h);   cudaGetSymbolAddress((void**)&w1l,   g_w1l);
    cudaGetSymbolAddress((void**)&w2h,   g_w2h);   cudaGetSymbolAddress((void**)&w2l,   g_w2l);
    cudaGetSymbolAddress((void**)&avh,   g_avh);   cudaGetSymbolAddress((void**)&avl,   g_avl);
    cudaGetSymbolAddress((void**)&aoh,   g_aoh);   cudaGetSymbolAddress((void**)&aol,   g_aol);
    cudaGetSymbolAddress((void**)&h1h,   g_h1h);   cudaGetSymbolAddress((void**)&h1l,   g_h1l);
    cudaGetSymbolAddress((void**)&qkvh,  g_qkvh);  cudaGetSymbolAddress((void**)&qkvl,  g_qkvl);

    static bool attr_done = false;
    if (!attr_done) {
        cudaFuncSetAttribute(tgemm_kernel<false, 0>,
                             cudaFuncAttributeMaxDynamicSharedMemorySize, TG_SMEM);
        cudaFuncSetAttribute(tgemm_kernel<false, 1>,
                             cudaFuncAttributeMaxDynamicSharedMemorySize, TG_SMEM);
        cudaFuncSetAttribute(tgemm_kernel<false, 2>,
                             cudaFuncAttributeMaxDynamicSharedMemorySize, TG_SMEM);
        cudaFuncSetAttribute(tgemm_kernel<true, 1>,
                             cudaFuncAttributeMaxDynamicSharedMemorySize, TG_SMEM);
        cudaFuncSetAttribute(attn_fused_kernel,
                             cudaFuncAttributeMaxDynamicSharedMemorySize, AT_SMEM);
        attr_done = true;
    }

    dim3 blk(256);

    split_kernel<<<(MROWS * DMODEL / 4 + 255) / 256, blk>>>(
        x, xh, xl, MROWS * DMODEL / 4);
    splitw_all_kernel<<<(SEG_TOTAL + 255) / 256, blk>>>(
        Wq, Wk, Wv, Wo, W1, W2, bq, bk, bv,
        wqkvh, wqkvl, woh, wol, w1h, w1l, w2h, w2l, bqkv);

    // fused QKV projection
    dim3 gqkv(3 * DMODEL / TBN, MROWS / TBM);
    tgemm_kernel<false, 2><<<gqkv, blk, TG_SMEM>>>(
        xh, xl, wqkvh, wqkvl, bqkv, nullptr, qkvh, qkvl, MROWS, 3 * DMODEL, DMODEL);

    // attention
    const size_t SLAB = (size_t)MROWS * DMODEL;
    attn_fused_kernel<<<dim3(8, BHDIM), blk, AT_SMEM>>>(
        qkvh, qkvl, qkvh + SLAB, qkvl + SLAB, qkvh + 2 * SLAB, qkvl + 2 * SLAB,
        rel, pm, avh, avl);

    // O projection
    dim3 gO(DMODEL / TBN, MROWS / TBM);
    tgemm_kernel<false, 0><<<gO, blk, TG_SMEM>>>(
        avh, avl, woh, wol, bo, attp, nullptr, nullptr, MROWS, DMODEL, DMODEL);

    // residual + LN (+ split)
    add_ln_kernel<true><<<MROWS, blk>>>(attp, x, attout, aoh, aol);

    // FFN
    dim3 g1(FFDIM / TBN, MROWS / TBM);
    tgemm_kernel<true, 1><<<g1, blk, TG_SMEM>>>(
        aoh, aol, w1h, w1l, b1, nullptr, h1h, h1l, MROWS, FFDIM, DMODEL);
    dim3 g2(DMODEL / TBN, MROWS / TBM);
    tgemm_kernel<false, 0><<<g2, blk, TG_SMEM>>>(
        h1h, h1l, w2h, w2l, b2, ff, nullptr, nullptr, MROWS, DMODEL, FFDIM);

    // final residual + LN
    add_ln_kernel<false><<<MROWS, blk>>>(ff, attout, out, nullptr, nullptr);
}

// round 10
// speedup vs baseline: 3.1621x; 1.0053x over previous
#include <cuda_runtime.h>
#include <cuda_bf16.h>
#include <math.h>
#include <stdint.h>

// ---------------------------------------------------------------------------
// EncoderBlock: B=4, L=1024, D=1024, F=4096, H=16, dh=64
// Round 10: tgemm register-pressure fix (B-frags per nt-pair, consumed
// immediately) to eliminate local-memory spills under the 128-reg cap.
// ---------------------------------------------------------------------------

#define LSEQ 1024
#define DMODEL 1024
#define BATCH 4
#define NHEAD 16
#define DHEAD 64
#define FFDIM 4096
#define BHDIM 64
#define MROWS 4096
#define LOG2E 1.4426950408889634f

// ---- fp32 scratch ----------------------------------------------------------
__device__ float g_attp[BATCH * LSEQ * DMODEL];
__device__ float g_attout[BATCH * LSEQ * DMODEL];
__device__ float g_ff[BATCH * LSEQ * DMODEL];
__device__ float g_bqkv[3 * DMODEL];

// ---- bf16 hi/lo scratch -----------------------------------------------------
__device__ __nv_bfloat16 g_xh[MROWS * DMODEL],  g_xl[MROWS * DMODEL];
__device__ __nv_bfloat16 g_wqkvh[3 * DMODEL * DMODEL], g_wqkvl[3 * DMODEL * DMODEL];
__device__ __nv_bfloat16 g_woh[DMODEL * DMODEL], g_wol[DMODEL * DMODEL];
__device__ __nv_bfloat16 g_w1h[FFDIM * DMODEL],  g_w1l[FFDIM * DMODEL];
__device__ __nv_bfloat16 g_w2h[DMODEL * FFDIM],  g_w2l[DMODEL * FFDIM];
__device__ __nv_bfloat16 g_qkvh[3 * MROWS * DMODEL], g_qkvl[3 * MROWS * DMODEL];
__device__ __nv_bfloat16 g_avh[MROWS * DMODEL],  g_avl[MROWS * DMODEL];
__device__ __nv_bfloat16 g_aoh[MROWS * DMODEL],  g_aol[MROWS * DMODEL];
__device__ __nv_bfloat16 g_h1h[(size_t)MROWS * FFDIM], g_h1l[(size_t)MROWS * FFDIM];

// ============================================================================
// helpers
// ============================================================================
__device__ __forceinline__ uint32_t smem_u32(const void* p) {
    uint32_t a;
    asm("{ .reg .u64 t; cvta.to.shared.u64 t, %1; cvt.u32.u64 %0, t; }"
        : "=r"(a) : "l"(p));
    return a;
}
__device__ __forceinline__ void cp16(uint32_t dst, const void* src) {
    asm volatile("cp.async.cg.shared.global [%0], [%1], 16;" :: "r"(dst), "l"(src));
}
__device__ __forceinline__ void ldsm_x4(uint32_t& r0, uint32_t& r1,
                                        uint32_t& r2, uint32_t& r3, uint32_t a) {
    asm volatile("ldmatrix.sync.aligned.m8n8.x4.shared.b16 {%0,%1,%2,%3}, [%4];"
                 : "=r"(r0), "=r"(r1), "=r"(r2), "=r"(r3) : "r"(a));
}
__device__ __forceinline__ void ldsm_x4t(uint32_t& r0, uint32_t& r1,
                                         uint32_t& r2, uint32_t& r3, uint32_t a) {
    asm volatile("ldmatrix.sync.aligned.m8n8.x4.trans.shared.b16 {%0,%1,%2,%3}, [%4];"
                 : "=r"(r0), "=r"(r1), "=r"(r2), "=r"(r3) : "r"(a));
}
__device__ __forceinline__ void mma_bf16(float* c, const uint32_t* a, const uint32_t* b) {
    asm volatile(
        "mma.sync.aligned.m16n8k16.row.col.f32.bf16.bf16.f32 "
        "{%0,%1,%2,%3}, {%4,%5,%6,%7}, {%8,%9}, {%0,%1,%2,%3};"
        : "+f"(c[0]), "+f"(c[1]), "+f"(c[2]), "+f"(c[3])
        : "r"(a[0]), "r"(a[1]), "r"(a[2]), "r"(a[3]), "r"(b[0]), "r"(b[1]));
}
__device__ __forceinline__ uint32_t cvt_bf2(float lo, float hi) {
    uint32_t r;
    asm("cvt.rn.bf16x2.f32 %0, %1, %2;" : "=r"(r) : "f"(hi), "f"(lo));
    return r;
}
__device__ __forceinline__ float bf2_lo_f(uint32_t r) {
    return __uint_as_float(r << 16);
}
__device__ __forceinline__ float bf2_hi_f(uint32_t r) {
    return __uint_as_float(r & 0xFFFF0000u);
}

// ============================================================================
// split: X(fp32) -> hi = bf16(X), lo = bf16(X - hi)
// ============================================================================
__global__ void __launch_bounds__(256) split_kernel(
    const float* __restrict__ X, __nv_bfloat16* __restrict__ H,
    __nv_bfloat16* __restrict__ L, int n4)
{
    int i = blockIdx.x * 256 + threadIdx.x;
    if (i >= n4) return;
    float4 v = ((const float4*)X)[i];
    uint32_t h01 = cvt_bf2(v.x, v.y);
    uint32_t h23 = cvt_bf2(v.z, v.w);
    uint32_t l01 = cvt_bf2(v.x - bf2_lo_f(h01), v.y - bf2_hi_f(h01));
    uint32_t l23 = cvt_bf2(v.z - bf2_lo_f(h23), v.w - bf2_hi_f(h23));
    ((uint2*)H)[i] = make_uint2(h01, h23);
    ((uint2*)L)[i] = make_uint2(l01, l23);
}

// ============================================================================
// One kernel splitting ALL weights + qkv bias pack.
// ============================================================================
#define SEG_QKV (3 * DMODEL * DMODEL / 4)
#define SEG_WO  (DMODEL * DMODEL / 4)
#define SEG_W1  (FFDIM * DMODEL / 4)
#define SEG_W2  (DMODEL * FFDIM / 4)
#define SEG_TOTAL (SEG_QKV + SEG_WO + SEG_W1 + SEG_W2)

__global__ void __launch_bounds__(256) splitw_all_kernel(
    const float* __restrict__ Wq, const float* __restrict__ Wk,
    const float* __restrict__ Wv, const float* __restrict__ Wo,
    const float* __restrict__ W1, const float* __restrict__ W2,
    const float* __restrict__ bq, const float* __restrict__ bk,
    const float* __restrict__ bv,
    __nv_bfloat16* __restrict__ QKVH, __nv_bfloat16* __restrict__ QKVL,
    __nv_bfloat16* __restrict__ WOH,  __nv_bfloat16* __restrict__ WOL,
    __nv_bfloat16* __restrict__ W1H,  __nv_bfloat16* __restrict__ W1L,
    __nv_bfloat16* __restrict__ W2H,  __nv_bfloat16* __restrict__ W2L,
    float* __restrict__ bpack)
{
    int i = blockIdx.x * 256 + threadIdx.x;
    if (i < 3 * DMODEL) {
        float b = (i < DMODEL) ? bq[i] : (i < 2 * DMODEL) ? bk[i - DMODEL]
                                                          : bv[i - 2 * DMODEL];
        bpack[i] = b;
    }
    if (i >= SEG_TOTAL) return;

    const float* src;
    __nv_bfloat16 *H, *L;
    int off;
    if (i < SEG_QKV) {
        const int n4m = DMODEL * DMODEL / 4;
        int m = i / n4m;
        off = i - m * n4m;
        src = (m == 0) ? Wq : (m == 1) ? Wk : Wv;
        H = QKVH + (size_t)m * DMODEL * DMODEL;
        L = QKVL + (size_t)m * DMODEL * DMODEL;
    } else if (i < SEG_QKV + SEG_WO) {
        off = i - SEG_QKV; src = Wo; H = WOH; L = WOL;
    } else if (i < SEG_QKV + SEG_WO + SEG_W1) {
        off = i - SEG_QKV - SEG_WO; src = W1; H = W1H; L = W1L;
    } else {
        off = i - SEG_QKV - SEG_WO - SEG_W1; src = W2; H = W2H; L = W2L;
    }

    float4 v = ((const float4*)src)[off];
    uint32_t h01 = cvt_bf2(v.x, v.y);
    uint32_t h23 = cvt_bf2(v.z, v.w);
    uint32_t l01 = cvt_bf2(v.x - bf2_lo_f(h01), v.y - bf2_hi_f(h01));
    uint32_t l23 = cvt_bf2(v.z - bf2_lo_f(h23), v.w - bf2_hi_f(h23));
    ((uint2*)H)[off] = make_uint2(h01, h23);
    ((uint2*)L)[off] = make_uint2(l01, l23);
}

// ============================================================================
// mma.sync GEMM: 3-stage pipeline; low-register inner loop (no spills at 128).
// ============================================================================
#define TBM 128
#define TBN 128
#define TBK 32
#define STG_BYTES 32768
#define TG_SMEM (3 * STG_BYTES)

__device__ __forceinline__ uint32_t sw_off(int r, int c) {
    return (uint32_t)(r * 64 + ((c ^ ((r >> 1) & 3)) << 4));
}

__device__ __forceinline__ void tg_load_stage(
    uint32_t sbuf, int t,
    const __nv_bfloat16* __restrict__ Ah, const __nv_bfloat16* __restrict__ Al,
    const __nv_bfloat16* __restrict__ Bh, const __nv_bfloat16* __restrict__ Bl,
    int rowBase, int colBase, int k0, int K)
{
#pragma unroll
    for (int j = 0; j < 8; j++) {
        int i   = j * 256 + t;
        int arr = i >> 9;
        int idx = i & 511;
        int r   = idx >> 2;
        int ch  = idx & 3;
        const __nv_bfloat16* base =
            (arr == 0) ? Ah : (arr == 1) ? Al : (arr == 2) ? Bh : Bl;
        int gr = ((arr < 2) ? rowBase : colBase) + r;
        cp16(sbuf + arr * 8192 + sw_off(r, ch),
             base + (size_t)gr * K + k0 + ch * 8);
    }
    asm volatile("cp.async.commit_group;" ::: "memory");
}

template <bool RELU, int OUT>
__global__ void __launch_bounds__(256, 2) tgemm_kernel(
    const __nv_bfloat16* __restrict__ Ah, const __nv_bfloat16* __restrict__ Al,
    const __nv_bfloat16* __restrict__ Bh, const __nv_bfloat16* __restrict__ Bl,
    const float* __restrict__ bias, float* __restrict__ C,
    __nv_bfloat16* __restrict__ Ch, __nv_bfloat16* __restrict__ Cl,
    int M, int N, int K)
{
    extern __shared__ __align__(16) char smem[];
    uint32_t sb = smem_u32(smem);
    const int t = threadIdx.x;
    const int w = t >> 5, lane = t & 31;
    const int wm = w >> 2;
    const int wn = w & 3;
    const int rowBase = blockIdx.y * TBM;
    const int colBase = blockIdx.x * TBN;
    const int KT = K / TBK;

    float acc[4][4][4];
#pragma unroll
    for (int mt = 0; mt < 4; mt++)
#pragma unroll
        for (int nt = 0; nt < 4; nt++)
#pragma unroll
            for (int e = 0; e < 4; e++) acc[mt][nt][e] = 0.f;

    tg_load_stage(sb,                 t, Ah, Al, Bh, Bl, rowBase, colBase, 0 * TBK, K);
    tg_load_stage(sb + 1 * STG_BYTES, t, Ah, Al, Bh, Bl, rowBase, colBase, 1 * TBK, K);

    int stage = 0;
    for (int kt = 0; kt < KT; kt++) {
        if (kt + 1 < KT)
            asm volatile("cp.async.wait_group 1;" ::: "memory");
        else
            asm volatile("cp.async.wait_group 0;" ::: "memory");
        __syncthreads();

        if (kt + 2 < KT) {
            int ps = stage + 2; if (ps >= 3) ps -= 3;
            tg_load_stage(sb + ps * STG_BYTES, t,
                          Ah, Al, Bh, Bl, rowBase, colBase, (kt + 2) * TBK, K);
        }

        uint32_t sbase = sb + stage * STG_BYTES;
#pragma unroll
        for (int ks = 0; ks < 2; ks++) {
            // A fragments stay live across the nt-pair loop (32 regs).
            uint32_t ah[4][4], al[4][4];
            const int arow0  = wm * 64 + (lane & 15);
            const int achunk = ks * 2 + (lane >> 4);
#pragma unroll
            for (int mt = 0; mt < 4; mt++) {
                int r = arow0 + mt * 16;
                uint32_t off = sw_off(r, achunk);
                ldsm_x4(ah[mt][0], ah[mt][1], ah[mt][2], ah[mt][3], sbase + off);
                ldsm_x4(al[mt][0], al[mt][1], al[mt][2], al[mt][3], sbase + 8192 + off);
            }
            // B fragments: loaded per nt-pair and consumed immediately (8 regs).
            const int brow = wn * 32 + ((lane >> 4) << 3) + (lane & 7);
            const int bch  = ks * 2 + ((lane >> 3) & 1);
#pragma unroll
            for (int np = 0; np < 2; np++) {
                uint32_t b2h[4], b2l[4];
                uint32_t off = sw_off(brow + np * 16, bch);
                ldsm_x4(b2h[0], b2h[1], b2h[2], b2h[3], sbase + 16384 + off);
                ldsm_x4(b2l[0], b2l[1], b2l[2], b2l[3], sbase + 24576 + off);
                // product-major across 8 independent accumulators
#pragma unroll
                for (int mt = 0; mt < 4; mt++) {
                    mma_bf16(acc[mt][2 * np],     ah[mt], b2h);
                    mma_bf16(acc[mt][2 * np + 1], ah[mt], b2h + 2);
                }
#pragma unroll
                for (int mt = 0; mt < 4; mt++) {
                    mma_bf16(acc[mt][2 * np],     ah[mt], b2l);
                    mma_bf16(acc[mt][2 * np + 1], ah[mt], b2l + 2);
                }
#pragma unroll
                for (int mt = 0; mt < 4; mt++) {
                    mma_bf16(acc[mt][2 * np],     al[mt], b2h);
                    mma_bf16(acc[mt][2 * np + 1], al[mt], b2h + 2);
                }
            }
        }
        stage++; if (stage == 3) stage = 0;
    }

    // Epilogue
#pragma unroll
    for (int nt = 0; nt < 4; nt++) {
        int c = colBase + wn * 32 + nt * 8 + (lane & 3) * 2;
        float b0 = __ldg(&bias[c]), b1 = __ldg(&bias[c + 1]);
        __nv_bfloat16* qh_t = Ch;
        __nv_bfloat16* ql_t = Cl;
        int cc = c;
        int on = N;
        if (OUT == 2) {
            int sel = c >> 10;
            qh_t = Ch + (size_t)sel * MROWS * DMODEL;
            ql_t = Cl + (size_t)sel * MROWS * DMODEL;
            cc = c & 1023;
            on = DMODEL;
        }
#pragma unroll
        for (int mt = 0; mt < 4; mt++) {
            int r0 = rowBase + wm * 64 + mt * 16 + (lane >> 2);
            float v0 = acc[mt][nt][0] + b0, v1 = acc[mt][nt][1] + b1;
            float v2 = acc[mt][nt][2] + b0, v3 = acc[mt][nt][3] + b1;
            if (RELU) {
                v0 = fmaxf(v0, 0.f); v1 = fmaxf(v1, 0.f);
                v2 = fmaxf(v2, 0.f); v3 = fmaxf(v3, 0.f);
            }
            if (OUT == 0) {
                *(float2*)(C + (size_t)r0 * N + c)       = make_float2(v0, v1);
                *(float2*)(C + (size_t)(r0 + 8) * N + c) = make_float2(v2, v3);
            } else {
                uint32_t hp0 = cvt_bf2(v0, v1), hp1 = cvt_bf2(v2, v3);
                uint32_t lp0 = cvt_bf2(v0 - bf2_lo_f(hp0), v1 - bf2_hi_f(hp0));
                uint32_t lp1 = cvt_bf2(v2 - bf2_lo_f(hp1), v3 - bf2_hi_f(hp1));
                *(uint32_t*)(qh_t + (size_t)r0 * on + cc)       = hp0;
                *(uint32_t*)(qh_t + (size_t)(r0 + 8) * on + cc) = hp1;
                *(uint32_t*)(ql_t + (size_t)r0 * on + cc)       = lp0;
                *(uint32_t*)(ql_t + (size_t)(r0 + 8) * on + cc) = lp1;
            }
        }
    }
}

// ============================================================================
// T5 relative-position bucket for displacement d
// ============================================================================
__device__ __forceinline__ int rel_bucket_d(int d)
{
    int ret = (d < 0) ? NHEAD : 0;
    int n   = abs(d);
    int b;
    if (n < 8) b = n;
    else {
        int j = (31 - __clz(n * n)) - 6;
        j = min(j, 7);
        b = 8 + j;
    }
    return ret + b;
}

// ============================================================================
// Fused flash attention (unchanged from R9)
// ============================================================================
#define AT_Q    0
#define AT_QL   16384
#define AT_KV   32768
#define AT_LM   163840
#define AT_BD   167936
#define AT_SMEM 176128

__device__ __forceinline__ uint32_t swz128(int r, int c) {
    return (uint32_t)(r * 128 + ((c ^ (r & 7)) << 4));
}

__device__ __forceinline__ void at_load_kv(
    uint32_t kvbase, int t, size_t slab, int kt,
    const __nv_bfloat16* __restrict__ KH, const __nv_bfloat16* __restrict__ KL,
    const __nv_bfloat16* __restrict__ VH, const __nv_bfloat16* __restrict__ VL)
{
    size_t gb = slab + (size_t)kt * 128 * DHEAD;
    for (int i = t; i < 1024; i += 256) {
        int r = i >> 3, c = i & 7;
        uint32_t off = swz128(r, c);
        size_t g = gb + r * DHEAD + c * 8;
        cp16(kvbase + off,         KH + g);
        cp16(kvbase + 16384 + off, KL + g);
        cp16(kvbase + 32768 + off, VH + g);
        cp16(kvbase + 49152 + off, VL + g);
    }
    asm volatile("cp.async.commit_group;" ::: "memory");
}

__global__ void __launch_bounds__(256, 1) attn_fused_kernel(
    const __nv_bfloat16* __restrict__ QH, const __nv_bfloat16* __restrict__ QL,
    const __nv_bfloat16* __restrict__ KH, const __nv_bfloat16* __restrict__ KL,
    const __nv_bfloat16* __restrict__ VH, const __nv_bfloat16* __restrict__ VL,
    const float* __restrict__ rel, const int* __restrict__ pm,
    __nv_bfloat16* __restrict__ OH, __nv_bfloat16* __restrict__ OL)
{
    extern __shared__ __align__(16) char smem[];
    uint32_t sb = smem_u32(smem);
    float* lm_s = (float*)(smem + AT_LM);
    float* bd_s = (float*)(smem + AT_BD);

    const int t = threadIdx.x, w = t >> 5, lane = t & 31;
    const int qt = blockIdx.x, bh = blockIdx.y;
    const int h = bh & (NHEAD - 1), b = bh >> 4;
    const size_t slab = (size_t)bh * (LSEQ * DHEAD);

    for (int i = t; i < LSEQ; i += 256)
        lm_s[i] = log2f((float)pm[b * LSEQ + i]);
    for (int i = t; i < 2047; i += 256)
        bd_s[i] = rel[rel_bucket_d(i - 1023) * NHEAD + h] * LOG2E;

    {
        size_t qbase = slab + (size_t)qt * 128 * DHEAD;
        for (int i = t; i < 1024; i += 256) {
            int r = i >> 3, c = i & 7;
            uint32_t off = swz128(r, c);
            size_t g = qbase + r * DHEAD + c * 8;
            cp16(sb + AT_Q  + off, QH + g);
            cp16(sb + AT_QL + off, QL + g);
        }
        at_load_kv(sb + AT_KV, t, slab, 0, KH, KL, VH, VL);
        at_load_kv(sb + AT_KV + 65536, t, slab, 1, KH, KL, VH, VL);
        asm volatile("cp.async.wait_group 1;" ::: "memory");
    }
    __syncthreads();

    uint32_t qfh[4][4], qfl[4][4];
    {
        int r = w * 16 + (lane & 15);
#pragma unroll
        for (int ks = 0; ks < 4; ks++) {
            int c = ks * 2 + (lane >> 4);
            uint32_t off = swz128(r, c);
            ldsm_x4(qfh[ks][0], qfh[ks][1], qfh[ks][2], qfh[ks][3], sb + AT_Q  + off);
            ldsm_x4(qfl[ks][0], qfl[ks][1], qfl[ks][2], qfl[ks][3], sb + AT_QL + off);
        }
    }

    float O[8][4];
#pragma unroll
    for (int nt = 0; nt < 8; nt++)
#pragma unroll
        for (int e = 0; e < 4; e++) O[nt][e] = 0.f;
    float m0 = -3.0e38f, m1 = -3.0e38f, l0 = 0.f, l1 = 0.f;

    const int r0 = qt * 128 + w * 16 + (lane >> 2);
    const int r1 = r0 + 8;

    for (int kt = 0; kt < 8; kt++) {
        if (kt > 0) {
            if (kt < 7)
                asm volatile("cp.async.wait_group 1;" ::: "memory");
            else
                asm volatile("cp.async.wait_group 0;" ::: "memory");
            __syncthreads();
        }
        uint32_t kv = sb + AT_KV + (kt & 1) * 65536;

        float S[16][4];
#pragma unroll
        for (int j = 0; j < 16; j++)
#pragma unroll
            for (int e = 0; e < 4; e++) S[j][e] = 0.f;

#pragma unroll
        for (int ks = 0; ks < 4; ks++) {
            const int krow = ((lane >> 4) << 3) + (lane & 7);
            const int kch  = ks * 2 + ((lane >> 3) & 1);
#pragma unroll
            for (int jq = 0; jq < 4; jq++) {
                uint32_t kb0[4], kl0[4], kb1[4], kl1[4];
                uint32_t off0 = swz128((2 * jq) * 16 + krow, kch);
                uint32_t off1 = swz128((2 * jq + 1) * 16 + krow, kch);
                ldsm_x4(kb0[0], kb0[1], kb0[2], kb0[3], kv + off0);
                ldsm_x4(kl0[0], kl0[1], kl0[2], kl0[3], kv + 16384 + off0);
                ldsm_x4(kb1[0], kb1[1], kb1[2], kb1[3], kv + off1);
                ldsm_x4(kl1[0], kl1[1], kl1[2], kl1[3], kv + 16384 + off1);
                mma_bf16(S[4 * jq + 0], qfh[ks], kb0);
                mma_bf16(S[4 * jq + 1], qfh[ks], kb0 + 2);
                mma_bf16(S[4 * jq + 2], qfh[ks], kb1);
                mma_bf16(S[4 * jq + 3], qfh[ks], kb1 + 2);
                mma_bf16(S[4 * jq + 0], qfh[ks], kl0);
                mma_bf16(S[4 * jq + 1], qfh[ks], kl0 + 2);
                mma_bf16(S[4 * jq + 2], qfh[ks], kl1);
                mma_bf16(S[4 * jq + 3], qfh[ks], kl1 + 2);
                mma_bf16(S[4 * jq + 0], qfl[ks], kb0);
                mma_bf16(S[4 * jq + 1], qfl[ks], kb0 + 2);
                mma_bf16(S[4 * jq + 2], qfl[ks], kb1);
                mma_bf16(S[4 * jq + 3], qfl[ks], kb1 + 2);
            }
        }

        const int ktbase = kt * 128;
#pragma unroll
        for (int j = 0; j < 16; j++) {
            int c = ktbase + j * 8 + (lane & 3) * 2;
            float t00 = bd_s[c - r0 + 1023] + lm_s[c];
            float t01 = bd_s[c + 1 - r0 + 1023] + lm_s[c + 1];
            float t10 = bd_s[c - r1 + 1023] + lm_s[c];
            float t11 = bd_s[c + 1 - r1 + 1023] + lm_s[c + 1];
            S[j][0] = fmaf(S[j][0], LOG2E, t00);
            S[j][1] = fmaf(S[j][1], LOG2E, t01);
            S[j][2] = fmaf(S[j][2], LOG2E, t10);
            S[j][3] = fmaf(S[j][3], LOG2E, t11);
        }

        float tm0 = -3.0e38f, tm1 = -3.0e38f;
#pragma unroll
        for (int j = 0; j < 16; j++) {
            tm0 = fmaxf(tm0, fmaxf(S[j][0], S[j][1]));
            tm1 = fmaxf(tm1, fmaxf(S[j][2], S[j][3]));
        }
        tm0 = fmaxf(tm0, __shfl_xor_sync(0xffffffffu, tm0, 1));
        tm0 = fmaxf(tm0, __shfl_xor_sync(0xffffffffu, tm0, 2));
        tm1 = fmaxf(tm1, __shfl_xor_sync(0xffffffffu, tm1, 1));
        tm1 = fmaxf(tm1, __shfl_xor_sync(0xffffffffu, tm1, 2));
        float mn0 = fmaxf(m0, tm0), mn1 = fmaxf(m1, tm1);
        float a0 = exp2f(m0 - mn0), a1 = exp2f(m1 - mn1);
        m0 = mn0; m1 = mn1;

        float s0 = 0.f, s1 = 0.f;
#pragma unroll
        for (int j = 0; j < 16; j++) {
            S[j][0] = exp2f(S[j][0] - mn0); s0 += S[j][0];
            S[j][1] = exp2f(S[j][1] - mn0); s0 += S[j][1];
            S[j][2] = exp2f(S[j][2] - mn1); s1 += S[j][2];
            S[j][3] = exp2f(S[j][3] - mn1); s1 += S[j][3];
        }
        s0 += __shfl_xor_sync(0xffffffffu, s0, 1);
        s0 += __shfl_xor_sync(0xffffffffu, s0, 2);
        s1 += __shfl_xor_sync(0xffffffffu, s1, 1);
        s1 += __shfl_xor_sync(0xffffffffu, s1, 2);
        l0 = l0 * a0 + s0;
        l1 = l1 * a1 + s1;

#pragma unroll
        for (int nt = 0; nt < 8; nt++) {
            O[nt][0] *= a0; O[nt][1] *= a0;
            O[nt][2] *= a1; O[nt][3] *= a1;
        }

#pragma unroll
        for (int kk = 0; kk < 8; kk++) {
            float* p0 = S[2 * kk];
            float* p1 = S[2 * kk + 1];
            uint32_t ph[4], pl[4];
            {
                ph[0] = cvt_bf2(p0[0], p0[1]);
                ph[1] = cvt_bf2(p0[2], p0[3]);
                ph[2] = cvt_bf2(p1[0], p1[1]);
                ph[3] = cvt_bf2(p1[2], p1[3]);
                pl[0] = cvt_bf2(p0[0] - bf2_lo_f(ph[0]), p0[1] - bf2_hi_f(ph[0]));
                pl[1] = cvt_bf2(p0[2] - bf2_lo_f(ph[1]), p0[3] - bf2_hi_f(ph[1]));
                pl[2] = cvt_bf2(p1[0] - bf2_lo_f(ph[2]), p1[1] - bf2_hi_f(ph[2]));
                pl[3] = cvt_bf2(p1[2] - bf2_lo_f(ph[3]), p1[3] - bf2_hi_f(ph[3]));
            }
            const int vrow = kk * 16 + (lane & 15);
            const int vcp  = (lane >> 4) & 1;
            uint32_t vh[4][4], vl[4][4];
#pragma unroll
            for (int np = 0; np < 4; np++) {
                uint32_t off = swz128(vrow, np * 2 + vcp);
                ldsm_x4t(vh[np][0], vh[np][1], vh[np][2], vh[np][3], kv + 32768 + off);
                ldsm_x4t(vl[np][0], vl[np][1], vl[np][2], vl[np][3], kv + 49152 + off);
            }
#pragma unroll
            for (int np = 0; np < 4; np++) {
                mma_bf16(O[2 * np],     ph, vh[np]);
                mma_bf16(O[2 * np + 1], ph, vh[np] + 2);
            }
#pragma unroll
            for (int np = 0; np < 4; np++) {
                mma_bf16(O[2 * np],     ph, vl[np]);
                mma_bf16(O[2 * np + 1], ph, vl[np] + 2);
            }
#pragma unroll
            for (int np = 0; np < 4; np++) {
                mma_bf16(O[2 * np],     pl, vh[np]);
                mma_bf16(O[2 * np + 1], pl, vh[np] + 2);
            }
        }

        __syncthreads();
        if (kt + 2 < 8)
            at_load_kv(sb + AT_KV + (kt & 1) * 65536, t, slab, kt + 2,
                       KH, KL, VH, VL);
    }

    float inv0 = 1.f / l0, inv1 = 1.f / l1;
    size_t ob0 = slab + (size_t)(qt * 128 + w * 16 + (lane >> 2)) * DHEAD;
    size_t ob1 = ob0 + 8 * DHEAD;
#pragma unroll
    for (int nt = 0; nt < 8; nt++) {
        int c = nt * 8 + (lane & 3) * 2;
        float v0 = O[nt][0] * inv0, v1 = O[nt][1] * inv0;
        float v2 = O[nt][2] * inv1, v3 = O[nt][3] * inv1;
        uint32_t hp0 = cvt_bf2(v0, v1), hp1 = cvt_bf2(v2, v3);
        uint32_t lp0 = cvt_bf2(v0 - bf2_lo_f(hp0), v1 - bf2_hi_f(hp0));
        uint32_t lp1 = cvt_bf2(v2 - bf2_lo_f(hp1), v3 - bf2_hi_f(hp1));
        *(uint32_t*)(OH + ob0 + c) = hp0;
        *(uint32_t*)(OH + ob1 + c) = hp1;
        *(uint32_t*)(OL + ob0 + c) = lp0;
        *(uint32_t*)(OL + ob1 + c) = lp1;
    }
}

// ============================================================================
// out = LayerNorm(A + B); optional bf16 hi/lo side output
// ============================================================================
template <bool SPLIT>
__global__ void __launch_bounds__(256) add_ln_kernel(
    const float* __restrict__ A, const float* __restrict__ B,
    float* __restrict__ out,
    __nv_bfloat16* __restrict__ OH, __nv_bfloat16* __restrict__ OL)
{
    __shared__ float sh[8];
    const size_t row = blockIdx.x;
    const int t = threadIdx.x;

    float4 a = ((const float4*)(A + row * DMODEL))[t];
    float4 b = ((const float4*)(B + row * DMODEL))[t];
    float4 x;
    x.x = a.x + b.x; x.y = a.y + b.y; x.z = a.z + b.z; x.w = a.w + b.w;

    float s = x.x + x.y + x.z + x.w;
#pragma unroll
    for (int o = 16; o; o >>= 1) s += __shfl_xor_sync(0xffffffffu, s, o);
    if ((t & 31) == 0) sh[t >> 5] = s;
    __syncthreads();
    float tot = sh[0];
#pragma unroll
    for (int i = 1; i < 8; i++) tot += sh[i];
    __syncthreads();
    float mean = tot * (1.f / DMODEL);

    float dx = x.x - mean, dy = x.y - mean, dz = x.z - mean, dw = x.w - mean;
    float s2 = dx * dx + dy * dy + dz * dz + dw * dw;
#pragma unroll
    for (int o = 16; o; o >>= 1) s2 += __shfl_xor_sync(0xffffffffu, s2, o);
    if ((t & 31) == 0) sh[t >> 5] = s2;
    __syncthreads();
    float tot2 = sh[0];
#pragma unroll
    for (int i = 1; i < 8; i++) tot2 += sh[i];
    float inv = rsqrtf(tot2 * (1.f / DMODEL));

    float4 o;
    o.x = dx * inv; o.y = dy * inv; o.z = dz * inv; o.w = dw * inv;
    ((float4*)(out + row * DMODEL))[t] = o;

    if (SPLIT) {
        uint32_t hp0 = cvt_bf2(o.x, o.y), hp1 = cvt_bf2(o.z, o.w);
        uint32_t lp0 = cvt_bf2(o.x - bf2_lo_f(hp0), o.y - bf2_hi_f(hp0));
        uint32_t lp1 = cvt_bf2(o.z - bf2_lo_f(hp1), o.w - bf2_hi_f(hp1));
        size_t base = row * DMODEL + t * 4;
        *(uint32_t*)(OH + base)     = hp0;
        *(uint32_t*)(OH + base + 2) = hp1;
        *(uint32_t*)(OL + base)     = lp0;
        *(uint32_t*)(OL + base + 2) = lp1;
    }
}

// ============================================================================
// Launch sequence
// ============================================================================
extern "C" void kernel_launch(void* const* d_in, const int* in_sizes, int n_in,
                              void* d_out, int out_size)
{
    const float* x   = (const float*)d_in[0];
    const int*   pm  = (const int*)  d_in[1];
    const float* Wq  = (const float*)d_in[2];
    const float* bq  = (const float*)d_in[3];
    const float* Wk  = (const float*)d_in[4];
    const float* bk  = (const float*)d_in[5];
    const float* Wv  = (const float*)d_in[6];
    const float* bv  = (const float*)d_in[7];
    const float* Wo  = (const float*)d_in[8];
    const float* bo  = (const float*)d_in[9];
    const float* rel = (const float*)d_in[10];
    const float* W1  = (const float*)d_in[11];
    const float* b1  = (const float*)d_in[12];
    const float* W2  = (const float*)d_in[13];
    const float* b2  = (const float*)d_in[14];
    float* out = (float*)d_out;

    float *attp, *attout, *ff, *bqkv;
    cudaGetSymbolAddress((void**)&attp,   g_attp);
    cudaGetSymbolAddress((void**)&attout, g_attout);
    cudaGetSymbolAddress((void**)&ff,     g_ff);
    cudaGetSymbolAddress((void**)&bqkv,   g_bqkv);

    __nv_bfloat16 *xh, *xl, *wqkvh, *wqkvl, *woh, *wol;
    __nv_bfloat16 *w1h, *w1l, *w2h, *w2l, *avh, *avl, *aoh, *aol, *h1h, *h1l;
    __nv_bfloat16 *qkvh, *qkvl;
    cudaGetSymbolAddress((void**)&xh,    g_xh);    cudaGetSymbolAddress((void**)&xl,    g_xl);
    cudaGetSymbolAddress((void**)&wqkvh, g_wqkvh); cudaGetSymbolAddress((void**)&wqkvl, g_wqkvl);
    cudaGetSymbolAddress((void**)&woh,   g_woh);   cudaGetSymbolAddress((void**)&wol,   g_wol);
    cudaGetSymbolAddress((void**)&w1h,   g_w1h);   cudaGetSymbolAddress((void**)&w1l,   g_w1l);
    cudaGetSymbolAddress((void**)&w2h,   g_w2h);   cudaGetSymbolAddress((void**)&w2l,   g_w2l);
    cudaGetSymbolAddress((void**)&avh,   g_avh);   cudaGetSymbolAddress((void**)&avl,   g_avl);
    cudaGetSymbolAddress((void**)&aoh,   g_aoh);   cudaGetSymbolAddress((void**)&aol,   g_aol);
    cudaGetSymbolAddress((void**)&h1h,   g_h1h);   cudaGetSymbolAddress((void**)&h1l,   g_h1l);
    cudaGetSymbolAddress((void**)&qkvh,  g_qkvh);  cudaGetSymbolAddress((void**)&qkvl,  g_qkvl);

    static bool attr_done = false;
    if (!attr_done) {
        cudaFuncSetAttribute(tgemm_kernel<false, 0>,
                             cudaFuncAttributeMaxDynamicSharedMemorySize, TG_SMEM);
        cudaFuncSetAttribute(tgemm_kernel<false, 1>,
                             cudaFuncAttributeMaxDynamicSharedMemorySize, TG_SMEM);
        cudaFuncSetAttribute(tgemm_kernel<false, 2>,
                             cudaFuncAttributeMaxDynamicSharedMemorySize, TG_SMEM);
        cudaFuncSetAttribute(tgemm_kernel<true, 1>,
                             cudaFuncAttributeMaxDynamicSharedMemorySize, TG_SMEM);
        cudaFuncSetAttribute(attn_fused_kernel,
                             cudaFuncAttributeMaxDynamicSharedMemorySize, AT_SMEM);
        attr_done = true;
    }

    dim3 blk(256);

    split_kernel<<<(MROWS * DMODEL / 4 + 255) / 256, blk>>>(
        x, xh, xl, MROWS * DMODEL / 4);
    splitw_all_kernel<<<(SEG_TOTAL + 255) / 256, blk>>>(
        Wq, Wk, Wv, Wo, W1, W2, bq, bk, bv,
        wqkvh, wqkvl, woh, wol, w1h, w1l, w2h, w2l, bqkv);

    // fused QKV projection
    dim3 gqkv(3 * DMODEL / TBN, MROWS / TBM);
    tgemm_kernel<false, 2><<<gqkv, blk, TG_SMEM>>>(
        xh, xl, wqkvh, wqkvl, bqkv, nullptr, qkvh, qkvl, MROWS, 3 * DMODEL, DMODEL);

    // attention
    const size_t SLAB = (size_t)MROWS * DMODEL;
    attn_fused_kernel<<<dim3(8, BHDIM), blk, AT_SMEM>>>(
        qkvh, qkvl, qkvh + SLAB, qkvl + SLAB, qkvh + 2 * SLAB, qkvl + 2 * SLAB,
        rel, pm, avh, avl);

    // O projection
    dim3 gO(DMODEL / TBN, MROWS / TBM);
    tgemm_kernel<false, 0><<<gO, blk, TG_SMEM>>>(
        avh, avl, woh, wol, bo, attp, nullptr, nullptr, MROWS, DMODEL, DMODEL);

    // residual + LN (+ split)
    add_ln_kernel<true><<<MROWS, blk>>>(attp, x, attout, aoh, aol);

    // FFN
    dim3 g1(FFDIM / TBN, MROWS / TBM);
    tgemm_kernel<true, 1><<<g1, blk, TG_SMEM>>>(
        aoh, aol, w1h, w1l, b1, nullptr, h1h, h1l, MROWS, FFDIM, DMODEL);
    dim3 g2(DMODEL / TBN, MROWS / TBM);
    tgemm_kernel<false, 0><<<g2, blk, TG_SMEM>>>(
        h1h, h1l, w2h, w2l, b2, ff, nullptr, nullptr, MROWS, DMODEL, FFDIM);

    // final residual + LN
    add_ln_kernel<false><<<MROWS, blk>>>(ff, attout, out, nullptr, nullptr);
}

// round 11
// speedup vs baseline: 4.4202x; 1.3979x over previous
#include <cuda_runtime.h>
#include <cuda_fp16.h>
#include <math.h>
#include <stdint.h>

// ---------------------------------------------------------------------------
// EncoderBlock: B=4, L=1024, D=1024, F=4096, H=16, dh=64
// Round 11: fp16 2-product split (A single fp16, B = fp16 hi+lo).
// MMA count x 2/3 vs bf16 3-product; error ~2^-11 one-sided (~3-5e-4 final).
// ---------------------------------------------------------------------------

#define LSEQ 1024
#define DMODEL 1024
#define BATCH 4
#define NHEAD 16
#define DHEAD 64
#define FFDIM 4096
#define BHDIM 64
#define MROWS 4096
#define LOG2E 1.4426950408889634f
#define SLAB_ELEMS (MROWS * DMODEL)

// ---- fp32 scratch ----------------------------------------------------------
__device__ float g_attp[BATCH * LSEQ * DMODEL];
__device__ float g_attout[BATCH * LSEQ * DMODEL];
__device__ float g_ff[BATCH * LSEQ * DMODEL];
__device__ float g_bqkv[3 * DMODEL];

// ---- fp16 scratch -----------------------------------------------------------
__device__ __half g_xf[SLAB_ELEMS];                       // x single
__device__ __half g_wqkvh[3 * DMODEL * DMODEL], g_wqkvl[3 * DMODEL * DMODEL];
__device__ __half g_woh[DMODEL * DMODEL], g_wol[DMODEL * DMODEL];
__device__ __half g_w1h[FFDIM * DMODEL],  g_w1l[FFDIM * DMODEL];
__device__ __half g_w2h[DMODEL * FFDIM],  g_w2l[DMODEL * FFDIM];
__device__ __half g_qf[SLAB_ELEMS];                        // Q single
__device__ __half g_kvh[2 * SLAB_ELEMS], g_kvl[2 * SLAB_ELEMS]; // K|V hi/lo
__device__ __half g_avf[SLAB_ELEMS];                       // attention out single
__device__ __half g_aof[SLAB_ELEMS];                       // LN out single
__device__ __half g_h1f[(size_t)MROWS * FFDIM];            // FFN1 out single

// ============================================================================
// helpers
// ============================================================================
__device__ __forceinline__ uint32_t smem_u32(const void* p) {
    uint32_t a;
    asm("{ .reg .u64 t; cvta.to.shared.u64 t, %1; cvt.u32.u64 %0, t; }"
        : "=r"(a) : "l"(p));
    return a;
}
__device__ __forceinline__ void cp16(uint32_t dst, const void* src) {
    asm volatile("cp.async.cg.shared.global [%0], [%1], 16;" :: "r"(dst), "l"(src));
}
__device__ __forceinline__ void ldsm_x4(uint32_t& r0, uint32_t& r1,
                                        uint32_t& r2, uint32_t& r3, uint32_t a) {
    asm volatile("ldmatrix.sync.aligned.m8n8.x4.shared.b16 {%0,%1,%2,%3}, [%4];"
                 : "=r"(r0), "=r"(r1), "=r"(r2), "=r"(r3) : "r"(a));
}
__device__ __forceinline__ void ldsm_x4t(uint32_t& r0, uint32_t& r1,
                                         uint32_t& r2, uint32_t& r3, uint32_t a) {
    asm volatile("ldmatrix.sync.aligned.m8n8.x4.trans.shared.b16 {%0,%1,%2,%3}, [%4];"
                 : "=r"(r0), "=r"(r1), "=r"(r2), "=r"(r3) : "r"(a));
}
__device__ __forceinline__ void mma_f16(float* c, const uint32_t* a, const uint32_t* b) {
    asm volatile(
        "mma.sync.aligned.m16n8k16.row.col.f32.f16.f16.f32 "
        "{%0,%1,%2,%3}, {%4,%5,%6,%7}, {%8,%9}, {%0,%1,%2,%3};"
        : "+f"(c[0]), "+f"(c[1]), "+f"(c[2]), "+f"(c[3])
        : "r"(a[0]), "r"(a[1]), "r"(a[2]), "r"(a[3]), "r"(b[0]), "r"(b[1]));
}
// pack two floats into f16x2 (lo in low half, hi in high half)
__device__ __forceinline__ uint32_t cvt_h2(float lo, float hi) {
    uint32_t r;
    asm("cvt.rn.f16x2.f32 %0, %1, %2;" : "=r"(r) : "f"(hi), "f"(lo));
    return r;
}
__device__ __forceinline__ float h2_lo_f(uint32_t r) {
    return __half2float(__ushort_as_half((unsigned short)(r & 0xFFFF)));
}
__device__ __forceinline__ float h2_hi_f(uint32_t r) {
    return __half2float(__ushort_as_half((unsigned short)(r >> 16)));
}

// ============================================================================
// split x: fp32 -> single fp16
// ============================================================================
__global__ void __launch_bounds__(256) splitx_kernel(
    const float* __restrict__ X, __half* __restrict__ F, int n4)
{
    int i = blockIdx.x * 256 + threadIdx.x;
    if (i >= n4) return;
    float4 v = ((const float4*)X)[i];
    uint32_t h01 = cvt_h2(v.x, v.y);
    uint32_t h23 = cvt_h2(v.z, v.w);
    ((uint2*)F)[i] = make_uint2(h01, h23);
}

// ============================================================================
// split ALL weights -> fp16 hi/lo; pack qkv bias.
// ============================================================================
#define SEG_QKV (3 * DMODEL * DMODEL / 4)
#define SEG_WO  (DMODEL * DMODEL / 4)
#define SEG_W1  (FFDIM * DMODEL / 4)
#define SEG_W2  (DMODEL * FFDIM / 4)
#define SEG_TOTAL (SEG_QKV + SEG_WO + SEG_W1 + SEG_W2)

__global__ void __launch_bounds__(256) splitw_all_kernel(
    const float* __restrict__ Wq, const float* __restrict__ Wk,
    const float* __restrict__ Wv, const float* __restrict__ Wo,
    const float* __restrict__ W1, const float* __restrict__ W2,
    const float* __restrict__ bq, const float* __restrict__ bk,
    const float* __restrict__ bv,
    __half* __restrict__ QKVH, __half* __restrict__ QKVL,
    __half* __restrict__ WOH,  __half* __restrict__ WOL,
    __half* __restrict__ W1H,  __half* __restrict__ W1L,
    __half* __restrict__ W2H,  __half* __restrict__ W2L,
    float* __restrict__ bpack)
{
    int i = blockIdx.x * 256 + threadIdx.x;
    if (i < 3 * DMODEL) {
        float b = (i < DMODEL) ? bq[i] : (i < 2 * DMODEL) ? bk[i - DMODEL]
                                                          : bv[i - 2 * DMODEL];
        bpack[i] = b;
    }
    if (i >= SEG_TOTAL) return;

    const float* src;
    __half *H, *L;
    int off;
    if (i < SEG_QKV) {
        const int n4m = DMODEL * DMODEL / 4;
        int m = i / n4m;
        off = i - m * n4m;
        src = (m == 0) ? Wq : (m == 1) ? Wk : Wv;
        H = QKVH + (size_t)m * DMODEL * DMODEL;
        L = QKVL + (size_t)m * DMODEL * DMODEL;
    } else if (i < SEG_QKV + SEG_WO) {
        off = i - SEG_QKV; src = Wo; H = WOH; L = WOL;
    } else if (i < SEG_QKV + SEG_WO + SEG_W1) {
        off = i - SEG_QKV - SEG_WO; src = W1; H = W1H; L = W1L;
    } else {
        off = i - SEG_QKV - SEG_WO - SEG_W1; src = W2; H = W2H; L = W2L;
    }

    float4 v = ((const float4*)src)[off];
    uint32_t h01 = cvt_h2(v.x, v.y);
    uint32_t h23 = cvt_h2(v.z, v.w);
    uint32_t l01 = cvt_h2(v.x - h2_lo_f(h01), v.y - h2_hi_f(h01));
    uint32_t l23 = cvt_h2(v.z - h2_lo_f(h23), v.w - h2_hi_f(h23));
    ((uint2*)H)[off] = make_uint2(h01, h23);
    ((uint2*)L)[off] = make_uint2(l01, l23);
}

// ============================================================================
// fp16 2-product GEMM: C[M,N] = A[M,K] @ (Bh+Bl)[N,K]^T + bias
// BM=BN=128, BK=32, 3-stage pipeline.
// OUT: 0 = fp32 C; 1 = fp16 single; 2 = QKV scatter (Q single, K/V hi/lo).
// ============================================================================
#define TBM 128
#define TBN 128
#define TBK 32
#define STG_BYTES 24576      /* A 8K | Bh 8K | Bl 8K */
#define TG_SMEM (3 * STG_BYTES)

__device__ __forceinline__ uint32_t sw_off(int r, int c) {
    return (uint32_t)(r * 64 + ((c ^ ((r >> 1) & 3)) << 4));
}

__device__ __forceinline__ void tg_load_stage(
    uint32_t sbuf, int t,
    const __half* __restrict__ Af,
    const __half* __restrict__ Bh, const __half* __restrict__ Bl,
    int rowBase, int colBase, int k0, int K)
{
#pragma unroll
    for (int j = 0; j < 6; j++) {
        int i   = j * 256 + t;      // 0..1535
        int arr = i >> 9;           // 0=A, 1=Bh, 2=Bl
        int idx = i & 511;
        int r   = idx >> 2;
        int ch  = idx & 3;
        const __half* base = (arr == 0) ? Af : (arr == 1) ? Bh : Bl;
        int gr = ((arr == 0) ? rowBase : colBase) + r;
        cp16(sbuf + arr * 8192 + sw_off(r, ch),
             base + (size_t)gr * K + k0 + ch * 8);
    }
    asm volatile("cp.async.commit_group;" ::: "memory");
}

template <bool RELU, int OUT>
__global__ void __launch_bounds__(256, 2) tgemm_kernel(
    const __half* __restrict__ Af,
    const __half* __restrict__ Bh, const __half* __restrict__ Bl,
    const float* __restrict__ bias, float* __restrict__ C,
    __half* __restrict__ F16O,
    __half* __restrict__ QF, __half* __restrict__ KVH, __half* __restrict__ KVL,
    int M, int N, int K)
{
    extern __shared__ __align__(16) char smem[];
    uint32_t sb = smem_u32(smem);
    const int t = threadIdx.x;
    const int w = t >> 5, lane = t & 31;
    const int wm = w >> 2;
    const int wn = w & 3;
    const int rowBase = blockIdx.y * TBM;
    const int colBase = blockIdx.x * TBN;
    const int KT = K / TBK;

    float acc[4][4][4];
#pragma unroll
    for (int mt = 0; mt < 4; mt++)
#pragma unroll
        for (int nt = 0; nt < 4; nt++)
#pragma unroll
            for (int e = 0; e < 4; e++) acc[mt][nt][e] = 0.f;

    tg_load_stage(sb,                 t, Af, Bh, Bl, rowBase, colBase, 0 * TBK, K);
    tg_load_stage(sb + 1 * STG_BYTES, t, Af, Bh, Bl, rowBase, colBase, 1 * TBK, K);

    int stage = 0;
    for (int kt = 0; kt < KT; kt++) {
        if (kt + 1 < KT)
            asm volatile("cp.async.wait_group 1;" ::: "memory");
        else
            asm volatile("cp.async.wait_group 0;" ::: "memory");
        __syncthreads();

        if (kt + 2 < KT) {
            int ps = stage + 2; if (ps >= 3) ps -= 3;
            tg_load_stage(sb + ps * STG_BYTES, t,
                          Af, Bh, Bl, rowBase, colBase, (kt + 2) * TBK, K);
        }

        uint32_t sbase = sb + stage * STG_BYTES;
#pragma unroll
        for (int ks = 0; ks < 2; ks++) {
            uint32_t ah[4][4];
            const int arow0  = wm * 64 + (lane & 15);
            const int achunk = ks * 2 + (lane >> 4);
#pragma unroll
            for (int mt = 0; mt < 4; mt++) {
                uint32_t off = sw_off(arow0 + mt * 16, achunk);
                ldsm_x4(ah[mt][0], ah[mt][1], ah[mt][2], ah[mt][3], sbase + off);
            }
            const int brow = wn * 32 + ((lane >> 4) << 3) + (lane & 7);
            const int bch  = ks * 2 + ((lane >> 3) & 1);
#pragma unroll
            for (int np = 0; np < 2; np++) {
                uint32_t b2h[4], b2l[4];
                uint32_t off = sw_off(brow + np * 16, bch);
                ldsm_x4(b2h[0], b2h[1], b2h[2], b2h[3], sbase + 8192 + off);
                ldsm_x4(b2l[0], b2l[1], b2l[2], b2l[3], sbase + 16384 + off);
#pragma unroll
                for (int mt = 0; mt < 4; mt++) {
                    mma_f16(acc[mt][2 * np],     ah[mt], b2h);
                    mma_f16(acc[mt][2 * np + 1], ah[mt], b2h + 2);
                }
#pragma unroll
                for (int mt = 0; mt < 4; mt++) {
                    mma_f16(acc[mt][2 * np],     ah[mt], b2l);
                    mma_f16(acc[mt][2 * np + 1], ah[mt], b2l + 2);
                }
            }
        }
        stage++; if (stage == 3) stage = 0;
    }

    // Epilogue
#pragma unroll
    for (int nt = 0; nt < 4; nt++) {
        int c = colBase + wn * 32 + nt * 8 + (lane & 3) * 2;
        float b0 = __ldg(&bias[c]), b1 = __ldg(&bias[c + 1]);
        int sel = 0, cc = c;
        if (OUT == 2) { sel = c >> 10; cc = c & 1023; }
#pragma unroll
        for (int mt = 0; mt < 4; mt++) {
            int r0 = rowBase + wm * 64 + mt * 16 + (lane >> 2);
            float v0 = acc[mt][nt][0] + b0, v1 = acc[mt][nt][1] + b1;
            float v2 = acc[mt][nt][2] + b0, v3 = acc[mt][nt][3] + b1;
            if (RELU) {
                v0 = fmaxf(v0, 0.f); v1 = fmaxf(v1, 0.f);
                v2 = fmaxf(v2, 0.f); v3 = fmaxf(v3, 0.f);
            }
            if (OUT == 0) {
                *(float2*)(C + (size_t)r0 * N + c)       = make_float2(v0, v1);
                *(float2*)(C + (size_t)(r0 + 8) * N + c) = make_float2(v2, v3);
            } else if (OUT == 1) {
                *(uint32_t*)(F16O + (size_t)r0 * N + c)       = cvt_h2(v0, v1);
                *(uint32_t*)(F16O + (size_t)(r0 + 8) * N + c) = cvt_h2(v2, v3);
            } else {
                if (sel == 0) {
                    *(uint32_t*)(QF + (size_t)r0 * DMODEL + cc)       = cvt_h2(v0, v1);
                    *(uint32_t*)(QF + (size_t)(r0 + 8) * DMODEL + cc) = cvt_h2(v2, v3);
                } else {
                    size_t base = (size_t)(sel - 1) * SLAB_ELEMS;
                    uint32_t hp0 = cvt_h2(v0, v1), hp1 = cvt_h2(v2, v3);
                    uint32_t lp0 = cvt_h2(v0 - h2_lo_f(hp0), v1 - h2_hi_f(hp0));
                    uint32_t lp1 = cvt_h2(v2 - h2_lo_f(hp1), v3 - h2_hi_f(hp1));
                    *(uint32_t*)(KVH + base + (size_t)r0 * DMODEL + cc)       = hp0;
                    *(uint32_t*)(KVH + base + (size_t)(r0 + 8) * DMODEL + cc) = hp1;
                    *(uint32_t*)(KVL + base + (size_t)r0 * DMODEL + cc)       = lp0;
                    *(uint32_t*)(KVL + base + (size_t)(r0 + 8) * DMODEL + cc) = lp1;
                }
            }
        }
    }
}

// ============================================================================
// T5 relative-position bucket for displacement d
// ============================================================================
__device__ __forceinline__ int rel_bucket_d(int d)
{
    int ret = (d < 0) ? NHEAD : 0;
    int n   = abs(d);
    int b;
    if (n < 8) b = n;
    else {
        int j = (31 - __clz(n * n)) - 6;
        j = min(j, 7);
        b = 8 + j;
    }
    return ret + b;
}

// ============================================================================
// Fused flash attention — fp16 2-product (Q single, K/V hi/lo, P single).
// smem: Q 16K | KV stage x2 (kh,kl,vh,vl 16K each = 64K) | lm 4K | bd 8K
// ============================================================================
#define AT_Q    0
#define AT_KV   16384
#define AT_LM   147456
#define AT_BD   151552
#define AT_SMEM 159744

__device__ __forceinline__ uint32_t swz128(int r, int c) {
    return (uint32_t)(r * 128 + ((c ^ (r & 7)) << 4));
}

__device__ __forceinline__ void at_load_kv(
    uint32_t kvbase, int t, size_t slab, int kt,
    const __half* __restrict__ KH, const __half* __restrict__ KL,
    const __half* __restrict__ VH, const __half* __restrict__ VL)
{
    size_t gb = slab + (size_t)kt * 128 * DHEAD;
    for (int i = t; i < 1024; i += 256) {
        int r = i >> 3, c = i & 7;
        uint32_t off = swz128(r, c);
        size_t g = gb + r * DHEAD + c * 8;
        cp16(kvbase + off,         KH + g);
        cp16(kvbase + 16384 + off, KL + g);
        cp16(kvbase + 32768 + off, VH + g);
        cp16(kvbase + 49152 + off, VL + g);
    }
    asm volatile("cp.async.commit_group;" ::: "memory");
}

__global__ void __launch_bounds__(256, 1) attn_fused_kernel(
    const __half* __restrict__ QF,
    const __half* __restrict__ KH, const __half* __restrict__ KL,
    const __half* __restrict__ VH, const __half* __restrict__ VL,
    const float* __restrict__ rel, const int* __restrict__ pm,
    __half* __restrict__ OF)
{
    extern __shared__ __align__(16) char smem[];
    uint32_t sb = smem_u32(smem);
    float* lm_s = (float*)(smem + AT_LM);
    float* bd_s = (float*)(smem + AT_BD);

    const int t = threadIdx.x, w = t >> 5, lane = t & 31;
    const int qt = blockIdx.x, bh = blockIdx.y;
    const int h = bh & (NHEAD - 1), b = bh >> 4;
    const size_t slab = (size_t)bh * (LSEQ * DHEAD);

    for (int i = t; i < LSEQ; i += 256)
        lm_s[i] = log2f((float)pm[b * LSEQ + i]);
    for (int i = t; i < 2047; i += 256)
        bd_s[i] = rel[rel_bucket_d(i - 1023) * NHEAD + h] * LOG2E;

    {
        size_t qbase = slab + (size_t)qt * 128 * DHEAD;
        for (int i = t; i < 1024; i += 256) {
            int r = i >> 3, c = i & 7;
            cp16(sb + AT_Q + swz128(r, c), QF + qbase + r * DHEAD + c * 8);
        }
        at_load_kv(sb + AT_KV, t, slab, 0, KH, KL, VH, VL);
        at_load_kv(sb + AT_KV + 65536, t, slab, 1, KH, KL, VH, VL);
        asm volatile("cp.async.wait_group 1;" ::: "memory");
    }
    __syncthreads();

    uint32_t qf[4][4];
    {
        int r = w * 16 + (lane & 15);
#pragma unroll
        for (int ks = 0; ks < 4; ks++) {
            int c = ks * 2 + (lane >> 4);
            ldsm_x4(qf[ks][0], qf[ks][1], qf[ks][2], qf[ks][3],
                    sb + AT_Q + swz128(r, c));
        }
    }

    float O[8][4];
#pragma unroll
    for (int nt = 0; nt < 8; nt++)
#pragma unroll
        for (int e = 0; e < 4; e++) O[nt][e] = 0.f;
    float m0 = -3.0e38f, m1 = -3.0e38f, l0 = 0.f, l1 = 0.f;

    const int r0 = qt * 128 + w * 16 + (lane >> 2);
    const int r1 = r0 + 8;

    for (int kt = 0; kt < 8; kt++) {
        if (kt > 0) {
            if (kt < 7)
                asm volatile("cp.async.wait_group 1;" ::: "memory");
            else
                asm volatile("cp.async.wait_group 0;" ::: "memory");
            __syncthreads();
        }
        uint32_t kv = sb + AT_KV + (kt & 1) * 65536;

        float S[16][4];
#pragma unroll
        for (int j = 0; j < 16; j++)
#pragma unroll
            for (int e = 0; e < 4; e++) S[j][e] = 0.f;

        // S = Q K^T : Q single, K hi/lo (2 products)
#pragma unroll
        for (int ks = 0; ks < 4; ks++) {
            const int krow = ((lane >> 4) << 3) + (lane & 7);
            const int kch  = ks * 2 + ((lane >> 3) & 1);
#pragma unroll
            for (int jq = 0; jq < 4; jq++) {
                uint32_t kb0[4], kl0[4], kb1[4], kl1[4];
                uint32_t off0 = swz128((2 * jq) * 16 + krow, kch);
                uint32_t off1 = swz128((2 * jq + 1) * 16 + krow, kch);
                ldsm_x4(kb0[0], kb0[1], kb0[2], kb0[3], kv + off0);
                ldsm_x4(kl0[0], kl0[1], kl0[2], kl0[3], kv + 16384 + off0);
                ldsm_x4(kb1[0], kb1[1], kb1[2], kb1[3], kv + off1);
                ldsm_x4(kl1[0], kl1[1], kl1[2], kl1[3], kv + 16384 + off1);
                mma_f16(S[4 * jq + 0], qf[ks], kb0);
                mma_f16(S[4 * jq + 1], qf[ks], kb0 + 2);
                mma_f16(S[4 * jq + 2], qf[ks], kb1);
                mma_f16(S[4 * jq + 3], qf[ks], kb1 + 2);
                mma_f16(S[4 * jq + 0], qf[ks], kl0);
                mma_f16(S[4 * jq + 1], qf[ks], kl0 + 2);
                mma_f16(S[4 * jq + 2], qf[ks], kl1);
                mma_f16(S[4 * jq + 3], qf[ks], kl1 + 2);
            }
        }

        const int ktbase = kt * 128;
#pragma unroll
        for (int j = 0; j < 16; j++) {
            int c = ktbase + j * 8 + (lane & 3) * 2;
            float t00 = bd_s[c - r0 + 1023] + lm_s[c];
            float t01 = bd_s[c + 1 - r0 + 1023] + lm_s[c + 1];
            float t10 = bd_s[c - r1 + 1023] + lm_s[c];
            float t11 = bd_s[c + 1 - r1 + 1023] + lm_s[c + 1];
            S[j][0] = fmaf(S[j][0], LOG2E, t00);
            S[j][1] = fmaf(S[j][1], LOG2E, t01);
            S[j][2] = fmaf(S[j][2], LOG2E, t10);
            S[j][3] = fmaf(S[j][3], LOG2E, t11);
        }

        float tm0 = -3.0e38f, tm1 = -3.0e38f;
#pragma unroll
        for (int j = 0; j < 16; j++) {
            tm0 = fmaxf(tm0, fmaxf(S[j][0], S[j][1]));
            tm1 = fmaxf(tm1, fmaxf(S[j][2], S[j][3]));
        }
        tm0 = fmaxf(tm0, __shfl_xor_sync(0xffffffffu, tm0, 1));
        tm0 = fmaxf(tm0, __shfl_xor_sync(0xffffffffu, tm0, 2));
        tm1 = fmaxf(tm1, __shfl_xor_sync(0xffffffffu, tm1, 1));
        tm1 = fmaxf(tm1, __shfl_xor_sync(0xffffffffu, tm1, 2));
        float mn0 = fmaxf(m0, tm0), mn1 = fmaxf(m1, tm1);
        float a0 = exp2f(m0 - mn0), a1 = exp2f(m1 - mn1);
        m0 = mn0; m1 = mn1;

        float s0 = 0.f, s1 = 0.f;
#pragma unroll
        for (int j = 0; j < 16; j++) {
            S[j][0] = exp2f(S[j][0] - mn0); s0 += S[j][0];
            S[j][1] = exp2f(S[j][1] - mn0); s0 += S[j][1];
            S[j][2] = exp2f(S[j][2] - mn1); s1 += S[j][2];
            S[j][3] = exp2f(S[j][3] - mn1); s1 += S[j][3];
        }
        s0 += __shfl_xor_sync(0xffffffffu, s0, 1);
        s0 += __shfl_xor_sync(0xffffffffu, s0, 2);
        s1 += __shfl_xor_sync(0xffffffffu, s1, 1);
        s1 += __shfl_xor_sync(0xffffffffu, s1, 2);
        l0 = l0 * a0 + s0;
        l1 = l1 * a1 + s1;

#pragma unroll
        for (int nt = 0; nt < 8; nt++) {
            O[nt][0] *= a0; O[nt][1] *= a0;
            O[nt][2] *= a1; O[nt][3] *= a1;
        }

        // O += P @ V : P single, V hi/lo (2 products)
#pragma unroll
        for (int kk = 0; kk < 8; kk++) {
            float* p0 = S[2 * kk];
            float* p1 = S[2 * kk + 1];
            uint32_t ph[4];
            ph[0] = cvt_h2(p0[0], p0[1]);
            ph[1] = cvt_h2(p0[2], p0[3]);
            ph[2] = cvt_h2(p1[0], p1[1]);
            ph[3] = cvt_h2(p1[2], p1[3]);
            const int vrow = kk * 16 + (lane & 15);
            const int vcp  = (lane >> 4) & 1;
            uint32_t vh[4][4], vl[4][4];
#pragma unroll
            for (int np = 0; np < 4; np++) {
                uint32_t off = swz128(vrow, np * 2 + vcp);
                ldsm_x4t(vh[np][0], vh[np][1], vh[np][2], vh[np][3], kv + 32768 + off);
                ldsm_x4t(vl[np][0], vl[np][1], vl[np][2], vl[np][3], kv + 49152 + off);
            }
#pragma unroll
            for (int np = 0; np < 4; np++) {
                mma_f16(O[2 * np],     ph, vh[np]);
                mma_f16(O[2 * np + 1], ph, vh[np] + 2);
            }
#pragma unroll
            for (int np = 0; np < 4; np++) {
                mma_f16(O[2 * np],     ph, vl[np]);
                mma_f16(O[2 * np + 1], ph, vl[np] + 2);
            }
        }

        __syncthreads();
        if (kt + 2 < 8)
            at_load_kv(sb + AT_KV + (kt & 1) * 65536, t, slab, kt + 2,
                       KH, KL, VH, VL);
    }

    float inv0 = 1.f / l0, inv1 = 1.f / l1;
    size_t ob0 = slab + (size_t)(qt * 128 + w * 16 + (lane >> 2)) * DHEAD;
    size_t ob1 = ob0 + 8 * DHEAD;
#pragma unroll
    for (int nt = 0; nt < 8; nt++) {
        int c = nt * 8 + (lane & 3) * 2;
        *(uint32_t*)(OF + ob0 + c) = cvt_h2(O[nt][0] * inv0, O[nt][1] * inv0);
        *(uint32_t*)(OF + ob1 + c) = cvt_h2(O[nt][2] * inv1, O[nt][3] * inv1);
    }
}

// ============================================================================
// out = LayerNorm(A + B); optional fp16 single side output
// ============================================================================
template <bool SPLIT>
__global__ void __launch_bounds__(256) add_ln_kernel(
    const float* __restrict__ A, const float* __restrict__ B,
    float* __restrict__ out, __half* __restrict__ OF)
{
    __shared__ float sh[8];
    const size_t row = blockIdx.x;
    const int t = threadIdx.x;

    float4 a = ((const float4*)(A + row * DMODEL))[t];
    float4 b = ((const float4*)(B + row * DMODEL))[t];
    float4 x;
    x.x = a.x + b.x; x.y = a.y + b.y; x.z = a.z + b.z; x.w = a.w + b.w;

    float s = x.x + x.y + x.z + x.w;
#pragma unroll
    for (int o = 16; o; o >>= 1) s += __shfl_xor_sync(0xffffffffu, s, o);
    if ((t & 31) == 0) sh[t >> 5] = s;
    __syncthreads();
    float tot = sh[0];
#pragma unroll
    for (int i = 1; i < 8; i++) tot += sh[i];
    __syncthreads();
    float mean = tot * (1.f / DMODEL);

    float dx = x.x - mean, dy = x.y - mean, dz = x.z - mean, dw = x.w - mean;
    float s2 = dx * dx + dy * dy + dz * dz + dw * dw;
#pragma unroll
    for (int o = 16; o; o >>= 1) s2 += __shfl_xor_sync(0xffffffffu, s2, o);
    if ((t & 31) == 0) sh[t >> 5] = s2;
    __syncthreads();
    float tot2 = sh[0];
#pragma unroll
    for (int i = 1; i < 8; i++) tot2 += sh[i];
    float inv = rsqrtf(tot2 * (1.f / DMODEL));

    float4 o;
    o.x = dx * inv; o.y = dy * inv; o.z = dz * inv; o.w = dw * inv;
    ((float4*)(out + row * DMODEL))[t] = o;

    if (SPLIT) {
        size_t base = row * DMODEL + t * 4;
        *(uint32_t*)(OF + base)     = cvt_h2(o.x, o.y);
        *(uint32_t*)(OF + base + 2) = cvt_h2(o.z, o.w);
    }
}

// ============================================================================
// Launch sequence
// ============================================================================
extern "C" void kernel_launch(void* const* d_in, const int* in_sizes, int n_in,
                              void* d_out, int out_size)
{
    const float* x   = (const float*)d_in[0];
    const int*   pm  = (const int*)  d_in[1];
    const float* Wq  = (const float*)d_in[2];
    const float* bq  = (const float*)d_in[3];
    const float* Wk  = (const float*)d_in[4];
    const float* bk  = (const float*)d_in[5];
    const float* Wv  = (const float*)d_in[6];
    const float* bv  = (const float*)d_in[7];
    const float* Wo  = (const float*)d_in[8];
    const float* bo  = (const float*)d_in[9];
    const float* rel = (const float*)d_in[10];
    const float* W1  = (const float*)d_in[11];
    const float* b1  = (const float*)d_in[12];
    const float* W2  = (const float*)d_in[13];
    const float* b2  = (const float*)d_in[14];
    float* out = (float*)d_out;

    float *attp, *attout, *ff, *bqkv;
    cudaGetSymbolAddress((void**)&attp,   g_attp);
    cudaGetSymbolAddress((void**)&attout, g_attout);
    cudaGetSymbolAddress((void**)&ff,     g_ff);
    cudaGetSymbolAddress((void**)&bqkv,   g_bqkv);

    __half *xf, *wqkvh, *wqkvl, *woh, *wol, *w1h, *w1l, *w2h, *w2l;
    __half *qf, *kvh, *kvl, *avf, *aof, *h1f;
    cudaGetSymbolAddress((void**)&xf,    g_xf);
    cudaGetSymbolAddress((void**)&wqkvh, g_wqkvh); cudaGetSymbolAddress((void**)&wqkvl, g_wqkvl);
    cudaGetSymbolAddress((void**)&woh,   g_woh);   cudaGetSymbolAddress((void**)&wol,   g_wol);
    cudaGetSymbolAddress((void**)&w1h,   g_w1h);   cudaGetSymbolAddress((void**)&w1l,   g_w1l);
    cudaGetSymbolAddress((void**)&w2h,   g_w2h);   cudaGetSymbolAddress((void**)&w2l,   g_w2l);
    cudaGetSymbolAddress((void**)&qf,    g_qf);
    cudaGetSymbolAddress((void**)&kvh,   g_kvh);   cudaGetSymbolAddress((void**)&kvl,   g_kvl);
    cudaGetSymbolAddress((void**)&avf,   g_avf);
    cudaGetSymbolAddress((void**)&aof,   g_aof);
    cudaGetSymbolAddress((void**)&h1f,   g_h1f);

    static bool attr_done = false;
    if (!attr_done) {
        cudaFuncSetAttribute(tgemm_kernel<false, 0>,
                             cudaFuncAttributeMaxDynamicSharedMemorySize, TG_SMEM);
        cudaFuncSetAttribute(tgemm_kernel<false, 2>,
                             cudaFuncAttributeMaxDynamicSharedMemorySize, TG_SMEM);
        cudaFuncSetAttribute(tgemm_kernel<true, 1>,
                             cudaFuncAttributeMaxDynamicSharedMemorySize, TG_SMEM);
        cudaFuncSetAttribute(attn_fused_kernel,
                             cudaFuncAttributeMaxDynamicSharedMemorySize, AT_SMEM);
        attr_done = true;
    }

    dim3 blk(256);

    splitx_kernel<<<(MROWS * DMODEL / 4 + 255) / 256, blk>>>(
        x, xf, MROWS * DMODEL / 4);
    splitw_all_kernel<<<(SEG_TOTAL + 255) / 256, blk>>>(
        Wq, Wk, Wv, Wo, W1, W2, bq, bk, bv,
        wqkvh, wqkvl, woh, wol, w1h, w1l, w2h, w2l, bqkv);

    // fused QKV projection -> Q single, K/V hi/lo
    dim3 gqkv(3 * DMODEL / TBN, MROWS / TBM);
    tgemm_kernel<false, 2><<<gqkv, blk, TG_SMEM>>>(
        xf, wqkvh, wqkvl, bqkv, nullptr, nullptr, qf, kvh, kvl,
        MROWS, 3 * DMODEL, DMODEL);

    // attention
    attn_fused_kernel<<<dim3(8, BHDIM), blk, AT_SMEM>>>(
        qf, kvh, kvl, kvh + SLAB_ELEMS, kvl + SLAB_ELEMS, rel, pm, avf);

    // O projection
    dim3 gO(DMODEL / TBN, MROWS / TBM);
    tgemm_kernel<false, 0><<<gO, blk, TG_SMEM>>>(
        avf, woh, wol, bo, attp, nullptr, nullptr, nullptr, nullptr,
        MROWS, DMODEL, DMODEL);

    // residual + LN (+ fp16 single out)
    add_ln_kernel<true><<<MROWS, blk>>>(attp, x, attout, aof);

    // FFN
    dim3 g1(FFDIM / TBN, MROWS / TBM);
    tgemm_kernel<true, 1><<<g1, blk, TG_SMEM>>>(
        aof, w1h, w1l, b1, nullptr, h1f, nullptr, nullptr, nullptr,
        MROWS, FFDIM, DMODEL);
    dim3 g2(DMODEL / TBN, MROWS / TBM);
    tgemm_kernel<false, 0><<<g2, blk, TG_SMEM>>>(
        h1f, w2h, w2l, b2, ff, nullptr, nullptr, nullptr, nullptr,
        MROWS, DMODEL, FFDIM);

    // final residual + LN
    add_ln_kernel<false><<<MROWS, blk>>>(ff, attout, out, nullptr);
}

// round 12
// speedup vs baseline: 7.2782x; 1.6466x over previous
#include <cuda_runtime.h>
#include <cuda_fp16.h>
#include <math.h>
#include <stdint.h>

// ---------------------------------------------------------------------------
// EncoderBlock: B=4, L=1024, D=1024, F=4096, H=16, dh=64
// Round 12: pure fp16 x fp16 MMAs (1 product per pair) with fp32 accumulate.
// Error ~2^-11 two-sided per GEMM -> final ~3-4.5e-4 (gate 1e-3).
// ---------------------------------------------------------------------------

#define LSEQ 1024
#define DMODEL 1024
#define BATCH 4
#define NHEAD 16
#define DHEAD 64
#define FFDIM 4096
#define BHDIM 64
#define MROWS 4096
#define LOG2E 1.4426950408889634f
#define SLAB_ELEMS (MROWS * DMODEL)

// ---- fp32 scratch ----------------------------------------------------------
__device__ float g_attp[BATCH * LSEQ * DMODEL];
__device__ float g_attout[BATCH * LSEQ * DMODEL];
__device__ float g_ff[BATCH * LSEQ * DMODEL];
__device__ float g_bqkv[3 * DMODEL];

// ---- fp16 scratch -----------------------------------------------------------
__device__ __half g_xf[SLAB_ELEMS];
__device__ __half g_wqkv[3 * DMODEL * DMODEL];
__device__ __half g_wo[DMODEL * DMODEL];
__device__ __half g_w1[FFDIM * DMODEL];
__device__ __half g_w2[DMODEL * FFDIM];
__device__ __half g_qkv[3 * SLAB_ELEMS];       // Q | K | V
__device__ __half g_avf[SLAB_ELEMS];
__device__ __half g_aof[SLAB_ELEMS];
__device__ __half g_h1f[(size_t)MROWS * FFDIM];

// ============================================================================
// helpers
// ============================================================================
__device__ __forceinline__ uint32_t smem_u32(const void* p) {
    uint32_t a;
    asm("{ .reg .u64 t; cvta.to.shared.u64 t, %1; cvt.u32.u64 %0, t; }"
        : "=r"(a) : "l"(p));
    return a;
}
__device__ __forceinline__ void cp16(uint32_t dst, const void* src) {
    asm volatile("cp.async.cg.shared.global [%0], [%1], 16;" :: "r"(dst), "l"(src));
}
__device__ __forceinline__ void ldsm_x4(uint32_t& r0, uint32_t& r1,
                                        uint32_t& r2, uint32_t& r3, uint32_t a) {
    asm volatile("ldmatrix.sync.aligned.m8n8.x4.shared.b16 {%0,%1,%2,%3}, [%4];"
                 : "=r"(r0), "=r"(r1), "=r"(r2), "=r"(r3) : "r"(a));
}
__device__ __forceinline__ void ldsm_x4t(uint32_t& r0, uint32_t& r1,
                                         uint32_t& r2, uint32_t& r3, uint32_t a) {
    asm volatile("ldmatrix.sync.aligned.m8n8.x4.trans.shared.b16 {%0,%1,%2,%3}, [%4];"
                 : "=r"(r0), "=r"(r1), "=r"(r2), "=r"(r3) : "r"(a));
}
__device__ __forceinline__ void mma_f16(float* c, const uint32_t* a, const uint32_t* b) {
    asm volatile(
        "mma.sync.aligned.m16n8k16.row.col.f32.f16.f16.f32 "
        "{%0,%1,%2,%3}, {%4,%5,%6,%7}, {%8,%9}, {%0,%1,%2,%3};"
        : "+f"(c[0]), "+f"(c[1]), "+f"(c[2]), "+f"(c[3])
        : "r"(a[0]), "r"(a[1]), "r"(a[2]), "r"(a[3]), "r"(b[0]), "r"(b[1]));
}
__device__ __forceinline__ uint32_t cvt_h2(float lo, float hi) {
    uint32_t r;
    asm("cvt.rn.f16x2.f32 %0, %1, %2;" : "=r"(r) : "f"(hi), "f"(lo));
    return r;
}

// ============================================================================
// convert fp32 -> fp16 (generic)
// ============================================================================
__global__ void __launch_bounds__(256) cvt16_kernel(
    const float* __restrict__ X, __half* __restrict__ F, int n4)
{
    int i = blockIdx.x * 256 + threadIdx.x;
    if (i >= n4) return;
    float4 v = ((const float4*)X)[i];
    ((uint2*)F)[i] = make_uint2(cvt_h2(v.x, v.y), cvt_h2(v.z, v.w));
}

// ============================================================================
// convert ALL weights -> fp16; pack qkv bias.
// ============================================================================
#define SEG_QKV (3 * DMODEL * DMODEL / 4)
#define SEG_WO  (DMODEL * DMODEL / 4)
#define SEG_W1  (FFDIM * DMODEL / 4)
#define SEG_W2  (DMODEL * FFDIM / 4)
#define SEG_TOTAL (SEG_QKV + SEG_WO + SEG_W1 + SEG_W2)

__global__ void __launch_bounds__(256) cvtw_all_kernel(
    const float* __restrict__ Wq, const float* __restrict__ Wk,
    const float* __restrict__ Wv, const float* __restrict__ Wo,
    const float* __restrict__ W1, const float* __restrict__ W2,
    const float* __restrict__ bq, const float* __restrict__ bk,
    const float* __restrict__ bv,
    __half* __restrict__ QKVW, __half* __restrict__ WOF,
    __half* __restrict__ W1F,  __half* __restrict__ W2F,
    float* __restrict__ bpack)
{
    int i = blockIdx.x * 256 + threadIdx.x;
    if (i < 3 * DMODEL) {
        float b = (i < DMODEL) ? bq[i] : (i < 2 * DMODEL) ? bk[i - DMODEL]
                                                          : bv[i - 2 * DMODEL];
        bpack[i] = b;
    }
    if (i >= SEG_TOTAL) return;

    const float* src;
    __half* F;
    int off;
    if (i < SEG_QKV) {
        const int n4m = DMODEL * DMODEL / 4;
        int m = i / n4m;
        off = i - m * n4m;
        src = (m == 0) ? Wq : (m == 1) ? Wk : Wv;
        F = QKVW + (size_t)m * DMODEL * DMODEL;
    } else if (i < SEG_QKV + SEG_WO) {
        off = i - SEG_QKV; src = Wo; F = WOF;
    } else if (i < SEG_QKV + SEG_WO + SEG_W1) {
        off = i - SEG_QKV - SEG_WO; src = W1; F = W1F;
    } else {
        off = i - SEG_QKV - SEG_WO - SEG_W1; src = W2; F = W2F;
    }

    float4 v = ((const float4*)src)[off];
    ((uint2*)F)[off] = make_uint2(cvt_h2(v.x, v.y), cvt_h2(v.z, v.w));
}

// ============================================================================
// fp16 GEMM: C[M,N] = A[M,K] @ B[N,K]^T + bias (fp32 accum)
// BM=BN=128, BK=32, 3-stage pipeline (16KB/stage).
// OUT: 0 = fp32 C; 1 = fp16; 2 = fp16 QKV slab (contiguous, N=3072).
// ============================================================================
#define TBM 128
#define TBN 128
#define TBK 32
#define STG_BYTES 16384      /* A 8K | B 8K */
#define TG_SMEM (3 * STG_BYTES)

__device__ __forceinline__ uint32_t sw_off(int r, int c) {
    return (uint32_t)(r * 64 + ((c ^ ((r >> 1) & 3)) << 4));
}

__device__ __forceinline__ void tg_load_stage(
    uint32_t sbuf, int t,
    const __half* __restrict__ Af, const __half* __restrict__ Bf,
    int rowBase, int colBase, int k0, int K)
{
#pragma unroll
    for (int j = 0; j < 4; j++) {
        int i   = j * 256 + t;      // 0..1023
        int arr = i >> 9;           // 0=A, 1=B
        int idx = i & 511;
        int r   = idx >> 2;
        int ch  = idx & 3;
        const __half* base = arr ? Bf : Af;
        int gr = (arr ? colBase : rowBase) + r;
        cp16(sbuf + arr * 8192 + sw_off(r, ch),
             base + (size_t)gr * K + k0 + ch * 8);
    }
    asm volatile("cp.async.commit_group;" ::: "memory");
}

template <bool RELU, int OUT>
__global__ void __launch_bounds__(256, 2) tgemm_kernel(
    const __half* __restrict__ Af, const __half* __restrict__ Bf,
    const float* __restrict__ bias, float* __restrict__ C,
    __half* __restrict__ F16O,
    int M, int N, int K)
{
    extern __shared__ __align__(16) char smem[];
    uint32_t sb = smem_u32(smem);
    const int t = threadIdx.x;
    const int w = t >> 5, lane = t & 31;
    const int wm = w >> 2;
    const int wn = w & 3;
    const int rowBase = blockIdx.y * TBM;
    const int colBase = blockIdx.x * TBN;
    const int KT = K / TBK;

    float acc[4][4][4];
#pragma unroll
    for (int mt = 0; mt < 4; mt++)
#pragma unroll
        for (int nt = 0; nt < 4; nt++)
#pragma unroll
            for (int e = 0; e < 4; e++) acc[mt][nt][e] = 0.f;

    tg_load_stage(sb,                 t, Af, Bf, rowBase, colBase, 0 * TBK, K);
    tg_load_stage(sb + 1 * STG_BYTES, t, Af, Bf, rowBase, colBase, 1 * TBK, K);

    int stage = 0;
    for (int kt = 0; kt < KT; kt++) {
        if (kt + 1 < KT)
            asm volatile("cp.async.wait_group 1;" ::: "memory");
        else
            asm volatile("cp.async.wait_group 0;" ::: "memory");
        __syncthreads();

        if (kt + 2 < KT) {
            int ps = stage + 2; if (ps >= 3) ps -= 3;
            tg_load_stage(sb + ps * STG_BYTES, t,
                          Af, Bf, rowBase, colBase, (kt + 2) * TBK, K);
        }

        uint32_t sbase = sb + stage * STG_BYTES;
#pragma unroll
        for (int ks = 0; ks < 2; ks++) {
            uint32_t ah[4][4];
            const int arow0  = wm * 64 + (lane & 15);
            const int achunk = ks * 2 + (lane >> 4);
#pragma unroll
            for (int mt = 0; mt < 4; mt++) {
                uint32_t off = sw_off(arow0 + mt * 16, achunk);
                ldsm_x4(ah[mt][0], ah[mt][1], ah[mt][2], ah[mt][3], sbase + off);
            }
            const int brow = wn * 32 + ((lane >> 4) << 3) + (lane & 7);
            const int bch  = ks * 2 + ((lane >> 3) & 1);
#pragma unroll
            for (int np = 0; np < 2; np++) {
                uint32_t b2[4];
                uint32_t off = sw_off(brow + np * 16, bch);
                ldsm_x4(b2[0], b2[1], b2[2], b2[3], sbase + 8192 + off);
#pragma unroll
                for (int mt = 0; mt < 4; mt++) {
                    mma_f16(acc[mt][2 * np],     ah[mt], b2);
                    mma_f16(acc[mt][2 * np + 1], ah[mt], b2 + 2);
                }
            }
        }
        stage++; if (stage == 3) stage = 0;
    }

    // Epilogue
#pragma unroll
    for (int nt = 0; nt < 4; nt++) {
        int c = colBase + wn * 32 + nt * 8 + (lane & 3) * 2;
        float b0 = __ldg(&bias[c]), b1 = __ldg(&bias[c + 1]);
#pragma unroll
        for (int mt = 0; mt < 4; mt++) {
            int r0 = rowBase + wm * 64 + mt * 16 + (lane >> 2);
            float v0 = acc[mt][nt][0] + b0, v1 = acc[mt][nt][1] + b1;
            float v2 = acc[mt][nt][2] + b0, v3 = acc[mt][nt][3] + b1;
            if (RELU) {
                v0 = fmaxf(v0, 0.f); v1 = fmaxf(v1, 0.f);
                v2 = fmaxf(v2, 0.f); v3 = fmaxf(v3, 0.f);
            }
            if (OUT == 0) {
                *(float2*)(C + (size_t)r0 * N + c)       = make_float2(v0, v1);
                *(float2*)(C + (size_t)(r0 + 8) * N + c) = make_float2(v2, v3);
            } else if (OUT == 1) {
                *(uint32_t*)(F16O + (size_t)r0 * N + c)       = cvt_h2(v0, v1);
                *(uint32_t*)(F16O + (size_t)(r0 + 8) * N + c) = cvt_h2(v2, v3);
            } else {
                // QKV scatter: column c -> slab (c>>10), local col c&1023
                int sel = c >> 10, cc = c & 1023;
                __half* dst = F16O + (size_t)sel * SLAB_ELEMS;
                *(uint32_t*)(dst + (size_t)r0 * DMODEL + cc)       = cvt_h2(v0, v1);
                *(uint32_t*)(dst + (size_t)(r0 + 8) * DMODEL + cc) = cvt_h2(v2, v3);
            }
        }
    }
}

// ============================================================================
// T5 relative-position bucket for displacement d
// ============================================================================
__device__ __forceinline__ int rel_bucket_d(int d)
{
    int ret = (d < 0) ? NHEAD : 0;
    int n   = abs(d);
    int b;
    if (n < 8) b = n;
    else {
        int j = (31 - __clz(n * n)) - 6;
        j = min(j, 7);
        b = 8 + j;
    }
    return ret + b;
}

// ============================================================================
// Fused flash attention — pure fp16 MMAs.
// smem: Q 16K | KV stage x2 (K 16K + V 16K) | lm 4K | bd 8K = 92K
// ============================================================================
#define AT_Q    0
#define AT_KV   16384
#define AT_LM   81920
#define AT_BD   86016
#define AT_SMEM 94208

__device__ __forceinline__ uint32_t swz128(int r, int c) {
    return (uint32_t)(r * 128 + ((c ^ (r & 7)) << 4));
}

__device__ __forceinline__ void at_load_kv(
    uint32_t kvbase, int t, size_t slab, int kt,
    const __half* __restrict__ KF, const __half* __restrict__ VF)
{
    size_t gb = slab + (size_t)kt * 128 * DHEAD;
    for (int i = t; i < 1024; i += 256) {
        int r = i >> 3, c = i & 7;
        uint32_t off = swz128(r, c);
        size_t g = gb + r * DHEAD + c * 8;
        cp16(kvbase + off,         KF + g);
        cp16(kvbase + 16384 + off, VF + g);
    }
    asm volatile("cp.async.commit_group;" ::: "memory");
}

__global__ void __launch_bounds__(256, 1) attn_fused_kernel(
    const __half* __restrict__ QF,
    const __half* __restrict__ KF, const __half* __restrict__ VF,
    const float* __restrict__ rel, const int* __restrict__ pm,
    __half* __restrict__ OF)
{
    extern __shared__ __align__(16) char smem[];
    uint32_t sb = smem_u32(smem);
    float* lm_s = (float*)(smem + AT_LM);
    float* bd_s = (float*)(smem + AT_BD);

    const int t = threadIdx.x, w = t >> 5, lane = t & 31;
    const int qt = blockIdx.x, bh = blockIdx.y;
    const int h = bh & (NHEAD - 1), b = bh >> 4;
    const size_t slab = (size_t)bh * (LSEQ * DHEAD);

    for (int i = t; i < LSEQ; i += 256)
        lm_s[i] = log2f((float)pm[b * LSEQ + i]);
    for (int i = t; i < 2047; i += 256)
        bd_s[i] = rel[rel_bucket_d(i - 1023) * NHEAD + h] * LOG2E;

    {
        size_t qbase = slab + (size_t)qt * 128 * DHEAD;
        for (int i = t; i < 1024; i += 256) {
            int r = i >> 3, c = i & 7;
            cp16(sb + AT_Q + swz128(r, c), QF + qbase + r * DHEAD + c * 8);
        }
        at_load_kv(sb + AT_KV, t, slab, 0, KF, VF);
        at_load_kv(sb + AT_KV + 32768, t, slab, 1, KF, VF);
        asm volatile("cp.async.wait_group 1;" ::: "memory");
    }
    __syncthreads();

    uint32_t qf[4][4];
    {
        int r = w * 16 + (lane & 15);
#pragma unroll
        for (int ks = 0; ks < 4; ks++) {
            int c = ks * 2 + (lane >> 4);
            ldsm_x4(qf[ks][0], qf[ks][1], qf[ks][2], qf[ks][3],
                    sb + AT_Q + swz128(r, c));
        }
    }

    float O[8][4];
#pragma unroll
    for (int nt = 0; nt < 8; nt++)
#pragma unroll
        for (int e = 0; e < 4; e++) O[nt][e] = 0.f;
    float m0 = -3.0e38f, m1 = -3.0e38f, l0 = 0.f, l1 = 0.f;

    const int r0 = qt * 128 + w * 16 + (lane >> 2);
    const int r1 = r0 + 8;

    for (int kt = 0; kt < 8; kt++) {
        if (kt > 0) {
            if (kt < 7)
                asm volatile("cp.async.wait_group 1;" ::: "memory");
            else
                asm volatile("cp.async.wait_group 0;" ::: "memory");
            __syncthreads();
        }
        uint32_t kv = sb + AT_KV + (kt & 1) * 32768;

        float S[16][4];
#pragma unroll
        for (int j = 0; j < 16; j++)
#pragma unroll
            for (int e = 0; e < 4; e++) S[j][e] = 0.f;

        // S = Q K^T (single product)
#pragma unroll
        for (int ks = 0; ks < 4; ks++) {
            const int krow = ((lane >> 4) << 3) + (lane & 7);
            const int kch  = ks * 2 + ((lane >> 3) & 1);
#pragma unroll
            for (int jq = 0; jq < 4; jq++) {
                uint32_t kb0[4], kb1[4];
                uint32_t off0 = swz128((2 * jq) * 16 + krow, kch);
                uint32_t off1 = swz128((2 * jq + 1) * 16 + krow, kch);
                ldsm_x4(kb0[0], kb0[1], kb0[2], kb0[3], kv + off0);
                ldsm_x4(kb1[0], kb1[1], kb1[2], kb1[3], kv + off1);
                mma_f16(S[4 * jq + 0], qf[ks], kb0);
                mma_f16(S[4 * jq + 1], qf[ks], kb0 + 2);
                mma_f16(S[4 * jq + 2], qf[ks], kb1);
                mma_f16(S[4 * jq + 3], qf[ks], kb1 + 2);
            }
        }

        const int ktbase = kt * 128;
#pragma unroll
        for (int j = 0; j < 16; j++) {
            int c = ktbase + j * 8 + (lane & 3) * 2;
            float t00 = bd_s[c - r0 + 1023] + lm_s[c];
            float t01 = bd_s[c + 1 - r0 + 1023] + lm_s[c + 1];
            float t10 = bd_s[c - r1 + 1023] + lm_s[c];
            float t11 = bd_s[c + 1 - r1 + 1023] + lm_s[c + 1];
            S[j][0] = fmaf(S[j][0], LOG2E, t00);
            S[j][1] = fmaf(S[j][1], LOG2E, t01);
            S[j][2] = fmaf(S[j][2], LOG2E, t10);
            S[j][3] = fmaf(S[j][3], LOG2E, t11);
        }

        float tm0 = -3.0e38f, tm1 = -3.0e38f;
#pragma unroll
        for (int j = 0; j < 16; j++) {
            tm0 = fmaxf(tm0, fmaxf(S[j][0], S[j][1]));
            tm1 = fmaxf(tm1, fmaxf(S[j][2], S[j][3]));
        }
        tm0 = fmaxf(tm0, __shfl_xor_sync(0xffffffffu, tm0, 1));
        tm0 = fmaxf(tm0, __shfl_xor_sync(0xffffffffu, tm0, 2));
        tm1 = fmaxf(tm1, __shfl_xor_sync(0xffffffffu, tm1, 1));
        tm1 = fmaxf(tm1, __shfl_xor_sync(0xffffffffu, tm1, 2));
        float mn0 = fmaxf(m0, tm0), mn1 = fmaxf(m1, tm1);
        float a0 = exp2f(m0 - mn0), a1 = exp2f(m1 - mn1);
        m0 = mn0; m1 = mn1;

        float s0 = 0.f, s1 = 0.f;
#pragma unroll
        for (int j = 0; j < 16; j++) {
            S[j][0] = exp2f(S[j][0] - mn0); s0 += S[j][0];
            S[j][1] = exp2f(S[j][1] - mn0); s0 += S[j][1];
            S[j][2] = exp2f(S[j][2] - mn1); s1 += S[j][2];
            S[j][3] = exp2f(S[j][3] - mn1); s1 += S[j][3];
        }
        s0 += __shfl_xor_sync(0xffffffffu, s0, 1);
        s0 += __shfl_xor_sync(0xffffffffu, s0, 2);
        s1 += __shfl_xor_sync(0xffffffffu, s1, 1);
        s1 += __shfl_xor_sync(0xffffffffu, s1, 2);
        l0 = l0 * a0 + s0;
        l1 = l1 * a1 + s1;

#pragma unroll
        for (int nt = 0; nt < 8; nt++) {
            O[nt][0] *= a0; O[nt][1] *= a0;
            O[nt][2] *= a1; O[nt][3] *= a1;
        }

        // O += P @ V (single product)
#pragma unroll
        for (int kk = 0; kk < 8; kk++) {
            float* p0 = S[2 * kk];
            float* p1 = S[2 * kk + 1];
            uint32_t ph[4];
            ph[0] = cvt_h2(p0[0], p0[1]);
            ph[1] = cvt_h2(p0[2], p0[3]);
            ph[2] = cvt_h2(p1[0], p1[1]);
            ph[3] = cvt_h2(p1[2], p1[3]);
            const int vrow = kk * 16 + (lane & 15);
            const int vcp  = (lane >> 4) & 1;
#pragma unroll
            for (int np = 0; np < 4; np++) {
                uint32_t vb[4];
                uint32_t off = swz128(vrow, np * 2 + vcp);
                ldsm_x4t(vb[0], vb[1], vb[2], vb[3], kv + 16384 + off);
                mma_f16(O[2 * np],     ph, vb);
                mma_f16(O[2 * np + 1], ph, vb + 2);
            }
        }

        __syncthreads();
        if (kt + 2 < 8)
            at_load_kv(sb + AT_KV + (kt & 1) * 32768, t, slab, kt + 2, KF, VF);
    }

    float inv0 = 1.f / l0, inv1 = 1.f / l1;
    size_t ob0 = slab + (size_t)(qt * 128 + w * 16 + (lane >> 2)) * DHEAD;
    size_t ob1 = ob0 + 8 * DHEAD;
#pragma unroll
    for (int nt = 0; nt < 8; nt++) {
        int c = nt * 8 + (lane & 3) * 2;
        *(uint32_t*)(OF + ob0 + c) = cvt_h2(O[nt][0] * inv0, O[nt][1] * inv0);
        *(uint32_t*)(OF + ob1 + c) = cvt_h2(O[nt][2] * inv1, O[nt][3] * inv1);
    }
}

// ============================================================================
// out = LayerNorm(A + B); optional fp16 side output
// ============================================================================
template <bool SPLIT>
__global__ void __launch_bounds__(256) add_ln_kernel(
    const float* __restrict__ A, const float* __restrict__ B,
    float* __restrict__ out, __half* __restrict__ OF)
{
    __shared__ float sh[8];
    const size_t row = blockIdx.x;
    const int t = threadIdx.x;

    float4 a = ((const float4*)(A + row * DMODEL))[t];
    float4 b = ((const float4*)(B + row * DMODEL))[t];
    float4 x;
    x.x = a.x + b.x; x.y = a.y + b.y; x.z = a.z + b.z; x.w = a.w + b.w;

    float s = x.x + x.y + x.z + x.w;
#pragma unroll
    for (int o = 16; o; o >>= 1) s += __shfl_xor_sync(0xffffffffu, s, o);
    if ((t & 31) == 0) sh[t >> 5] = s;
    __syncthreads();
    float tot = sh[0];
#pragma unroll
    for (int i = 1; i < 8; i++) tot += sh[i];
    __syncthreads();
    float mean = tot * (1.f / DMODEL);

    float dx = x.x - mean, dy = x.y - mean, dz = x.z - mean, dw = x.w - mean;
    float s2 = dx * dx + dy * dy + dz * dz + dw * dw;
#pragma unroll
    for (int o = 16; o; o >>= 1) s2 += __shfl_xor_sync(0xffffffffu, s2, o);
    if ((t & 31) == 0) sh[t >> 5] = s2;
    __syncthreads();
    float tot2 = sh[0];
#pragma unroll
    for (int i = 1; i < 8; i++) tot2 += sh[i];
    float inv = rsqrtf(tot2 * (1.f / DMODEL));

    float4 o;
    o.x = dx * inv; o.y = dy * inv; o.z = dz * inv; o.w = dw * inv;
    ((float4*)(out + row * DMODEL))[t] = o;

    if (SPLIT) {
        size_t base = row * DMODEL + t * 4;
        *(uint32_t*)(OF + base)     = cvt_h2(o.x, o.y);
        *(uint32_t*)(OF + base + 2) = cvt_h2(o.z, o.w);
    }
}

// ============================================================================
// Launch sequence
// ============================================================================
extern "C" void kernel_launch(void* const* d_in, const int* in_sizes, int n_in,
                              void* d_out, int out_size)
{
    const float* x   = (const float*)d_in[0];
    const int*   pm  = (const int*)  d_in[1];
    const float* Wq  = (const float*)d_in[2];
    const float* bq  = (const float*)d_in[3];
    const float* Wk  = (const float*)d_in[4];
    const float* bk  = (const float*)d_in[5];
    const float* Wv  = (const float*)d_in[6];
    const float* bv  = (const float*)d_in[7];
    const float* Wo  = (const float*)d_in[8];
    const float* bo  = (const float*)d_in[9];
    const float* rel = (const float*)d_in[10];
    const float* W1  = (const float*)d_in[11];
    const float* b1  = (const float*)d_in[12];
    const float* W2  = (const float*)d_in[13];
    const float* b2  = (const float*)d_in[14];
    float* out = (float*)d_out;

    float *attp, *attout, *ff, *bqkv;
    cudaGetSymbolAddress((void**)&attp,   g_attp);
    cudaGetSymbolAddress((void**)&attout, g_attout);
    cudaGetSymbolAddress((void**)&ff,     g_ff);
    cudaGetSymbolAddress((void**)&bqkv,   g_bqkv);

    __half *xf, *wqkv, *wo, *w1, *w2, *qkv, *avf, *aof, *h1f;
    cudaGetSymbolAddress((void**)&xf,   g_xf);
    cudaGetSymbolAddress((void**)&wqkv, g_wqkv);
    cudaGetSymbolAddress((void**)&wo,   g_wo);
    cudaGetSymbolAddress((void**)&w1,   g_w1);
    cudaGetSymbolAddress((void**)&w2,   g_w2);
    cudaGetSymbolAddress((void**)&qkv,  g_qkv);
    cudaGetSymbolAddress((void**)&avf,  g_avf);
    cudaGetSymbolAddress((void**)&aof,  g_aof);
    cudaGetSymbolAddress((void**)&h1f,  g_h1f);

    static bool attr_done = false;
    if (!attr_done) {
        cudaFuncSetAttribute(tgemm_kernel<false, 0>,
                             cudaFuncAttributeMaxDynamicSharedMemorySize, TG_SMEM);
        cudaFuncSetAttribute(tgemm_kernel<false, 2>,
                             cudaFuncAttributeMaxDynamicSharedMemorySize, TG_SMEM);
        cudaFuncSetAttribute(tgemm_kernel<true, 1>,
                             cudaFuncAttributeMaxDynamicSharedMemorySize, TG_SMEM);
        cudaFuncSetAttribute(attn_fused_kernel,
                             cudaFuncAttributeMaxDynamicSharedMemorySize, AT_SMEM);
        attr_done = true;
    }

    dim3 blk(256);

    cvt16_kernel<<<(MROWS * DMODEL / 4 + 255) / 256, blk>>>(
        x, xf, MROWS * DMODEL / 4);
    cvtw_all_kernel<<<(SEG_TOTAL + 255) / 256, blk>>>(
        Wq, Wk, Wv, Wo, W1, W2, bq, bk, bv, wqkv, wo, w1, w2, bqkv);

    // fused QKV projection -> Q | K | V fp16 slabs
    dim3 gqkv(3 * DMODEL / TBN, MROWS / TBM);
    tgemm_kernel<false, 2><<<gqkv, blk, TG_SMEM>>>(
        xf, wqkv, bqkv, nullptr, qkv, MROWS, 3 * DMODEL, DMODEL);

    // attention
    attn_fused_kernel<<<dim3(8, BHDIM), blk, AT_SMEM>>>(
        qkv, qkv + SLAB_ELEMS, qkv + 2 * SLAB_ELEMS, rel, pm, avf);

    // O projection
    dim3 gO(DMODEL / TBN, MROWS / TBM);
    tgemm_kernel<false, 0><<<gO, blk, TG_SMEM>>>(
        avf, wo, bo, attp, nullptr, MROWS, DMODEL, DMODEL);

    // residual + LN (+ fp16 out)
    add_ln_kernel<true><<<MROWS, blk>>>(attp, x, attout, aof);

    // FFN
    dim3 g1(FFDIM / TBN, MROWS / TBM);
    tgemm_kernel<true, 1><<<g1, blk, TG_SMEM>>>(
        aof, w1, b1, nullptr, h1f, MROWS, FFDIM, DMODEL);
    dim3 g2(DMODEL / TBN, MROWS / TBM);
    tgemm_kernel<false, 0><<<g2, blk, TG_SMEM>>>(
        h1f, w2, b2, ff, nullptr, MROWS, DMODEL, FFDIM);

    // final residual + LN
    add_ln_kernel<false><<<MROWS, blk>>>(ff, attout, out, nullptr);
}

// round 13
// speedup vs baseline: 7.2888x; 1.0015x over previous
#include <cuda_runtime.h>
#include <cuda_fp16.h>
#include <math.h>
#include <stdint.h>

// ---------------------------------------------------------------------------
// EncoderBlock: B=4, L=1024, D=1024, F=4096, H=16, dh=64
// Round 13: dense GEMM TBK=64 (half the barriers, 64 MMA per window);
// attention bias+max loop fusion. Numerics unchanged from R12.
// ---------------------------------------------------------------------------

#define LSEQ 1024
#define DMODEL 1024
#define BATCH 4
#define NHEAD 16
#define DHEAD 64
#define FFDIM 4096
#define BHDIM 64
#define MROWS 4096
#define LOG2E 1.4426950408889634f
#define SLAB_ELEMS (MROWS * DMODEL)

// ---- fp32 scratch ----------------------------------------------------------
__device__ float g_attp[BATCH * LSEQ * DMODEL];
__device__ float g_attout[BATCH * LSEQ * DMODEL];
__device__ float g_ff[BATCH * LSEQ * DMODEL];
__device__ float g_bqkv[3 * DMODEL];

// ---- fp16 scratch -----------------------------------------------------------
__device__ __half g_xf[SLAB_ELEMS];
__device__ __half g_wqkv[3 * DMODEL * DMODEL];
__device__ __half g_wo[DMODEL * DMODEL];
__device__ __half g_w1[FFDIM * DMODEL];
__device__ __half g_w2[DMODEL * FFDIM];
__device__ __half g_qkv[3 * SLAB_ELEMS];       // Q | K | V
__device__ __half g_avf[SLAB_ELEMS];
__device__ __half g_aof[SLAB_ELEMS];
__device__ __half g_h1f[(size_t)MROWS * FFDIM];

// ============================================================================
// helpers
// ============================================================================
__device__ __forceinline__ uint32_t smem_u32(const void* p) {
    uint32_t a;
    asm("{ .reg .u64 t; cvta.to.shared.u64 t, %1; cvt.u32.u64 %0, t; }"
        : "=r"(a) : "l"(p));
    return a;
}
__device__ __forceinline__ void cp16(uint32_t dst, const void* src) {
    asm volatile("cp.async.cg.shared.global [%0], [%1], 16;" :: "r"(dst), "l"(src));
}
__device__ __forceinline__ void ldsm_x4(uint32_t& r0, uint32_t& r1,
                                        uint32_t& r2, uint32_t& r3, uint32_t a) {
    asm volatile("ldmatrix.sync.aligned.m8n8.x4.shared.b16 {%0,%1,%2,%3}, [%4];"
                 : "=r"(r0), "=r"(r1), "=r"(r2), "=r"(r3) : "r"(a));
}
__device__ __forceinline__ void ldsm_x4t(uint32_t& r0, uint32_t& r1,
                                         uint32_t& r2, uint32_t& r3, uint32_t a) {
    asm volatile("ldmatrix.sync.aligned.m8n8.x4.trans.shared.b16 {%0,%1,%2,%3}, [%4];"
                 : "=r"(r0), "=r"(r1), "=r"(r2), "=r"(r3) : "r"(a));
}
__device__ __forceinline__ void mma_f16(float* c, const uint32_t* a, const uint32_t* b) {
    asm volatile(
        "mma.sync.aligned.m16n8k16.row.col.f32.f16.f16.f32 "
        "{%0,%1,%2,%3}, {%4,%5,%6,%7}, {%8,%9}, {%0,%1,%2,%3};"
        : "+f"(c[0]), "+f"(c[1]), "+f"(c[2]), "+f"(c[3])
        : "r"(a[0]), "r"(a[1]), "r"(a[2]), "r"(a[3]), "r"(b[0]), "r"(b[1]));
}
__device__ __forceinline__ uint32_t cvt_h2(float lo, float hi) {
    uint32_t r;
    asm("cvt.rn.f16x2.f32 %0, %1, %2;" : "=r"(r) : "f"(hi), "f"(lo));
    return r;
}

// 128-byte-row swizzle (conflict-free ldmatrix)
__device__ __forceinline__ uint32_t swz128(int r, int c) {
    return (uint32_t)(r * 128 + ((c ^ (r & 7)) << 4));
}

// ============================================================================
// convert fp32 -> fp16 (generic)
// ============================================================================
__global__ void __launch_bounds__(256) cvt16_kernel(
    const float* __restrict__ X, __half* __restrict__ F, int n4)
{
    int i = blockIdx.x * 256 + threadIdx.x;
    if (i >= n4) return;
    float4 v = ((const float4*)X)[i];
    ((uint2*)F)[i] = make_uint2(cvt_h2(v.x, v.y), cvt_h2(v.z, v.w));
}

// ============================================================================
// convert ALL weights -> fp16; pack qkv bias.
// ============================================================================
#define SEG_QKV (3 * DMODEL * DMODEL / 4)
#define SEG_WO  (DMODEL * DMODEL / 4)
#define SEG_W1  (FFDIM * DMODEL / 4)
#define SEG_W2  (DMODEL * FFDIM / 4)
#define SEG_TOTAL (SEG_QKV + SEG_WO + SEG_W1 + SEG_W2)

__global__ void __launch_bounds__(256) cvtw_all_kernel(
    const float* __restrict__ Wq, const float* __restrict__ Wk,
    const float* __restrict__ Wv, const float* __restrict__ Wo,
    const float* __restrict__ W1, const float* __restrict__ W2,
    const float* __restrict__ bq, const float* __restrict__ bk,
    const float* __restrict__ bv,
    __half* __restrict__ QKVW, __half* __restrict__ WOF,
    __half* __restrict__ W1F,  __half* __restrict__ W2F,
    float* __restrict__ bpack)
{
    int i = blockIdx.x * 256 + threadIdx.x;
    if (i < 3 * DMODEL) {
        float b = (i < DMODEL) ? bq[i] : (i < 2 * DMODEL) ? bk[i - DMODEL]
                                                          : bv[i - 2 * DMODEL];
        bpack[i] = b;
    }
    if (i >= SEG_TOTAL) return;

    const float* src;
    __half* F;
    int off;
    if (i < SEG_QKV) {
        const int n4m = DMODEL * DMODEL / 4;
        int m = i / n4m;
        off = i - m * n4m;
        src = (m == 0) ? Wq : (m == 1) ? Wk : Wv;
        F = QKVW + (size_t)m * DMODEL * DMODEL;
    } else if (i < SEG_QKV + SEG_WO) {
        off = i - SEG_QKV; src = Wo; F = WOF;
    } else if (i < SEG_QKV + SEG_WO + SEG_W1) {
        off = i - SEG_QKV - SEG_WO; src = W1; F = W1F;
    } else {
        off = i - SEG_QKV - SEG_WO - SEG_W1; src = W2; F = W2F;
    }

    float4 v = ((const float4*)src)[off];
    ((uint2*)F)[off] = make_uint2(cvt_h2(v.x, v.y), cvt_h2(v.z, v.w));
}

// ============================================================================
// fp16 GEMM: C[M,N] = A[M,K] @ B[N,K]^T + bias (fp32 accum)
// BM=BN=128, BK=64, 3-stage pipeline (32KB/stage), 2 blocks/SM.
// OUT: 0 = fp32 C; 1 = fp16; 2 = fp16 QKV slab scatter.
// ============================================================================
#define TBM 128
#define TBN 128
#define TBK 64
#define STG_BYTES 32768      /* A 16K | B 16K */
#define TG_SMEM (3 * STG_BYTES)

__device__ __forceinline__ void tg_load_stage(
    uint32_t sbuf, int t,
    const __half* __restrict__ Af, const __half* __restrict__ Bf,
    int rowBase, int colBase, int k0, int K)
{
#pragma unroll
    for (int j = 0; j < 8; j++) {
        int i   = j * 256 + t;      // 0..2047
        int arr = i >> 10;          // 0=A, 1=B
        int idx = i & 1023;
        int r   = idx >> 3;         // 0..127
        int ch  = idx & 7;          // 0..7 (16B chunks of 128B row)
        const __half* base = arr ? Bf : Af;
        int gr = (arr ? colBase : rowBase) + r;
        cp16(sbuf + arr * 16384 + swz128(r, ch),
             base + (size_t)gr * K + k0 + ch * 8);
    }
    asm volatile("cp.async.commit_group;" ::: "memory");
}

template <bool RELU, int OUT>
__global__ void __launch_bounds__(256, 2) tgemm_kernel(
    const __half* __restrict__ Af, const __half* __restrict__ Bf,
    const float* __restrict__ bias, float* __restrict__ C,
    __half* __restrict__ F16O,
    int M, int N, int K)
{
    extern __shared__ __align__(16) char smem[];
    uint32_t sb = smem_u32(smem);
    const int t = threadIdx.x;
    const int w = t >> 5, lane = t & 31;
    const int wm = w >> 2;
    const int wn = w & 3;
    const int rowBase = blockIdx.y * TBM;
    const int colBase = blockIdx.x * TBN;
    const int KT = K / TBK;

    float acc[4][4][4];
#pragma unroll
    for (int mt = 0; mt < 4; mt++)
#pragma unroll
        for (int nt = 0; nt < 4; nt++)
#pragma unroll
            for (int e = 0; e < 4; e++) acc[mt][nt][e] = 0.f;

    tg_load_stage(sb,                 t, Af, Bf, rowBase, colBase, 0 * TBK, K);
    tg_load_stage(sb + 1 * STG_BYTES, t, Af, Bf, rowBase, colBase, 1 * TBK, K);

    int stage = 0;
    for (int kt = 0; kt < KT; kt++) {
        if (kt + 1 < KT)
            asm volatile("cp.async.wait_group 1;" ::: "memory");
        else
            asm volatile("cp.async.wait_group 0;" ::: "memory");
        __syncthreads();

        if (kt + 2 < KT) {
            int ps = stage + 2; if (ps >= 3) ps -= 3;
            tg_load_stage(sb + ps * STG_BYTES, t,
                          Af, Bf, rowBase, colBase, (kt + 2) * TBK, K);
        }

        uint32_t sbase = sb + stage * STG_BYTES;
#pragma unroll
        for (int ks = 0; ks < 4; ks++) {
            uint32_t ah[4][4];
            const int arow0  = wm * 64 + (lane & 15);
            const int achunk = ks * 2 + (lane >> 4);
#pragma unroll
            for (int mt = 0; mt < 4; mt++) {
                uint32_t off = swz128(arow0 + mt * 16, achunk);
                ldsm_x4(ah[mt][0], ah[mt][1], ah[mt][2], ah[mt][3], sbase + off);
            }
            const int brow = wn * 32 + ((lane >> 4) << 3) + (lane & 7);
            const int bch  = ks * 2 + ((lane >> 3) & 1);
#pragma unroll
            for (int np = 0; np < 2; np++) {
                uint32_t b2[4];
                uint32_t off = swz128(brow + np * 16, bch);
                ldsm_x4(b2[0], b2[1], b2[2], b2[3], sbase + 16384 + off);
#pragma unroll
                for (int mt = 0; mt < 4; mt++) {
                    mma_f16(acc[mt][2 * np],     ah[mt], b2);
                    mma_f16(acc[mt][2 * np + 1], ah[mt], b2 + 2);
                }
            }
        }
        stage++; if (stage == 3) stage = 0;
    }

    // Epilogue
#pragma unroll
    for (int nt = 0; nt < 4; nt++) {
        int c = colBase + wn * 32 + nt * 8 + (lane & 3) * 2;
        float b0 = __ldg(&bias[c]), b1 = __ldg(&bias[c + 1]);
#pragma unroll
        for (int mt = 0; mt < 4; mt++) {
            int r0 = rowBase + wm * 64 + mt * 16 + (lane >> 2);
            float v0 = acc[mt][nt][0] + b0, v1 = acc[mt][nt][1] + b1;
            float v2 = acc[mt][nt][2] + b0, v3 = acc[mt][nt][3] + b1;
            if (RELU) {
                v0 = fmaxf(v0, 0.f); v1 = fmaxf(v1, 0.f);
                v2 = fmaxf(v2, 0.f); v3 = fmaxf(v3, 0.f);
            }
            if (OUT == 0) {
                *(float2*)(C + (size_t)r0 * N + c)       = make_float2(v0, v1);
                *(float2*)(C + (size_t)(r0 + 8) * N + c) = make_float2(v2, v3);
            } else if (OUT == 1) {
                *(uint32_t*)(F16O + (size_t)r0 * N + c)       = cvt_h2(v0, v1);
                *(uint32_t*)(F16O + (size_t)(r0 + 8) * N + c) = cvt_h2(v2, v3);
            } else {
                int sel = c >> 10, cc = c & 1023;
                __half* dst = F16O + (size_t)sel * SLAB_ELEMS;
                *(uint32_t*)(dst + (size_t)r0 * DMODEL + cc)       = cvt_h2(v0, v1);
                *(uint32_t*)(dst + (size_t)(r0 + 8) * DMODEL + cc) = cvt_h2(v2, v3);
            }
        }
    }
}

// ============================================================================
// T5 relative-position bucket for displacement d
// ============================================================================
__device__ __forceinline__ int rel_bucket_d(int d)
{
    int ret = (d < 0) ? NHEAD : 0;
    int n   = abs(d);
    int b;
    if (n < 8) b = n;
    else {
        int j = (31 - __clz(n * n)) - 6;
        j = min(j, 7);
        b = 8 + j;
    }
    return ret + b;
}

// ============================================================================
// Fused flash attention — pure fp16 MMAs; fused bias+max loop.
// smem: Q 16K | KV stage x2 (K 16K + V 16K) | lm 4K | bd 8K
// ============================================================================
#define AT_Q    0
#define AT_KV   16384
#define AT_LM   81920
#define AT_BD   86016
#define AT_SMEM 94208

__device__ __forceinline__ void at_load_kv(
    uint32_t kvbase, int t, size_t slab, int kt,
    const __half* __restrict__ KF, const __half* __restrict__ VF)
{
    size_t gb = slab + (size_t)kt * 128 * DHEAD;
    for (int i = t; i < 1024; i += 256) {
        int r = i >> 3, c = i & 7;
        uint32_t off = swz128(r, c);
        size_t g = gb + r * DHEAD + c * 8;
        cp16(kvbase + off,         KF + g);
        cp16(kvbase + 16384 + off, VF + g);
    }
    asm volatile("cp.async.commit_group;" ::: "memory");
}

__global__ void __launch_bounds__(256, 1) attn_fused_kernel(
    const __half* __restrict__ QF,
    const __half* __restrict__ KF, const __half* __restrict__ VF,
    const float* __restrict__ rel, const int* __restrict__ pm,
    __half* __restrict__ OF)
{
    extern __shared__ __align__(16) char smem[];
    uint32_t sb = smem_u32(smem);
    float* lm_s = (float*)(smem + AT_LM);
    float* bd_s = (float*)(smem + AT_BD);

    const int t = threadIdx.x, w = t >> 5, lane = t & 31;
    const int qt = blockIdx.x, bh = blockIdx.y;
    const int h = bh & (NHEAD - 1), b = bh >> 4;
    const size_t slab = (size_t)bh * (LSEQ * DHEAD);

    for (int i = t; i < LSEQ; i += 256)
        lm_s[i] = log2f((float)pm[b * LSEQ + i]);
    for (int i = t; i < 2047; i += 256)
        bd_s[i] = rel[rel_bucket_d(i - 1023) * NHEAD + h] * LOG2E;

    {
        size_t qbase = slab + (size_t)qt * 128 * DHEAD;
        for (int i = t; i < 1024; i += 256) {
            int r = i >> 3, c = i & 7;
            cp16(sb + AT_Q + swz128(r, c), QF + qbase + r * DHEAD + c * 8);
        }
        at_load_kv(sb + AT_KV, t, slab, 0, KF, VF);
        at_load_kv(sb + AT_KV + 32768, t, slab, 1, KF, VF);
        asm volatile("cp.async.wait_group 1;" ::: "memory");
    }
    __syncthreads();

    uint32_t qf[4][4];
    {
        int r = w * 16 + (lane & 15);
#pragma unroll
        for (int ks = 0; ks < 4; ks++) {
            int c = ks * 2 + (lane >> 4);
            ldsm_x4(qf[ks][0], qf[ks][1], qf[ks][2], qf[ks][3],
                    sb + AT_Q + swz128(r, c));
        }
    }

    float O[8][4];
#pragma unroll
    for (int nt = 0; nt < 8; nt++)
#pragma unroll
        for (int e = 0; e < 4; e++) O[nt][e] = 0.f;
    float m0 = -3.0e38f, m1 = -3.0e38f, l0 = 0.f, l1 = 0.f;

    const int r0 = qt * 128 + w * 16 + (lane >> 2);
    const int r1 = r0 + 8;

    for (int kt = 0; kt < 8; kt++) {
        if (kt > 0) {
            if (kt < 7)
                asm volatile("cp.async.wait_group 1;" ::: "memory");
            else
                asm volatile("cp.async.wait_group 0;" ::: "memory");
            __syncthreads();
        }
        uint32_t kv = sb + AT_KV + (kt & 1) * 32768;

        float S[16][4];
#pragma unroll
        for (int j = 0; j < 16; j++)
#pragma unroll
            for (int e = 0; e < 4; e++) S[j][e] = 0.f;

        // S = Q K^T (single product)
#pragma unroll
        for (int ks = 0; ks < 4; ks++) {
            const int krow = ((lane >> 4) << 3) + (lane & 7);
            const int kch  = ks * 2 + ((lane >> 3) & 1);
#pragma unroll
            for (int jq = 0; jq < 4; jq++) {
                uint32_t kb0[4], kb1[4];
                uint32_t off0 = swz128((2 * jq) * 16 + krow, kch);
                uint32_t off1 = swz128((2 * jq + 1) * 16 + krow, kch);
                ldsm_x4(kb0[0], kb0[1], kb0[2], kb0[3], kv + off0);
                ldsm_x4(kb1[0], kb1[1], kb1[2], kb1[3], kv + off1);
                mma_f16(S[4 * jq + 0], qf[ks], kb0);
                mma_f16(S[4 * jq + 1], qf[ks], kb0 + 2);
                mma_f16(S[4 * jq + 2], qf[ks], kb1);
                mma_f16(S[4 * jq + 3], qf[ks], kb1 + 2);
            }
        }

        // fused: bias (log2 domain) + tile max
        const int ktbase = kt * 128;
        float tm0 = -3.0e38f, tm1 = -3.0e38f;
#pragma unroll
        for (int j = 0; j < 16; j++) {
            int c = ktbase + j * 8 + (lane & 3) * 2;
            float t00 = bd_s[c - r0 + 1023] + lm_s[c];
            float t01 = bd_s[c + 1 - r0 + 1023] + lm_s[c + 1];
            float t10 = bd_s[c - r1 + 1023] + lm_s[c];
            float t11 = bd_s[c + 1 - r1 + 1023] + lm_s[c + 1];
            S[j][0] = fmaf(S[j][0], LOG2E, t00);
            S[j][1] = fmaf(S[j][1], LOG2E, t01);
            S[j][2] = fmaf(S[j][2], LOG2E, t10);
            S[j][3] = fmaf(S[j][3], LOG2E, t11);
            tm0 = fmaxf(tm0, fmaxf(S[j][0], S[j][1]));
            tm1 = fmaxf(tm1, fmaxf(S[j][2], S[j][3]));
        }
        tm0 = fmaxf(tm0, __shfl_xor_sync(0xffffffffu, tm0, 1));
        tm0 = fmaxf(tm0, __shfl_xor_sync(0xffffffffu, tm0, 2));
        tm1 = fmaxf(tm1, __shfl_xor_sync(0xffffffffu, tm1, 1));
        tm1 = fmaxf(tm1, __shfl_xor_sync(0xffffffffu, tm1, 2));
        float mn0 = fmaxf(m0, tm0), mn1 = fmaxf(m1, tm1);
        float a0 = exp2f(m0 - mn0), a1 = exp2f(m1 - mn1);
        m0 = mn0; m1 = mn1;

        float s0 = 0.f, s1 = 0.f;
#pragma unroll
        for (int j = 0; j < 16; j++) {
            S[j][0] = exp2f(S[j][0] - mn0); s0 += S[j][0];
            S[j][1] = exp2f(S[j][1] - mn0); s0 += S[j][1];
            S[j][2] = exp2f(S[j][2] - mn1); s1 += S[j][2];
            S[j][3] = exp2f(S[j][3] - mn1); s1 += S[j][3];
        }
        s0 += __shfl_xor_sync(0xffffffffu, s0, 1);
        s0 += __shfl_xor_sync(0xffffffffu, s0, 2);
        s1 += __shfl_xor_sync(0xffffffffu, s1, 1);
        s1 += __shfl_xor_sync(0xffffffffu, s1, 2);
        l0 = l0 * a0 + s0;
        l1 = l1 * a1 + s1;

#pragma unroll
        for (int nt = 0; nt < 8; nt++) {
            O[nt][0] *= a0; O[nt][1] *= a0;
            O[nt][2] *= a1; O[nt][3] *= a1;
        }

        // O += P @ V (single product)
#pragma unroll
        for (int kk = 0; kk < 8; kk++) {
            float* p0 = S[2 * kk];
            float* p1 = S[2 * kk + 1];
            uint32_t ph[4];
            ph[0] = cvt_h2(p0[0], p0[1]);
            ph[1] = cvt_h2(p0[2], p0[3]);
            ph[2] = cvt_h2(p1[0], p1[1]);
            ph[3] = cvt_h2(p1[2], p1[3]);
            const int vrow = kk * 16 + (lane & 15);
            const int vcp  = (lane >> 4) & 1;
#pragma unroll
            for (int np = 0; np < 4; np++) {
                uint32_t vb[4];
                uint32_t off = swz128(vrow, np * 2 + vcp);
                ldsm_x4t(vb[0], vb[1], vb[2], vb[3], kv + 16384 + off);
                mma_f16(O[2 * np],     ph, vb);
                mma_f16(O[2 * np + 1], ph, vb + 2);
            }
        }

        __syncthreads();
        if (kt + 2 < 8)
            at_load_kv(sb + AT_KV + (kt & 1) * 32768, t, slab, kt + 2, KF, VF);
    }

    float inv0 = 1.f / l0, inv1 = 1.f / l1;
    size_t ob0 = slab + (size_t)(qt * 128 + w * 16 + (lane >> 2)) * DHEAD;
    size_t ob1 = ob0 + 8 * DHEAD;
#pragma unroll
    for (int nt = 0; nt < 8; nt++) {
        int c = nt * 8 + (lane & 3) * 2;
        *(uint32_t*)(OF + ob0 + c) = cvt_h2(O[nt][0] * inv0, O[nt][1] * inv0);
        *(uint32_t*)(OF + ob1 + c) = cvt_h2(O[nt][2] * inv1, O[nt][3] * inv1);
    }
}

// ============================================================================
// out = LayerNorm(A + B); optional fp16 side output
// ============================================================================
template <bool SPLIT>
__global__ void __launch_bounds__(256) add_ln_kernel(
    const float* __restrict__ A, const float* __restrict__ B,
    float* __restrict__ out, __half* __restrict__ OF)
{
    __shared__ float sh[8];
    const size_t row = blockIdx.x;
    const int t = threadIdx.x;

    float4 a = ((const float4*)(A + row * DMODEL))[t];
    float4 b = ((const float4*)(B + row * DMODEL))[t];
    float4 x;
    x.x = a.x + b.x; x.y = a.y + b.y; x.z = a.z + b.z; x.w = a.w + b.w;

    float s = x.x + x.y + x.z + x.w;
#pragma unroll
    for (int o = 16; o; o >>= 1) s += __shfl_xor_sync(0xffffffffu, s, o);
    if ((t & 31) == 0) sh[t >> 5] = s;
    __syncthreads();
    float tot = sh[0];
#pragma unroll
    for (int i = 1; i < 8; i++) tot += sh[i];
    __syncthreads();
    float mean = tot * (1.f / DMODEL);

    float dx = x.x - mean, dy = x.y - mean, dz = x.z - mean, dw = x.w - mean;
    float s2 = dx * dx + dy * dy + dz * dz + dw * dw;
#pragma unroll
    for (int o = 16; o; o >>= 1) s2 += __shfl_xor_sync(0xffffffffu, s2, o);
    if ((t & 31) == 0) sh[t >> 5] = s2;
    __syncthreads();
    float tot2 = sh[0];
#pragma unroll
    for (int i = 1; i < 8; i++) tot2 += sh[i];
    float inv = rsqrtf(tot2 * (1.f / DMODEL));

    float4 o;
    o.x = dx * inv; o.y = dy * inv; o.z = dz * inv; o.w = dw * inv;
    ((float4*)(out + row * DMODEL))[t] = o;

    if (SPLIT) {
        size_t base = row * DMODEL + t * 4;
        *(uint32_t*)(OF + base)     = cvt_h2(o.x, o.y);
        *(uint32_t*)(OF + base + 2) = cvt_h2(o.z, o.w);
    }
}

// ============================================================================
// Launch sequence
// ============================================================================
extern "C" void kernel_launch(void* const* d_in, const int* in_sizes, int n_in,
                              void* d_out, int out_size)
{
    const float* x   = (const float*)d_in[0];
    const int*   pm  = (const int*)  d_in[1];
    const float* Wq  = (const float*)d_in[2];
    const float* bq  = (const float*)d_in[3];
    const float* Wk  = (const float*)d_in[4];
    const float* bk  = (const float*)d_in[5];
    const float* Wv  = (const float*)d_in[6];
    const float* bv  = (const float*)d_in[7];
    const float* Wo  = (const float*)d_in[8];
    const float* bo  = (const float*)d_in[9];
    const float* rel = (const float*)d_in[10];
    const float* W1  = (const float*)d_in[11];
    const float* b1  = (const float*)d_in[12];
    const float* W2  = (const float*)d_in[13];
    const float* b2  = (const float*)d_in[14];
    float* out = (float*)d_out;

    float *attp, *attout, *ff, *bqkv;
    cudaGetSymbolAddress((void**)&attp,   g_attp);
    cudaGetSymbolAddress((void**)&attout, g_attout);
    cudaGetSymbolAddress((void**)&ff,     g_ff);
    cudaGetSymbolAddress((void**)&bqkv,   g_bqkv);

    __half *xf, *wqkv, *wo, *w1, *w2, *qkv, *avf, *aof, *h1f;
    cudaGetSymbolAddress((void**)&xf,   g_xf);
    cudaGetSymbolAddress((void**)&wqkv, g_wqkv);
    cudaGetSymbolAddress((void**)&wo,   g_wo);
    cudaGetSymbolAddress((void**)&w1,   g_w1);
    cudaGetSymbolAddress((void**)&w2,   g_w2);
    cudaGetSymbolAddress((void**)&qkv,  g_qkv);
    cudaGetSymbolAddress((void**)&avf,  g_avf);
    cudaGetSymbolAddress((void**)&aof,  g_aof);
    cudaGetSymbolAddress((void**)&h1f,  g_h1f);

    static bool attr_done = false;
    if (!attr_done) {
        cudaFuncSetAttribute(tgemm_kernel<false, 0>,
                             cudaFuncAttributeMaxDynamicSharedMemorySize, TG_SMEM);
        cudaFuncSetAttribute(tgemm_kernel<false, 2>,
                             cudaFuncAttributeMaxDynamicSharedMemorySize, TG_SMEM);
        cudaFuncSetAttribute(tgemm_kernel<true, 1>,
                             cudaFuncAttributeMaxDynamicSharedMemorySize, TG_SMEM);
        cudaFuncSetAttribute(attn_fused_kernel,
                             cudaFuncAttributeMaxDynamicSharedMemorySize, AT_SMEM);
        attr_done = true;
    }

    dim3 blk(256);

    cvt16_kernel<<<(MROWS * DMODEL / 4 + 255) / 256, blk>>>(
        x, xf, MROWS * DMODEL / 4);
    cvtw_all_kernel<<<(SEG_TOTAL + 255) / 256, blk>>>(
        Wq, Wk, Wv, Wo, W1, W2, bq, bk, bv, wqkv, wo, w1, w2, bqkv);

    // fused QKV projection -> Q | K | V fp16 slabs
    dim3 gqkv(3 * DMODEL / TBN, MROWS / TBM);
    tgemm_kernel<false, 2><<<gqkv, blk, TG_SMEM>>>(
        xf, wqkv, bqkv, nullptr, qkv, MROWS, 3 * DMODEL, DMODEL);

    // attention
    attn_fused_kernel<<<dim3(8, BHDIM), blk, AT_SMEM>>>(
        qkv, qkv + SLAB_ELEMS, qkv + 2 * SLAB_ELEMS, rel, pm, avf);

    // O projection
    dim3 gO(DMODEL / TBN, MROWS / TBM);
    tgemm_kernel<false, 0><<<gO, blk, TG_SMEM>>>(
        avf, wo, bo, attp, nullptr, MROWS, DMODEL, DMODEL);

    // residual + LN (+ fp16 out)
    add_ln_kernel<true><<<MROWS, blk>>>(attp, x, attout, aof);

    // FFN
    dim3 g1(FFDIM / TBN, MROWS / TBM);
    tgemm_kernel<true, 1><<<g1, blk, TG_SMEM>>>(
        aof, w1, b1, nullptr, h1f, MROWS, FFDIM, DMODEL);
    dim3 g2(DMODEL / TBN, MROWS / TBM);
    tgemm_kernel<false, 0><<<g2, blk, TG_SMEM>>>(
        h1f, w2, b2, ff, nullptr, MROWS, DMODEL, FFDIM);

    // final residual + LN
    add_ln_kernel<false><<<MROWS, blk>>>(ff, attout, out, nullptr);
}

// round 14
// speedup vs baseline: 7.3553x; 1.0091x over previous
#include <cuda_runtime.h>
#include <cuda_fp16.h>
#include <math.h>
#include <stdint.h>

// ---------------------------------------------------------------------------
// EncoderBlock: B=4, L=1024, D=1024, F=4096, H=16, dh=64
// Round 14: attention MUFU fix — ex2.approx.f16x2 (half the MUFU ops) and
// row-sums computed by an extra ones-operand MMA (no scalar sum pass).
// Dense GEMMs unchanged from R13.
// ---------------------------------------------------------------------------

#define LSEQ 1024
#define DMODEL 1024
#define BATCH 4
#define NHEAD 16
#define DHEAD 64
#define FFDIM 4096
#define BHDIM 64
#define MROWS 4096
#define LOG2E 1.4426950408889634f
#define SLAB_ELEMS (MROWS * DMODEL)
#define ONES_H2 0x3C003C00u

// ---- fp32 scratch ----------------------------------------------------------
__device__ float g_attp[BATCH * LSEQ * DMODEL];
__device__ float g_attout[BATCH * LSEQ * DMODEL];
__device__ float g_ff[BATCH * LSEQ * DMODEL];
__device__ float g_bqkv[3 * DMODEL];

// ---- fp16 scratch -----------------------------------------------------------
__device__ __half g_xf[SLAB_ELEMS];
__device__ __half g_wqkv[3 * DMODEL * DMODEL];
__device__ __half g_wo[DMODEL * DMODEL];
__device__ __half g_w1[FFDIM * DMODEL];
__device__ __half g_w2[DMODEL * FFDIM];
__device__ __half g_qkv[3 * SLAB_ELEMS];
__device__ __half g_avf[SLAB_ELEMS];
__device__ __half g_aof[SLAB_ELEMS];
__device__ __half g_h1f[(size_t)MROWS * FFDIM];

// ============================================================================
// helpers
// ============================================================================
__device__ __forceinline__ uint32_t smem_u32(const void* p) {
    uint32_t a;
    asm("{ .reg .u64 t; cvta.to.shared.u64 t, %1; cvt.u32.u64 %0, t; }"
        : "=r"(a) : "l"(p));
    return a;
}
__device__ __forceinline__ void cp16(uint32_t dst, const void* src) {
    asm volatile("cp.async.cg.shared.global [%0], [%1], 16;" :: "r"(dst), "l"(src));
}
__device__ __forceinline__ void ldsm_x4(uint32_t& r0, uint32_t& r1,
                                        uint32_t& r2, uint32_t& r3, uint32_t a) {
    asm volatile("ldmatrix.sync.aligned.m8n8.x4.shared.b16 {%0,%1,%2,%3}, [%4];"
                 : "=r"(r0), "=r"(r1), "=r"(r2), "=r"(r3) : "r"(a));
}
__device__ __forceinline__ void ldsm_x4t(uint32_t& r0, uint32_t& r1,
                                         uint32_t& r2, uint32_t& r3, uint32_t a) {
    asm volatile("ldmatrix.sync.aligned.m8n8.x4.trans.shared.b16 {%0,%1,%2,%3}, [%4];"
                 : "=r"(r0), "=r"(r1), "=r"(r2), "=r"(r3) : "r"(a));
}
__device__ __forceinline__ void mma_f16(float* c, const uint32_t* a, const uint32_t* b) {
    asm volatile(
        "mma.sync.aligned.m16n8k16.row.col.f32.f16.f16.f32 "
        "{%0,%1,%2,%3}, {%4,%5,%6,%7}, {%8,%9}, {%0,%1,%2,%3};"
        : "+f"(c[0]), "+f"(c[1]), "+f"(c[2]), "+f"(c[3])
        : "r"(a[0]), "r"(a[1]), "r"(a[2]), "r"(a[3]), "r"(b[0]), "r"(b[1]));
}
__device__ __forceinline__ uint32_t cvt_h2(float lo, float hi) {
    uint32_t r;
    asm("cvt.rn.f16x2.f32 %0, %1, %2;" : "=r"(r) : "f"(hi), "f"(lo));
    return r;
}
__device__ __forceinline__ uint32_t ex2_h2(uint32_t x) {
    uint32_t r;
    asm("ex2.approx.f16x2 %0, %1;" : "=r"(r) : "r"(x));
    return r;
}

// 128-byte-row swizzle (conflict-free ldmatrix)
__device__ __forceinline__ uint32_t swz128(int r, int c) {
    return (uint32_t)(r * 128 + ((c ^ (r & 7)) << 4));
}

// ============================================================================
// convert fp32 -> fp16 (generic)
// ============================================================================
__global__ void __launch_bounds__(256) cvt16_kernel(
    const float* __restrict__ X, __half* __restrict__ F, int n4)
{
    int i = blockIdx.x * 256 + threadIdx.x;
    if (i >= n4) return;
    float4 v = ((const float4*)X)[i];
    ((uint2*)F)[i] = make_uint2(cvt_h2(v.x, v.y), cvt_h2(v.z, v.w));
}

// ============================================================================
// convert ALL weights -> fp16; pack qkv bias.
// ============================================================================
#define SEG_QKV (3 * DMODEL * DMODEL / 4)
#define SEG_WO  (DMODEL * DMODEL / 4)
#define SEG_W1  (FFDIM * DMODEL / 4)
#define SEG_W2  (DMODEL * FFDIM / 4)
#define SEG_TOTAL (SEG_QKV + SEG_WO + SEG_W1 + SEG_W2)

__global__ void __launch_bounds__(256) cvtw_all_kernel(
    const float* __restrict__ Wq, const float* __restrict__ Wk,
    const float* __restrict__ Wv, const float* __restrict__ Wo,
    const float* __restrict__ W1, const float* __restrict__ W2,
    const float* __restrict__ bq, const float* __restrict__ bk,
    const float* __restrict__ bv,
    __half* __restrict__ QKVW, __half* __restrict__ WOF,
    __half* __restrict__ W1F,  __half* __restrict__ W2F,
    float* __restrict__ bpack)
{
    int i = blockIdx.x * 256 + threadIdx.x;
    if (i < 3 * DMODEL) {
        float b = (i < DMODEL) ? bq[i] : (i < 2 * DMODEL) ? bk[i - DMODEL]
                                                          : bv[i - 2 * DMODEL];
        bpack[i] = b;
    }
    if (i >= SEG_TOTAL) return;

    const float* src;
    __half* F;
    int off;
    if (i < SEG_QKV) {
        const int n4m = DMODEL * DMODEL / 4;
        int m = i / n4m;
        off = i - m * n4m;
        src = (m == 0) ? Wq : (m == 1) ? Wk : Wv;
        F = QKVW + (size_t)m * DMODEL * DMODEL;
    } else if (i < SEG_QKV + SEG_WO) {
        off = i - SEG_QKV; src = Wo; F = WOF;
    } else if (i < SEG_QKV + SEG_WO + SEG_W1) {
        off = i - SEG_QKV - SEG_WO; src = W1; F = W1F;
    } else {
        off = i - SEG_QKV - SEG_WO - SEG_W1; src = W2; F = W2F;
    }

    float4 v = ((const float4*)src)[off];
    ((uint2*)F)[off] = make_uint2(cvt_h2(v.x, v.y), cvt_h2(v.z, v.w));
}

// ============================================================================
// fp16 GEMM (unchanged from R13)
// ============================================================================
#define TBM 128
#define TBN 128
#define TBK 64
#define STG_BYTES 32768
#define TG_SMEM (3 * STG_BYTES)

__device__ __forceinline__ void tg_load_stage(
    uint32_t sbuf, int t,
    const __half* __restrict__ Af, const __half* __restrict__ Bf,
    int rowBase, int colBase, int k0, int K)
{
#pragma unroll
    for (int j = 0; j < 8; j++) {
        int i   = j * 256 + t;
        int arr = i >> 10;
        int idx = i & 1023;
        int r   = idx >> 3;
        int ch  = idx & 7;
        const __half* base = arr ? Bf : Af;
        int gr = (arr ? colBase : rowBase) + r;
        cp16(sbuf + arr * 16384 + swz128(r, ch),
             base + (size_t)gr * K + k0 + ch * 8);
    }
    asm volatile("cp.async.commit_group;" ::: "memory");
}

template <bool RELU, int OUT>
__global__ void __launch_bounds__(256, 2) tgemm_kernel(
    const __half* __restrict__ Af, const __half* __restrict__ Bf,
    const float* __restrict__ bias, float* __restrict__ C,
    __half* __restrict__ F16O,
    int M, int N, int K)
{
    extern __shared__ __align__(16) char smem[];
    uint32_t sb = smem_u32(smem);
    const int t = threadIdx.x;
    const int w = t >> 5, lane = t & 31;
    const int wm = w >> 2;
    const int wn = w & 3;
    const int rowBase = blockIdx.y * TBM;
    const int colBase = blockIdx.x * TBN;
    const int KT = K / TBK;

    float acc[4][4][4];
#pragma unroll
    for (int mt = 0; mt < 4; mt++)
#pragma unroll
        for (int nt = 0; nt < 4; nt++)
#pragma unroll
            for (int e = 0; e < 4; e++) acc[mt][nt][e] = 0.f;

    tg_load_stage(sb,                 t, Af, Bf, rowBase, colBase, 0 * TBK, K);
    tg_load_stage(sb + 1 * STG_BYTES, t, Af, Bf, rowBase, colBase, 1 * TBK, K);

    int stage = 0;
    for (int kt = 0; kt < KT; kt++) {
        if (kt + 1 < KT)
            asm volatile("cp.async.wait_group 1;" ::: "memory");
        else
            asm volatile("cp.async.wait_group 0;" ::: "memory");
        __syncthreads();

        if (kt + 2 < KT) {
            int ps = stage + 2; if (ps >= 3) ps -= 3;
            tg_load_stage(sb + ps * STG_BYTES, t,
                          Af, Bf, rowBase, colBase, (kt + 2) * TBK, K);
        }

        uint32_t sbase = sb + stage * STG_BYTES;
#pragma unroll
        for (int ks = 0; ks < 4; ks++) {
            uint32_t ah[4][4];
            const int arow0  = wm * 64 + (lane & 15);
            const int achunk = ks * 2 + (lane >> 4);
#pragma unroll
            for (int mt = 0; mt < 4; mt++) {
                uint32_t off = swz128(arow0 + mt * 16, achunk);
                ldsm_x4(ah[mt][0], ah[mt][1], ah[mt][2], ah[mt][3], sbase + off);
            }
            const int brow = wn * 32 + ((lane >> 4) << 3) + (lane & 7);
            const int bch  = ks * 2 + ((lane >> 3) & 1);
#pragma unroll
            for (int np = 0; np < 2; np++) {
                uint32_t b2[4];
                uint32_t off = swz128(brow + np * 16, bch);
                ldsm_x4(b2[0], b2[1], b2[2], b2[3], sbase + 16384 + off);
#pragma unroll
                for (int mt = 0; mt < 4; mt++) {
                    mma_f16(acc[mt][2 * np],     ah[mt], b2);
                    mma_f16(acc[mt][2 * np + 1], ah[mt], b2 + 2);
                }
            }
        }
        stage++; if (stage == 3) stage = 0;
    }

#pragma unroll
    for (int nt = 0; nt < 4; nt++) {
        int c = colBase + wn * 32 + nt * 8 + (lane & 3) * 2;
        float b0 = __ldg(&bias[c]), b1 = __ldg(&bias[c + 1]);
#pragma unroll
        for (int mt = 0; mt < 4; mt++) {
            int r0 = rowBase + wm * 64 + mt * 16 + (lane >> 2);
            float v0 = acc[mt][nt][0] + b0, v1 = acc[mt][nt][1] + b1;
            float v2 = acc[mt][nt][2] + b0, v3 = acc[mt][nt][3] + b1;
            if (RELU) {
                v0 = fmaxf(v0, 0.f); v1 = fmaxf(v1, 0.f);
                v2 = fmaxf(v2, 0.f); v3 = fmaxf(v3, 0.f);
            }
            if (OUT == 0) {
                *(float2*)(C + (size_t)r0 * N + c)       = make_float2(v0, v1);
                *(float2*)(C + (size_t)(r0 + 8) * N + c) = make_float2(v2, v3);
            } else if (OUT == 1) {
                *(uint32_t*)(F16O + (size_t)r0 * N + c)       = cvt_h2(v0, v1);
                *(uint32_t*)(F16O + (size_t)(r0 + 8) * N + c) = cvt_h2(v2, v3);
            } else {
                int sel = c >> 10, cc = c & 1023;
                __half* dst = F16O + (size_t)sel * SLAB_ELEMS;
                *(uint32_t*)(dst + (size_t)r0 * DMODEL + cc)       = cvt_h2(v0, v1);
                *(uint32_t*)(dst + (size_t)(r0 + 8) * DMODEL + cc) = cvt_h2(v2, v3);
            }
        }
    }
}

// ============================================================================
// T5 relative-position bucket for displacement d
// ============================================================================
__device__ __forceinline__ int rel_bucket_d(int d)
{
    int ret = (d < 0) ? NHEAD : 0;
    int n   = abs(d);
    int b;
    if (n < 8) b = n;
    else {
        int j = (31 - __clz(n * n)) - 6;
        j = min(j, 7);
        b = 8 + j;
    }
    return ret + b;
}

// ============================================================================
// Fused flash attention — f16x2 ex2 + ones-MMA row sums.
// ============================================================================
#define AT_Q    0
#define AT_KV   16384
#define AT_LM   81920
#define AT_BD   86016
#define AT_SMEM 94208

__device__ __forceinline__ void at_load_kv(
    uint32_t kvbase, int t, size_t slab, int kt,
    const __half* __restrict__ KF, const __half* __restrict__ VF)
{
    size_t gb = slab + (size_t)kt * 128 * DHEAD;
    for (int i = t; i < 1024; i += 256) {
        int r = i >> 3, c = i & 7;
        uint32_t off = swz128(r, c);
        size_t g = gb + r * DHEAD + c * 8;
        cp16(kvbase + off,         KF + g);
        cp16(kvbase + 16384 + off, VF + g);
    }
    asm volatile("cp.async.commit_group;" ::: "memory");
}

__global__ void __launch_bounds__(256, 1) attn_fused_kernel(
    const __half* __restrict__ QF,
    const __half* __restrict__ KF, const __half* __restrict__ VF,
    const float* __restrict__ rel, const int* __restrict__ pm,
    __half* __restrict__ OF)
{
    extern __shared__ __align__(16) char smem[];
    uint32_t sb = smem_u32(smem);
    float* lm_s = (float*)(smem + AT_LM);
    float* bd_s = (float*)(smem + AT_BD);

    const int t = threadIdx.x, w = t >> 5, lane = t & 31;
    const int qt = blockIdx.x, bh = blockIdx.y;
    const int h = bh & (NHEAD - 1), b = bh >> 4;
    const size_t slab = (size_t)bh * (LSEQ * DHEAD);

    for (int i = t; i < LSEQ; i += 256)
        lm_s[i] = log2f((float)pm[b * LSEQ + i]);
    for (int i = t; i < 2047; i += 256)
        bd_s[i] = rel[rel_bucket_d(i - 1023) * NHEAD + h] * LOG2E;

    {
        size_t qbase = slab + (size_t)qt * 128 * DHEAD;
        for (int i = t; i < 1024; i += 256) {
            int r = i >> 3, c = i & 7;
            cp16(sb + AT_Q + swz128(r, c), QF + qbase + r * DHEAD + c * 8);
        }
        at_load_kv(sb + AT_KV, t, slab, 0, KF, VF);
        at_load_kv(sb + AT_KV + 32768, t, slab, 1, KF, VF);
        asm volatile("cp.async.wait_group 1;" ::: "memory");
    }
    __syncthreads();

    uint32_t qf[4][4];
    {
        int r = w * 16 + (lane & 15);
#pragma unroll
        for (int ks = 0; ks < 4; ks++) {
            int c = ks * 2 + (lane >> 4);
            ldsm_x4(qf[ks][0], qf[ks][1], qf[ks][2], qf[ks][3],
                    sb + AT_Q + swz128(r, c));
        }
    }

    float O[8][4];
#pragma unroll
    for (int nt = 0; nt < 8; nt++)
#pragma unroll
        for (int e = 0; e < 4; e++) O[nt][e] = 0.f;
    float Lc[4] = {0.f, 0.f, 0.f, 0.f};          // row-sum accumulator (ones MMA)
    float m0 = -3.0e38f, m1 = -3.0e38f;

    const uint32_t onesb[2] = {ONES_H2, ONES_H2};
    const int r0 = qt * 128 + w * 16 + (lane >> 2);
    const int r1 = r0 + 8;

    for (int kt = 0; kt < 8; kt++) {
        if (kt > 0) {
            if (kt < 7)
                asm volatile("cp.async.wait_group 1;" ::: "memory");
            else
                asm volatile("cp.async.wait_group 0;" ::: "memory");
            __syncthreads();
        }
        uint32_t kv = sb + AT_KV + (kt & 1) * 32768;

        float S[16][4];
#pragma unroll
        for (int j = 0; j < 16; j++)
#pragma unroll
            for (int e = 0; e < 4; e++) S[j][e] = 0.f;

        // S = Q K^T
#pragma unroll
        for (int ks = 0; ks < 4; ks++) {
            const int krow = ((lane >> 4) << 3) + (lane & 7);
            const int kch  = ks * 2 + ((lane >> 3) & 1);
#pragma unroll
            for (int jq = 0; jq < 4; jq++) {
                uint32_t kb0[4], kb1[4];
                uint32_t off0 = swz128((2 * jq) * 16 + krow, kch);
                uint32_t off1 = swz128((2 * jq + 1) * 16 + krow, kch);
                ldsm_x4(kb0[0], kb0[1], kb0[2], kb0[3], kv + off0);
                ldsm_x4(kb1[0], kb1[1], kb1[2], kb1[3], kv + off1);
                mma_f16(S[4 * jq + 0], qf[ks], kb0);
                mma_f16(S[4 * jq + 1], qf[ks], kb0 + 2);
                mma_f16(S[4 * jq + 2], qf[ks], kb1);
                mma_f16(S[4 * jq + 3], qf[ks], kb1 + 2);
            }
        }

        // fused: bias (log2 domain) + tile max
        const int ktbase = kt * 128;
        float tm0 = -3.0e38f, tm1 = -3.0e38f;
#pragma unroll
        for (int j = 0; j < 16; j++) {
            int c = ktbase + j * 8 + (lane & 3) * 2;
            float t00 = bd_s[c - r0 + 1023] + lm_s[c];
            float t01 = bd_s[c + 1 - r0 + 1023] + lm_s[c + 1];
            float t10 = bd_s[c - r1 + 1023] + lm_s[c];
            float t11 = bd_s[c + 1 - r1 + 1023] + lm_s[c + 1];
            S[j][0] = fmaf(S[j][0], LOG2E, t00);
            S[j][1] = fmaf(S[j][1], LOG2E, t01);
            S[j][2] = fmaf(S[j][2], LOG2E, t10);
            S[j][3] = fmaf(S[j][3], LOG2E, t11);
            tm0 = fmaxf(tm0, fmaxf(S[j][0], S[j][1]));
            tm1 = fmaxf(tm1, fmaxf(S[j][2], S[j][3]));
        }
        tm0 = fmaxf(tm0, __shfl_xor_sync(0xffffffffu, tm0, 1));
        tm0 = fmaxf(tm0, __shfl_xor_sync(0xffffffffu, tm0, 2));
        tm1 = fmaxf(tm1, __shfl_xor_sync(0xffffffffu, tm1, 1));
        tm1 = fmaxf(tm1, __shfl_xor_sync(0xffffffffu, tm1, 2));
        float mn0 = fmaxf(m0, tm0), mn1 = fmaxf(m1, tm1);
        float a0 = exp2f(m0 - mn0), a1 = exp2f(m1 - mn1);
        m0 = mn0; m1 = mn1;

        // rescale O and L accumulators
#pragma unroll
        for (int nt = 0; nt < 8; nt++) {
            O[nt][0] *= a0; O[nt][1] *= a0;
            O[nt][2] *= a1; O[nt][3] *= a1;
        }
        Lc[0] *= a0; Lc[1] *= a0; Lc[2] *= a1; Lc[3] *= a1;

        // P = exp2(S - m) in f16x2 (one MUFU per pair); O += P@V; L += P@1
#pragma unroll
        for (int kk = 0; kk < 8; kk++) {
            float* p0 = S[2 * kk];
            float* p1 = S[2 * kk + 1];
            uint32_t ph[4];
            ph[0] = ex2_h2(cvt_h2(p0[0] - mn0, p0[1] - mn0));
            ph[1] = ex2_h2(cvt_h2(p0[2] - mn1, p0[3] - mn1));
            ph[2] = ex2_h2(cvt_h2(p1[0] - mn0, p1[1] - mn0));
            ph[3] = ex2_h2(cvt_h2(p1[2] - mn1, p1[3] - mn1));
            const int vrow = kk * 16 + (lane & 15);
            const int vcp  = (lane >> 4) & 1;
#pragma unroll
            for (int np = 0; np < 4; np++) {
                uint32_t vb[4];
                uint32_t off = swz128(vrow, np * 2 + vcp);
                ldsm_x4t(vb[0], vb[1], vb[2], vb[3], kv + 16384 + off);
                mma_f16(O[2 * np],     ph, vb);
                mma_f16(O[2 * np + 1], ph, vb + 2);
            }
            mma_f16(Lc, ph, onesb);     // row sums via tensor core
        }

        __syncthreads();
        if (kt + 2 < 8)
            at_load_kv(sb + AT_KV + (kt & 1) * 32768, t, slab, kt + 2, KF, VF);
    }

    float inv0 = 1.f / Lc[0], inv1 = 1.f / Lc[2];
    size_t ob0 = slab + (size_t)(qt * 128 + w * 16 + (lane >> 2)) * DHEAD;
    size_t ob1 = ob0 + 8 * DHEAD;
#pragma unroll
    for (int nt = 0; nt < 8; nt++) {
        int c = nt * 8 + (lane & 3) * 2;
        *(uint32_t*)(OF + ob0 + c) = cvt_h2(O[nt][0] * inv0, O[nt][1] * inv0);
        *(uint32_t*)(OF + ob1 + c) = cvt_h2(O[nt][2] * inv1, O[nt][3] * inv1);
    }
}

// ============================================================================
// out = LayerNorm(A + B); optional fp16 side output
// ============================================================================
template <bool SPLIT>
__global__ void __launch_bounds__(256) add_ln_kernel(
    const float* __restrict__ A, const float* __restrict__ B,
    float* __restrict__ out, __half* __restrict__ OF)
{
    __shared__ float sh[8];
    const size_t row = blockIdx.x;
    const int t = threadIdx.x;

    float4 a = ((const float4*)(A + row * DMODEL))[t];
    float4 b = ((const float4*)(B + row * DMODEL))[t];
    float4 x;
    x.x = a.x + b.x; x.y = a.y + b.y; x.z = a.z + b.z; x.w = a.w + b.w;

    float s = x.x + x.y + x.z + x.w;
#pragma unroll
    for (int o = 16; o; o >>= 1) s += __shfl_xor_sync(0xffffffffu, s, o);
    if ((t & 31) == 0) sh[t >> 5] = s;
    __syncthreads();
    float tot = sh[0];
#pragma unroll
    for (int i = 1; i < 8; i++) tot += sh[i];
    __syncthreads();
    float mean = tot * (1.f / DMODEL);

    float dx = x.x - mean, dy = x.y - mean, dz = x.z - mean, dw = x.w - mean;
    float s2 = dx * dx + dy * dy + dz * dz + dw * dw;
#pragma unroll
    for (int o = 16; o; o >>= 1) s2 += __shfl_xor_sync(0xffffffffu, s2, o);
    if ((t & 31) == 0) sh[t >> 5] = s2;
    __syncthreads();
    float tot2 = sh[0];
#pragma unroll
    for (int i = 1; i < 8; i++) tot2 += sh[i];
    float inv = rsqrtf(tot2 * (1.f / DMODEL));

    float4 o;
    o.x = dx * inv; o.y = dy * inv; o.z = dz * inv; o.w = dw * inv;
    ((float4*)(out + row * DMODEL))[t] = o;

    if (SPLIT) {
        size_t base = row * DMODEL + t * 4;
        *(uint32_t*)(OF + base)     = cvt_h2(o.x, o.y);
        *(uint32_t*)(OF + base + 2) = cvt_h2(o.z, o.w);
    }
}

// ============================================================================
// Launch sequence
// ============================================================================
extern "C" void kernel_launch(void* const* d_in, const int* in_sizes, int n_in,
                              void* d_out, int out_size)
{
    const float* x   = (const float*)d_in[0];
    const int*   pm  = (const int*)  d_in[1];
    const float* Wq  = (const float*)d_in[2];
    const float* bq  = (const float*)d_in[3];
    const float* Wk  = (const float*)d_in[4];
    const float* bk  = (const float*)d_in[5];
    const float* Wv  = (const float*)d_in[6];
    const float* bv  = (const float*)d_in[7];
    const float* Wo  = (const float*)d_in[8];
    const float* bo  = (const float*)d_in[9];
    const float* rel = (const float*)d_in[10];
    const float* W1  = (const float*)d_in[11];
    const float* b1  = (const float*)d_in[12];
    const float* W2  = (const float*)d_in[13];
    const float* b2  = (const float*)d_in[14];
    float* out = (float*)d_out;

    float *attp, *attout, *ff, *bqkv;
    cudaGetSymbolAddress((void**)&attp,   g_attp);
    cudaGetSymbolAddress((void**)&attout, g_attout);
    cudaGetSymbolAddress((void**)&ff,     g_ff);
    cudaGetSymbolAddress((void**)&bqkv,   g_bqkv);

    __half *xf, *wqkv, *wo, *w1, *w2, *qkv, *avf, *aof, *h1f;
    cudaGetSymbolAddress((void**)&xf,   g_xf);
    cudaGetSymbolAddress((void**)&wqkv, g_wqkv);
    cudaGetSymbolAddress((void**)&wo,   g_wo);
    cudaGetSymbolAddress((void**)&w1,   g_w1);
    cudaGetSymbolAddress((void**)&w2,   g_w2);
    cudaGetSymbolAddress((void**)&qkv,  g_qkv);
    cudaGetSymbolAddress((void**)&avf,  g_avf);
    cudaGetSymbolAddress((void**)&aof,  g_aof);
    cudaGetSymbolAddress((void**)&h1f,  g_h1f);

    static bool attr_done = false;
    if (!attr_done) {
        cudaFuncSetAttribute(tgemm_kernel<false, 0>,
                             cudaFuncAttributeMaxDynamicSharedMemorySize, TG_SMEM);
        cudaFuncSetAttribute(tgemm_kernel<false, 2>,
                             cudaFuncAttributeMaxDynamicSharedMemorySize, TG_SMEM);
        cudaFuncSetAttribute(tgemm_kernel<true, 1>,
                             cudaFuncAttributeMaxDynamicSharedMemorySize, TG_SMEM);
        cudaFuncSetAttribute(attn_fused_kernel,
                             cudaFuncAttributeMaxDynamicSharedMemorySize, AT_SMEM);
        attr_done = true;
    }

    dim3 blk(256);

    cvt16_kernel<<<(MROWS * DMODEL / 4 + 255) / 256, blk>>>(
        x, xf, MROWS * DMODEL / 4);
    cvtw_all_kernel<<<(SEG_TOTAL + 255) / 256, blk>>>(
        Wq, Wk, Wv, Wo, W1, W2, bq, bk, bv, wqkv, wo, w1, w2, bqkv);

    dim3 gqkv(3 * DMODEL / TBN, MROWS / TBM);
    tgemm_kernel<false, 2><<<gqkv, blk, TG_SMEM>>>(
        xf, wqkv, bqkv, nullptr, qkv, MROWS, 3 * DMODEL, DMODEL);

    attn_fused_kernel<<<dim3(8, BHDIM), blk, AT_SMEM>>>(
        qkv, qkv + SLAB_ELEMS, qkv + 2 * SLAB_ELEMS, rel, pm, avf);

    dim3 gO(DMODEL / TBN, MROWS / TBM);
    tgemm_kernel<false, 0><<<gO, blk, TG_SMEM>>>(
        avf, wo, bo, attp, nullptr, MROWS, DMODEL, DMODEL);

    add_ln_kernel<true><<<MROWS, blk>>>(attp, x, attout, aof);

    dim3 g1(FFDIM / TBN, MROWS / TBM);
    tgemm_kernel<true, 1><<<g1, blk, TG_SMEM>>>(
        aof, w1, b1, nullptr, h1f, MROWS, FFDIM, DMODEL);
    dim3 g2(DMODEL / TBN, MROWS / TBM);
    tgemm_kernel<false, 0><<<g2, blk, TG_SMEM>>>(
        h1f, w2, b2, ff, nullptr, MROWS, DMODEL, FFDIM);

    add_ln_kernel<false><<<MROWS, blk>>>(ff, attout, out, nullptr);
}

// round 15
// speedup vs baseline: 7.4300x; 1.0102x over previous
#include <cuda_runtime.h>
#include <cuda_fp16.h>
#include <math.h>
#include <stdint.h>

// ---------------------------------------------------------------------------
// EncoderBlock: B=4, L=1024, D=1024, F=4096, H=16, dh=64
// Round 15: attention occupancy 2 blocks/SM (64-key tiles, S[8][4],
// 60KB smem, <=128 regs). Dense GEMMs unchanged from R14.
// ---------------------------------------------------------------------------

#define LSEQ 1024
#define DMODEL 1024
#define BATCH 4
#define NHEAD 16
#define DHEAD 64
#define FFDIM 4096
#define BHDIM 64
#define MROWS 4096
#define LOG2E 1.4426950408889634f
#define SLAB_ELEMS (MROWS * DMODEL)
#define ONES_H2 0x3C003C00u

// ---- fp32 scratch ----------------------------------------------------------
__device__ float g_attp[BATCH * LSEQ * DMODEL];
__device__ float g_attout[BATCH * LSEQ * DMODEL];
__device__ float g_ff[BATCH * LSEQ * DMODEL];
__device__ float g_bqkv[3 * DMODEL];

// ---- fp16 scratch -----------------------------------------------------------
__device__ __half g_xf[SLAB_ELEMS];
__device__ __half g_wqkv[3 * DMODEL * DMODEL];
__device__ __half g_wo[DMODEL * DMODEL];
__device__ __half g_w1[FFDIM * DMODEL];
__device__ __half g_w2[DMODEL * FFDIM];
__device__ __half g_qkv[3 * SLAB_ELEMS];
__device__ __half g_avf[SLAB_ELEMS];
__device__ __half g_aof[SLAB_ELEMS];
__device__ __half g_h1f[(size_t)MROWS * FFDIM];

// ============================================================================
// helpers
// ============================================================================
__device__ __forceinline__ uint32_t smem_u32(const void* p) {
    uint32_t a;
    asm("{ .reg .u64 t; cvta.to.shared.u64 t, %1; cvt.u32.u64 %0, t; }"
        : "=r"(a) : "l"(p));
    return a;
}
__device__ __forceinline__ void cp16(uint32_t dst, const void* src) {
    asm volatile("cp.async.cg.shared.global [%0], [%1], 16;" :: "r"(dst), "l"(src));
}
__device__ __forceinline__ void ldsm_x4(uint32_t& r0, uint32_t& r1,
                                        uint32_t& r2, uint32_t& r3, uint32_t a) {
    asm volatile("ldmatrix.sync.aligned.m8n8.x4.shared.b16 {%0,%1,%2,%3}, [%4];"
                 : "=r"(r0), "=r"(r1), "=r"(r2), "=r"(r3) : "r"(a));
}
__device__ __forceinline__ void ldsm_x4t(uint32_t& r0, uint32_t& r1,
                                         uint32_t& r2, uint32_t& r3, uint32_t a) {
    asm volatile("ldmatrix.sync.aligned.m8n8.x4.trans.shared.b16 {%0,%1,%2,%3}, [%4];"
                 : "=r"(r0), "=r"(r1), "=r"(r2), "=r"(r3) : "r"(a));
}
__device__ __forceinline__ void mma_f16(float* c, const uint32_t* a, const uint32_t* b) {
    asm volatile(
        "mma.sync.aligned.m16n8k16.row.col.f32.f16.f16.f32 "
        "{%0,%1,%2,%3}, {%4,%5,%6,%7}, {%8,%9}, {%0,%1,%2,%3};"
        : "+f"(c[0]), "+f"(c[1]), "+f"(c[2]), "+f"(c[3])
        : "r"(a[0]), "r"(a[1]), "r"(a[2]), "r"(a[3]), "r"(b[0]), "r"(b[1]));
}
__device__ __forceinline__ uint32_t cvt_h2(float lo, float hi) {
    uint32_t r;
    asm("cvt.rn.f16x2.f32 %0, %1, %2;" : "=r"(r) : "f"(hi), "f"(lo));
    return r;
}
__device__ __forceinline__ uint32_t ex2_h2(uint32_t x) {
    uint32_t r;
    asm("ex2.approx.f16x2 %0, %1;" : "=r"(r) : "r"(x));
    return r;
}

// 128-byte-row swizzle (conflict-free ldmatrix)
__device__ __forceinline__ uint32_t swz128(int r, int c) {
    return (uint32_t)(r * 128 + ((c ^ (r & 7)) << 4));
}

// ============================================================================
// convert fp32 -> fp16 (generic)
// ============================================================================
__global__ void __launch_bounds__(256) cvt16_kernel(
    const float* __restrict__ X, __half* __restrict__ F, int n4)
{
    int i = blockIdx.x * 256 + threadIdx.x;
    if (i >= n4) return;
    float4 v = ((const float4*)X)[i];
    ((uint2*)F)[i] = make_uint2(cvt_h2(v.x, v.y), cvt_h2(v.z, v.w));
}

// ============================================================================
// convert ALL weights -> fp16; pack qkv bias.
// ============================================================================
#define SEG_QKV (3 * DMODEL * DMODEL / 4)
#define SEG_WO  (DMODEL * DMODEL / 4)
#define SEG_W1  (FFDIM * DMODEL / 4)
#define SEG_W2  (DMODEL * FFDIM / 4)
#define SEG_TOTAL (SEG_QKV + SEG_WO + SEG_W1 + SEG_W2)

__global__ void __launch_bounds__(256) cvtw_all_kernel(
    const float* __restrict__ Wq, const float* __restrict__ Wk,
    const float* __restrict__ Wv, const float* __restrict__ Wo,
    const float* __restrict__ W1, const float* __restrict__ W2,
    const float* __restrict__ bq, const float* __restrict__ bk,
    const float* __restrict__ bv,
    __half* __restrict__ QKVW, __half* __restrict__ WOF,
    __half* __restrict__ W1F,  __half* __restrict__ W2F,
    float* __restrict__ bpack)
{
    int i = blockIdx.x * 256 + threadIdx.x;
    if (i < 3 * DMODEL) {
        float b = (i < DMODEL) ? bq[i] : (i < 2 * DMODEL) ? bk[i - DMODEL]
                                                          : bv[i - 2 * DMODEL];
        bpack[i] = b;
    }
    if (i >= SEG_TOTAL) return;

    const float* src;
    __half* F;
    int off;
    if (i < SEG_QKV) {
        const int n4m = DMODEL * DMODEL / 4;
        int m = i / n4m;
        off = i - m * n4m;
        src = (m == 0) ? Wq : (m == 1) ? Wk : Wv;
        F = QKVW + (size_t)m * DMODEL * DMODEL;
    } else if (i < SEG_QKV + SEG_WO) {
        off = i - SEG_QKV; src = Wo; F = WOF;
    } else if (i < SEG_QKV + SEG_WO + SEG_W1) {
        off = i - SEG_QKV - SEG_WO; src = W1; F = W1F;
    } else {
        off = i - SEG_QKV - SEG_WO - SEG_W1; src = W2; F = W2F;
    }

    float4 v = ((const float4*)src)[off];
    ((uint2*)F)[off] = make_uint2(cvt_h2(v.x, v.y), cvt_h2(v.z, v.w));
}

// ============================================================================
// fp16 GEMM (unchanged from R13/R14)
// ============================================================================
#define TBM 128
#define TBN 128
#define TBK 64
#define STG_BYTES 32768
#define TG_SMEM (3 * STG_BYTES)

__device__ __forceinline__ void tg_load_stage(
    uint32_t sbuf, int t,
    const __half* __restrict__ Af, const __half* __restrict__ Bf,
    int rowBase, int colBase, int k0, int K)
{
#pragma unroll
    for (int j = 0; j < 8; j++) {
        int i   = j * 256 + t;
        int arr = i >> 10;
        int idx = i & 1023;
        int r   = idx >> 3;
        int ch  = idx & 7;
        const __half* base = arr ? Bf : Af;
        int gr = (arr ? colBase : rowBase) + r;
        cp16(sbuf + arr * 16384 + swz128(r, ch),
             base + (size_t)gr * K + k0 + ch * 8);
    }
    asm volatile("cp.async.commit_group;" ::: "memory");
}

template <bool RELU, int OUT>
__global__ void __launch_bounds__(256, 2) tgemm_kernel(
    const __half* __restrict__ Af, const __half* __restrict__ Bf,
    const float* __restrict__ bias, float* __restrict__ C,
    __half* __restrict__ F16O,
    int M, int N, int K)
{
    extern __shared__ __align__(16) char smem[];
    uint32_t sb = smem_u32(smem);
    const int t = threadIdx.x;
    const int w = t >> 5, lane = t & 31;
    const int wm = w >> 2;
    const int wn = w & 3;
    const int rowBase = blockIdx.y * TBM;
    const int colBase = blockIdx.x * TBN;
    const int KT = K / TBK;

    float acc[4][4][4];
#pragma unroll
    for (int mt = 0; mt < 4; mt++)
#pragma unroll
        for (int nt = 0; nt < 4; nt++)
#pragma unroll
            for (int e = 0; e < 4; e++) acc[mt][nt][e] = 0.f;

    tg_load_stage(sb,                 t, Af, Bf, rowBase, colBase, 0 * TBK, K);
    tg_load_stage(sb + 1 * STG_BYTES, t, Af, Bf, rowBase, colBase, 1 * TBK, K);

    int stage = 0;
    for (int kt = 0; kt < KT; kt++) {
        if (kt + 1 < KT)
            asm volatile("cp.async.wait_group 1;" ::: "memory");
        else
            asm volatile("cp.async.wait_group 0;" ::: "memory");
        __syncthreads();

        if (kt + 2 < KT) {
            int ps = stage + 2; if (ps >= 3) ps -= 3;
            tg_load_stage(sb + ps * STG_BYTES, t,
                          Af, Bf, rowBase, colBase, (kt + 2) * TBK, K);
        }

        uint32_t sbase = sb + stage * STG_BYTES;
#pragma unroll
        for (int ks = 0; ks < 4; ks++) {
            uint32_t ah[4][4];
            const int arow0  = wm * 64 + (lane & 15);
            const int achunk = ks * 2 + (lane >> 4);
#pragma unroll
            for (int mt = 0; mt < 4; mt++) {
                uint32_t off = swz128(arow0 + mt * 16, achunk);
                ldsm_x4(ah[mt][0], ah[mt][1], ah[mt][2], ah[mt][3], sbase + off);
            }
            const int brow = wn * 32 + ((lane >> 4) << 3) + (lane & 7);
            const int bch  = ks * 2 + ((lane >> 3) & 1);
#pragma unroll
            for (int np = 0; np < 2; np++) {
                uint32_t b2[4];
                uint32_t off = swz128(brow + np * 16, bch);
                ldsm_x4(b2[0], b2[1], b2[2], b2[3], sbase + 16384 + off);
#pragma unroll
                for (int mt = 0; mt < 4; mt++) {
                    mma_f16(acc[mt][2 * np],     ah[mt], b2);
                    mma_f16(acc[mt][2 * np + 1], ah[mt], b2 + 2);
                }
            }
        }
        stage++; if (stage == 3) stage = 0;
    }

#pragma unroll
    for (int nt = 0; nt < 4; nt++) {
        int c = colBase + wn * 32 + nt * 8 + (lane & 3) * 2;
        float b0 = __ldg(&bias[c]), b1 = __ldg(&bias[c + 1]);
#pragma unroll
        for (int mt = 0; mt < 4; mt++) {
            int r0 = rowBase + wm * 64 + mt * 16 + (lane >> 2);
            float v0 = acc[mt][nt][0] + b0, v1 = acc[mt][nt][1] + b1;
            float v2 = acc[mt][nt][2] + b0, v3 = acc[mt][nt][3] + b1;
            if (RELU) {
                v0 = fmaxf(v0, 0.f); v1 = fmaxf(v1, 0.f);
                v2 = fmaxf(v2, 0.f); v3 = fmaxf(v3, 0.f);
            }
            if (OUT == 0) {
                *(float2*)(C + (size_t)r0 * N + c)       = make_float2(v0, v1);
                *(float2*)(C + (size_t)(r0 + 8) * N + c) = make_float2(v2, v3);
            } else if (OUT == 1) {
                *(uint32_t*)(F16O + (size_t)r0 * N + c)       = cvt_h2(v0, v1);
                *(uint32_t*)(F16O + (size_t)(r0 + 8) * N + c) = cvt_h2(v2, v3);
            } else {
                int sel = c >> 10, cc = c & 1023;
                __half* dst = F16O + (size_t)sel * SLAB_ELEMS;
                *(uint32_t*)(dst + (size_t)r0 * DMODEL + cc)       = cvt_h2(v0, v1);
                *(uint32_t*)(dst + (size_t)(r0 + 8) * DMODEL + cc) = cvt_h2(v2, v3);
            }
        }
    }
}

// ============================================================================
// T5 relative-position bucket for displacement d
// ============================================================================
__device__ __forceinline__ int rel_bucket_d(int d)
{
    int ret = (d < 0) ? NHEAD : 0;
    int n   = abs(d);
    int b;
    if (n < 8) b = n;
    else {
        int j = (31 - __clz(n * n)) - 6;
        j = min(j, 7);
        b = 8 + j;
    }
    return ret + b;
}

// ============================================================================
// Fused flash attention — 64-key tiles, 2 blocks/SM.
// smem: Q 16K | KV stage x2 (K 8K + V 8K each) | lm 4K | bd 8K = 60K
// ============================================================================
#define AT_Q    0
#define AT_KV   16384          /* stage stride 16384: K at +0, V at +8192 */
#define AT_LM   49152
#define AT_BD   53248
#define AT_SMEM 61440
#define KTILE   64
#define NKT     (LSEQ / KTILE)  /* 16 */

__device__ __forceinline__ void at_load_kv(
    uint32_t kvbase, int t, size_t slab, int kt,
    const __half* __restrict__ KF, const __half* __restrict__ VF)
{
    size_t gb = slab + (size_t)kt * KTILE * DHEAD;
    for (int i = t; i < 512; i += 256) {
        int r = i >> 3, c = i & 7;
        uint32_t off = swz128(r, c);
        size_t g = gb + r * DHEAD + c * 8;
        cp16(kvbase + off,        KF + g);
        cp16(kvbase + 8192 + off, VF + g);
    }
    asm volatile("cp.async.commit_group;" ::: "memory");
}

__global__ void __launch_bounds__(256, 2) attn_fused_kernel(
    const __half* __restrict__ QF,
    const __half* __restrict__ KF, const __half* __restrict__ VF,
    const float* __restrict__ rel, const int* __restrict__ pm,
    __half* __restrict__ OF)
{
    extern __shared__ __align__(16) char smem[];
    uint32_t sb = smem_u32(smem);
    float* lm_s = (float*)(smem + AT_LM);
    float* bd_s = (float*)(smem + AT_BD);

    const int t = threadIdx.x, w = t >> 5, lane = t & 31;
    const int qt = blockIdx.x, bh = blockIdx.y;
    const int h = bh & (NHEAD - 1), b = bh >> 4;
    const size_t slab = (size_t)bh * (LSEQ * DHEAD);

    for (int i = t; i < LSEQ; i += 256)
        lm_s[i] = log2f((float)pm[b * LSEQ + i]);
    for (int i = t; i < 2047; i += 256)
        bd_s[i] = rel[rel_bucket_d(i - 1023) * NHEAD + h] * LOG2E;

    {
        size_t qbase = slab + (size_t)qt * 128 * DHEAD;
        for (int i = t; i < 1024; i += 256) {
            int r = i >> 3, c = i & 7;
            cp16(sb + AT_Q + swz128(r, c), QF + qbase + r * DHEAD + c * 8);
        }
        at_load_kv(sb + AT_KV, t, slab, 0, KF, VF);
        at_load_kv(sb + AT_KV + 16384, t, slab, 1, KF, VF);
        asm volatile("cp.async.wait_group 1;" ::: "memory");
    }
    __syncthreads();

    uint32_t qf[4][4];
    {
        int r = w * 16 + (lane & 15);
#pragma unroll
        for (int ks = 0; ks < 4; ks++) {
            int c = ks * 2 + (lane >> 4);
            ldsm_x4(qf[ks][0], qf[ks][1], qf[ks][2], qf[ks][3],
                    sb + AT_Q + swz128(r, c));
        }
    }

    float O[8][4];
#pragma unroll
    for (int nt = 0; nt < 8; nt++)
#pragma unroll
        for (int e = 0; e < 4; e++) O[nt][e] = 0.f;
    float Lc[4] = {0.f, 0.f, 0.f, 0.f};
    float m0 = -3.0e38f, m1 = -3.0e38f;

    const uint32_t onesb[2] = {ONES_H2, ONES_H2};
    const int r0 = qt * 128 + w * 16 + (lane >> 2);
    const int r1 = r0 + 8;

    for (int kt = 0; kt < NKT; kt++) {
        if (kt > 0) {
            if (kt < NKT - 1)
                asm volatile("cp.async.wait_group 1;" ::: "memory");
            else
                asm volatile("cp.async.wait_group 0;" ::: "memory");
            __syncthreads();
        }
        uint32_t kv = sb + AT_KV + (kt & 1) * 16384;

        float S[8][4];
#pragma unroll
        for (int j = 0; j < 8; j++)
#pragma unroll
            for (int e = 0; e < 4; e++) S[j][e] = 0.f;

        // S = Q K^T over 64 keys
#pragma unroll
        for (int ks = 0; ks < 4; ks++) {
            const int krow = ((lane >> 4) << 3) + (lane & 7);
            const int kch  = ks * 2 + ((lane >> 3) & 1);
#pragma unroll
            for (int jq = 0; jq < 2; jq++) {
                uint32_t kb0[4], kb1[4];
                uint32_t off0 = swz128((2 * jq) * 16 + krow, kch);
                uint32_t off1 = swz128((2 * jq + 1) * 16 + krow, kch);
                ldsm_x4(kb0[0], kb0[1], kb0[2], kb0[3], kv + off0);
                ldsm_x4(kb1[0], kb1[1], kb1[2], kb1[3], kv + off1);
                mma_f16(S[4 * jq + 0], qf[ks], kb0);
                mma_f16(S[4 * jq + 1], qf[ks], kb0 + 2);
                mma_f16(S[4 * jq + 2], qf[ks], kb1);
                mma_f16(S[4 * jq + 3], qf[ks], kb1 + 2);
            }
        }

        // fused bias (log2 domain) + tile max
        const int ktbase = kt * KTILE;
        float tm0 = -3.0e38f, tm1 = -3.0e38f;
#pragma unroll
        for (int j = 0; j < 8; j++) {
            int c = ktbase + j * 8 + (lane & 3) * 2;
            float t00 = bd_s[c - r0 + 1023] + lm_s[c];
            float t01 = bd_s[c + 1 - r0 + 1023] + lm_s[c + 1];
            float t10 = bd_s[c - r1 + 1023] + lm_s[c];
            float t11 = bd_s[c + 1 - r1 + 1023] + lm_s[c + 1];
            S[j][0] = fmaf(S[j][0], LOG2E, t00);
            S[j][1] = fmaf(S[j][1], LOG2E, t01);
            S[j][2] = fmaf(S[j][2], LOG2E, t10);
            S[j][3] = fmaf(S[j][3], LOG2E, t11);
            tm0 = fmaxf(tm0, fmaxf(S[j][0], S[j][1]));
            tm1 = fmaxf(tm1, fmaxf(S[j][2], S[j][3]));
        }
        tm0 = fmaxf(tm0, __shfl_xor_sync(0xffffffffu, tm0, 1));
        tm0 = fmaxf(tm0, __shfl_xor_sync(0xffffffffu, tm0, 2));
        tm1 = fmaxf(tm1, __shfl_xor_sync(0xffffffffu, tm1, 1));
        tm1 = fmaxf(tm1, __shfl_xor_sync(0xffffffffu, tm1, 2));
        float mn0 = fmaxf(m0, tm0), mn1 = fmaxf(m1, tm1);
        float a0 = exp2f(m0 - mn0), a1 = exp2f(m1 - mn1);
        m0 = mn0; m1 = mn1;

#pragma unroll
        for (int nt = 0; nt < 8; nt++) {
            O[nt][0] *= a0; O[nt][1] *= a0;
            O[nt][2] *= a1; O[nt][3] *= a1;
        }
        Lc[0] *= a0; Lc[1] *= a0; Lc[2] *= a1; Lc[3] *= a1;

        // P = exp2(S - m) in f16x2; O += P@V; L += P@1
#pragma unroll
        for (int kk = 0; kk < 4; kk++) {
            float* p0 = S[2 * kk];
            float* p1 = S[2 * kk + 1];
            uint32_t ph[4];
            ph[0] = ex2_h2(cvt_h2(p0[0] - mn0, p0[1] - mn0));
            ph[1] = ex2_h2(cvt_h2(p0[2] - mn1, p0[3] - mn1));
            ph[2] = ex2_h2(cvt_h2(p1[0] - mn0, p1[1] - mn0));
            ph[3] = ex2_h2(cvt_h2(p1[2] - mn1, p1[3] - mn1));
            const int vrow = kk * 16 + (lane & 15);
            const int vcp  = (lane >> 4) & 1;
#pragma unroll
            for (int np = 0; np < 4; np++) {
                uint32_t vb[4];
                uint32_t off = swz128(vrow, np * 2 + vcp);
                ldsm_x4t(vb[0], vb[1], vb[2], vb[3], kv + 8192 + off);
                mma_f16(O[2 * np],     ph, vb);
                mma_f16(O[2 * np + 1], ph, vb + 2);
            }
            mma_f16(Lc, ph, onesb);
        }

        __syncthreads();
        if (kt + 2 < NKT)
            at_load_kv(sb + AT_KV + (kt & 1) * 16384, t, slab, kt + 2, KF, VF);
    }

    float inv0 = 1.f / Lc[0], inv1 = 1.f / Lc[2];
    size_t ob0 = slab + (size_t)(qt * 128 + w * 16 + (lane >> 2)) * DHEAD;
    size_t ob1 = ob0 + 8 * DHEAD;
#pragma unroll
    for (int nt = 0; nt < 8; nt++) {
        int c = nt * 8 + (lane & 3) * 2;
        *(uint32_t*)(OF + ob0 + c) = cvt_h2(O[nt][0] * inv0, O[nt][1] * inv0);
        *(uint32_t*)(OF + ob1 + c) = cvt_h2(O[nt][2] * inv1, O[nt][3] * inv1);
    }
}

// ============================================================================
// out = LayerNorm(A + B); optional fp16 side output
// ============================================================================
template <bool SPLIT>
__global__ void __launch_bounds__(256) add_ln_kernel(
    const float* __restrict__ A, const float* __restrict__ B,
    float* __restrict__ out, __half* __restrict__ OF)
{
    __shared__ float sh[8];
    const size_t row = blockIdx.x;
    const int t = threadIdx.x;

    float4 a = ((const float4*)(A + row * DMODEL))[t];
    float4 b = ((const float4*)(B + row * DMODEL))[t];
    float4 x;
    x.x = a.x + b.x; x.y = a.y + b.y; x.z = a.z + b.z; x.w = a.w + b.w;

    float s = x.x + x.y + x.z + x.w;
#pragma unroll
    for (int o = 16; o; o >>= 1) s += __shfl_xor_sync(0xffffffffu, s, o);
    if ((t & 31) == 0) sh[t >> 5] = s;
    __syncthreads();
    float tot = sh[0];
#pragma unroll
    for (int i = 1; i < 8; i++) tot += sh[i];
    __syncthreads();
    float mean = tot * (1.f / DMODEL);

    float dx = x.x - mean, dy = x.y - mean, dz = x.z - mean, dw = x.w - mean;
    float s2 = dx * dx + dy * dy + dz * dz + dw * dw;
#pragma unroll
    for (int o = 16; o; o >>= 1) s2 += __shfl_xor_sync(0xffffffffu, s2, o);
    if ((t & 31) == 0) sh[t >> 5] = s2;
    __syncthreads();
    float tot2 = sh[0];
#pragma unroll
    for (int i = 1; i < 8; i++) tot2 += sh[i];
    float inv = rsqrtf(tot2 * (1.f / DMODEL));

    float4 o;
    o.x = dx * inv; o.y = dy * inv; o.z = dz * inv; o.w = dw * inv;
    ((float4*)(out + row * DMODEL))[t] = o;

    if (SPLIT) {
        size_t base = row * DMODEL + t * 4;
        *(uint32_t*)(OF + base)     = cvt_h2(o.x, o.y);
        *(uint32_t*)(OF + base + 2) = cvt_h2(o.z, o.w);
    }
}

// ============================================================================
// Launch sequence
// ============================================================================
extern "C" void kernel_launch(void* const* d_in, const int* in_sizes, int n_in,
                              void* d_out, int out_size)
{
    const float* x   = (const float*)d_in[0];
    const int*   pm  = (const int*)  d_in[1];
    const float* Wq  = (const float*)d_in[2];
    const float* bq  = (const float*)d_in[3];
    const float* Wk  = (const float*)d_in[4];
    const float* bk  = (const float*)d_in[5];
    const float* Wv  = (const float*)d_in[6];
    const float* bv  = (const float*)d_in[7];
    const float* Wo  = (const float*)d_in[8];
    const float* bo  = (const float*)d_in[9];
    const float* rel = (const float*)d_in[10];
    const float* W1  = (const float*)d_in[11];
    const float* b1  = (const float*)d_in[12];
    const float* W2  = (const float*)d_in[13];
    const float* b2  = (const float*)d_in[14];
    float* out = (float*)d_out;

    float *attp, *attout, *ff, *bqkv;
    cudaGetSymbolAddress((void**)&attp,   g_attp);
    cudaGetSymbolAddress((void**)&attout, g_attout);
    cudaGetSymbolAddress((void**)&ff,     g_ff);
    cudaGetSymbolAddress((void**)&bqkv,   g_bqkv);

    __half *xf, *wqkv, *wo, *w1, *w2, *qkv, *avf, *aof, *h1f;
    cudaGetSymbolAddress((void**)&xf,   g_xf);
    cudaGetSymbolAddress((void**)&wqkv, g_wqkv);
    cudaGetSymbolAddress((void**)&wo,   g_wo);
    cudaGetSymbolAddress((void**)&w1,   g_w1);
    cudaGetSymbolAddress((void**)&w2,   g_w2);
    cudaGetSymbolAddress((void**)&qkv,  g_qkv);
    cudaGetSymbolAddress((void**)&avf,  g_avf);
    cudaGetSymbolAddress((void**)&aof,  g_aof);
    cudaGetSymbolAddress((void**)&h1f,  g_h1f);

    static bool attr_done = false;
    if (!attr_done) {
        cudaFuncSetAttribute(tgemm_kernel<false, 0>,
                             cudaFuncAttributeMaxDynamicSharedMemorySize, TG_SMEM);
        cudaFuncSetAttribute(tgemm_kernel<false, 2>,
                             cudaFuncAttributeMaxDynamicSharedMemorySize, TG_SMEM);
        cudaFuncSetAttribute(tgemm_kernel<true, 1>,
                             cudaFuncAttributeMaxDynamicSharedMemorySize, TG_SMEM);
        cudaFuncSetAttribute(attn_fused_kernel,
                             cudaFuncAttributeMaxDynamicSharedMemorySize, AT_SMEM);
        attr_done = true;
    }

    dim3 blk(256);

    cvt16_kernel<<<(MROWS * DMODEL / 4 + 255) / 256, blk>>>(
        x, xf, MROWS * DMODEL / 4);
    cvtw_all_kernel<<<(SEG_TOTAL + 255) / 256, blk>>>(
        Wq, Wk, Wv, Wo, W1, W2, bq, bk, bv, wqkv, wo, w1, w2, bqkv);

    dim3 gqkv(3 * DMODEL / TBN, MROWS / TBM);
    tgemm_kernel<false, 2><<<gqkv, blk, TG_SMEM>>>(
        xf, wqkv, bqkv, nullptr, qkv, MROWS, 3 * DMODEL, DMODEL);

    attn_fused_kernel<<<dim3(8, BHDIM), blk, AT_SMEM>>>(
        qkv, qkv + SLAB_ELEMS, qkv + 2 * SLAB_ELEMS, rel, pm, avf);

    dim3 gO(DMODEL / TBN, MROWS / TBM);
    tgemm_kernel<false, 0><<<gO, blk, TG_SMEM>>>(
        avf, wo, bo, attp, nullptr, MROWS, DMODEL, DMODEL);

    add_ln_kernel<true><<<MROWS, blk>>>(attp, x, attout, aof);

    dim3 g1(FFDIM / TBN, MROWS / TBM);
    tgemm_kernel<true, 1><<<g1, blk, TG_SMEM>>>(
        aof, w1, b1, nullptr, h1f, MROWS, FFDIM, DMODEL);
    dim3 g2(DMODEL / TBN, MROWS / TBM);
    tgemm_kernel<false, 0><<<g2, blk, TG_SMEM>>>(
        h1f, w2, b2, ff, nullptr, MROWS, DMODEL, FFDIM);

    add_ln_kernel<false><<<MROWS, blk>>>(ff, attout, out, nullptr);
}